// round 8
// baseline (speedup 1.0000x reference)
#include <cuda_runtime.h>
#include <cuda_bf16.h>
#include <stdint.h>
#include <math.h>

#define BB 4
#define NN 8192
#define DD 512
#define HH 8
#define DH 64
#define MM 256
#define BH 32
#define KS 16

__device__ __align__(16) float g_xn  [(size_t)BB*NN*DD];
__device__ __align__(16) float g_q   [(size_t)BH*NN*DH];
__device__ __align__(16) float g_k   [(size_t)BH*NN*DH];
__device__ __align__(16) float g_v   [(size_t)BH*NN*DH];
__device__ __align__(16) float g_ql  [(size_t)BH*MM*DH];
__device__ __align__(16) float g_kl  [(size_t)BH*MM*DH];
__device__ __align__(16) float g_attn2[(size_t)BH*MM*MM];
__device__ __align__(16) float g_z   [(size_t)BH*MM*MM];
__device__ __align__(16) float g_z2  [(size_t)BH*MM*MM];
__device__ __align__(16) float g_xz  [(size_t)BH*MM*MM];
__device__ __align__(16) float g_t   [(size_t)BH*MM*MM];
__device__ __align__(16) float g_u   [(size_t)BH*MM*MM];
__device__ __align__(16) __nv_bfloat16 g_h3[(size_t)BH*MM*NN];
__device__ __align__(16) __nv_bfloat16 g_h1[(size_t)BH*NN*MM];
__device__ __align__(16) float g_p3  [(size_t)BH*KS*MM*DH];
__device__ __align__(16) float g_out3[(size_t)BH*MM*DH];
__device__ __align__(16) float g_wc  [(size_t)BH*MM*DH];
__device__ __align__(16) float g_y   [(size_t)BB*NN*DD];
__device__ int g_maxA;
__device__ int g_maxB;

__device__ __forceinline__ uint32_t f2tf(float f) {
    uint32_t u;
    asm("cvt.rna.tf32.f32 %0, %1;" : "=r"(u) : "f"(f));
    return u;
}
__device__ __forceinline__ uint32_t f2bf2(float lo, float hi) {
    uint32_t r;
    asm("cvt.rn.bf16x2.f32 %0, %1, %2;" : "=r"(r) : "f"(hi), "f"(lo));
    return r;
}
__device__ __forceinline__ void mma8(float* d, const uint32_t* a, const uint32_t* b) {
    asm volatile(
        "mma.sync.aligned.m16n8k8.row.col.f32.tf32.tf32.f32 "
        "{%0,%1,%2,%3}, {%4,%5,%6,%7}, {%8,%9}, {%0,%1,%2,%3};"
        : "+f"(d[0]), "+f"(d[1]), "+f"(d[2]), "+f"(d[3])
        : "r"(a[0]), "r"(a[1]), "r"(a[2]), "r"(a[3]), "r"(b[0]), "r"(b[1]));
}
__device__ __forceinline__ void mma16(float* d, const uint32_t* a, const uint32_t* b) {
    asm volatile(
        "mma.sync.aligned.m16n8k16.row.col.f32.bf16.bf16.f32 "
        "{%0,%1,%2,%3}, {%4,%5,%6,%7}, {%8,%9}, {%0,%1,%2,%3};"
        : "+f"(d[0]), "+f"(d[1]), "+f"(d[2]), "+f"(d[3])
        : "r"(a[0]), "r"(a[1]), "r"(a[2]), "r"(a[3]), "r"(b[0]), "r"(b[1]));
}

// ---------------------------------------------------------------------------
// TF32 GEMM (pinv + Wc), double-buffered, BK=16. EPI: 2=store 4=alpha/beta
// ---------------------------------------------------------------------------
template<int EPI, int BM, int BN, int BK>
__global__ __launch_bounds__(256) void tc_gemm(
    const float* __restrict__ A, const float* __restrict__ Bg,
    float* __restrict__ C, const float* __restrict__ X1,
    int N, int K, int lda, int ldb,
    long long bsA, long long bsB, long long bsC,
    float alpha, float beta)
{
    constexpr int PA = BM + 8, PB = BN + 8;
    constexpr int MT = (BM / 2) / 16;
    constexpr int NT = (BN / 4) / 8;
    constexpr int RA = (BM * BK) / 1024;
    constexpr int RB = (BK * BN) / 1024;
    __shared__ uint32_t As[2][BK][PA];
    __shared__ uint32_t Bs[2][BK][PB];
    float4 ra[RA], rb[RB];

    int tid = threadIdx.x, lane = tid & 31, warp = tid >> 5;
    int wm0 = (warp >> 2) * (BM / 2);
    int wn0 = (warp & 3) * (BN / 4);
    int z = blockIdx.z;
    int m0 = blockIdx.y * BM, n0 = blockIdx.x * BN;
    const float* Ab = A  + (size_t)z * bsA;
    const float* Bb = Bg + (size_t)z * bsB;

    float acc[MT][NT][4];
    #pragma unroll
    for (int i = 0; i < MT; i++)
        #pragma unroll
        for (int j = 0; j < NT; j++)
            #pragma unroll
            for (int r = 0; r < 4; r++) acc[i][j][r] = 0.f;

    auto LOAD = [&](int kb) {
        #pragma unroll
        for (int c = 0; c < RA; c++) {
            int id = c * 256 + tid;
            int m = id / (BK / 4), kq = id % (BK / 4);
            ra[c] = *(const float4*)(Ab + (size_t)(m0 + m) * lda + kb * BK + kq * 4);
        }
        #pragma unroll
        for (int c = 0; c < RB; c++) {
            int id = c * 256 + tid;
            int k = id / (BN / 4), nq = id % (BN / 4);
            rb[c] = *(const float4*)(Bb + (size_t)(kb * BK + k) * ldb + n0 + nq * 4);
        }
    };
    auto COMMIT = [&](int bf) {
        #pragma unroll
        for (int c = 0; c < RA; c++) {
            int id = c * 256 + tid;
            int m = id / (BK / 4), kq = id % (BK / 4);
            As[bf][kq*4+0][m] = f2tf(ra[c].x); As[bf][kq*4+1][m] = f2tf(ra[c].y);
            As[bf][kq*4+2][m] = f2tf(ra[c].z); As[bf][kq*4+3][m] = f2tf(ra[c].w);
        }
        #pragma unroll
        for (int c = 0; c < RB; c++) {
            int id = c * 256 + tid;
            int k = id / (BN / 4), nq = id % (BN / 4);
            Bs[bf][k][nq*4+0] = f2tf(rb[c].x); Bs[bf][k][nq*4+1] = f2tf(rb[c].y);
            Bs[bf][k][nq*4+2] = f2tf(rb[c].z); Bs[bf][k][nq*4+3] = f2tf(rb[c].w);
        }
    };
    auto MMA = [&](int bf) {
        #pragma unroll
        for (int ks = 0; ks < BK / 8; ks++) {
            uint32_t af[MT][4], bfr[NT][2];
            int kr = ks * 8 + (lane & 3);
            int mr = wm0 + (lane >> 2);
            #pragma unroll
            for (int mt = 0; mt < MT; mt++) {
                af[mt][0] = As[bf][kr    ][mr + mt*16];
                af[mt][1] = As[bf][kr    ][mr + mt*16 + 8];
                af[mt][2] = As[bf][kr + 4][mr + mt*16];
                af[mt][3] = As[bf][kr + 4][mr + mt*16 + 8];
            }
            int nr = wn0 + (lane >> 2);
            #pragma unroll
            for (int nt = 0; nt < NT; nt++) {
                bfr[nt][0] = Bs[bf][kr    ][nr + nt*8];
                bfr[nt][1] = Bs[bf][kr + 4][nr + nt*8];
            }
            #pragma unroll
            for (int mt = 0; mt < MT; mt++)
                #pragma unroll
                for (int nt = 0; nt < NT; nt++)
                    mma8(acc[mt][nt], af[mt], bfr[nt]);
        }
    };

    int nk = K / BK;
    LOAD(0); COMMIT(0);
    __syncthreads();
    for (int kb = 1; kb < nk; kb++) {
        LOAD(kb);
        MMA((kb - 1) & 1);
        COMMIT(kb & 1);
        __syncthreads();
    }
    MMA((nk - 1) & 1);

    #pragma unroll
    for (int mt = 0; mt < MT; mt++) {
        #pragma unroll
        for (int nt = 0; nt < NT; nt++) {
            int row = m0 + wm0 + mt * 16 + (lane >> 2);
            int col = n0 + wn0 + nt * 8 + (lane & 3) * 2;
            float2 lo = make_float2(acc[mt][nt][0], acc[mt][nt][1]);
            float2 hi = make_float2(acc[mt][nt][2], acc[mt][nt][3]);
            if constexpr (EPI == 2) {
                size_t base = (size_t)z * bsC;
                *(float2*)(C + base + (size_t)row       * N + col) = lo;
                *(float2*)(C + base + (size_t)(row + 8) * N + col) = hi;
            } else if constexpr (EPI == 4) {
                size_t base = (size_t)z * (MM * MM);
                size_t r1 = base + (size_t)row * MM + col;
                size_t r2 = base + (size_t)(row + 8) * MM + col;
                float2 rv1 = make_float2(0.f, 0.f), rv2 = make_float2(0.f, 0.f);
                if (beta != 0.f) {
                    rv1 = *(const float2*)(X1 + r1);
                    rv2 = *(const float2*)(X1 + r2);
                }
                *(float2*)(C + r1) = make_float2(alpha*lo.x + beta*rv1.x, alpha*lo.y + beta*rv1.y);
                *(float2*)(C + r2) = make_float2(alpha*hi.x + beta*rv2.x, alpha*hi.y + beta*rv2.y);
            }
        }
    }
}

// ---------------------------------------------------------------------------
// BF16 GEMM (m16n8k16), double-buffered. EPI: 0=QKV 1=out+bias+x 3=p3
// 5=y+= 6=bf16 store.  TRB: B is [N,K]; BFA: A already bf16
// ---------------------------------------------------------------------------
template<int EPI, int BM, int BN, int BK, bool TRB, bool BFA>
__global__ __launch_bounds__(256) void bf_gemm(
    const void* __restrict__ Av, const float* __restrict__ Bg,
    void* __restrict__ Cv, const float* __restrict__ X1, const float* __restrict__ X2,
    int N, int K, int lda, int ldb,
    long long bsA, long long bsB, long long bsC)
{
    constexpr int PA = BM + 8, PB = BN + 8;
    constexpr int MT = (BM / 2) / 16;
    constexpr int NT = (BN / 4) / 8;
    constexpr int KP = BK / 2;
    constexpr bool AH = (BFA || EPI == 3);
    constexpr int RAH = (BM * BK) / 2048;
    constexpr int RAF = (BM * BK) / 1024;
    constexpr int RBN = (KP * (BN / 4)) / 256;
    constexpr int RBT = (BN * BK) / 1024;
    __shared__ uint32_t As[2][KP][PA];
    __shared__ uint32_t Bs[2][KP][PB];
    uint4  rah[AH ? RAH : 1];
    float4 raf[AH ? 1 : RAF];
    float4 rb0[TRB ? 1 : RBN], rb1[TRB ? 1 : RBN];
    float4 rbt[TRB ? RBT : 1];

    int tid = threadIdx.x, lane = tid & 31, warp = tid >> 5;
    int wm0 = (warp >> 2) * (BM / 2);
    int wn0 = (warp & 3) * (BN / 4);
    int z = blockIdx.z;
    int m0 = blockIdx.y * BM, n0 = blockIdx.x * BN;

    const float* Bb;
    const float* Abf = nullptr;
    const __nv_bfloat16* Abh = nullptr;
    if constexpr (EPI == 3) {
        int bh = z >> 4, ks = z & 15;
        Abh = (const __nv_bfloat16*)Av + (size_t)bh * MM * NN + (size_t)ks * 512;
        Bb  = Bg + (size_t)bh * NN * DH + (size_t)ks * 512 * DH;
    } else {
        if constexpr (BFA) Abh = (const __nv_bfloat16*)Av + (size_t)z * bsA;
        else               Abf = (const float*)Av + (size_t)z * bsA;
        Bb = Bg + (size_t)z * bsB;
    }

    float acc[MT][NT][4];
    #pragma unroll
    for (int i = 0; i < MT; i++)
        #pragma unroll
        for (int j = 0; j < NT; j++)
            #pragma unroll
            for (int r = 0; r < 4; r++) acc[i][j][r] = 0.f;

    auto LOAD = [&](int kb) {
        if constexpr (AH) {
            #pragma unroll
            for (int c = 0; c < RAH; c++) {
                int id = c * 256 + tid;
                int m = id / (BK / 8), kq = id % (BK / 8);
                rah[c] = *(const uint4*)(Abh + (size_t)(m0 + m) * lda + kb * BK + kq * 8);
            }
        } else {
            #pragma unroll
            for (int c = 0; c < RAF; c++) {
                int id = c * 256 + tid;
                int m = id / (BK / 4), kq = id % (BK / 4);
                raf[c] = *(const float4*)(Abf + (size_t)(m0 + m) * lda + kb * BK + kq * 4);
            }
        }
        if constexpr (!TRB) {
            #pragma unroll
            for (int c = 0; c < RBN; c++) {
                int id = c * 256 + tid;
                int kp = id / (BN / 4), nq = id % (BN / 4);
                rb0[c] = *(const float4*)(Bb + (size_t)(kb*BK + 2*kp    ) * ldb + n0 + nq * 4);
                rb1[c] = *(const float4*)(Bb + (size_t)(kb*BK + 2*kp + 1) * ldb + n0 + nq * 4);
            }
        } else {
            #pragma unroll
            for (int c = 0; c < RBT; c++) {
                int id = c * 256 + tid;
                int n = id / (BK / 4), kq = id % (BK / 4);
                rbt[c] = *(const float4*)(Bb + (size_t)(n0 + n) * ldb + kb * BK + kq * 4);
            }
        }
    };
    auto COMMIT = [&](int bf) {
        if constexpr (AH) {
            #pragma unroll
            for (int c = 0; c < RAH; c++) {
                int id = c * 256 + tid;
                int m = id / (BK / 8), kq = id % (BK / 8);
                As[bf][kq*4+0][m] = rah[c].x; As[bf][kq*4+1][m] = rah[c].y;
                As[bf][kq*4+2][m] = rah[c].z; As[bf][kq*4+3][m] = rah[c].w;
            }
        } else {
            #pragma unroll
            for (int c = 0; c < RAF; c++) {
                int id = c * 256 + tid;
                int m = id / (BK / 4), kq = id % (BK / 4);
                As[bf][kq*2+0][m] = f2bf2(raf[c].x, raf[c].y);
                As[bf][kq*2+1][m] = f2bf2(raf[c].z, raf[c].w);
            }
        }
        if constexpr (!TRB) {
            #pragma unroll
            for (int c = 0; c < RBN; c++) {
                int id = c * 256 + tid;
                int kp = id / (BN / 4), nq = id % (BN / 4);
                Bs[bf][kp][nq*4+0] = f2bf2(rb0[c].x, rb1[c].x);
                Bs[bf][kp][nq*4+1] = f2bf2(rb0[c].y, rb1[c].y);
                Bs[bf][kp][nq*4+2] = f2bf2(rb0[c].z, rb1[c].z);
                Bs[bf][kp][nq*4+3] = f2bf2(rb0[c].w, rb1[c].w);
            }
        } else {
            #pragma unroll
            for (int c = 0; c < RBT; c++) {
                int id = c * 256 + tid;
                int n = id / (BK / 4), kq = id % (BK / 4);
                Bs[bf][kq*2+0][n] = f2bf2(rbt[c].x, rbt[c].y);
                Bs[bf][kq*2+1][n] = f2bf2(rbt[c].z, rbt[c].w);
            }
        }
    };
    auto MMA = [&](int bf) {
        #pragma unroll
        for (int ks = 0; ks < BK / 16; ks++) {
            uint32_t af[MT][4], bfr[NT][2];
            int kr = ks * 8 + (lane & 3);
            int mr = wm0 + (lane >> 2);
            #pragma unroll
            for (int mt = 0; mt < MT; mt++) {
                af[mt][0] = As[bf][kr    ][mr + mt*16];
                af[mt][1] = As[bf][kr    ][mr + mt*16 + 8];
                af[mt][2] = As[bf][kr + 4][mr + mt*16];
                af[mt][3] = As[bf][kr + 4][mr + mt*16 + 8];
            }
            int nr = wn0 + (lane >> 2);
            #pragma unroll
            for (int nt = 0; nt < NT; nt++) {
                bfr[nt][0] = Bs[bf][kr    ][nr + nt*8];
                bfr[nt][1] = Bs[bf][kr + 4][nr + nt*8];
            }
            #pragma unroll
            for (int mt = 0; mt < MT; mt++)
                #pragma unroll
                for (int nt = 0; nt < NT; nt++)
                    mma16(acc[mt][nt], af[mt], bfr[nt]);
        }
    };

    int nk = K / BK;
    LOAD(0); COMMIT(0);
    __syncthreads();
    for (int kb = 1; kb < nk; kb++) {
        LOAD(kb);
        MMA((kb - 1) & 1);
        COMMIT(kb & 1);
        __syncthreads();
    }
    MMA((nk - 1) & 1);

    #pragma unroll
    for (int mt = 0; mt < MT; mt++) {
        #pragma unroll
        for (int nt = 0; nt < NT; nt++) {
            int row = m0 + wm0 + mt * 16 + (lane >> 2);
            int col = n0 + wn0 + nt * 8 + (lane & 3) * 2;
            float2 lo = make_float2(acc[mt][nt][0], acc[mt][nt][1]);
            float2 hi = make_float2(acc[mt][nt][2], acc[mt][nt][3]);
            if constexpr (EPI == 0) {
                int which = col >> 9, inner = col & 511;
                int h = inner >> 6, d = inner & 63;
                float* dst = which == 0 ? g_q : (which == 1 ? g_k : g_v);
                float s = (which == 0) ? 0.125f : 1.f;
                int bq = row >> 13, n = row & (NN - 1);
                *(float2*)(dst + (((size_t)(bq*HH+h))*NN + n    )*DH + d) = make_float2(lo.x*s, lo.y*s);
                *(float2*)(dst + (((size_t)(bq*HH+h))*NN + n + 8)*DH + d) = make_float2(hi.x*s, hi.y*s);
            } else if constexpr (EPI == 1) {
                float* C = (float*)Cv;
                float2 bv = *(const float2*)(X1 + col);
                size_t r1 = (size_t)row * DD + col, r2 = (size_t)(row + 8) * DD + col;
                float2 x1 = *(const float2*)(X2 + r1);
                float2 x2 = *(const float2*)(X2 + r2);
                *(float2*)(C + r1) = make_float2(lo.x + bv.x + x1.x, lo.y + bv.y + x1.y);
                *(float2*)(C + r2) = make_float2(hi.x + bv.x + x2.x, hi.y + bv.y + x2.y);
            } else if constexpr (EPI == 3) {
                float* C = (float*)Cv;
                size_t base = (size_t)z * (MM * DH);
                *(float2*)(C + base + (row    ) * DH + col) = lo;
                *(float2*)(C + base + (row + 8) * DH + col) = hi;
            } else if constexpr (EPI == 5) {
                float* C = (float*)Cv;
                int b = z >> 3, h = z & 7;
                size_t r1 = ((size_t)b * NN + row    ) * DD + h * 64 + col;
                size_t r2 = ((size_t)b * NN + row + 8) * DD + h * 64 + col;
                float2 y1 = *(float2*)(C + r1);
                float2 y2 = *(float2*)(C + r2);
                *(float2*)(C + r1) = make_float2(y1.x + lo.x, y1.y + lo.y);
                *(float2*)(C + r2) = make_float2(y2.x + hi.x, y2.y + hi.y);
            } else if constexpr (EPI == 6) {
                __nv_bfloat16* C = (__nv_bfloat16*)Cv;
                size_t base = (size_t)z * bsC;
                *(uint32_t*)(C + base + (size_t)row       * N + col) = f2bf2(lo.x, lo.y);
                *(uint32_t*)(C + base + (size_t)(row + 8) * N + col) = f2bf2(hi.x, hi.y);
            }
        }
    }
}

// ---------------------------------------------------------------------------
// Fused sim1 + softmax (unchanged from R6)
// ---------------------------------------------------------------------------
__global__ __launch_bounds__(256) void sim1_fused() {
    __shared__ uint32_t As[16][72];
    __shared__ uint32_t Bs[16][264];
    __shared__ float rmax[64][5];
    __shared__ float rsum[64][5];

    int tid = threadIdx.x, lane = tid & 31, warp = tid >> 5;
    int wm0 = (warp >> 2) * 32;
    int wn0 = (warp & 3) * 64;
    int bh = blockIdx.z;
    int m0 = blockIdx.y * 64;
    const float* Ab = g_q  + ((size_t)bh * NN + m0) * DH;
    const float* Bb = g_kl + (size_t)bh * MM * DH;

    float acc[2][8][4];
    #pragma unroll
    for (int i = 0; i < 2; i++)
        #pragma unroll
        for (int j = 0; j < 8; j++)
            #pragma unroll
            for (int r = 0; r < 4; r++) acc[i][j][r] = 0.f;

    for (int k0 = 0; k0 < 64; k0 += 32) {
        #pragma unroll
        for (int c = 0; c < 2; c++) {
            int id = c * 256 + tid;
            int m = id >> 3, kq = id & 7;
            float4 v = *(const float4*)(Ab + (size_t)m * DH + k0 + kq * 4);
            As[kq*2+0][m] = f2bf2(v.x, v.y);
            As[kq*2+1][m] = f2bf2(v.z, v.w);
        }
        #pragma unroll
        for (int c = 0; c < 8; c++) {
            int id = c * 256 + tid;
            int n = id >> 3, kq = id & 7;
            float4 v = *(const float4*)(Bb + (size_t)n * DH + k0 + kq * 4);
            Bs[kq*2+0][n] = f2bf2(v.x, v.y);
            Bs[kq*2+1][n] = f2bf2(v.z, v.w);
        }
        __syncthreads();
        #pragma unroll
        for (int ks = 0; ks < 2; ks++) {
            uint32_t af[2][4], bfr[8][2];
            int kr = ks * 8 + (lane & 3);
            int mr = wm0 + (lane >> 2);
            #pragma unroll
            for (int mt = 0; mt < 2; mt++) {
                af[mt][0] = As[kr    ][mr + mt*16];
                af[mt][1] = As[kr    ][mr + mt*16 + 8];
                af[mt][2] = As[kr + 4][mr + mt*16];
                af[mt][3] = As[kr + 4][mr + mt*16 + 8];
            }
            int nr = wn0 + (lane >> 2);
            #pragma unroll
            for (int nt = 0; nt < 8; nt++) {
                bfr[nt][0] = Bs[kr    ][nr + nt*8];
                bfr[nt][1] = Bs[kr + 4][nr + nt*8];
            }
            #pragma unroll
            for (int mt = 0; mt < 2; mt++)
                #pragma unroll
                for (int nt = 0; nt < 8; nt++)
                    mma16(acc[mt][nt], af[mt], bfr[nt]);
        }
        __syncthreads();
    }

    int g = lane >> 2, q4 = lane & 3;
    int wn = warp & 3;
    #pragma unroll
    for (int mt = 0; mt < 2; mt++) {
        int r0 = wm0 + mt * 16 + g;
        float m0v = -1e30f, m1v = -1e30f;
        #pragma unroll
        for (int nt = 0; nt < 8; nt++) {
            m0v = fmaxf(m0v, fmaxf(acc[mt][nt][0], acc[mt][nt][1]));
            m1v = fmaxf(m1v, fmaxf(acc[mt][nt][2], acc[mt][nt][3]));
        }
        #pragma unroll
        for (int o = 1; o < 4; o <<= 1) {
            m0v = fmaxf(m0v, __shfl_xor_sync(~0u, m0v, o));
            m1v = fmaxf(m1v, __shfl_xor_sync(~0u, m1v, o));
        }
        if (q4 == 0) { rmax[r0][wn] = m0v; rmax[r0 + 8][wn] = m1v; }
    }
    __syncthreads();
    #pragma unroll
    for (int mt = 0; mt < 2; mt++) {
        int r0 = wm0 + mt * 16 + g;
        float M0 = fmaxf(fmaxf(rmax[r0][0], rmax[r0][1]), fmaxf(rmax[r0][2], rmax[r0][3]));
        float M1 = fmaxf(fmaxf(rmax[r0+8][0], rmax[r0+8][1]), fmaxf(rmax[r0+8][2], rmax[r0+8][3]));
        float s0 = 0.f, s1 = 0.f;
        #pragma unroll
        for (int nt = 0; nt < 8; nt++) {
            acc[mt][nt][0] = __expf(acc[mt][nt][0] - M0);
            acc[mt][nt][1] = __expf(acc[mt][nt][1] - M0);
            acc[mt][nt][2] = __expf(acc[mt][nt][2] - M1);
            acc[mt][nt][3] = __expf(acc[mt][nt][3] - M1);
            s0 += acc[mt][nt][0] + acc[mt][nt][1];
            s1 += acc[mt][nt][2] + acc[mt][nt][3];
        }
        #pragma unroll
        for (int o = 1; o < 4; o <<= 1) {
            s0 += __shfl_xor_sync(~0u, s0, o);
            s1 += __shfl_xor_sync(~0u, s1, o);
        }
        if (q4 == 0) { rsum[r0][wn] = s0; rsum[r0 + 8][wn] = s1; }
    }
    __syncthreads();
    __nv_bfloat16* O = g_h1 + ((size_t)bh * NN + m0) * MM;
    #pragma unroll
    for (int mt = 0; mt < 2; mt++) {
        int r0 = wm0 + mt * 16 + g;
        float i0 = 1.f / (rsum[r0][0] + rsum[r0][1] + rsum[r0][2] + rsum[r0][3]);
        float i1 = 1.f / (rsum[r0+8][0] + rsum[r0+8][1] + rsum[r0+8][2] + rsum[r0+8][3]);
        #pragma unroll
        for (int nt = 0; nt < 8; nt++) {
            int col = wn0 + nt * 8 + q4 * 2;
            *(uint32_t*)(O + (size_t)r0 * MM + col) =
                f2bf2(acc[mt][nt][0] * i0, acc[mt][nt][1] * i0);
            *(uint32_t*)(O + (size_t)(r0 + 8) * MM + col) =
                f2bf2(acc[mt][nt][2] * i1, acc[mt][nt][3] * i1);
        }
    }
}

__global__ __launch_bounds__(128) void ln_kernel(const float* __restrict__ x,
                                                 const float* __restrict__ w,
                                                 const float* __restrict__ bia) {
    int row = blockIdx.x, tid = threadIdx.x;
    const float4* xr = reinterpret_cast<const float4*>(x + (size_t)row * DD);
    float4 v = xr[tid];
    float s  = v.x + v.y + v.z + v.w;
    float sq = v.x*v.x + v.y*v.y + v.z*v.z + v.w*v.w;
    __shared__ float sm[4], sm2[4];
    #pragma unroll
    for (int o = 16; o > 0; o >>= 1) {
        s  += __shfl_down_sync(0xffffffffu, s,  o);
        sq += __shfl_down_sync(0xffffffffu, sq, o);
    }
    if ((tid & 31) == 0) { sm[tid >> 5] = s; sm2[tid >> 5] = sq; }
    __syncthreads();
    if (tid == 0) {
        float a = 0.f, b2 = 0.f;
        #pragma unroll
        for (int i = 0; i < 4; i++) { a += sm[i]; b2 += sm2[i]; }
        sm[0] = a; sm2[0] = b2;
    }
    __syncthreads();
    float mean = sm[0] * (1.f / 512.f);
    float var  = sm2[0] * (1.f / 512.f) - mean * mean;
    float rstd = rsqrtf(var + 1e-5f);
    float4 wv = reinterpret_cast<const float4*>(w)[tid];
    float4 bv = reinterpret_cast<const float4*>(bia)[tid];
    float4 o;
    o.x = (v.x - mean) * rstd * wv.x + bv.x;
    o.y = (v.y - mean) * rstd * wv.y + bv.y;
    o.z = (v.z - mean) * rstd * wv.z + bv.z;
    o.w = (v.w - mean) * rstd * wv.w + bv.w;
    reinterpret_cast<float4*>(g_xn + (size_t)row * DD)[tid] = o;
}

__global__ void landmark_kernel() {
    int m = blockIdx.x, bh = blockIdx.y;
    int d = threadIdx.x;
    size_t base = ((size_t)bh * NN + (size_t)m * 32) * DH + d;
    float sq = 0.f, sk = 0.f;
    #pragma unroll
    for (int j = 0; j < 32; j++) {
        sq += g_q[base + (size_t)j * DH];
        sk += g_k[base + (size_t)j * DH];
    }
    size_t o = ((size_t)bh * MM + m) * DH + d;
    g_ql[o] = sq * (1.f / 32.f);
    g_kl[o] = sk * (1.f / 32.f);
}

__global__ __launch_bounds__(256) void gemm_sim2() {
    __shared__ float As[32][132];
    __shared__ float Bs[32][132];
    int bh = blockIdx.z;
    int n0 = blockIdx.x * 128, m0 = blockIdx.y * 128;
    const float* Ab = g_ql + ((size_t)bh * MM + m0) * DH;
    const float* Bb = g_kl + ((size_t)bh * MM + n0) * DH;
    float* Cb = g_attn2 + (size_t)bh * MM * MM;
    int tid = threadIdx.x;
    int tx = tid & 15, ty = tid >> 4;
    float acc[8][8] = {};
    for (int kk = 0; kk < 64; kk += 32) {
        #pragma unroll
        for (int u = 0; u < 4; u++) {
            int g = u * 256 + tid;
            int m = g >> 3, k4 = g & 7;
            float4 av = *(const float4*)(Ab + (size_t)m * DH + kk + k4 * 4);
            As[k4*4+0][m] = av.x; As[k4*4+1][m] = av.y;
            As[k4*4+2][m] = av.z; As[k4*4+3][m] = av.w;
        }
        #pragma unroll
        for (int u = 0; u < 4; u++) {
            int g = u * 256 + tid;
            int m = g >> 3, k4 = g & 7;
            float4 bv = *(const float4*)(Bb + (size_t)m * DH + kk + k4 * 4);
            Bs[k4*4+0][m] = bv.x; Bs[k4*4+1][m] = bv.y;
            Bs[k4*4+2][m] = bv.z; Bs[k4*4+3][m] = bv.w;
        }
        __syncthreads();
        #pragma unroll
        for (int k = 0; k < 32; k++) {
            float a[8], b[8];
            *(float4*)&a[0] = *(const float4*)&As[k][ty*8];
            *(float4*)&a[4] = *(const float4*)&As[k][ty*8+4];
            *(float4*)&b[0] = *(const float4*)&Bs[k][tx*8];
            *(float4*)&b[4] = *(const float4*)&Bs[k][tx*8+4];
            #pragma unroll
            for (int i = 0; i < 8; i++)
                #pragma unroll
                for (int j = 0; j < 8; j++)
                    acc[i][j] += a[i] * b[j];
        }
        __syncthreads();
    }
    #pragma unroll
    for (int i = 0; i < 8; i++) {
        size_t r = (size_t)(m0 + ty * 8 + i) * MM + n0 + tx * 8;
        *(float4*)(Cb + r)     = make_float4(acc[i][0], acc[i][1], acc[i][2], acc[i][3]);
        *(float4*)(Cb + r + 4) = make_float4(acc[i][4], acc[i][5], acc[i][6], acc[i][7]);
    }
}

__global__ __launch_bounds__(256) void softmax256() {
    int row = blockIdx.x, tid = threadIdx.x;
    float* p = g_attn2 + (size_t)row * MM;
    float v = p[tid];
    __shared__ float red[8];
    float m = v;
    #pragma unroll
    for (int o = 16; o; o >>= 1) m = fmaxf(m, __shfl_xor_sync(~0u, m, o));
    if ((tid & 31) == 0) red[tid >> 5] = m;
    __syncthreads();
    if (tid < 32) {
        float t = (tid < 8) ? red[tid] : -1e30f;
        #pragma unroll
        for (int o = 4; o; o >>= 1) t = fmaxf(t, __shfl_xor_sync(~0u, t, o));
        if (tid == 0) red[0] = t;
    }
    __syncthreads();
    float mx = red[0];
    __syncthreads();
    float e = __expf(v - mx);
    float s = e;
    #pragma unroll
    for (int o = 16; o; o >>= 1) s += __shfl_xor_sync(~0u, s, o);
    if ((tid & 31) == 0) red[tid >> 5] = s;
    __syncthreads();
    if (tid < 32) {
        float t = (tid < 8) ? red[tid] : 0.f;
        #pragma unroll
        for (int o = 4; o; o >>= 1) t += __shfl_xor_sync(~0u, t, o);
        if (tid == 0) red[0] = t;
    }
    __syncthreads();
    p[tid] = e / red[0];
}

__global__ __launch_bounds__(256) void softmax8192bf() {
    int row = blockIdx.x, tid = threadIdx.x;
    uint4* p = (uint4*)(g_h3 + (size_t)row * NN);
    uint4 u[4];
    float f[32];
    float mx = -1e30f;
    #pragma unroll
    for (int i = 0; i < 4; i++) {
        u[i] = p[tid + i * 256];
        const uint32_t* w = (const uint32_t*)&u[i];
        #pragma unroll
        for (int j = 0; j < 4; j++) {
            float2 d = __bfloat1622float2(*(const __nv_bfloat162*)&w[j]);
            f[i*8 + j*2]     = d.x;
            f[i*8 + j*2 + 1] = d.y;
            mx = fmaxf(mx, fmaxf(d.x, d.y));
        }
    }
    __shared__ float red[8];
    #pragma unroll
    for (int o = 16; o; o >>= 1) mx = fmaxf(mx, __shfl_xor_sync(~0u, mx, o));
    if ((tid & 31) == 0) red[tid >> 5] = mx;
    __syncthreads();
    if (tid < 32) {
        float t = (tid < 8) ? red[tid] : -1e30f;
        #pragma unroll
        for (int o = 4; o; o >>= 1) t = fmaxf(t, __shfl_xor_sync(~0u, t, o));
        if (tid == 0) red[0] = t;
    }
    __syncthreads();
    float MX = red[0];
    __syncthreads();
    float s = 0.f;
    #pragma unroll
    for (int i = 0; i < 32; i++) { f[i] = __expf(f[i] - MX); s += f[i]; }
    #pragma unroll
    for (int o = 16; o; o >>= 1) s += __shfl_xor_sync(~0u, s, o);
    if ((tid & 31) == 0) red[tid >> 5] = s;
    __syncthreads();
    if (tid < 32) {
        float t = (tid < 8) ? red[tid] : 0.f;
        #pragma unroll
        for (int o = 4; o; o >>= 1) t += __shfl_xor_sync(~0u, t, o);
        if (tid == 0) red[0] = t;
    }
    __syncthreads();
    float inv = 1.f / red[0];
    #pragma unroll
    for (int i = 0; i < 4; i++) {
        uint32_t* w = (uint32_t*)&u[i];
        #pragma unroll
        for (int j = 0; j < 4; j++)
            w[j] = f2bf2(f[i*8 + j*2] * inv, f[i*8 + j*2 + 1] * inv);
        p[tid + i * 256] = u[i];
    }
}

__global__ void init_max_kernel() { g_maxA = 0; g_maxB = 0; }

__global__ __launch_bounds__(256) void colrowmax_kernel() {
    int bh = blockIdx.x, tid = threadIdx.x;
    const float* a = g_attn2 + (size_t)bh * MM * MM;
    float cs = 0.f, rs = 0.f;
    for (int m = 0; m < MM; m++) cs += fabsf(a[(size_t)m * MM + tid]);
    for (int n = 0; n < MM; n++) rs += fabsf(a[(size_t)tid * MM + n]);
    __shared__ float r1[8], r2[8];
    #pragma unroll
    for (int o = 16; o; o >>= 1) {
        cs = fmaxf(cs, __shfl_xor_sync(~0u, cs, o));
        rs = fmaxf(rs, __shfl_xor_sync(~0u, rs, o));
    }
    if ((tid & 31) == 0) { r1[tid >> 5] = cs; r2[tid >> 5] = rs; }
    __syncthreads();
    if (tid == 0) {
        float a1 = r1[0], a2 = r2[0];
        #pragma unroll
        for (int i = 1; i < 8; i++) { a1 = fmaxf(a1, r1[i]); a2 = fmaxf(a2, r2[i]); }
        atomicMax(&g_maxA, __float_as_int(a1));
        atomicMax(&g_maxB, __float_as_int(a2));
    }
}

__global__ __launch_bounds__(256) void z0_kernel() {
    int bh = blockIdx.z;
    int c0 = blockIdx.x * 32, r0 = blockIdx.y * 32;
    int tid = threadIdx.x;
    __shared__ float t[32][33];
    const float* a = g_attn2 + (size_t)bh * MM * MM;
    #pragma unroll
    for (int rr = 0; rr < 4; rr++) {
        int r = rr * 8 + (tid >> 5), c = tid & 31;
        t[r][c] = a[(size_t)(r0 + r) * MM + c0 + c];
    }
    __syncthreads();
    float s = 1.f / (__int_as_float(g_maxA) * __int_as_float(g_maxB));
    float* z = g_z + (size_t)bh * MM * MM;
    #pragma unroll
    for (int rr = 0; rr < 4; rr++) {
        int r = rr * 8 + (tid >> 5), c = tid & 31;
        z[(size_t)(c0 + r) * MM + r0 + c] = t[c][r] * s;
    }
}

__global__ __launch_bounds__(256) void matmul_ba128(const float* __restrict__ P,
                                                    const float* __restrict__ Q,
                                                    const float* __restrict__ R,
                                                    float* __restrict__ C,
                                                    float alpha, float beta) {
    __shared__ float As[16][132];
    __shared__ float Bs[16][132];
    size_t base = (size_t)blockIdx.z * (MM * MM);
    int m0 = blockIdx.y * 128, n0 = blockIdx.x * 128;
    int tid = threadIdx.x;
    int tx = tid & 15, ty = tid >> 4;
    float acc[8][8] = {};
    for (int kk = 0; kk < 256; kk += 16) {
        #pragma unroll
        for (int u = 0; u < 2; u++) {
            int g = u * 256 + tid;
            int m = g >> 2, k4 = g & 3;
            float4 av = *(const float4*)(P + base + (size_t)(m0 + m) * MM + kk + k4 * 4);
            As[k4*4+0][m] = av.x; As[k4*4+1][m] = av.y;
            As[k4*4+2][m] = av.z; As[k4*4+3][m] = av.w;
        }
        #pragma unroll
        for (int u = 0; u < 2; u++) {
            int g = u * 256 + tid;
            int k = g >> 5, n4 = g & 31;
            *(float4*)&Bs[k][n4*4] =
                *(const float4*)(Q + base + (size_t)(kk + k) * MM + n0 + n4 * 4);
        }
        __syncthreads();
        #pragma unroll
        for (int k = 0; k < 16; k++) {
            float a[8], b[8];
            *(float4*)&a[0] = *(const float4*)&As[k][ty*8];
            *(float4*)&a[4] = *(const float4*)&As[k][ty*8+4];
            *(float4*)&b[0] = *(const float4*)&Bs[k][tx*8];
            *(float4*)&b[4] = *(const float4*)&Bs[k][tx*8+4];
            #pragma unroll
            for (int i = 0; i < 8; i++)
                #pragma unroll
                for (int j = 0; j < 8; j++)
                    acc[i][j] += a[i] * b[j];
        }
        __syncthreads();
    }
    #pragma unroll
    for (int i = 0; i < 8; i++) {
        #pragma unroll
        for (int jj = 0; jj < 2; jj++) {
            size_t off = base + (size_t)(m0 + ty * 8 + i) * MM + n0 + tx * 8 + jj * 4;
            float4 rv = make_float4(0.f, 0.f, 0.f, 0.f);
            if (beta != 0.f) rv = *(const float4*)(R + off);
            float4 o;
            o.x = alpha * acc[i][jj*4+0] + beta * rv.x;
            o.y = alpha * acc[i][jj*4+1] + beta * rv.y;
            o.z = alpha * acc[i][jj*4+2] + beta * rv.z;
            o.w = alpha * acc[i][jj*4+3] + beta * rv.w;
            *(float4*)(C + off) = o;
        }
    }
}

__global__ __launch_bounds__(256) void reduce_p3() {
    size_t t = (size_t)blockIdx.x * 256 + threadIdx.x;
    size_t bh = t >> 14, rem = t & 16383;
    float s = 0.f;
    #pragma unroll
    for (int ks = 0; ks < KS; ks++)
        s += g_p3[((bh * KS + ks) << 14) + rem];
    g_out3[t] = s;
}

__global__ __launch_bounds__(256) void conv_kernel(const float* __restrict__ res_w) {
    __shared__ float sv[160][64];
    __shared__ float sw[33];
    int bh = blockIdx.y, n0 = blockIdx.x * 128;
    int b = bh >> 3, h = bh & 7;
    int tid = threadIdx.x;
    if (tid < 33) sw[tid] = res_w[h * 33 + tid];
    const float* vb = g_v + (size_t)bh * NN * DH;
    #pragma unroll
    for (int i = 0; i < 10; i++) {
        int idx = tid + i * 256;
        int r = idx >> 4, c4 = idx & 15;
        int tok = n0 - 16 + r;
        float4 val = make_float4(0.f, 0.f, 0.f, 0.f);
        if (tok >= 0 && tok < NN)
            val = *(const float4*)(vb + (size_t)tok * DH + c4 * 4);
        *(float4*)&sv[r][c4 * 4] = val;
    }
    __syncthreads();
    #pragma unroll
    for (int i = 0; i < 8; i++) {
        int idx = tid + i * 256;
        int nl = idx >> 4, dg = idx & 15;
        float4 acc = make_float4(0.f, 0.f, 0.f, 0.f);
        #pragma unroll
        for (int j = 0; j < 33; j++) {
            float w = sw[j];
            float4 vv = *(const float4*)&sv[nl + j][dg * 4];
            acc.x += w * vv.x; acc.y += w * vv.y;
            acc.z += w * vv.z; acc.w += w * vv.w;
        }
        *(float4*)(g_y + ((size_t)b * NN + n0 + nl) * DD + h * 64 + dg * 4) = acc;
    }
}

extern "C" void kernel_launch(void* const* d_in, const int* in_sizes, int n_in,
                              void* d_out, int out_size) {
    const float* x     = (const float*)d_in[0];
    const float* ln_w  = (const float*)d_in[1];
    const float* ln_b  = (const float*)d_in[2];
    const float* w_qkv = (const float*)d_in[3];
    const float* w_out = (const float*)d_in[4];
    const float* b_out = (const float*)d_in[5];
    const float* res_w = (const float*)d_in[6];
    float* out = (float*)d_out;

    float *p_xn, *p_q, *p_k, *p_v, *p_ql, *p_kl, *p_attn2;
    float *p_z, *p_z2, *p_xz, *p_t, *p_u;
    float *p_p3, *p_out3, *p_wc, *p_y;
    void *p_h3, *p_h1;
    cudaGetSymbolAddress((void**)&p_xn, g_xn);
    cudaGetSymbolAddress((void**)&p_q,  g_q);
    cudaGetSymbolAddress((void**)&p_k,  g_k);
    cudaGetSymbolAddress((void**)&p_v,  g_v);
    cudaGetSymbolAddress((void**)&p_ql, g_ql);
    cudaGetSymbolAddress((void**)&p_kl, g_kl);
    cudaGetSymbolAddress((void**)&p_attn2, g_attn2);
    cudaGetSymbolAddress((void**)&p_z,  g_z);
    cudaGetSymbolAddress((void**)&p_z2, g_z2);
    cudaGetSymbolAddress((void**)&p_xz, g_xz);
    cudaGetSymbolAddress((void**)&p_t,  g_t);
    cudaGetSymbolAddress((void**)&p_u,  g_u);
    cudaGetSymbolAddress(&p_h3, g_h3);
    cudaGetSymbolAddress(&p_h1, g_h1);
    cudaGetSymbolAddress((void**)&p_p3, g_p3);
    cudaGetSymbolAddress((void**)&p_out3, g_out3);
    cudaGetSymbolAddress((void**)&p_wc, g_wc);
    cudaGetSymbolAddress((void**)&p_y,  g_y);

    ln_kernel<<<BB * NN, 128>>>(x, ln_w, ln_b);
    bf_gemm<0,128,128,32,false,false><<<dim3(12, 256, 1), 256>>>(
        p_xn, w_qkv, nullptr, nullptr, nullptr,
        1536, 512, 512, 1536, 0, 0, 0);
    landmark_kernel<<<dim3(MM, BH), 64>>>();

    gemm_sim2<<<dim3(2, 2, BH), 256>>>();
    bf_gemm<6,128,128,32,true,false><<<dim3(64, 2, BH), 256>>>(
        p_ql, p_k, p_h3, nullptr, nullptr,
        NN, 64, 64, 64, (long long)MM*DH, (long long)NN*DH, (long long)MM*NN);
    sim1_fused<<<dim3(1, 128, BH), 256>>>();

    softmax256<<<BH * MM, 256>>>();
    softmax8192bf<<<BH * MM, 256>>>();

    init_max_kernel<<<1, 1>>>();
    colrowmax_kernel<<<BH, 256>>>();
    z0_kernel<<<dim3(8, 8, BH), 256>>>();

    dim3 gba(2, 2, BH);
    float *zc = p_z, *zn = p_z2;
    for (int it = 0; it < 5; it++) {
        tc_gemm<4,128,128,16><<<gba, 256>>>(p_attn2, zc, p_xz, nullptr,
            MM, 256, 256, 256, (long long)MM*MM, (long long)MM*MM, (long long)MM*MM, 1.f, 0.f);
        tc_gemm<4,128,128,16><<<gba, 256>>>(p_xz, p_xz, p_t, p_xz,
            MM, 256, 256, 256, (long long)MM*MM, (long long)MM*MM, (long long)MM*MM, -1.f, 7.f);
        tc_gemm<4,128,128,16><<<gba, 256>>>(p_xz, p_t, p_u, p_xz,
            MM, 256, 256, 256, (long long)MM*MM, (long long)MM*MM, (long long)MM*MM, -1.f, 15.f);
        tc_gemm<4,128,128,16><<<gba, 256>>>(zc, p_u, zn, zc,
            MM, 256, 256, 256, (long long)MM*MM, (long long)MM*MM, (long long)MM*MM, -0.25f, 3.25f);
        float* tmp = zc; zc = zn; zn = tmp;
    }
    matmul_ba128<<<gba, 256>>>(p_attn2, zc, nullptr, p_xz, 1.f, 0.f);
    matmul_ba128<<<gba, 256>>>(p_xz, p_xz, p_xz, p_t, -1.f, 7.f);
    matmul_ba128<<<gba, 256>>>(p_xz, p_t, p_xz, p_u, -1.f, 15.f);
    matmul_ba128<<<gba, 256>>>(zc, p_u, zc, zn, -0.25f, 3.25f);
    { float* tmp = zc; zc = zn; zn = tmp; }

    bf_gemm<3,128,64,32,false,true><<<dim3(1, 2, BH * KS), 256>>>(
        p_h3, p_v, p_p3, nullptr, nullptr,
        64, 512, NN, 64, 0, 0, 0);
    reduce_p3<<<2048, 256>>>();

    tc_gemm<2,128,64,16><<<dim3(1, 2, BH), 256>>>(
        zc, p_out3, p_wc, nullptr,
        64, 256, 256, 64, (long long)MM*MM, (long long)MM*DH, (long long)MM*DH, 0.f, 0.f);

    conv_kernel<<<dim3(64, BH), 256>>>(res_w);
    bf_gemm<5,128,64,32,false,true><<<dim3(1, 64, BH), 256>>>(
        p_h1, p_wc, p_y, nullptr, nullptr,
        64, 256, 256, 64, (long long)NN*MM, (long long)MM*DH, 0);

    bf_gemm<1,128,128,32,false,false><<<dim3(4, 256, 1), 256>>>(
        p_y, w_out, out, b_out, x,
        512, 512, 512, 512, 0, 0, 0);
}

// round 9
// speedup vs baseline: 1.0621x; 1.0621x over previous
#include <cuda_runtime.h>
#include <cuda_bf16.h>
#include <stdint.h>
#include <math.h>

#define BB 4
#define NN 8192
#define DD 512
#define HH 8
#define DH 64
#define MM 256
#define BH 32
#define KS 16

__device__ __align__(16) float g_xn  [(size_t)BB*NN*DD];
__device__ __align__(16) float g_q   [(size_t)BH*NN*DH];
__device__ __align__(16) float g_k   [(size_t)BH*NN*DH];
__device__ __align__(16) float g_v   [(size_t)BH*NN*DH];
__device__ __align__(16) float g_ql  [(size_t)BH*MM*DH];
__device__ __align__(16) float g_kl  [(size_t)BH*MM*DH];
__device__ __align__(16) float g_attn2[(size_t)BH*MM*MM];
__device__ __align__(16) float g_z   [(size_t)BH*MM*MM];
__device__ __align__(16) float g_z2  [(size_t)BH*MM*MM];
__device__ __align__(16) float g_xz  [(size_t)BH*MM*MM];
__device__ __align__(16) float g_t   [(size_t)BH*MM*MM];
__device__ __align__(16) float g_u   [(size_t)BH*MM*MM];
__device__ __align__(16) __nv_bfloat16 g_h1[(size_t)BH*NN*MM];
__device__ __align__(16) float g_p3  [(size_t)BH*KS*MM*DH];
__device__ __align__(16) float g_m3  [(size_t)BH*KS*MM];
__device__ __align__(16) float g_l3  [(size_t)BH*KS*MM];
__device__ __align__(16) float g_out3[(size_t)BH*MM*DH];
__device__ __align__(16) float g_wc  [(size_t)BH*MM*DH];
__device__ __align__(16) float g_y   [(size_t)BB*NN*DD];
__device__ int g_maxA;
__device__ int g_maxB;

__device__ __forceinline__ uint32_t f2tf(float f) {
    uint32_t u;
    asm("cvt.rna.tf32.f32 %0, %1;" : "=r"(u) : "f"(f));
    return u;
}
__device__ __forceinline__ uint32_t f2bf2(float lo, float hi) {
    uint32_t r;
    asm("cvt.rn.bf16x2.f32 %0, %1, %2;" : "=r"(r) : "f"(hi), "f"(lo));
    return r;
}
__device__ __forceinline__ void mma8(float* d, const uint32_t* a, const uint32_t* b) {
    asm volatile(
        "mma.sync.aligned.m16n8k8.row.col.f32.tf32.tf32.f32 "
        "{%0,%1,%2,%3}, {%4,%5,%6,%7}, {%8,%9}, {%0,%1,%2,%3};"
        : "+f"(d[0]), "+f"(d[1]), "+f"(d[2]), "+f"(d[3])
        : "r"(a[0]), "r"(a[1]), "r"(a[2]), "r"(a[3]), "r"(b[0]), "r"(b[1]));
}
__device__ __forceinline__ void mma16(float* d, const uint32_t* a, const uint32_t* b) {
    asm volatile(
        "mma.sync.aligned.m16n8k16.row.col.f32.bf16.bf16.f32 "
        "{%0,%1,%2,%3}, {%4,%5,%6,%7}, {%8,%9}, {%0,%1,%2,%3};"
        : "+f"(d[0]), "+f"(d[1]), "+f"(d[2]), "+f"(d[3])
        : "r"(a[0]), "r"(a[1]), "r"(a[2]), "r"(a[3]), "r"(b[0]), "r"(b[1]));
}

// ---------------------------------------------------------------------------
// Flash split-KV attn3: out3 = softmax(ql @ k^T) @ v, per (bh, ksplit)
// block: 128 q rows; loop 8 key-tiles of 64; partials (o,m,l)
// ---------------------------------------------------------------------------
__global__ __launch_bounds__(256) void flash3() {
    extern __shared__ char smraw[];
    uint32_t* Qs = (uint32_t*)smraw;            // [32][136] bf16x2
    uint32_t* Ksm = Qs + 32*136;                // [32][72]
    uint32_t* Vsm = Ksm + 32*72;                // [32][72]
    uint32_t* Ps = Vsm + 32*72;                 // [32][136]
    float* wmax = (float*)(Ps + 32*136);        // [128][4]
    float* wsum = wmax + 512;                   // [128][4]
    float* mrun = wsum + 512;                   // [128]
    float* lrun = mrun + 128;                   // [128]

    int tid = threadIdx.x, lane = tid & 31, warp = tid >> 5;
    int g = lane >> 2, q4 = lane & 3;
    int wm0 = (warp >> 2) * 64;
    int wn0 = (warp & 3) * 16;
    int wn = warp & 3;
    int m0 = blockIdx.x * 128;
    int ksp = blockIdx.y, bh = blockIdx.z;

    const float* Qg = g_ql + ((size_t)bh * MM + m0) * DH;
    #pragma unroll
    for (int c = 0; c < 8; c++) {
        int id = c * 256 + tid;
        int m = id >> 4, qq = id & 15;
        float4 v = *(const float4*)(Qg + (size_t)m * DH + qq * 4);
        Qs[(qq*2+0)*136 + m] = f2bf2(v.x, v.y);
        Qs[(qq*2+1)*136 + m] = f2bf2(v.z, v.w);
    }
    if (tid < 128) { mrun[tid] = -1e30f; lrun[tid] = 0.f; }

    float acc[4][2][4];
    #pragma unroll
    for (int a = 0; a < 4; a++)
        #pragma unroll
        for (int b = 0; b < 2; b++)
            #pragma unroll
            for (int r = 0; r < 4; r++) acc[a][b][r] = 0.f;

    const float* Kg = g_k + ((size_t)bh * NN + ksp * 512) * DH;
    const float* Vg = g_v + ((size_t)bh * NN + ksp * 512) * DH;

    for (int t = 0; t < 8; t++) {
        __syncthreads();
        #pragma unroll
        for (int c = 0; c < 4; c++) {
            int id = c * 256 + tid;
            int n = id >> 4, qq = id & 15;
            float4 v = *(const float4*)(Kg + (size_t)(t*64 + n) * DH + qq * 4);
            Ksm[(qq*2+0)*72 + n] = f2bf2(v.x, v.y);
            Ksm[(qq*2+1)*72 + n] = f2bf2(v.z, v.w);
        }
        #pragma unroll
        for (int c = 0; c < 2; c++) {
            int id = c * 256 + tid;
            int kp = id >> 4, qq = id & 15;
            float4 lo = *(const float4*)(Vg + (size_t)(t*64 + 2*kp    ) * DH + qq * 4);
            float4 hi = *(const float4*)(Vg + (size_t)(t*64 + 2*kp + 1) * DH + qq * 4);
            Vsm[kp*72 + qq*4+0] = f2bf2(lo.x, hi.x);
            Vsm[kp*72 + qq*4+1] = f2bf2(lo.y, hi.y);
            Vsm[kp*72 + qq*4+2] = f2bf2(lo.z, hi.z);
            Vsm[kp*72 + qq*4+3] = f2bf2(lo.w, hi.w);
        }
        __syncthreads();

        float S[4][2][4];
        #pragma unroll
        for (int a = 0; a < 4; a++)
            #pragma unroll
            for (int b = 0; b < 2; b++)
                #pragma unroll
                for (int r = 0; r < 4; r++) S[a][b][r] = 0.f;
        #pragma unroll
        for (int k2 = 0; k2 < 4; k2++) {
            int kr = k2 * 8 + q4;
            uint32_t af[4][4], bfr[2][2];
            int mr = wm0 + g;
            #pragma unroll
            for (int mt = 0; mt < 4; mt++) {
                af[mt][0] = Qs[kr*136 + mr + mt*16];
                af[mt][1] = Qs[kr*136 + mr + mt*16 + 8];
                af[mt][2] = Qs[(kr+4)*136 + mr + mt*16];
                af[mt][3] = Qs[(kr+4)*136 + mr + mt*16 + 8];
            }
            int nr = wn0 + g;
            #pragma unroll
            for (int nt = 0; nt < 2; nt++) {
                bfr[nt][0] = Ksm[kr*72 + nr + nt*8];
                bfr[nt][1] = Ksm[(kr+4)*72 + nr + nt*8];
            }
            #pragma unroll
            for (int mt = 0; mt < 4; mt++)
                #pragma unroll
                for (int nt = 0; nt < 2; nt++)
                    mma16(S[mt][nt], af[mt], bfr[nt]);
        }

        #pragma unroll
        for (int mt = 0; mt < 4; mt++) {
            float m0v = fmaxf(fmaxf(S[mt][0][0], S[mt][0][1]), fmaxf(S[mt][1][0], S[mt][1][1]));
            float m1v = fmaxf(fmaxf(S[mt][0][2], S[mt][0][3]), fmaxf(S[mt][1][2], S[mt][1][3]));
            #pragma unroll
            for (int o = 1; o < 4; o <<= 1) {
                m0v = fmaxf(m0v, __shfl_xor_sync(~0u, m0v, o));
                m1v = fmaxf(m1v, __shfl_xor_sync(~0u, m1v, o));
            }
            if (q4 == 0) {
                wmax[(wm0 + mt*16 + g)*4 + wn] = m0v;
                wmax[(wm0 + mt*16 + g + 8)*4 + wn] = m1v;
            }
        }
        __syncthreads();

        #pragma unroll
        for (int mt = 0; mt < 4; mt++) {
            int r0 = wm0 + mt*16 + g, r1 = r0 + 8;
            float mo0 = mrun[r0];
            float mt0 = fmaxf(fmaxf(wmax[r0*4+0], wmax[r0*4+1]), fmaxf(wmax[r0*4+2], wmax[r0*4+3]));
            float mn0 = fmaxf(mo0, mt0);
            float sc0 = __expf(mo0 - mn0);
            float mo1 = mrun[r1];
            float mt1 = fmaxf(fmaxf(wmax[r1*4+0], wmax[r1*4+1]), fmaxf(wmax[r1*4+2], wmax[r1*4+3]));
            float mn1 = fmaxf(mo1, mt1);
            float sc1 = __expf(mo1 - mn1);
            float s0 = 0.f, s1 = 0.f;
            #pragma unroll
            for (int nt = 0; nt < 2; nt++) {
                S[mt][nt][0] = __expf(S[mt][nt][0] - mn0);
                S[mt][nt][1] = __expf(S[mt][nt][1] - mn0);
                S[mt][nt][2] = __expf(S[mt][nt][2] - mn1);
                S[mt][nt][3] = __expf(S[mt][nt][3] - mn1);
                s0 += S[mt][nt][0] + S[mt][nt][1];
                s1 += S[mt][nt][2] + S[mt][nt][3];
                int cp = wn * 8 + nt * 4 + q4;
                Ps[cp*136 + r0] = f2bf2(S[mt][nt][0], S[mt][nt][1]);
                Ps[cp*136 + r1] = f2bf2(S[mt][nt][2], S[mt][nt][3]);
                acc[mt][nt][0] *= sc0; acc[mt][nt][1] *= sc0;
                acc[mt][nt][2] *= sc1; acc[mt][nt][3] *= sc1;
            }
            #pragma unroll
            for (int o = 1; o < 4; o <<= 1) {
                s0 += __shfl_xor_sync(~0u, s0, o);
                s1 += __shfl_xor_sync(~0u, s1, o);
            }
            if (q4 == 0) { wsum[r0*4+wn] = s0; wsum[r1*4+wn] = s1; }
        }
        __syncthreads();

        if (tid < 128) {
            float mo = mrun[tid];
            float mt2 = fmaxf(fmaxf(wmax[tid*4+0], wmax[tid*4+1]), fmaxf(wmax[tid*4+2], wmax[tid*4+3]));
            float mn = fmaxf(mo, mt2);
            mrun[tid] = mn;
            lrun[tid] = lrun[tid]*__expf(mo - mn) +
                        wsum[tid*4+0] + wsum[tid*4+1] + wsum[tid*4+2] + wsum[tid*4+3];
        }
        #pragma unroll
        for (int k2 = 0; k2 < 4; k2++) {
            int kr = k2 * 8 + q4;
            uint32_t af[4][4], bfr[2][2];
            int mr = wm0 + g;
            #pragma unroll
            for (int mt = 0; mt < 4; mt++) {
                af[mt][0] = Ps[kr*136 + mr + mt*16];
                af[mt][1] = Ps[kr*136 + mr + mt*16 + 8];
                af[mt][2] = Ps[(kr+4)*136 + mr + mt*16];
                af[mt][3] = Ps[(kr+4)*136 + mr + mt*16 + 8];
            }
            int nr = wn0 + g;
            #pragma unroll
            for (int nt = 0; nt < 2; nt++) {
                bfr[nt][0] = Vsm[kr*72 + nr + nt*8];
                bfr[nt][1] = Vsm[(kr+4)*72 + nr + nt*8];
            }
            #pragma unroll
            for (int mt = 0; mt < 4; mt++)
                #pragma unroll
                for (int nt = 0; nt < 2; nt++)
                    mma16(acc[mt][nt], af[mt], bfr[nt]);
        }
    }
    __syncthreads();

    size_t ob = (size_t)(bh * KS + ksp) * MM + m0;
    #pragma unroll
    for (int mt = 0; mt < 4; mt++) {
        #pragma unroll
        for (int nt = 0; nt < 2; nt++) {
            int r0 = wm0 + mt*16 + g;
            int c = wn0 + nt*8 + q4*2;
            *(float2*)(g_p3 + (ob + r0)*DH + c)     = make_float2(acc[mt][nt][0], acc[mt][nt][1]);
            *(float2*)(g_p3 + (ob + r0 + 8)*DH + c) = make_float2(acc[mt][nt][2], acc[mt][nt][3]);
        }
    }
    if (tid < 128) {
        g_m3[ob + tid] = mrun[tid];
        g_l3[ob + tid] = lrun[tid];
    }
}

// combine split-KV partials -> g_out3 (one warp per (bh,row))
__global__ __launch_bounds__(256) void combine3() {
    int warp = threadIdx.x >> 5, lane = threadIdx.x & 31;
    int rowg = blockIdx.x * 8 + warp;
    int bh = rowg >> 8, r = rowg & 255;
    size_t base = (size_t)(bh * KS) * MM + r;
    float mv = (lane < 16) ? g_m3[base + (size_t)lane * MM] : -1e30f;
    #pragma unroll
    for (int o = 16; o; o >>= 1) mv = fmaxf(mv, __shfl_xor_sync(~0u, mv, o));
    float M = mv;
    float lv = (lane < 16) ? g_l3[base + (size_t)lane * MM] *
                             __expf(g_m3[base + (size_t)lane * MM] - M) : 0.f;
    #pragma unroll
    for (int o = 16; o; o >>= 1) lv += __shfl_xor_sync(~0u, lv, o);
    float invL = 1.f / lv;
    float a0 = 0.f, a1 = 0.f;
    for (int kk = 0; kk < KS; kk++) {
        float w = __expf(g_m3[base + (size_t)kk * MM] - M);
        float2 p = *(const float2*)(g_p3 + (base + (size_t)kk * MM) * DH + lane * 2);
        a0 += p.x * w; a1 += p.y * w;
    }
    *(float2*)(g_out3 + ((size_t)bh * MM + r) * DH + lane * 2) =
        make_float2(a0 * invL, a1 * invL);
}

// ---------------------------------------------------------------------------
// TF32 GEMM (pinv + Wc), double-buffered, BK=16. EPI: 2=store 4=alpha/beta
// ---------------------------------------------------------------------------
template<int EPI, int BM, int BN, int BK>
__global__ __launch_bounds__(256) void tc_gemm(
    const float* __restrict__ A, const float* __restrict__ Bg,
    float* __restrict__ C, const float* __restrict__ X1,
    int N, int K, int lda, int ldb,
    long long bsA, long long bsB, long long bsC,
    float alpha, float beta)
{
    constexpr int PA = BM + 8, PB = BN + 8;
    constexpr int MT = (BM / 2) / 16;
    constexpr int NT = (BN / 4) / 8;
    constexpr int RA = (BM * BK) / 1024;
    constexpr int RB = (BK * BN) / 1024;
    __shared__ uint32_t As[2][BK][PA];
    __shared__ uint32_t Bs[2][BK][PB];
    float4 ra[RA], rb[RB];

    int tid = threadIdx.x, lane = tid & 31, warp = tid >> 5;
    int wm0 = (warp >> 2) * (BM / 2);
    int wn0 = (warp & 3) * (BN / 4);
    int z = blockIdx.z;
    int m0 = blockIdx.y * BM, n0 = blockIdx.x * BN;
    const float* Ab = A  + (size_t)z * bsA;
    const float* Bb = Bg + (size_t)z * bsB;

    float acc[MT][NT][4];
    #pragma unroll
    for (int i = 0; i < MT; i++)
        #pragma unroll
        for (int j = 0; j < NT; j++)
            #pragma unroll
            for (int r = 0; r < 4; r++) acc[i][j][r] = 0.f;

    auto LOAD = [&](int kb) {
        #pragma unroll
        for (int c = 0; c < RA; c++) {
            int id = c * 256 + tid;
            int m = id / (BK / 4), kq = id % (BK / 4);
            ra[c] = *(const float4*)(Ab + (size_t)(m0 + m) * lda + kb * BK + kq * 4);
        }
        #pragma unroll
        for (int c = 0; c < RB; c++) {
            int id = c * 256 + tid;
            int k = id / (BN / 4), nq = id % (BN / 4);
            rb[c] = *(const float4*)(Bb + (size_t)(kb * BK + k) * ldb + n0 + nq * 4);
        }
    };
    auto COMMIT = [&](int bf) {
        #pragma unroll
        for (int c = 0; c < RA; c++) {
            int id = c * 256 + tid;
            int m = id / (BK / 4), kq = id % (BK / 4);
            As[bf][kq*4+0][m] = f2tf(ra[c].x); As[bf][kq*4+1][m] = f2tf(ra[c].y);
            As[bf][kq*4+2][m] = f2tf(ra[c].z); As[bf][kq*4+3][m] = f2tf(ra[c].w);
        }
        #pragma unroll
        for (int c = 0; c < RB; c++) {
            int id = c * 256 + tid;
            int k = id / (BN / 4), nq = id % (BN / 4);
            Bs[bf][k][nq*4+0] = f2tf(rb[c].x); Bs[bf][k][nq*4+1] = f2tf(rb[c].y);
            Bs[bf][k][nq*4+2] = f2tf(rb[c].z); Bs[bf][k][nq*4+3] = f2tf(rb[c].w);
        }
    };
    auto MMA = [&](int bf) {
        #pragma unroll
        for (int ks = 0; ks < BK / 8; ks++) {
            uint32_t af[MT][4], bfr[NT][2];
            int kr = ks * 8 + (lane & 3);
            int mr = wm0 + (lane >> 2);
            #pragma unroll
            for (int mt = 0; mt < MT; mt++) {
                af[mt][0] = As[bf][kr    ][mr + mt*16];
                af[mt][1] = As[bf][kr    ][mr + mt*16 + 8];
                af[mt][2] = As[bf][kr + 4][mr + mt*16];
                af[mt][3] = As[bf][kr + 4][mr + mt*16 + 8];
            }
            int nr = wn0 + (lane >> 2);
            #pragma unroll
            for (int nt = 0; nt < NT; nt++) {
                bfr[nt][0] = Bs[bf][kr    ][nr + nt*8];
                bfr[nt][1] = Bs[bf][kr + 4][nr + nt*8];
            }
            #pragma unroll
            for (int mt = 0; mt < MT; mt++)
                #pragma unroll
                for (int nt = 0; nt < NT; nt++)
                    mma8(acc[mt][nt], af[mt], bfr[nt]);
        }
    };

    int nk = K / BK;
    LOAD(0); COMMIT(0);
    __syncthreads();
    for (int kb = 1; kb < nk; kb++) {
        LOAD(kb);
        MMA((kb - 1) & 1);
        COMMIT(kb & 1);
        __syncthreads();
    }
    MMA((nk - 1) & 1);

    #pragma unroll
    for (int mt = 0; mt < MT; mt++) {
        #pragma unroll
        for (int nt = 0; nt < NT; nt++) {
            int row = m0 + wm0 + mt * 16 + (lane >> 2);
            int col = n0 + wn0 + nt * 8 + (lane & 3) * 2;
            float2 lo = make_float2(acc[mt][nt][0], acc[mt][nt][1]);
            float2 hi = make_float2(acc[mt][nt][2], acc[mt][nt][3]);
            if constexpr (EPI == 2) {
                size_t base = (size_t)z * bsC;
                *(float2*)(C + base + (size_t)row       * N + col) = lo;
                *(float2*)(C + base + (size_t)(row + 8) * N + col) = hi;
            } else if constexpr (EPI == 4) {
                size_t base = (size_t)z * (MM * MM);
                size_t r1 = base + (size_t)row * MM + col;
                size_t r2 = base + (size_t)(row + 8) * MM + col;
                float2 rv1 = make_float2(0.f, 0.f), rv2 = make_float2(0.f, 0.f);
                if (beta != 0.f) {
                    rv1 = *(const float2*)(X1 + r1);
                    rv2 = *(const float2*)(X1 + r2);
                }
                *(float2*)(C + r1) = make_float2(alpha*lo.x + beta*rv1.x, alpha*lo.y + beta*rv1.y);
                *(float2*)(C + r2) = make_float2(alpha*hi.x + beta*rv2.x, alpha*hi.y + beta*rv2.y);
            }
        }
    }
}

// ---------------------------------------------------------------------------
// BF16 GEMM, double-buffered. EPI: 0=QKV 1=out+bias+x 5=y+=  TRB/BFA as before
// ---------------------------------------------------------------------------
template<int EPI, int BM, int BN, int BK, bool TRB, bool BFA>
__global__ __launch_bounds__(256) void bf_gemm(
    const void* __restrict__ Av, const float* __restrict__ Bg,
    void* __restrict__ Cv, const float* __restrict__ X1, const float* __restrict__ X2,
    int N, int K, int lda, int ldb,
    long long bsA, long long bsB, long long bsC)
{
    constexpr int PA = BM + 8, PB = BN + 8;
    constexpr int MT = (BM / 2) / 16;
    constexpr int NT = (BN / 4) / 8;
    constexpr int KP = BK / 2;
    constexpr int RAH = (BM * BK) / 2048;
    constexpr int RAF = (BM * BK) / 1024;
    constexpr int RBN = (KP * (BN / 4)) / 256;
    __shared__ uint32_t As[2][KP][PA];
    __shared__ uint32_t Bs[2][KP][PB];
    uint4  rah[BFA ? RAH : 1];
    float4 raf[BFA ? 1 : RAF];
    float4 rb0[RBN], rb1[RBN];

    int tid = threadIdx.x, lane = tid & 31, warp = tid >> 5;
    int wm0 = (warp >> 2) * (BM / 2);
    int wn0 = (warp & 3) * (BN / 4);
    int z = blockIdx.z;
    int m0 = blockIdx.y * BM, n0 = blockIdx.x * BN;

    const float* Bb = Bg + (size_t)z * bsB;
    const float* Abf = nullptr;
    const __nv_bfloat16* Abh = nullptr;
    if constexpr (BFA) Abh = (const __nv_bfloat16*)Av + (size_t)z * bsA;
    else               Abf = (const float*)Av + (size_t)z * bsA;

    float acc[MT][NT][4];
    #pragma unroll
    for (int i = 0; i < MT; i++)
        #pragma unroll
        for (int j = 0; j < NT; j++)
            #pragma unroll
            for (int r = 0; r < 4; r++) acc[i][j][r] = 0.f;

    auto LOAD = [&](int kb) {
        if constexpr (BFA) {
            #pragma unroll
            for (int c = 0; c < RAH; c++) {
                int id = c * 256 + tid;
                int m = id / (BK / 8), kq = id % (BK / 8);
                rah[c] = *(const uint4*)(Abh + (size_t)(m0 + m) * lda + kb * BK + kq * 8);
            }
        } else {
            #pragma unroll
            for (int c = 0; c < RAF; c++) {
                int id = c * 256 + tid;
                int m = id / (BK / 4), kq = id % (BK / 4);
                raf[c] = *(const float4*)(Abf + (size_t)(m0 + m) * lda + kb * BK + kq * 4);
            }
        }
        #pragma unroll
        for (int c = 0; c < RBN; c++) {
            int id = c * 256 + tid;
            int kp = id / (BN / 4), nq = id % (BN / 4);
            rb0[c] = *(const float4*)(Bb + (size_t)(kb*BK + 2*kp    ) * ldb + n0 + nq * 4);
            rb1[c] = *(const float4*)(Bb + (size_t)(kb*BK + 2*kp + 1) * ldb + n0 + nq * 4);
        }
    };
    auto COMMIT = [&](int bf) {
        if constexpr (BFA) {
            #pragma unroll
            for (int c = 0; c < RAH; c++) {
                int id = c * 256 + tid;
                int m = id / (BK / 8), kq = id % (BK / 8);
                As[bf][kq*4+0][m] = rah[c].x; As[bf][kq*4+1][m] = rah[c].y;
                As[bf][kq*4+2][m] = rah[c].z; As[bf][kq*4+3][m] = rah[c].w;
            }
        } else {
            #pragma unroll
            for (int c = 0; c < RAF; c++) {
                int id = c * 256 + tid;
                int m = id / (BK / 4), kq = id % (BK / 4);
                As[bf][kq*2+0][m] = f2bf2(raf[c].x, raf[c].y);
                As[bf][kq*2+1][m] = f2bf2(raf[c].z, raf[c].w);
            }
        }
        #pragma unroll
        for (int c = 0; c < RBN; c++) {
            int id = c * 256 + tid;
            int kp = id / (BN / 4), nq = id % (BN / 4);
            Bs[bf][kp][nq*4+0] = f2bf2(rb0[c].x, rb1[c].x);
            Bs[bf][kp][nq*4+1] = f2bf2(rb0[c].y, rb1[c].y);
            Bs[bf][kp][nq*4+2] = f2bf2(rb0[c].z, rb1[c].z);
            Bs[bf][kp][nq*4+3] = f2bf2(rb0[c].w, rb1[c].w);
        }
    };
    auto MMA = [&](int bf) {
        #pragma unroll
        for (int ks = 0; ks < BK / 16; ks++) {
            uint32_t af[MT][4], bfr[NT][2];
            int kr = ks * 8 + (lane & 3);
            int mr = wm0 + (lane >> 2);
            #pragma unroll
            for (int mt = 0; mt < MT; mt++) {
                af[mt][0] = As[bf][kr    ][mr + mt*16];
                af[mt][1] = As[bf][kr    ][mr + mt*16 + 8];
                af[mt][2] = As[bf][kr + 4][mr + mt*16];
                af[mt][3] = As[bf][kr + 4][mr + mt*16 + 8];
            }
            int nr = wn0 + (lane >> 2);
            #pragma unroll
            for (int nt = 0; nt < NT; nt++) {
                bfr[nt][0] = Bs[bf][kr    ][nr + nt*8];
                bfr[nt][1] = Bs[bf][kr + 4][nr + nt*8];
            }
            #pragma unroll
            for (int mt = 0; mt < MT; mt++)
                #pragma unroll
                for (int nt = 0; nt < NT; nt++)
                    mma16(acc[mt][nt], af[mt], bfr[nt]);
        }
    };

    int nk = K / BK;
    LOAD(0); COMMIT(0);
    __syncthreads();
    for (int kb = 1; kb < nk; kb++) {
        LOAD(kb);
        MMA((kb - 1) & 1);
        COMMIT(kb & 1);
        __syncthreads();
    }
    MMA((nk - 1) & 1);

    #pragma unroll
    for (int mt = 0; mt < MT; mt++) {
        #pragma unroll
        for (int nt = 0; nt < NT; nt++) {
            int row = m0 + wm0 + mt * 16 + (lane >> 2);
            int col = n0 + wn0 + nt * 8 + (lane & 3) * 2;
            float2 lo = make_float2(acc[mt][nt][0], acc[mt][nt][1]);
            float2 hi = make_float2(acc[mt][nt][2], acc[mt][nt][3]);
            if constexpr (EPI == 0) {
                int which = col >> 9, inner = col & 511;
                int h = inner >> 6, d = inner & 63;
                float* dst = which == 0 ? g_q : (which == 1 ? g_k : g_v);
                float s = (which == 0) ? 0.125f : 1.f;
                int bq = row >> 13, n = row & (NN - 1);
                *(float2*)(dst + (((size_t)(bq*HH+h))*NN + n    )*DH + d) = make_float2(lo.x*s, lo.y*s);
                *(float2*)(dst + (((size_t)(bq*HH+h))*NN + n + 8)*DH + d) = make_float2(hi.x*s, hi.y*s);
            } else if constexpr (EPI == 1) {
                float* C = (float*)Cv;
                float2 bv = *(const float2*)(X1 + col);
                size_t r1 = (size_t)row * DD + col, r2 = (size_t)(row + 8) * DD + col;
                float2 x1 = *(const float2*)(X2 + r1);
                float2 x2 = *(const float2*)(X2 + r2);
                *(float2*)(C + r1) = make_float2(lo.x + bv.x + x1.x, lo.y + bv.y + x1.y);
                *(float2*)(C + r2) = make_float2(hi.x + bv.x + x2.x, hi.y + bv.y + x2.y);
            } else if constexpr (EPI == 5) {
                float* C = (float*)Cv;
                int b = z >> 3, h = z & 7;
                size_t r1 = ((size_t)b * NN + row    ) * DD + h * 64 + col;
                size_t r2 = ((size_t)b * NN + row + 8) * DD + h * 64 + col;
                float2 y1 = *(float2*)(C + r1);
                float2 y2 = *(float2*)(C + r2);
                *(float2*)(C + r1) = make_float2(y1.x + lo.x, y1.y + lo.y);
                *(float2*)(C + r2) = make_float2(y2.x + hi.x, y2.y + hi.y);
            }
        }
    }
}

// ---------------------------------------------------------------------------
// Fused sim1 + softmax -> h1 bf16 (unchanged)
// ---------------------------------------------------------------------------
__global__ __launch_bounds__(256) void sim1_fused() {
    __shared__ uint32_t As[16][72];
    __shared__ uint32_t Bs[16][264];
    __shared__ float rmax[64][5];
    __shared__ float rsum[64][5];

    int tid = threadIdx.x, lane = tid & 31, warp = tid >> 5;
    int wm0 = (warp >> 2) * 32;
    int wn0 = (warp & 3) * 64;
    int bh = blockIdx.z;
    int m0 = blockIdx.y * 64;
    const float* Ab = g_q  + ((size_t)bh * NN + m0) * DH;
    const float* Bb = g_kl + (size_t)bh * MM * DH;

    float acc[2][8][4];
    #pragma unroll
    for (int i = 0; i < 2; i++)
        #pragma unroll
        for (int j = 0; j < 8; j++)
            #pragma unroll
            for (int r = 0; r < 4; r++) acc[i][j][r] = 0.f;

    for (int k0 = 0; k0 < 64; k0 += 32) {
        #pragma unroll
        for (int c = 0; c < 2; c++) {
            int id = c * 256 + tid;
            int m = id >> 3, kq = id & 7;
            float4 v = *(const float4*)(Ab + (size_t)m * DH + k0 + kq * 4);
            As[kq*2+0][m] = f2bf2(v.x, v.y);
            As[kq*2+1][m] = f2bf2(v.z, v.w);
        }
        #pragma unroll
        for (int c = 0; c < 8; c++) {
            int id = c * 256 + tid;
            int n = id >> 3, kq = id & 7;
            float4 v = *(const float4*)(Bb + (size_t)n * DH + k0 + kq * 4);
            Bs[kq*2+0][n] = f2bf2(v.x, v.y);
            Bs[kq*2+1][n] = f2bf2(v.z, v.w);
        }
        __syncthreads();
        #pragma unroll
        for (int ks = 0; ks < 2; ks++) {
            uint32_t af[2][4], bfr[8][2];
            int kr = ks * 8 + (lane & 3);
            int mr = wm0 + (lane >> 2);
            #pragma unroll
            for (int mt = 0; mt < 2; mt++) {
                af[mt][0] = As[kr    ][mr + mt*16];
                af[mt][1] = As[kr    ][mr + mt*16 + 8];
                af[mt][2] = As[kr + 4][mr + mt*16];
                af[mt][3] = As[kr + 4][mr + mt*16 + 8];
            }
            int nr = wn0 + (lane >> 2);
            #pragma unroll
            for (int nt = 0; nt < 8; nt++) {
                bfr[nt][0] = Bs[kr    ][nr + nt*8];
                bfr[nt][1] = Bs[kr + 4][nr + nt*8];
            }
            #pragma unroll
            for (int mt = 0; mt < 2; mt++)
                #pragma unroll
                for (int nt = 0; nt < 8; nt++)
                    mma16(acc[mt][nt], af[mt], bfr[nt]);
        }
        __syncthreads();
    }

    int g = lane >> 2, q4 = lane & 3;
    int wn = warp & 3;
    #pragma unroll
    for (int mt = 0; mt < 2; mt++) {
        int r0 = wm0 + mt * 16 + g;
        float m0v = -1e30f, m1v = -1e30f;
        #pragma unroll
        for (int nt = 0; nt < 8; nt++) {
            m0v = fmaxf(m0v, fmaxf(acc[mt][nt][0], acc[mt][nt][1]));
            m1v = fmaxf(m1v, fmaxf(acc[mt][nt][2], acc[mt][nt][3]));
        }
        #pragma unroll
        for (int o = 1; o < 4; o <<= 1) {
            m0v = fmaxf(m0v, __shfl_xor_sync(~0u, m0v, o));
            m1v = fmaxf(m1v, __shfl_xor_sync(~0u, m1v, o));
        }
        if (q4 == 0) { rmax[r0][wn] = m0v; rmax[r0 + 8][wn] = m1v; }
    }
    __syncthreads();
    #pragma unroll
    for (int mt = 0; mt < 2; mt++) {
        int r0 = wm0 + mt * 16 + g;
        float M0 = fmaxf(fmaxf(rmax[r0][0], rmax[r0][1]), fmaxf(rmax[r0][2], rmax[r0][3]));
        float M1 = fmaxf(fmaxf(rmax[r0+8][0], rmax[r0+8][1]), fmaxf(rmax[r0+8][2], rmax[r0+8][3]));
        float s0 = 0.f, s1 = 0.f;
        #pragma unroll
        for (int nt = 0; nt < 8; nt++) {
            acc[mt][nt][0] = __expf(acc[mt][nt][0] - M0);
            acc[mt][nt][1] = __expf(acc[mt][nt][1] - M0);
            acc[mt][nt][2] = __expf(acc[mt][nt][2] - M1);
            acc[mt][nt][3] = __expf(acc[mt][nt][3] - M1);
            s0 += acc[mt][nt][0] + acc[mt][nt][1];
            s1 += acc[mt][nt][2] + acc[mt][nt][3];
        }
        #pragma unroll
        for (int o = 1; o < 4; o <<= 1) {
            s0 += __shfl_xor_sync(~0u, s0, o);
            s1 += __shfl_xor_sync(~0u, s1, o);
        }
        if (q4 == 0) { rsum[r0][wn] = s0; rsum[r0 + 8][wn] = s1; }
    }
    __syncthreads();
    __nv_bfloat16* O = g_h1 + ((size_t)bh * NN + m0) * MM;
    #pragma unroll
    for (int mt = 0; mt < 2; mt++) {
        int r0 = wm0 + mt * 16 + g;
        float i0 = 1.f / (rsum[r0][0] + rsum[r0][1] + rsum[r0][2] + rsum[r0][3]);
        float i1 = 1.f / (rsum[r0+8][0] + rsum[r0+8][1] + rsum[r0+8][2] + rsum[r0+8][3]);
        #pragma unroll
        for (int nt = 0; nt < 8; nt++) {
            int col = wn0 + nt * 8 + q4 * 2;
            *(uint32_t*)(O + (size_t)r0 * MM + col) =
                f2bf2(acc[mt][nt][0] * i0, acc[mt][nt][1] * i0);
            *(uint32_t*)(O + (size_t)(r0 + 8) * MM + col) =
                f2bf2(acc[mt][nt][2] * i1, acc[mt][nt][3] * i1);
        }
    }
}

__global__ __launch_bounds__(128) void ln_kernel(const float* __restrict__ x,
                                                 const float* __restrict__ w,
                                                 const float* __restrict__ bia) {
    int row = blockIdx.x, tid = threadIdx.x;
    const float4* xr = reinterpret_cast<const float4*>(x + (size_t)row * DD);
    float4 v = xr[tid];
    float s  = v.x + v.y + v.z + v.w;
    float sq = v.x*v.x + v.y*v.y + v.z*v.z + v.w*v.w;
    __shared__ float sm[4], sm2[4];
    #pragma unroll
    for (int o = 16; o > 0; o >>= 1) {
        s  += __shfl_down_sync(0xffffffffu, s,  o);
        sq += __shfl_down_sync(0xffffffffu, sq, o);
    }
    if ((tid & 31) == 0) { sm[tid >> 5] = s; sm2[tid >> 5] = sq; }
    __syncthreads();
    if (tid == 0) {
        float a = 0.f, b2 = 0.f;
        #pragma unroll
        for (int i = 0; i < 4; i++) { a += sm[i]; b2 += sm2[i]; }
        sm[0] = a; sm2[0] = b2;
    }
    __syncthreads();
    float mean = sm[0] * (1.f / 512.f);
    float var  = sm2[0] * (1.f / 512.f) - mean * mean;
    float rstd = rsqrtf(var + 1e-5f);
    float4 wv = reinterpret_cast<const float4*>(w)[tid];
    float4 bv = reinterpret_cast<const float4*>(bia)[tid];
    float4 o;
    o.x = (v.x - mean) * rstd * wv.x + bv.x;
    o.y = (v.y - mean) * rstd * wv.y + bv.y;
    o.z = (v.z - mean) * rstd * wv.z + bv.z;
    o.w = (v.w - mean) * rstd * wv.w + bv.w;
    reinterpret_cast<float4*>(g_xn + (size_t)row * DD)[tid] = o;
}

__global__ void landmark_kernel() {
    int m = blockIdx.x, bh = blockIdx.y;
    int d = threadIdx.x;
    size_t base = ((size_t)bh * NN + (size_t)m * 32) * DH + d;
    float sq = 0.f, sk = 0.f;
    #pragma unroll
    for (int j = 0; j < 32; j++) {
        sq += g_q[base + (size_t)j * DH];
        sk += g_k[base + (size_t)j * DH];
    }
    size_t o = ((size_t)bh * MM + m) * DH + d;
    g_ql[o] = sq * (1.f / 32.f);
    g_kl[o] = sk * (1.f / 32.f);
}

__global__ __launch_bounds__(256) void gemm_sim2() {
    __shared__ float As[32][132];
    __shared__ float Bs[32][132];
    int bh = blockIdx.z;
    int n0 = blockIdx.x * 128, m0 = blockIdx.y * 128;
    const float* Ab = g_ql + ((size_t)bh * MM + m0) * DH;
    const float* Bb = g_kl + ((size_t)bh * MM + n0) * DH;
    float* Cb = g_attn2 + (size_t)bh * MM * MM;
    int tid = threadIdx.x;
    int tx = tid & 15, ty = tid >> 4;
    float acc[8][8] = {};
    for (int kk = 0; kk < 64; kk += 32) {
        #pragma unroll
        for (int u = 0; u < 4; u++) {
            int g = u * 256 + tid;
            int m = g >> 3, k4 = g & 7;
            float4 av = *(const float4*)(Ab + (size_t)m * DH + kk + k4 * 4);
            As[k4*4+0][m] = av.x; As[k4*4+1][m] = av.y;
            As[k4*4+2][m] = av.z; As[k4*4+3][m] = av.w;
        }
        #pragma unroll
        for (int u = 0; u < 4; u++) {
            int g = u * 256 + tid;
            int m = g >> 3, k4 = g & 7;
            float4 bv = *(const float4*)(Bb + (size_t)m * DH + kk + k4 * 4);
            Bs[k4*4+0][m] = bv.x; Bs[k4*4+1][m] = bv.y;
            Bs[k4*4+2][m] = bv.z; Bs[k4*4+3][m] = bv.w;
        }
        __syncthreads();
        #pragma unroll
        for (int k = 0; k < 32; k++) {
            float a[8], b[8];
            *(float4*)&a[0] = *(const float4*)&As[k][ty*8];
            *(float4*)&a[4] = *(const float4*)&As[k][ty*8+4];
            *(float4*)&b[0] = *(const float4*)&Bs[k][tx*8];
            *(float4*)&b[4] = *(const float4*)&Bs[k][tx*8+4];
            #pragma unroll
            for (int i = 0; i < 8; i++)
                #pragma unroll
                for (int j = 0; j < 8; j++)
                    acc[i][j] += a[i] * b[j];
        }
        __syncthreads();
    }
    #pragma unroll
    for (int i = 0; i < 8; i++) {
        size_t r = (size_t)(m0 + ty * 8 + i) * MM + n0 + tx * 8;
        *(float4*)(Cb + r)     = make_float4(acc[i][0], acc[i][1], acc[i][2], acc[i][3]);
        *(float4*)(Cb + r + 4) = make_float4(acc[i][4], acc[i][5], acc[i][6], acc[i][7]);
    }
}

__global__ __launch_bounds__(256) void softmax256() {
    int row = blockIdx.x, tid = threadIdx.x;
    float* p = g_attn2 + (size_t)row * MM;
    float v = p[tid];
    __shared__ float red[8];
    float m = v;
    #pragma unroll
    for (int o = 16; o; o >>= 1) m = fmaxf(m, __shfl_xor_sync(~0u, m, o));
    if ((tid & 31) == 0) red[tid >> 5] = m;
    __syncthreads();
    if (tid < 32) {
        float t = (tid < 8) ? red[tid] : -1e30f;
        #pragma unroll
        for (int o = 4; o; o >>= 1) t = fmaxf(t, __shfl_xor_sync(~0u, t, o));
        if (tid == 0) red[0] = t;
    }
    __syncthreads();
    float mx = red[0];
    __syncthreads();
    float e = __expf(v - mx);
    float s = e;
    #pragma unroll
    for (int o = 16; o; o >>= 1) s += __shfl_xor_sync(~0u, s, o);
    if ((tid & 31) == 0) red[tid >> 5] = s;
    __syncthreads();
    if (tid < 32) {
        float t = (tid < 8) ? red[tid] : 0.f;
        #pragma unroll
        for (int o = 4; o; o >>= 1) t += __shfl_xor_sync(~0u, t, o);
        if (tid == 0) red[0] = t;
    }
    __syncthreads();
    p[tid] = e / red[0];
}

__global__ void init_max_kernel() { g_maxA = 0; g_maxB = 0; }

__global__ __launch_bounds__(256) void colrowmax_kernel() {
    int bh = blockIdx.x, tid = threadIdx.x;
    const float* a = g_attn2 + (size_t)bh * MM * MM;
    float cs = 0.f, rs = 0.f;
    for (int m = 0; m < MM; m++) cs += fabsf(a[(size_t)m * MM + tid]);
    for (int n = 0; n < MM; n++) rs += fabsf(a[(size_t)tid * MM + n]);
    __shared__ float r1[8], r2[8];
    #pragma unroll
    for (int o = 16; o; o >>= 1) {
        cs = fmaxf(cs, __shfl_xor_sync(~0u, cs, o));
        rs = fmaxf(rs, __shfl_xor_sync(~0u, rs, o));
    }
    if ((tid & 31) == 0) { r1[tid >> 5] = cs; r2[tid >> 5] = rs; }
    __syncthreads();
    if (tid == 0) {
        float a1 = r1[0], a2 = r2[0];
        #pragma unroll
        for (int i = 1; i < 8; i++) { a1 = fmaxf(a1, r1[i]); a2 = fmaxf(a2, r2[i]); }
        atomicMax(&g_maxA, __float_as_int(a1));
        atomicMax(&g_maxB, __float_as_int(a2));
    }
}

__global__ __launch_bounds__(256) void z0_kernel() {
    int bh = blockIdx.z;
    int c0 = blockIdx.x * 32, r0 = blockIdx.y * 32;
    int tid = threadIdx.x;
    __shared__ float t[32][33];
    const float* a = g_attn2 + (size_t)bh * MM * MM;
    #pragma unroll
    for (int rr = 0; rr < 4; rr++) {
        int r = rr * 8 + (tid >> 5), c = tid & 31;
        t[r][c] = a[(size_t)(r0 + r) * MM + c0 + c];
    }
    __syncthreads();
    float s = 1.f / (__int_as_float(g_maxA) * __int_as_float(g_maxB));
    float* z = g_z + (size_t)bh * MM * MM;
    #pragma unroll
    for (int rr = 0; rr < 4; rr++) {
        int r = rr * 8 + (tid >> 5), c = tid & 31;
        z[(size_t)(c0 + r) * MM + r0 + c] = t[c][r] * s;
    }
}

__global__ __launch_bounds__(256) void matmul_ba128(const float* __restrict__ P,
                                                    const float* __restrict__ Q,
                                                    const float* __restrict__ R,
                                                    float* __restrict__ C,
                                                    float alpha, float beta) {
    __shared__ float As[16][132];
    __shared__ float Bs[16][132];
    size_t base = (size_t)blockIdx.z * (MM * MM);
    int m0 = blockIdx.y * 128, n0 = blockIdx.x * 128;
    int tid = threadIdx.x;
    int tx = tid & 15, ty = tid >> 4;
    float acc[8][8] = {};
    for (int kk = 0; kk < 256; kk += 16) {
        #pragma unroll
        for (int u = 0; u < 2; u++) {
            int g = u * 256 + tid;
            int m = g >> 2, k4 = g & 3;
            float4 av = *(const float4*)(P + base + (size_t)(m0 + m) * MM + kk + k4 * 4);
            As[k4*4+0][m] = av.x; As[k4*4+1][m] = av.y;
            As[k4*4+2][m] = av.z; As[k4*4+3][m] = av.w;
        }
        #pragma unroll
        for (int u = 0; u < 2; u++) {
            int g = u * 256 + tid;
            int k = g >> 5, n4 = g & 31;
            *(float4*)&Bs[k][n4*4] =
                *(const float4*)(Q + base + (size_t)(kk + k) * MM + n0 + n4 * 4);
        }
        __syncthreads();
        #pragma unroll
        for (int k = 0; k < 16; k++) {
            float a[8], b[8];
            *(float4*)&a[0] = *(const float4*)&As[k][ty*8];
            *(float4*)&a[4] = *(const float4*)&As[k][ty*8+4];
            *(float4*)&b[0] = *(const float4*)&Bs[k][tx*8];
            *(float4*)&b[4] = *(const float4*)&Bs[k][tx*8+4];
            #pragma unroll
            for (int i = 0; i < 8; i++)
                #pragma unroll
                for (int j = 0; j < 8; j++)
                    acc[i][j] += a[i] * b[j];
        }
        __syncthreads();
    }
    #pragma unroll
    for (int i = 0; i < 8; i++) {
        #pragma unroll
        for (int jj = 0; jj < 2; jj++) {
            size_t off = base + (size_t)(m0 + ty * 8 + i) * MM + n0 + tx * 8 + jj * 4;
            float4 rv = make_float4(0.f, 0.f, 0.f, 0.f);
            if (beta != 0.f) rv = *(const float4*)(R + off);
            float4 o;
            o.x = alpha * acc[i][jj*4+0] + beta * rv.x;
            o.y = alpha * acc[i][jj*4+1] + beta * rv.y;
            o.z = alpha * acc[i][jj*4+2] + beta * rv.z;
            o.w = alpha * acc[i][jj*4+3] + beta * rv.w;
            *(float4*)(C + off) = o;
        }
    }
}

__global__ __launch_bounds__(256) void conv_kernel(const float* __restrict__ res_w) {
    __shared__ float sv[160][64];
    __shared__ float sw[33];
    int bh = blockIdx.y, n0 = blockIdx.x * 128;
    int b = bh >> 3, h = bh & 7;
    int tid = threadIdx.x;
    if (tid < 33) sw[tid] = res_w[h * 33 + tid];
    const float* vb = g_v + (size_t)bh * NN * DH;
    #pragma unroll
    for (int i = 0; i < 10; i++) {
        int idx = tid + i * 256;
        int r = idx >> 4, c4 = idx & 15;
        int tok = n0 - 16 + r;
        float4 val = make_float4(0.f, 0.f, 0.f, 0.f);
        if (tok >= 0 && tok < NN)
            val = *(const float4*)(vb + (size_t)tok * DH + c4 * 4);
        *(float4*)&sv[r][c4 * 4] = val;
    }
    __syncthreads();
    #pragma unroll
    for (int i = 0; i < 8; i++) {
        int idx = tid + i * 256;
        int nl = idx >> 4, dg = idx & 15;
        float4 acc = make_float4(0.f, 0.f, 0.f, 0.f);
        #pragma unroll
        for (int j = 0; j < 33; j++) {
            float w = sw[j];
            float4 vv = *(const float4*)&sv[nl + j][dg * 4];
            acc.x += w * vv.x; acc.y += w * vv.y;
            acc.z += w * vv.z; acc.w += w * vv.w;
        }
        *(float4*)(g_y + ((size_t)b * NN + n0 + nl) * DD + h * 64 + dg * 4) = acc;
    }
}

extern "C" void kernel_launch(void* const* d_in, const int* in_sizes, int n_in,
                              void* d_out, int out_size) {
    const float* x     = (const float*)d_in[0];
    const float* ln_w  = (const float*)d_in[1];
    const float* ln_b  = (const float*)d_in[2];
    const float* w_qkv = (const float*)d_in[3];
    const float* w_out = (const float*)d_in[4];
    const float* b_out = (const float*)d_in[5];
    const float* res_w = (const float*)d_in[6];
    float* out = (float*)d_out;

    float *p_xn, *p_attn2, *p_z, *p_z2, *p_xz, *p_t, *p_u;
    float *p_out3, *p_wc, *p_y;
    void *p_h1;
    cudaGetSymbolAddress((void**)&p_xn, g_xn);
    cudaGetSymbolAddress((void**)&p_attn2, g_attn2);
    cudaGetSymbolAddress((void**)&p_z,  g_z);
    cudaGetSymbolAddress((void**)&p_z2, g_z2);
    cudaGetSymbolAddress((void**)&p_xz, g_xz);
    cudaGetSymbolAddress((void**)&p_t,  g_t);
    cudaGetSymbolAddress((void**)&p_u,  g_u);
    cudaGetSymbolAddress(&p_h1, g_h1);
    cudaGetSymbolAddress((void**)&p_out3, g_out3);
    cudaGetSymbolAddress((void**)&p_wc, g_wc);
    cudaGetSymbolAddress((void**)&p_y,  g_y);

    cudaFuncSetAttribute(flash3, cudaFuncAttributeMaxDynamicSharedMemorySize, 58368);

    ln_kernel<<<BB * NN, 128>>>(x, ln_w, ln_b);
    bf_gemm<0,128,128,32,false,false><<<dim3(12, 256, 1), 256>>>(
        p_xn, w_qkv, nullptr, nullptr, nullptr,
        1536, 512, 512, 1536, 0, 0, 0);
    landmark_kernel<<<dim3(MM, BH), 64>>>();

    gemm_sim2<<<dim3(2, 2, BH), 256>>>();
    sim1_fused<<<dim3(1, 128, BH), 256>>>();

    // flash attn3 (replaces sim3 + softmax8192 + pv + reduce)
    flash3<<<dim3(2, KS, BH), 256, 58368>>>();
    combine3<<<1024, 256>>>();

    softmax256<<<BH * MM, 256>>>();

    init_max_kernel<<<1, 1>>>();
    colrowmax_kernel<<<BH, 256>>>();
    z0_kernel<<<dim3(8, 8, BH), 256>>>();

    dim3 gba(2, 2, BH);
    float *zc = p_z, *zn = p_z2;
    for (int it = 0; it < 5; it++) {
        tc_gemm<4,128,128,16><<<gba, 256>>>(p_attn2, zc, p_xz, nullptr,
            MM, 256, 256, 256, (long long)MM*MM, (long long)MM*MM, (long long)MM*MM, 1.f, 0.f);
        tc_gemm<4,128,128,16><<<gba, 256>>>(p_xz, p_xz, p_t, p_xz,
            MM, 256, 256, 256, (long long)MM*MM, (long long)MM*MM, (long long)MM*MM, -1.f, 7.f);
        tc_gemm<4,128,128,16><<<gba, 256>>>(p_xz, p_t, p_u, p_xz,
            MM, 256, 256, 256, (long long)MM*MM, (long long)MM*MM, (long long)MM*MM, -1.f, 15.f);
        tc_gemm<4,128,128,16><<<gba, 256>>>(zc, p_u, zn, zc,
            MM, 256, 256, 256, (long long)MM*MM, (long long)MM*MM, (long long)MM*MM, -0.25f, 3.25f);
        float* tmp = zc; zc = zn; zn = tmp;
    }
    matmul_ba128<<<gba, 256>>>(p_attn2, zc, nullptr, p_xz, 1.f, 0.f);
    matmul_ba128<<<gba, 256>>>(p_xz, p_xz, p_xz, p_t, -1.f, 7.f);
    matmul_ba128<<<gba, 256>>>(p_xz, p_t, p_xz, p_u, -1.f, 15.f);
    matmul_ba128<<<gba, 256>>>(zc, p_u, zc, zn, -0.25f, 3.25f);
    { float* tmp = zc; zc = zn; zn = tmp; }

    tc_gemm<2,128,64,16><<<dim3(1, 2, BH), 256>>>(
        zc, p_out3, p_wc, nullptr,
        64, 256, 256, 64, (long long)MM*MM, (long long)MM*DH, (long long)MM*DH, 0.f, 0.f);

    conv_kernel<<<dim3(64, BH), 256>>>(res_w);
    bf_gemm<5,128,64,32,false,true><<<dim3(1, 64, BH), 256>>>(
        p_h1, p_wc, p_y, nullptr, nullptr,
        64, 256, 256, 64, (long long)NN*MM, (long long)MM*DH, 0);

    bf_gemm<1,128,128,32,false,false><<<dim3(4, 256, 1), 256>>>(
        p_y, w_out, out, b_out, x,
        512, 512, 512, 512, 0, 0, 0);
}

// round 11
// speedup vs baseline: 1.3421x; 1.2636x over previous
#include <cuda_runtime.h>
#include <cuda_bf16.h>
#include <stdint.h>
#include <math.h>

#define BB 4
#define NN 8192
#define DD 512
#define HH 8
#define DH 64
#define MM 256
#define BH 32
#define KS 16

__device__ __align__(16) float g_xn  [(size_t)BB*NN*DD];
__device__ __align__(16) float g_q   [(size_t)BH*NN*DH];
__device__ __align__(16) float g_k   [(size_t)BH*NN*DH];
__device__ __align__(16) float g_v   [(size_t)BH*NN*DH];
__device__ __align__(16) float g_ql  [(size_t)BH*MM*DH];
__device__ __align__(16) float g_kl  [(size_t)BH*MM*DH];
__device__ __align__(16) float g_attn2[(size_t)BH*MM*MM];
__device__ __align__(16) float g_z   [(size_t)BH*MM*MM];
__device__ __align__(16) float g_z2  [(size_t)BH*MM*MM];
__device__ __align__(16) float g_xz  [(size_t)BH*MM*MM];
__device__ __align__(16) float g_t   [(size_t)BH*MM*MM];
__device__ __align__(16) float g_u   [(size_t)BH*MM*MM];
__device__ __align__(16) float g_p3  [(size_t)BH*KS*MM*DH];
__device__ __align__(16) float g_m3  [(size_t)BH*KS*MM];
__device__ __align__(16) float g_l3  [(size_t)BH*KS*MM];
__device__ __align__(16) float g_out3[(size_t)BH*MM*DH];
__device__ __align__(16) float g_wc  [(size_t)BH*MM*DH];
__device__ __align__(16) float g_y   [(size_t)BB*NN*DD];
__device__ int g_maxA;
__device__ int g_maxB;
__device__ int g_barc[32];

__device__ __forceinline__ uint32_t f2tf(float f) {
    uint32_t u;
    asm("cvt.rna.tf32.f32 %0, %1;" : "=r"(u) : "f"(f));
    return u;
}
__device__ __forceinline__ uint32_t f2bf2(float lo, float hi) {
    uint32_t r;
    asm("cvt.rn.bf16x2.f32 %0, %1, %2;" : "=r"(r) : "f"(hi), "f"(lo));
    return r;
}
__device__ __forceinline__ void mma8(float* d, const uint32_t* a, const uint32_t* b) {
    asm volatile(
        "mma.sync.aligned.m16n8k8.row.col.f32.tf32.tf32.f32 "
        "{%0,%1,%2,%3}, {%4,%5,%6,%7}, {%8,%9}, {%0,%1,%2,%3};"
        : "+f"(d[0]), "+f"(d[1]), "+f"(d[2]), "+f"(d[3])
        : "r"(a[0]), "r"(a[1]), "r"(a[2]), "r"(a[3]), "r"(b[0]), "r"(b[1]));
}
__device__ __forceinline__ void mma16(float* d, const uint32_t* a, const uint32_t* b) {
    asm volatile(
        "mma.sync.aligned.m16n8k16.row.col.f32.bf16.bf16.f32 "
        "{%0,%1,%2,%3}, {%4,%5,%6,%7}, {%8,%9}, {%0,%1,%2,%3};"
        : "+f"(d[0]), "+f"(d[1]), "+f"(d[2]), "+f"(d[3])
        : "r"(a[0]), "r"(a[1]), "r"(a[2]), "r"(a[3]), "r"(b[0]), "r"(b[1]));
}

// ---------------------------------------------------------------------------
// Flash split-KV attn3 (unchanged from R9)
// ---------------------------------------------------------------------------
__global__ __launch_bounds__(256) void flash3() {
    extern __shared__ char smraw[];
    uint32_t* Qs = (uint32_t*)smraw;
    uint32_t* Ksm = Qs + 32*136;
    uint32_t* Vsm = Ksm + 32*72;
    uint32_t* Ps = Vsm + 32*72;
    float* wmax = (float*)(Ps + 32*136);
    float* wsum = wmax + 512;
    float* mrun = wsum + 512;
    float* lrun = mrun + 128;

    int tid = threadIdx.x, lane = tid & 31, warp = tid >> 5;
    int g = lane >> 2, q4 = lane & 3;
    int wm0 = (warp >> 2) * 64;
    int wn0 = (warp & 3) * 16;
    int wn = warp & 3;
    int m0 = blockIdx.x * 128;
    int ksp = blockIdx.y, bh = blockIdx.z;

    const float* Qg = g_ql + ((size_t)bh * MM + m0) * DH;
    #pragma unroll
    for (int c = 0; c < 8; c++) {
        int id = c * 256 + tid;
        int m = id >> 4, qq = id & 15;
        float4 v = *(const float4*)(Qg + (size_t)m * DH + qq * 4);
        Qs[(qq*2+0)*136 + m] = f2bf2(v.x, v.y);
        Qs[(qq*2+1)*136 + m] = f2bf2(v.z, v.w);
    }
    if (tid < 128) { mrun[tid] = -1e30f; lrun[tid] = 0.f; }

    float acc[4][2][4];
    #pragma unroll
    for (int a = 0; a < 4; a++)
        #pragma unroll
        for (int b = 0; b < 2; b++)
            #pragma unroll
            for (int r = 0; r < 4; r++) acc[a][b][r] = 0.f;

    const float* Kg = g_k + ((size_t)bh * NN + ksp * 512) * DH;
    const float* Vg = g_v + ((size_t)bh * NN + ksp * 512) * DH;

    for (int t = 0; t < 8; t++) {
        __syncthreads();
        #pragma unroll
        for (int c = 0; c < 4; c++) {
            int id = c * 256 + tid;
            int n = id >> 4, qq = id & 15;
            float4 v = *(const float4*)(Kg + (size_t)(t*64 + n) * DH + qq * 4);
            Ksm[(qq*2+0)*72 + n] = f2bf2(v.x, v.y);
            Ksm[(qq*2+1)*72 + n] = f2bf2(v.z, v.w);
        }
        #pragma unroll
        for (int c = 0; c < 2; c++) {
            int id = c * 256 + tid;
            int kp = id >> 4, qq = id & 15;
            float4 lo = *(const float4*)(Vg + (size_t)(t*64 + 2*kp    ) * DH + qq * 4);
            float4 hi = *(const float4*)(Vg + (size_t)(t*64 + 2*kp + 1) * DH + qq * 4);
            Vsm[kp*72 + qq*4+0] = f2bf2(lo.x, hi.x);
            Vsm[kp*72 + qq*4+1] = f2bf2(lo.y, hi.y);
            Vsm[kp*72 + qq*4+2] = f2bf2(lo.z, hi.z);
            Vsm[kp*72 + qq*4+3] = f2bf2(lo.w, hi.w);
        }
        __syncthreads();

        float S[4][2][4];
        #pragma unroll
        for (int a = 0; a < 4; a++)
            #pragma unroll
            for (int b = 0; b < 2; b++)
                #pragma unroll
                for (int r = 0; r < 4; r++) S[a][b][r] = 0.f;
        #pragma unroll
        for (int k2 = 0; k2 < 4; k2++) {
            int kr = k2 * 8 + q4;
            uint32_t af[4][4], bfr[2][2];
            int mr = wm0 + g;
            #pragma unroll
            for (int mt = 0; mt < 4; mt++) {
                af[mt][0] = Qs[kr*136 + mr + mt*16];
                af[mt][1] = Qs[kr*136 + mr + mt*16 + 8];
                af[mt][2] = Qs[(kr+4)*136 + mr + mt*16];
                af[mt][3] = Qs[(kr+4)*136 + mr + mt*16 + 8];
            }
            int nr = wn0 + g;
            #pragma unroll
            for (int nt = 0; nt < 2; nt++) {
                bfr[nt][0] = Ksm[kr*72 + nr + nt*8];
                bfr[nt][1] = Ksm[(kr+4)*72 + nr + nt*8];
            }
            #pragma unroll
            for (int mt = 0; mt < 4; mt++)
                #pragma unroll
                for (int nt = 0; nt < 2; nt++)
                    mma16(S[mt][nt], af[mt], bfr[nt]);
        }

        #pragma unroll
        for (int mt = 0; mt < 4; mt++) {
            float m0v = fmaxf(fmaxf(S[mt][0][0], S[mt][0][1]), fmaxf(S[mt][1][0], S[mt][1][1]));
            float m1v = fmaxf(fmaxf(S[mt][0][2], S[mt][0][3]), fmaxf(S[mt][1][2], S[mt][1][3]));
            #pragma unroll
            for (int o = 1; o < 4; o <<= 1) {
                m0v = fmaxf(m0v, __shfl_xor_sync(~0u, m0v, o));
                m1v = fmaxf(m1v, __shfl_xor_sync(~0u, m1v, o));
            }
            if (q4 == 0) {
                wmax[(wm0 + mt*16 + g)*4 + wn] = m0v;
                wmax[(wm0 + mt*16 + g + 8)*4 + wn] = m1v;
            }
        }
        __syncthreads();

        #pragma unroll
        for (int mt = 0; mt < 4; mt++) {
            int r0 = wm0 + mt*16 + g, r1 = r0 + 8;
            float mo0 = mrun[r0];
            float mt0 = fmaxf(fmaxf(wmax[r0*4+0], wmax[r0*4+1]), fmaxf(wmax[r0*4+2], wmax[r0*4+3]));
            float mn0 = fmaxf(mo0, mt0);
            float sc0 = __expf(mo0 - mn0);
            float mo1 = mrun[r1];
            float mt1 = fmaxf(fmaxf(wmax[r1*4+0], wmax[r1*4+1]), fmaxf(wmax[r1*4+2], wmax[r1*4+3]));
            float mn1 = fmaxf(mo1, mt1);
            float sc1 = __expf(mo1 - mn1);
            float s0 = 0.f, s1 = 0.f;
            #pragma unroll
            for (int nt = 0; nt < 2; nt++) {
                S[mt][nt][0] = __expf(S[mt][nt][0] - mn0);
                S[mt][nt][1] = __expf(S[mt][nt][1] - mn0);
                S[mt][nt][2] = __expf(S[mt][nt][2] - mn1);
                S[mt][nt][3] = __expf(S[mt][nt][3] - mn1);
                s0 += S[mt][nt][0] + S[mt][nt][1];
                s1 += S[mt][nt][2] + S[mt][nt][3];
                int cp = wn * 8 + nt * 4 + q4;
                Ps[cp*136 + r0] = f2bf2(S[mt][nt][0], S[mt][nt][1]);
                Ps[cp*136 + r1] = f2bf2(S[mt][nt][2], S[mt][nt][3]);
                acc[mt][nt][0] *= sc0; acc[mt][nt][1] *= sc0;
                acc[mt][nt][2] *= sc1; acc[mt][nt][3] *= sc1;
            }
            #pragma unroll
            for (int o = 1; o < 4; o <<= 1) {
                s0 += __shfl_xor_sync(~0u, s0, o);
                s1 += __shfl_xor_sync(~0u, s1, o);
            }
            if (q4 == 0) { wsum[r0*4+wn] = s0; wsum[r1*4+wn] = s1; }
        }
        __syncthreads();

        if (tid < 128) {
            float mo = mrun[tid];
            float mt2 = fmaxf(fmaxf(wmax[tid*4+0], wmax[tid*4+1]), fmaxf(wmax[tid*4+2], wmax[tid*4+3]));
            float mn = fmaxf(mo, mt2);
            mrun[tid] = mn;
            lrun[tid] = lrun[tid]*__expf(mo - mn) +
                        wsum[tid*4+0] + wsum[tid*4+1] + wsum[tid*4+2] + wsum[tid*4+3];
        }
        #pragma unroll
        for (int k2 = 0; k2 < 4; k2++) {
            int kr = k2 * 8 + q4;
            uint32_t af[4][4], bfr[2][2];
            int mr = wm0 + g;
            #pragma unroll
            for (int mt = 0; mt < 4; mt++) {
                af[mt][0] = Ps[kr*136 + mr + mt*16];
                af[mt][1] = Ps[kr*136 + mr + mt*16 + 8];
                af[mt][2] = Ps[(kr+4)*136 + mr + mt*16];
                af[mt][3] = Ps[(kr+4)*136 + mr + mt*16 + 8];
            }
            int nr = wn0 + g;
            #pragma unroll
            for (int nt = 0; nt < 2; nt++) {
                bfr[nt][0] = Vsm[kr*72 + nr + nt*8];
                bfr[nt][1] = Vsm[(kr+4)*72 + nr + nt*8];
            }
            #pragma unroll
            for (int mt = 0; mt < 4; mt++)
                #pragma unroll
                for (int nt = 0; nt < 2; nt++)
                    mma16(acc[mt][nt], af[mt], bfr[nt]);
        }
    }
    __syncthreads();

    size_t ob = (size_t)(bh * KS + ksp) * MM + m0;
    #pragma unroll
    for (int mt = 0; mt < 4; mt++) {
        #pragma unroll
        for (int nt = 0; nt < 2; nt++) {
            int r0 = wm0 + mt*16 + g;
            int c = wn0 + nt*8 + q4*2;
            *(float2*)(g_p3 + (ob + r0)*DH + c)     = make_float2(acc[mt][nt][0], acc[mt][nt][1]);
            *(float2*)(g_p3 + (ob + r0 + 8)*DH + c) = make_float2(acc[mt][nt][2], acc[mt][nt][3]);
        }
    }
    if (tid < 128) {
        g_m3[ob + tid] = mrun[tid];
        g_l3[ob + tid] = lrun[tid];
    }
}

__global__ __launch_bounds__(256) void combine3() {
    int warp = threadIdx.x >> 5, lane = threadIdx.x & 31;
    int rowg = blockIdx.x * 8 + warp;
    int bh = rowg >> 8, r = rowg & 255;
    size_t base = (size_t)(bh * KS) * MM + r;
    float mv = (lane < 16) ? g_m3[base + (size_t)lane * MM] : -1e30f;
    #pragma unroll
    for (int o = 16; o; o >>= 1) mv = fmaxf(mv, __shfl_xor_sync(~0u, mv, o));
    float M = mv;
    float lv = (lane < 16) ? g_l3[base + (size_t)lane * MM] *
                             __expf(g_m3[base + (size_t)lane * MM] - M) : 0.f;
    #pragma unroll
    for (int o = 16; o; o >>= 1) lv += __shfl_xor_sync(~0u, lv, o);
    float invL = 1.f / lv;
    float a0 = 0.f, a1 = 0.f;
    for (int kk = 0; kk < KS; kk++) {
        float w = __expf(g_m3[base + (size_t)kk * MM] - M);
        float2 p = *(const float2*)(g_p3 + (base + (size_t)kk * MM) * DH + lane * 2);
        a0 += p.x * w; a1 += p.y * w;
    }
    *(float2*)(g_out3 + ((size_t)bh * MM + r) * DH + lane * 2) =
        make_float2(a0 * invL, a1 * invL);
}

// ---------------------------------------------------------------------------
// TF32 128x128xK device matmul (used by persistent pinv)
// ---------------------------------------------------------------------------
__device__ __forceinline__ void tc_tile(
    const float* Ab, const float* Bb, float* C, const float* X1,
    int N, int K, int lda, int ldb, long long cbase,
    float alpha, float beta, int m0, int n0,
    uint32_t (*As)[16][136], uint32_t (*Bs)[16][136])
{
    constexpr int BK = 16;
    int tid = threadIdx.x, lane = tid & 31, warp = tid >> 5;
    int wm0 = (warp >> 2) * 64;
    int wn0 = (warp & 3) * 32;
    float4 ra[2], rb[2];
    float acc[4][4][4];
    #pragma unroll
    for (int i = 0; i < 4; i++)
        #pragma unroll
        for (int j = 0; j < 4; j++)
            #pragma unroll
            for (int r = 0; r < 4; r++) acc[i][j][r] = 0.f;

    auto LOAD = [&](int kb) {
        #pragma unroll
        for (int c = 0; c < 2; c++) {
            int id = c * 256 + tid;
            int m = id >> 2, kq = id & 3;
            ra[c] = *(const float4*)(Ab + (size_t)(m0 + m) * lda + kb * BK + kq * 4);
        }
        #pragma unroll
        for (int c = 0; c < 2; c++) {
            int id = c * 256 + tid;
            int k = id >> 5, nq = id & 31;
            rb[c] = *(const float4*)(Bb + (size_t)(kb * BK + k) * ldb + n0 + nq * 4);
        }
    };
    auto COMMIT = [&](int bf) {
        #pragma unroll
        for (int c = 0; c < 2; c++) {
            int id = c * 256 + tid;
            int m = id >> 2, kq = id & 3;
            As[bf][kq*4+0][m] = f2tf(ra[c].x); As[bf][kq*4+1][m] = f2tf(ra[c].y);
            As[bf][kq*4+2][m] = f2tf(ra[c].z); As[bf][kq*4+3][m] = f2tf(ra[c].w);
        }
        #pragma unroll
        for (int c = 0; c < 2; c++) {
            int id = c * 256 + tid;
            int k = id >> 5, nq = id & 31;
            Bs[bf][k][nq*4+0] = f2tf(rb[c].x); Bs[bf][k][nq*4+1] = f2tf(rb[c].y);
            Bs[bf][k][nq*4+2] = f2tf(rb[c].z); Bs[bf][k][nq*4+3] = f2tf(rb[c].w);
        }
    };
    auto MMA = [&](int bf) {
        #pragma unroll
        for (int ks = 0; ks < 2; ks++) {
            uint32_t af[4][4], bfr[4][2];
            int kr = ks * 8 + (lane & 3);
            int mr = wm0 + (lane >> 2);
            #pragma unroll
            for (int mt = 0; mt < 4; mt++) {
                af[mt][0] = As[bf][kr    ][mr + mt*16];
                af[mt][1] = As[bf][kr    ][mr + mt*16 + 8];
                af[mt][2] = As[bf][kr + 4][mr + mt*16];
                af[mt][3] = As[bf][kr + 4][mr + mt*16 + 8];
            }
            int nr = wn0 + (lane >> 2);
            #pragma unroll
            for (int nt = 0; nt < 4; nt++) {
                bfr[nt][0] = Bs[bf][kr    ][nr + nt*8];
                bfr[nt][1] = Bs[bf][kr + 4][nr + nt*8];
            }
            #pragma unroll
            for (int mt = 0; mt < 4; mt++)
                #pragma unroll
                for (int nt = 0; nt < 4; nt++)
                    mma8(acc[mt][nt], af[mt], bfr[nt]);
        }
    };

    int nk = K / BK;
    LOAD(0); COMMIT(0);
    __syncthreads();
    for (int kb = 1; kb < nk; kb++) {
        LOAD(kb);
        MMA((kb - 1) & 1);
        COMMIT(kb & 1);
        __syncthreads();
    }
    MMA((nk - 1) & 1);

    #pragma unroll
    for (int mt = 0; mt < 4; mt++) {
        #pragma unroll
        for (int nt = 0; nt < 4; nt++) {
            int row = m0 + wm0 + mt * 16 + (lane >> 2);
            int col = n0 + wn0 + nt * 8 + (lane & 3) * 2;
            size_t r1 = cbase + (size_t)row * N + col;
            size_t r2 = cbase + (size_t)(row + 8) * N + col;
            float2 lo = make_float2(acc[mt][nt][0], acc[mt][nt][1]);
            float2 hi = make_float2(acc[mt][nt][2], acc[mt][nt][3]);
            float2 rv1 = make_float2(0.f, 0.f), rv2 = make_float2(0.f, 0.f);
            if (beta != 0.f) {
                rv1 = *(const float2*)(X1 + r1);
                rv2 = *(const float2*)(X1 + r2);
            }
            *(float2*)(C + r1) = make_float2(alpha*lo.x + beta*rv1.x, alpha*lo.y + beta*rv1.y);
            *(float2*)(C + r2) = make_float2(alpha*hi.x + beta*rv2.x, alpha*hi.y + beta*rv2.y);
        }
    }
}

__device__ __forceinline__ void gridbar(int i) {
    __syncthreads();
    if (threadIdx.x == 0) {
        __threadfence();
        atomicAdd(&g_barc[i], 1);
        while (((volatile int*)g_barc)[i] < 128) { }
        __threadfence();
    }
    __syncthreads();
}

__global__ __launch_bounds__(256) void pinv_iters() {
    __shared__ uint32_t As[2][16][136];
    __shared__ uint32_t Bs[2][16][136];
    int m0 = blockIdx.y * 128, n0 = blockIdx.x * 128;
    long long base = (long long)blockIdx.z * (MM * MM);
    float* zc = g_z;
    float* zn = g_z2;
    int bi = 0;
    #pragma unroll 1
    for (int it = 0; it < 5; it++) {
        tc_tile(g_attn2 + base, zc + base, g_xz, nullptr, MM, MM, MM, MM, base,
                1.f, 0.f, m0, n0, As, Bs);
        gridbar(bi++);
        tc_tile(g_xz + base, g_xz + base, g_t, g_xz, MM, MM, MM, MM, base,
                -1.f, 7.f, m0, n0, As, Bs);
        gridbar(bi++);
        tc_tile(g_xz + base, g_t + base, g_u, g_xz, MM, MM, MM, MM, base,
                -1.f, 15.f, m0, n0, As, Bs);
        gridbar(bi++);
        tc_tile(zc + base, g_u + base, zn, zc, MM, MM, MM, MM, base,
                -0.25f, 3.25f, m0, n0, As, Bs);
        if (it < 4) gridbar(bi++);
        float* tmp = zc; zc = zn; zn = tmp;
    }
}

// Wc = z_final(g_z) @ out3, tf32
__global__ __launch_bounds__(256) void wc_gemm() {
    __shared__ uint32_t As[2][16][136];
    __shared__ uint32_t Bs[2][16][136];
    constexpr int BK = 16;
    int tid = threadIdx.x, lane = tid & 31, warp = tid >> 5;
    int wm0 = (warp >> 2) * 64;
    int wn0 = (warp & 3) * 16;
    int m0 = blockIdx.y * 128;
    long long abase = (long long)blockIdx.z * (MM * MM);
    long long cbase = (long long)blockIdx.z * (MM * DH);
    const float* Ab = g_z + abase;
    const float* Bb = g_out3 + cbase;
    float4 ra[2];
    float4 rb;
    float acc[4][2][4];
    #pragma unroll
    for (int i = 0; i < 4; i++)
        #pragma unroll
        for (int j = 0; j < 2; j++)
            #pragma unroll
            for (int r = 0; r < 4; r++) acc[i][j][r] = 0.f;

    auto LOAD = [&](int kb) {
        #pragma unroll
        for (int c = 0; c < 2; c++) {
            int id = c * 256 + tid;
            int m = id >> 2, kq = id & 3;
            ra[c] = *(const float4*)(Ab + (size_t)(m0 + m) * MM + kb * BK + kq * 4);
        }
        {
            int k = tid >> 4, nq = tid & 15;
            rb = *(const float4*)(Bb + (size_t)(kb * BK + k) * DH + nq * 4);
        }
    };
    auto COMMIT = [&](int bf) {
        #pragma unroll
        for (int c = 0; c < 2; c++) {
            int id = c * 256 + tid;
            int m = id >> 2, kq = id & 3;
            As[bf][kq*4+0][m] = f2tf(ra[c].x); As[bf][kq*4+1][m] = f2tf(ra[c].y);
            As[bf][kq*4+2][m] = f2tf(ra[c].z); As[bf][kq*4+3][m] = f2tf(ra[c].w);
        }
        {
            int k = tid >> 4, nq = tid & 15;
            Bs[bf][k][nq*4+0] = f2tf(rb.x); Bs[bf][k][nq*4+1] = f2tf(rb.y);
            Bs[bf][k][nq*4+2] = f2tf(rb.z); Bs[bf][k][nq*4+3] = f2tf(rb.w);
        }
    };
    auto MMA = [&](int bf) {
        #pragma unroll
        for (int ks = 0; ks < 2; ks++) {
            uint32_t af[4][4], bfr[2][2];
            int kr = ks * 8 + (lane & 3);
            int mr = wm0 + (lane >> 2);
            #pragma unroll
            for (int mt = 0; mt < 4; mt++) {
                af[mt][0] = As[bf][kr    ][mr + mt*16];
                af[mt][1] = As[bf][kr    ][mr + mt*16 + 8];
                af[mt][2] = As[bf][kr + 4][mr + mt*16];
                af[mt][3] = As[bf][kr + 4][mr + mt*16 + 8];
            }
            int nr = wn0 + (lane >> 2);
            #pragma unroll
            for (int nt = 0; nt < 2; nt++) {
                bfr[nt][0] = Bs[bf][kr    ][nr + nt*8];
                bfr[nt][1] = Bs[bf][kr + 4][nr + nt*8];
            }
            #pragma unroll
            for (int mt = 0; mt < 4; mt++)
                #pragma unroll
                for (int nt = 0; nt < 2; nt++)
                    mma8(acc[mt][nt], af[mt], bfr[nt]);
        }
    };

    LOAD(0); COMMIT(0);
    __syncthreads();
    for (int kb = 1; kb < 16; kb++) {
        LOAD(kb);
        MMA((kb - 1) & 1);
        COMMIT(kb & 1);
        __syncthreads();
    }
    MMA(1);

    #pragma unroll
    for (int mt = 0; mt < 4; mt++) {
        #pragma unroll
        for (int nt = 0; nt < 2; nt++) {
            int row = m0 + wm0 + mt * 16 + (lane >> 2);
            int col = wn0 + nt * 8 + (lane & 3) * 2;
            *(float2*)(g_wc + cbase + (size_t)row * DH + col) =
                make_float2(acc[mt][nt][0], acc[mt][nt][1]);
            *(float2*)(g_wc + cbase + (size_t)(row + 8) * DH + col) =
                make_float2(acc[mt][nt][2], acc[mt][nt][3]);
        }
    }
}

// ---------------------------------------------------------------------------
// BF16 GEMM (QKV, out-proj)
// ---------------------------------------------------------------------------
template<int EPI, int BM, int BN, int BK>
__global__ __launch_bounds__(256) void bf_gemm(
    const float* __restrict__ Af, const float* __restrict__ Bg,
    float* __restrict__ C, const float* __restrict__ X1, const float* __restrict__ X2,
    int N, int K, int lda, int ldb)
{
    constexpr int PA = BM + 8, PB = BN + 8;
    constexpr int MT = (BM / 2) / 16;
    constexpr int NT = (BN / 4) / 8;
    constexpr int KP = BK / 2;
    constexpr int RAF = (BM * BK) / 1024;
    constexpr int RBN = (KP * (BN / 4)) / 256;
    __shared__ uint32_t As[2][KP][PA];
    __shared__ uint32_t Bs[2][KP][PB];
    float4 raf[RAF];
    float4 rb0[RBN], rb1[RBN];

    int tid = threadIdx.x, lane = tid & 31, warp = tid >> 5;
    int wm0 = (warp >> 2) * (BM / 2);
    int wn0 = (warp & 3) * (BN / 4);
    int m0 = blockIdx.y * BM, n0 = blockIdx.x * BN;

    float acc[MT][NT][4];
    #pragma unroll
    for (int i = 0; i < MT; i++)
        #pragma unroll
        for (int j = 0; j < NT; j++)
            #pragma unroll
            for (int r = 0; r < 4; r++) acc[i][j][r] = 0.f;

    auto LOAD = [&](int kb) {
        #pragma unroll
        for (int c = 0; c < RAF; c++) {
            int id = c * 256 + tid;
            int m = id / (BK / 4), kq = id % (BK / 4);
            raf[c] = *(const float4*)(Af + (size_t)(m0 + m) * lda + kb * BK + kq * 4);
        }
        #pragma unroll
        for (int c = 0; c < RBN; c++) {
            int id = c * 256 + tid;
            int kp = id / (BN / 4), nq = id % (BN / 4);
            rb0[c] = *(const float4*)(Bg + (size_t)(kb*BK + 2*kp    ) * ldb + n0 + nq * 4);
            rb1[c] = *(const float4*)(Bg + (size_t)(kb*BK + 2*kp + 1) * ldb + n0 + nq * 4);
        }
    };
    auto COMMIT = [&](int bf) {
        #pragma unroll
        for (int c = 0; c < RAF; c++) {
            int id = c * 256 + tid;
            int m = id / (BK / 4), kq = id % (BK / 4);
            As[bf][kq*2+0][m] = f2bf2(raf[c].x, raf[c].y);
            As[bf][kq*2+1][m] = f2bf2(raf[c].z, raf[c].w);
        }
        #pragma unroll
        for (int c = 0; c < RBN; c++) {
            int id = c * 256 + tid;
            int kp = id / (BN / 4), nq = id % (BN / 4);
            Bs[bf][kp][nq*4+0] = f2bf2(rb0[c].x, rb1[c].x);
            Bs[bf][kp][nq*4+1] = f2bf2(rb0[c].y, rb1[c].y);
            Bs[bf][kp][nq*4+2] = f2bf2(rb0[c].z, rb1[c].z);
            Bs[bf][kp][nq*4+3] = f2bf2(rb0[c].w, rb1[c].w);
        }
    };
    auto MMA = [&](int bf) {
        #pragma unroll
        for (int ks = 0; ks < BK / 16; ks++) {
            uint32_t af[MT][4], bfr[NT][2];
            int kr = ks * 8 + (lane & 3);
            int mr = wm0 + (lane >> 2);
            #pragma unroll
            for (int mt = 0; mt < MT; mt++) {
                af[mt][0] = As[bf][kr    ][mr + mt*16];
                af[mt][1] = As[bf][kr    ][mr + mt*16 + 8];
                af[mt][2] = As[bf][kr + 4][mr + mt*16];
                af[mt][3] = As[bf][kr + 4][mr + mt*16 + 8];
            }
            int nr = wn0 + (lane >> 2);
            #pragma unroll
            for (int nt = 0; nt < NT; nt++) {
                bfr[nt][0] = Bs[bf][kr    ][nr + nt*8];
                bfr[nt][1] = Bs[bf][kr + 4][nr + nt*8];
            }
            #pragma unroll
            for (int mt = 0; mt < MT; mt++)
                #pragma unroll
                for (int nt = 0; nt < NT; nt++)
                    mma16(acc[mt][nt], af[mt], bfr[nt]);
        }
    };

    int nk = K / BK;
    LOAD(0); COMMIT(0);
    __syncthreads();
    for (int kb = 1; kb < nk; kb++) {
        LOAD(kb);
        MMA((kb - 1) & 1);
        COMMIT(kb & 1);
        __syncthreads();
    }
    MMA((nk - 1) & 1);

    #pragma unroll
    for (int mt = 0; mt < MT; mt++) {
        #pragma unroll
        for (int nt = 0; nt < NT; nt++) {
            int row = m0 + wm0 + mt * 16 + (lane >> 2);
            int col = n0 + wn0 + nt * 8 + (lane & 3) * 2;
            float2 lo = make_float2(acc[mt][nt][0], acc[mt][nt][1]);
            float2 hi = make_float2(acc[mt][nt][2], acc[mt][nt][3]);
            if constexpr (EPI == 0) {
                int which = col >> 9, inner = col & 511;
                int h = inner >> 6, d = inner & 63;
                float* dst = which == 0 ? g_q : (which == 1 ? g_k : g_v);
                float s = (which == 0) ? 0.125f : 1.f;
                int bq = row >> 13, n = row & (NN - 1);
                *(float2*)(dst + (((size_t)(bq*HH+h))*NN + n    )*DH + d) = make_float2(lo.x*s, lo.y*s);
                *(float2*)(dst + (((size_t)(bq*HH+h))*NN + n + 8)*DH + d) = make_float2(hi.x*s, hi.y*s);
            } else if constexpr (EPI == 1) {
                float2 bv = *(const float2*)(X1 + col);
                size_t r1 = (size_t)row * DD + col, r2 = (size_t)(row + 8) * DD + col;
                float2 x1 = *(const float2*)(X2 + r1);
                float2 x2 = *(const float2*)(X2 + r2);
                *(float2*)(C + r1) = make_float2(lo.x + bv.x + x1.x, lo.y + bv.y + x1.y);
                *(float2*)(C + r2) = make_float2(hi.x + bv.x + x2.x, hi.y + bv.y + x2.y);
            }
        }
    }
}

// ---------------------------------------------------------------------------
// Fused attn1: y += softmax(q @ kl^T) @ Wc   (Wcs stride FIXED: 40 -> 72)
// ---------------------------------------------------------------------------
__global__ __launch_bounds__(256) void attn1_fused() {
    extern __shared__ char smraw[];
    uint32_t* As  = (uint32_t*)smraw;       // [16][72]
    uint32_t* Bs  = As + 16*72;             // [16][264]
    uint32_t* Ps  = Bs + 16*264;            // [128][72]  P k-major
    uint32_t* Wcs = Ps + 128*72;            // [128][72]  Wc k-major (64 cols + pad)
    float* rmax = (float*)(Wcs + 128*72);   // [64][5]
    float* rsum = rmax + 320;               // [64][5]

    int tid = threadIdx.x, lane = tid & 31, warp = tid >> 5;
    int g = lane >> 2, q4 = lane & 3;
    int bh = blockIdx.y;
    int b = bh >> 3, h = bh & 7;
    int m0 = blockIdx.x * 64;
    const float* Ab = g_q  + ((size_t)bh * NN + m0) * DH;
    const float* Bb = g_kl + (size_t)bh * MM * DH;
    const float* Wg = g_wc + (size_t)bh * MM * DH;

    // load Wc into k-major smem (256x64 -> [128 pairs][64])
    #pragma unroll
    for (int c = 0; c < 8; c++) {
        int id = c * 256 + tid;
        int kp = id >> 4, n4 = id & 15;
        float4 lo = *(const float4*)(Wg + (size_t)(2*kp    ) * DH + n4 * 4);
        float4 hi = *(const float4*)(Wg + (size_t)(2*kp + 1) * DH + n4 * 4);
        Wcs[kp*72 + n4*4+0] = f2bf2(lo.x, hi.x);
        Wcs[kp*72 + n4*4+1] = f2bf2(lo.y, hi.y);
        Wcs[kp*72 + n4*4+2] = f2bf2(lo.z, hi.z);
        Wcs[kp*72 + n4*4+3] = f2bf2(lo.w, hi.w);
    }

    // ---- S = q @ kl^T (64x256), warps (2m x 4n)
    int wm0q = (warp >> 2) * 32;
    int wn0q = (warp & 3) * 64;
    int wnq = warp & 3;
    float acc[2][8][4];
    #pragma unroll
    for (int i = 0; i < 2; i++)
        #pragma unroll
        for (int j = 0; j < 8; j++)
            #pragma unroll
            for (int r = 0; r < 4; r++) acc[i][j][r] = 0.f;

    for (int k0 = 0; k0 < 64; k0 += 32) {
        #pragma unroll
        for (int c = 0; c < 2; c++) {
            int id = c * 256 + tid;
            int m = id >> 3, kq = id & 7;
            float4 v = *(const float4*)(Ab + (size_t)m * DH + k0 + kq * 4);
            As[(kq*2+0)*72 + m] = f2bf2(v.x, v.y);
            As[(kq*2+1)*72 + m] = f2bf2(v.z, v.w);
        }
        #pragma unroll
        for (int c = 0; c < 8; c++) {
            int id = c * 256 + tid;
            int n = id >> 3, kq = id & 7;
            float4 v = *(const float4*)(Bb + (size_t)n * DH + k0 + kq * 4);
            Bs[(kq*2+0)*264 + n] = f2bf2(v.x, v.y);
            Bs[(kq*2+1)*264 + n] = f2bf2(v.z, v.w);
        }
        __syncthreads();
        #pragma unroll
        for (int ks = 0; ks < 2; ks++) {
            uint32_t af[2][4], bfr[8][2];
            int kr = ks * 8 + q4;
            int mr = wm0q + g;
            #pragma unroll
            for (int mt = 0; mt < 2; mt++) {
                af[mt][0] = As[kr*72 + mr + mt*16];
                af[mt][1] = As[kr*72 + mr + mt*16 + 8];
                af[mt][2] = As[(kr+4)*72 + mr + mt*16];
                af[mt][3] = As[(kr+4)*72 + mr + mt*16 + 8];
            }
            int nr = wn0q + g;
            #pragma unroll
            for (int nt = 0; nt < 8; nt++) {
                bfr[nt][0] = Bs[kr*264 + nr + nt*8];
                bfr[nt][1] = Bs[(kr+4)*264 + nr + nt*8];
            }
            #pragma unroll
            for (int mt = 0; mt < 2; mt++)
                #pragma unroll
                for (int nt = 0; nt < 8; nt++)
                    mma16(acc[mt][nt], af[mt], bfr[nt]);
        }
        __syncthreads();
    }

    // ---- softmax over 256-wide rows
    #pragma unroll
    for (int mt = 0; mt < 2; mt++) {
        int r0 = wm0q + mt * 16 + g;
        float m0v = -1e30f, m1v = -1e30f;
        #pragma unroll
        for (int nt = 0; nt < 8; nt++) {
            m0v = fmaxf(m0v, fmaxf(acc[mt][nt][0], acc[mt][nt][1]));
            m1v = fmaxf(m1v, fmaxf(acc[mt][nt][2], acc[mt][nt][3]));
        }
        #pragma unroll
        for (int o = 1; o < 4; o <<= 1) {
            m0v = fmaxf(m0v, __shfl_xor_sync(~0u, m0v, o));
            m1v = fmaxf(m1v, __shfl_xor_sync(~0u, m1v, o));
        }
        if (q4 == 0) { rmax[r0*5 + wnq] = m0v; rmax[(r0+8)*5 + wnq] = m1v; }
    }
    __syncthreads();
    #pragma unroll
    for (int mt = 0; mt < 2; mt++) {
        int r0 = wm0q + mt * 16 + g;
        float M0 = fmaxf(fmaxf(rmax[r0*5+0], rmax[r0*5+1]), fmaxf(rmax[r0*5+2], rmax[r0*5+3]));
        float M1 = fmaxf(fmaxf(rmax[(r0+8)*5+0], rmax[(r0+8)*5+1]),
                         fmaxf(rmax[(r0+8)*5+2], rmax[(r0+8)*5+3]));
        float s0 = 0.f, s1 = 0.f;
        #pragma unroll
        for (int nt = 0; nt < 8; nt++) {
            acc[mt][nt][0] = __expf(acc[mt][nt][0] - M0);
            acc[mt][nt][1] = __expf(acc[mt][nt][1] - M0);
            acc[mt][nt][2] = __expf(acc[mt][nt][2] - M1);
            acc[mt][nt][3] = __expf(acc[mt][nt][3] - M1);
            s0 += acc[mt][nt][0] + acc[mt][nt][1];
            s1 += acc[mt][nt][2] + acc[mt][nt][3];
        }
        #pragma unroll
        for (int o = 1; o < 4; o <<= 1) {
            s0 += __shfl_xor_sync(~0u, s0, o);
            s1 += __shfl_xor_sync(~0u, s1, o);
        }
        if (q4 == 0) { rsum[r0*5 + wnq] = s0; rsum[(r0+8)*5 + wnq] = s1; }
    }
    __syncthreads();
    // normalize + write P k-major to smem
    #pragma unroll
    for (int mt = 0; mt < 2; mt++) {
        int r0 = wm0q + mt * 16 + g, r1 = r0 + 8;
        float i0 = 1.f / (rsum[r0*5+0] + rsum[r0*5+1] + rsum[r0*5+2] + rsum[r0*5+3]);
        float i1 = 1.f / (rsum[r1*5+0] + rsum[r1*5+1] + rsum[r1*5+2] + rsum[r1*5+3]);
        #pragma unroll
        for (int nt = 0; nt < 8; nt++) {
            int kp = (wn0q >> 1) + nt * 4 + q4;
            Ps[kp*72 + r0] = f2bf2(acc[mt][nt][0] * i0, acc[mt][nt][1] * i0);
            Ps[kp*72 + r1] = f2bf2(acc[mt][nt][2] * i1, acc[mt][nt][3] * i1);
        }
    }
    __syncthreads();

    // ---- y += P @ Wc : 64x64 out, warps (2m x 4n)
    int wm0p = (warp >> 2) * 32;
    int wn0p = (warp & 3) * 16;
    float yacc[2][2][4];
    #pragma unroll
    for (int i = 0; i < 2; i++)
        #pragma unroll
        for (int j = 0; j < 2; j++)
            #pragma unroll
            for (int r = 0; r < 4; r++) yacc[i][j][r] = 0.f;
    #pragma unroll
    for (int kc = 0; kc < 16; kc++) {
        int kr = kc * 8 + q4;
        uint32_t af[2][4], bfr[2][2];
        int mr = wm0p + g;
        #pragma unroll
        for (int mt = 0; mt < 2; mt++) {
            af[mt][0] = Ps[kr*72 + mr + mt*16];
            af[mt][1] = Ps[kr*72 + mr + mt*16 + 8];
            af[mt][2] = Ps[(kr+4)*72 + mr + mt*16];
            af[mt][3] = Ps[(kr+4)*72 + mr + mt*16 + 8];
        }
        int nr = wn0p + g;
        #pragma unroll
        for (int nt = 0; nt < 2; nt++) {
            bfr[nt][0] = Wcs[kr*72 + nr + nt*8];
            bfr[nt][1] = Wcs[(kr+4)*72 + nr + nt*8];
        }
        #pragma unroll
        for (int mt = 0; mt < 2; mt++)
            #pragma unroll
            for (int nt = 0; nt < 2; nt++)
                mma16(yacc[mt][nt], af[mt], bfr[nt]);
    }
    #pragma unroll
    for (int mt = 0; mt < 2; mt++) {
        #pragma unroll
        for (int nt = 0; nt < 2; nt++) {
            int row = m0 + wm0p + mt * 16 + g;
            int col = wn0p + nt * 8 + q4 * 2;
            size_t r1 = ((size_t)b * NN + row    ) * DD + h * 64 + col;
            size_t r2 = ((size_t)b * NN + row + 8) * DD + h * 64 + col;
            float2 y1 = *(float2*)(g_y + r1);
            float2 y2 = *(float2*)(g_y + r2);
            *(float2*)(g_y + r1) = make_float2(y1.x + yacc[mt][nt][0], y1.y + yacc[mt][nt][1]);
            *(float2*)(g_y + r2) = make_float2(y2.x + yacc[mt][nt][2], y2.y + yacc[mt][nt][3]);
        }
    }
}

// ---------------------------------------------------------------------------
// LN / landmarks / sim2 / softmax256 / init / colrowmax / z0 / fp32 mm / conv
// ---------------------------------------------------------------------------
__global__ __launch_bounds__(128) void ln_kernel(const float* __restrict__ x,
                                                 const float* __restrict__ w,
                                                 const float* __restrict__ bia) {
    int row = blockIdx.x, tid = threadIdx.x;
    const float4* xr = reinterpret_cast<const float4*>(x + (size_t)row * DD);
    float4 v = xr[tid];
    float s  = v.x + v.y + v.z + v.w;
    float sq = v.x*v.x + v.y*v.y + v.z*v.z + v.w*v.w;
    __shared__ float sm[4], sm2[4];
    #pragma unroll
    for (int o = 16; o > 0; o >>= 1) {
        s  += __shfl_down_sync(0xffffffffu, s,  o);
        sq += __shfl_down_sync(0xffffffffu, sq, o);
    }
    if ((tid & 31) == 0) { sm[tid >> 5] = s; sm2[tid >> 5] = sq; }
    __syncthreads();
    if (tid == 0) {
        float a = 0.f, b2 = 0.f;
        #pragma unroll
        for (int i = 0; i < 4; i++) { a += sm[i]; b2 += sm2[i]; }
        sm[0] = a; sm2[0] = b2;
    }
    __syncthreads();
    float mean = sm[0] * (1.f / 512.f);
    float var  = sm2[0] * (1.f / 512.f) - mean * mean;
    float rstd = rsqrtf(var + 1e-5f);
    float4 wv = reinterpret_cast<const float4*>(w)[tid];
    float4 bv = reinterpret_cast<const float4*>(bia)[tid];
    float4 o;
    o.x = (v.x - mean) * rstd * wv.x + bv.x;
    o.y = (v.y - mean) * rstd * wv.y + bv.y;
    o.z = (v.z - mean) * rstd * wv.z + bv.z;
    o.w = (v.w - mean) * rstd * wv.w + bv.w;
    reinterpret_cast<float4*>(g_xn + (size_t)row * DD)[tid] = o;
}

__global__ void landmark_kernel() {
    int m = blockIdx.x, bh = blockIdx.y;
    int d = threadIdx.x;
    size_t base = ((size_t)bh * NN + (size_t)m * 32) * DH + d;
    float sq = 0.f, sk = 0.f;
    #pragma unroll
    for (int j = 0; j < 32; j++) {
        sq += g_q[base + (size_t)j * DH];
        sk += g_k[base + (size_t)j * DH];
    }
    size_t o = ((size_t)bh * MM + m) * DH + d;
    g_ql[o] = sq * (1.f / 32.f);
    g_kl[o] = sk * (1.f / 32.f);
}

__global__ __launch_bounds__(256) void gemm_sim2() {
    __shared__ float As[32][132];
    __shared__ float Bs[32][132];
    int bh = blockIdx.z;
    int n0 = blockIdx.x * 128, m0 = blockIdx.y * 128;
    const float* Ab = g_ql + ((size_t)bh * MM + m0) * DH;
    const float* Bb = g_kl + ((size_t)bh * MM + n0) * DH;
    float* Cb = g_attn2 + (size_t)bh * MM * MM;
    int tid = threadIdx.x;
    int tx = tid & 15, ty = tid >> 4;
    float acc[8][8] = {};
    for (int kk = 0; kk < 64; kk += 32) {
        #pragma unroll
        for (int u = 0; u < 4; u++) {
            int g = u * 256 + tid;
            int m = g >> 3, k4 = g & 7;
            float4 av = *(const float4*)(Ab + (size_t)m * DH + kk + k4 * 4);
            As[k4*4+0][m] = av.x; As[k4*4+1][m] = av.y;
            As[k4*4+2][m] = av.z; As[k4*4+3][m] = av.w;
        }
        #pragma unroll
        for (int u = 0; u < 4; u++) {
            int g = u * 256 + tid;
            int m = g >> 3, k4 = g & 7;
            float4 bv = *(const float4*)(Bb + (size_t)m * DH + kk + k4 * 4);
            Bs[k4*4+0][m] = bv.x; Bs[k4*4+1][m] = bv.y;
            Bs[k4*4+2][m] = bv.z; Bs[k4*4+3][m] = bv.w;
        }
        __syncthreads();
        #pragma unroll
        for (int k = 0; k < 32; k++) {
            float a[8], b[8];
            *(float4*)&a[0] = *(const float4*)&As[k][ty*8];
            *(float4*)&a[4] = *(const float4*)&As[k][ty*8+4];
            *(float4*)&b[0] = *(const float4*)&Bs[k][tx*8];
            *(float4*)&b[4] = *(const float4*)&Bs[k][tx*8+4];
            #pragma unroll
            for (int i = 0; i < 8; i++)
                #pragma unroll
                for (int j = 0; j < 8; j++)
                    acc[i][j] += a[i] * b[j];
        }
        __syncthreads();
    }
    #pragma unroll
    for (int i = 0; i < 8; i++) {
        size_t r = (size_t)(m0 + ty * 8 + i) * MM + n0 + tx * 8;
        *(float4*)(Cb + r)     = make_float4(acc[i][0], acc[i][1], acc[i][2], acc[i][3]);
        *(float4*)(Cb + r + 4) = make_float4(acc[i][4], acc[i][5], acc[i][6], acc[i][7]);
    }
}

__global__ __launch_bounds__(256) void softmax256() {
    int row = blockIdx.x, tid = threadIdx.x;
    float* p = g_attn2 + (size_t)row * MM;
    float v = p[tid];
    __shared__ float red[8];
    float m = v;
    #pragma unroll
    for (int o = 16; o; o >>= 1) m = fmaxf(m, __shfl_xor_sync(~0u, m, o));
    if ((tid & 31) == 0) red[tid >> 5] = m;
    __syncthreads();
    if (tid < 32) {
        float t = (tid < 8) ? red[tid] : -1e30f;
        #pragma unroll
        for (int o = 4; o; o >>= 1) t = fmaxf(t, __shfl_xor_sync(~0u, t, o));
        if (tid == 0) red[0] = t;
    }
    __syncthreads();
    float mx = red[0];
    __syncthreads();
    float e = __expf(v - mx);
    float s = e;
    #pragma unroll
    for (int o = 16; o; o >>= 1) s += __shfl_xor_sync(~0u, s, o);
    if ((tid & 31) == 0) red[tid >> 5] = s;
    __syncthreads();
    if (tid < 32) {
        float t = (tid < 8) ? red[tid] : 0.f;
        #pragma unroll
        for (int o = 4; o; o >>= 1) t += __shfl_xor_sync(~0u, t, o);
        if (tid == 0) red[0] = t;
    }
    __syncthreads();
    p[tid] = e / red[0];
}

__global__ void init_kernel() {
    g_maxA = 0; g_maxB = 0;
    if (threadIdx.x < 32) g_barc[threadIdx.x] = 0;
}

__global__ __launch_bounds__(256) void colrowmax_kernel() {
    int bh = blockIdx.x, tid = threadIdx.x;
    const float* a = g_attn2 + (size_t)bh * MM * MM;
    float cs = 0.f, rs = 0.f;
    for (int m = 0; m < MM; m++) cs += fabsf(a[(size_t)m * MM + tid]);
    for (int n = 0; n < MM; n++) rs += fabsf(a[(size_t)tid * MM + n]);
    __shared__ float r1[8], r2[8];
    #pragma unroll
    for (int o = 16; o; o >>= 1) {
        cs = fmaxf(cs, __shfl_xor_sync(~0u, cs, o));
        rs = fmaxf(rs, __shfl_xor_sync(~0u, rs, o));
    }
    if ((tid & 31) == 0) { r1[tid >> 5] = cs; r2[tid >> 5] = rs; }
    __syncthreads();
    if (tid == 0) {
        float a1 = r1[0], a2 = r2[0];
        #pragma unroll
        for (int i = 1; i < 8; i++) { a1 = fmaxf(a1, r1[i]); a2 = fmaxf(a2, r2[i]); }
        atomicMax(&g_maxA, __float_as_int(a1));
        atomicMax(&g_maxB, __float_as_int(a2));
    }
}

__global__ __launch_bounds__(256) void z0_kernel() {
    int bh = blockIdx.z;
    int c0 = blockIdx.x * 32, r0 = blockIdx.y * 32;
    int tid = threadIdx.x;
    __shared__ float t[32][33];
    const float* a = g_attn2 + (size_t)bh * MM * MM;
    #pragma unroll
    for (int rr = 0; rr < 4; rr++) {
        int r = rr * 8 + (tid >> 5), c = tid & 31;
        t[r][c] = a[(size_t)(r0 + r) * MM + c0 + c];
    }
    __syncthreads();
    float s = 1.f / (__int_as_float(g_maxA) * __int_as_float(g_maxB));
    float* z = g_z + (size_t)bh * MM * MM;
    #pragma unroll
    for (int rr = 0; rr < 4; rr++) {
        int r = rr * 8 + (tid >> 5), c = tid & 31;
        z[(size_t)(c0 + r) * MM + r0 + c] = t[c][r] * s;
    }
}

__global__ __launch_bounds__(256) void matmul_ba128(const float* __restrict__ P,
                                                    const float* __restrict__ Q,
                                                    const float* __restrict__ R,
                                                    float* __restrict__ C,
                                                    float alpha, float beta) {
    __shared__ float As[16][132];
    __shared__ float Bs[16][132];
    size_t base = (size_t)blockIdx.z * (MM * MM);
    int m0 = blockIdx.y * 128, n0 = blockIdx.x * 128;
    int tid = threadIdx.x;
    int tx = tid & 15, ty = tid >> 4;
    float acc[8][8] = {};
    for (int kk = 0; kk < 256; kk += 16) {
        #pragma unroll
        for (int u = 0; u < 2; u++) {
            int g = u * 256 + tid;
            int m = g >> 2, k4 = g & 3;
            float4 av = *(const float4*)(P + base + (size_t)(m0 + m) * MM + kk + k4 * 4);
            As[k4*4+0][m] = av.x; As[k4*4+1][m] = av.y;
            As[k4*4+2][m] = av.z; As[k4*4+3][m] = av.w;
        }
        #pragma unroll
        for (int u = 0; u < 2; u++) {
            int g = u * 256 + tid;
            int k = g >> 5, n4 = g & 31;
            *(float4*)&Bs[k][n4*4] =
                *(const float4*)(Q + base + (size_t)(kk + k) * MM + n0 + n4 * 4);
        }
        __syncthreads();
        #pragma unroll
        for (int k = 0; k < 16; k++) {
            float a[8], b[8];
            *(float4*)&a[0] = *(const float4*)&As[k][ty*8];
            *(float4*)&a[4] = *(const float4*)&As[k][ty*8+4];
            *(float4*)&b[0] = *(const float4*)&Bs[k][tx*8];
            *(float4*)&b[4] = *(const float4*)&Bs[k][tx*8+4];
            #pragma unroll
            for (int i = 0; i < 8; i++)
                #pragma unroll
                for (int j = 0; j < 8; j++)
                    acc[i][j] += a[i] * b[j];
        }
        __syncthreads();
    }
    #pragma unroll
    for (int i = 0; i < 8; i++) {
        #pragma unroll
        for (int jj = 0; jj < 2; jj++) {
            size_t off = base + (size_t)(m0 + ty * 8 + i) * MM + n0 + tx * 8 + jj * 4;
            float4 rv = make_float4(0.f, 0.f, 0.f, 0.f);
            if (beta != 0.f) rv = *(const float4*)(R + off);
            float4 o;
            o.x = alpha * acc[i][jj*4+0] + beta * rv.x;
            o.y = alpha * acc[i][jj*4+1] + beta * rv.y;
            o.z = alpha * acc[i][jj*4+2] + beta * rv.z;
            o.w = alpha * acc[i][jj*4+3] + beta * rv.w;
            *(float4*)(C + off) = o;
        }
    }
}

__global__ __launch_bounds__(256) void conv_kernel(const float* __restrict__ res_w) {
    __shared__ float sv[160][64];
    __shared__ float sw[33];
    int bh = blockIdx.y, n0 = blockIdx.x * 128;
    int b = bh >> 3, h = bh & 7;
    int tid = threadIdx.x;
    if (tid < 33) sw[tid] = res_w[h * 33 + tid];
    const float* vb = g_v + (size_t)bh * NN * DH;
    #pragma unroll
    for (int i = 0; i < 10; i++) {
        int idx = tid + i * 256;
        int r = idx >> 4, c4 = idx & 15;
        int tok = n0 - 16 + r;
        float4 val = make_float4(0.f, 0.f, 0.f, 0.f);
        if (tok >= 0 && tok < NN)
            val = *(const float4*)(vb + (size_t)tok * DH + c4 * 4);
        *(float4*)&sv[r][c4 * 4] = val;
    }
    __syncthreads();
    #pragma unroll
    for (int i = 0; i < 8; i++) {
        int idx = tid + i * 256;
        int nl = idx >> 4, dg = idx & 15;
        float4 acc = make_float4(0.f, 0.f, 0.f, 0.f);
        #pragma unroll
        for (int j = 0; j < 33; j++) {
            float w = sw[j];
            float4 vv = *(const float4*)&sv[nl + j][dg * 4];
            acc.x += w * vv.x; acc.y += w * vv.y;
            acc.z += w * vv.z; acc.w += w * vv.w;
        }
        *(float4*)(g_y + ((size_t)b * NN + n0 + nl) * DD + h * 64 + dg * 4) = acc;
    }
}

// ---------------------------------------------------------------------------
// Launch
// ---------------------------------------------------------------------------
extern "C" void kernel_launch(void* const* d_in, const int* in_sizes, int n_in,
                              void* d_out, int out_size) {
    const float* x     = (const float*)d_in[0];
    const float* ln_w  = (const float*)d_in[1];
    const float* ln_b  = (const float*)d_in[2];
    const float* w_qkv = (const float*)d_in[3];
    const float* w_out = (const float*)d_in[4];
    const float* b_out = (const float*)d_in[5];
    const float* res_w = (const float*)d_in[6];
    float* out = (float*)d_out;

    float *p_xn, *p_attn2, *p_z, *p_z2, *p_xz, *p_t, *p_u, *p_y;
    cudaGetSymbolAddress((void**)&p_xn, g_xn);
    cudaGetSymbolAddress((void**)&p_attn2, g_attn2);
    cudaGetSymbolAddress((void**)&p_z,  g_z);
    cudaGetSymbolAddress((void**)&p_z2, g_z2);
    cudaGetSymbolAddress((void**)&p_xz, g_xz);
    cudaGetSymbolAddress((void**)&p_t,  g_t);
    cudaGetSymbolAddress((void**)&p_u,  g_u);
    cudaGetSymbolAddress((void**)&p_y,  g_y);

    cudaFuncSetAttribute(flash3, cudaFuncAttributeMaxDynamicSharedMemorySize, 58368);
    cudaFuncSetAttribute(attn1_fused, cudaFuncAttributeMaxDynamicSharedMemorySize, 98304);

    ln_kernel<<<BB * NN, 128>>>(x, ln_w, ln_b);
    bf_gemm<0,128,128,32><<<dim3(12, 256, 1), 256>>>(
        p_xn, w_qkv, nullptr, nullptr, nullptr, 1536, 512, 512, 1536);
    landmark_kernel<<<dim3(MM, BH), 64>>>();

    gemm_sim2<<<dim3(2, 2, BH), 256>>>();
    flash3<<<dim3(2, KS, BH), 256, 58368>>>();
    combine3<<<1024, 256>>>();
    softmax256<<<BH * MM, 256>>>();

    init_kernel<<<1, 32>>>();
    colrowmax_kernel<<<BH, 256>>>();
    z0_kernel<<<dim3(8, 8, BH), 256>>>();

    // 5 tf32 NS iterations in one persistent kernel (result lands in g_z2)
    pinv_iters<<<dim3(2, 2, BH), 256>>>();
    // final fp32 FFMA iteration: reads g_z2, writes g_z
    dim3 gba(2, 2, BH);
    matmul_ba128<<<gba, 256>>>(p_attn2, p_z2, nullptr, p_xz, 1.f, 0.f);
    matmul_ba128<<<gba, 256>>>(p_xz, p_xz, p_xz, p_t, -1.f, 7.f);
    matmul_ba128<<<gba, 256>>>(p_xz, p_t, p_xz, p_u, -1.f, 15.f);
    matmul_ba128<<<gba, 256>>>(p_z2, p_u, p_z2, p_z, -0.25f, 3.25f);

    // Wc = z_final(g_z) @ out3 (tf32)
    wc_gemm<<<dim3(1, 2, BH), 256>>>();

    conv_kernel<<<dim3(64, BH), 256>>>(res_w);
    attn1_fused<<<dim3(128, BH), 256, 98304>>>();

    bf_gemm<1,128,128,32><<<dim3(4, 256, 1), 256>>>(
        p_y, w_out, out, b_out, x, 512, 512, 512, 512);
}

// round 12
// speedup vs baseline: 1.4745x; 1.0987x over previous
#include <cuda_runtime.h>
#include <cuda_bf16.h>
#include <stdint.h>
#include <math.h>

#define BB 4
#define NN 8192
#define DD 512
#define HH 8
#define DH 64
#define MM 256
#define BH 32
#define KS 16

__device__ __align__(16) float g_xn  [(size_t)BB*NN*DD];
__device__ __align__(16) __nv_bfloat16 g_qh[(size_t)BH*NN*DH];
__device__ __align__(16) __nv_bfloat16 g_kh[(size_t)BH*NN*DH];
__device__ __align__(16) __nv_bfloat16 g_vh[(size_t)BH*NN*DH];
__device__ __align__(16) float g_ql  [(size_t)BH*MM*DH];
__device__ __align__(16) float g_kl  [(size_t)BH*MM*DH];
__device__ __align__(16) float g_attn2[(size_t)BH*MM*MM];
__device__ __align__(16) float g_z   [(size_t)BH*MM*MM];
__device__ __align__(16) float g_z2  [(size_t)BH*MM*MM];
__device__ __align__(16) float g_xz  [(size_t)BH*MM*MM];
__device__ __align__(16) float g_t   [(size_t)BH*MM*MM];
__device__ __align__(16) float g_u   [(size_t)BH*MM*MM];
__device__ __align__(16) float g_p3  [(size_t)BH*KS*MM*DH];
__device__ __align__(16) float g_m3  [(size_t)BH*KS*MM];
__device__ __align__(16) float g_l3  [(size_t)BH*KS*MM];
__device__ __align__(16) float g_out3[(size_t)BH*MM*DH];
__device__ __align__(16) float g_wc  [(size_t)BH*MM*DH];
__device__ __align__(16) float g_y   [(size_t)BB*NN*DD];
__device__ int g_maxA;
__device__ int g_maxB;
__device__ int g_barc[32];

__device__ __forceinline__ uint32_t f2tf(float f) {
    uint32_t u;
    asm("cvt.rna.tf32.f32 %0, %1;" : "=r"(u) : "f"(f));
    return u;
}
__device__ __forceinline__ uint32_t f2bf2(float lo, float hi) {
    uint32_t r;
    asm("cvt.rn.bf16x2.f32 %0, %1, %2;" : "=r"(r) : "f"(hi), "f"(lo));
    return r;
}
__device__ __forceinline__ void mma8(float* d, const uint32_t* a, const uint32_t* b) {
    asm volatile(
        "mma.sync.aligned.m16n8k8.row.col.f32.tf32.tf32.f32 "
        "{%0,%1,%2,%3}, {%4,%5,%6,%7}, {%8,%9}, {%0,%1,%2,%3};"
        : "+f"(d[0]), "+f"(d[1]), "+f"(d[2]), "+f"(d[3])
        : "r"(a[0]), "r"(a[1]), "r"(a[2]), "r"(a[3]), "r"(b[0]), "r"(b[1]));
}
__device__ __forceinline__ void mma16(float* d, const uint32_t* a, const uint32_t* b) {
    asm volatile(
        "mma.sync.aligned.m16n8k16.row.col.f32.bf16.bf16.f32 "
        "{%0,%1,%2,%3}, {%4,%5,%6,%7}, {%8,%9}, {%0,%1,%2,%3};"
        : "+f"(d[0]), "+f"(d[1]), "+f"(d[2]), "+f"(d[3])
        : "r"(a[0]), "r"(a[1]), "r"(a[2]), "r"(a[3]), "r"(b[0]), "r"(b[1]));
}

// ---------------------------------------------------------------------------
// Flash split-KV attn3: K/V now bf16 in gmem (direct uint4 loads)
// ---------------------------------------------------------------------------
__global__ __launch_bounds__(256) void flash3() {
    extern __shared__ char smraw[];
    uint32_t* Qs = (uint32_t*)smraw;
    uint32_t* Ksm = Qs + 32*136;
    uint32_t* Vsm = Ksm + 32*72;
    uint32_t* Ps = Vsm + 32*72;
    float* wmax = (float*)(Ps + 32*136);
    float* wsum = wmax + 512;
    float* mrun = wsum + 512;
    float* lrun = mrun + 128;

    int tid = threadIdx.x, lane = tid & 31, warp = tid >> 5;
    int g = lane >> 2, q4 = lane & 3;
    int wm0 = (warp >> 2) * 64;
    int wn0 = (warp & 3) * 16;
    int wn = warp & 3;
    int m0 = blockIdx.x * 128;
    int ksp = blockIdx.y, bh = blockIdx.z;

    const float* Qg = g_ql + ((size_t)bh * MM + m0) * DH;
    #pragma unroll
    for (int c = 0; c < 8; c++) {
        int id = c * 256 + tid;
        int m = id >> 4, qq = id & 15;
        float4 v = *(const float4*)(Qg + (size_t)m * DH + qq * 4);
        Qs[(qq*2+0)*136 + m] = f2bf2(v.x, v.y);
        Qs[(qq*2+1)*136 + m] = f2bf2(v.z, v.w);
    }
    if (tid < 128) { mrun[tid] = -1e30f; lrun[tid] = 0.f; }

    float acc[4][2][4];
    #pragma unroll
    for (int a = 0; a < 4; a++)
        #pragma unroll
        for (int b = 0; b < 2; b++)
            #pragma unroll
            for (int r = 0; r < 4; r++) acc[a][b][r] = 0.f;

    const __nv_bfloat16* Kg = g_kh + ((size_t)bh * NN + ksp * 512) * DH;
    const __nv_bfloat16* Vg = g_vh + ((size_t)bh * NN + ksp * 512) * DH;

    for (int t = 0; t < 8; t++) {
        __syncthreads();
        #pragma unroll
        for (int c = 0; c < 2; c++) {           // K: 64 rows x 8 uint4
            int id = c * 256 + tid;
            int n = id >> 3, qq = id & 7;
            uint4 v = *(const uint4*)(Kg + (size_t)(t*64 + n) * DH + qq * 8);
            Ksm[(qq*4+0)*72 + n] = v.x; Ksm[(qq*4+1)*72 + n] = v.y;
            Ksm[(qq*4+2)*72 + n] = v.z; Ksm[(qq*4+3)*72 + n] = v.w;
        }
        #pragma unroll
        for (int c = 0; c < 2; c++) {           // V: interleave row pairs
            int id = c * 256 + tid;
            int kp = id >> 4, qg = id & 15;
            uint2 a = *(const uint2*)(Vg + (size_t)(t*64 + 2*kp    ) * DH + qg * 4);
            uint2 b = *(const uint2*)(Vg + (size_t)(t*64 + 2*kp + 1) * DH + qg * 4);
            Vsm[kp*72 + qg*4+0] = __byte_perm(a.x, b.x, 0x5410);
            Vsm[kp*72 + qg*4+1] = __byte_perm(a.x, b.x, 0x7632);
            Vsm[kp*72 + qg*4+2] = __byte_perm(a.y, b.y, 0x5410);
            Vsm[kp*72 + qg*4+3] = __byte_perm(a.y, b.y, 0x7632);
        }
        __syncthreads();

        float S[4][2][4];
        #pragma unroll
        for (int a = 0; a < 4; a++)
            #pragma unroll
            for (int b = 0; b < 2; b++)
                #pragma unroll
                for (int r = 0; r < 4; r++) S[a][b][r] = 0.f;
        #pragma unroll
        for (int k2 = 0; k2 < 4; k2++) {
            int kr = k2 * 8 + q4;
            uint32_t af[4][4], bfr[2][2];
            int mr = wm0 + g;
            #pragma unroll
            for (int mt = 0; mt < 4; mt++) {
                af[mt][0] = Qs[kr*136 + mr + mt*16];
                af[mt][1] = Qs[kr*136 + mr + mt*16 + 8];
                af[mt][2] = Qs[(kr+4)*136 + mr + mt*16];
                af[mt][3] = Qs[(kr+4)*136 + mr + mt*16 + 8];
            }
            int nr = wn0 + g;
            #pragma unroll
            for (int nt = 0; nt < 2; nt++) {
                bfr[nt][0] = Ksm[kr*72 + nr + nt*8];
                bfr[nt][1] = Ksm[(kr+4)*72 + nr + nt*8];
            }
            #pragma unroll
            for (int mt = 0; mt < 4; mt++)
                #pragma unroll
                for (int nt = 0; nt < 2; nt++)
                    mma16(S[mt][nt], af[mt], bfr[nt]);
        }

        #pragma unroll
        for (int mt = 0; mt < 4; mt++) {
            float m0v = fmaxf(fmaxf(S[mt][0][0], S[mt][0][1]), fmaxf(S[mt][1][0], S[mt][1][1]));
            float m1v = fmaxf(fmaxf(S[mt][0][2], S[mt][0][3]), fmaxf(S[mt][1][2], S[mt][1][3]));
            #pragma unroll
            for (int o = 1; o < 4; o <<= 1) {
                m0v = fmaxf(m0v, __shfl_xor_sync(~0u, m0v, o));
                m1v = fmaxf(m1v, __shfl_xor_sync(~0u, m1v, o));
            }
            if (q4 == 0) {
                wmax[(wm0 + mt*16 + g)*4 + wn] = m0v;
                wmax[(wm0 + mt*16 + g + 8)*4 + wn] = m1v;
            }
        }
        __syncthreads();

        #pragma unroll
        for (int mt = 0; mt < 4; mt++) {
            int r0 = wm0 + mt*16 + g, r1 = r0 + 8;
            float mo0 = mrun[r0];
            float mt0 = fmaxf(fmaxf(wmax[r0*4+0], wmax[r0*4+1]), fmaxf(wmax[r0*4+2], wmax[r0*4+3]));
            float mn0 = fmaxf(mo0, mt0);
            float sc0 = __expf(mo0 - mn0);
            float mo1 = mrun[r1];
            float mt1 = fmaxf(fmaxf(wmax[r1*4+0], wmax[r1*4+1]), fmaxf(wmax[r1*4+2], wmax[r1*4+3]));
            float mn1 = fmaxf(mo1, mt1);
            float sc1 = __expf(mo1 - mn1);
            float s0 = 0.f, s1 = 0.f;
            #pragma unroll
            for (int nt = 0; nt < 2; nt++) {
                S[mt][nt][0] = __expf(S[mt][nt][0] - mn0);
                S[mt][nt][1] = __expf(S[mt][nt][1] - mn0);
                S[mt][nt][2] = __expf(S[mt][nt][2] - mn1);
                S[mt][nt][3] = __expf(S[mt][nt][3] - mn1);
                s0 += S[mt][nt][0] + S[mt][nt][1];
                s1 += S[mt][nt][2] + S[mt][nt][3];
                int cp = wn * 8 + nt * 4 + q4;
                Ps[cp*136 + r0] = f2bf2(S[mt][nt][0], S[mt][nt][1]);
                Ps[cp*136 + r1] = f2bf2(S[mt][nt][2], S[mt][nt][3]);
                acc[mt][nt][0] *= sc0; acc[mt][nt][1] *= sc0;
                acc[mt][nt][2] *= sc1; acc[mt][nt][3] *= sc1;
            }
            #pragma unroll
            for (int o = 1; o < 4; o <<= 1) {
                s0 += __shfl_xor_sync(~0u, s0, o);
                s1 += __shfl_xor_sync(~0u, s1, o);
            }
            if (q4 == 0) { wsum[r0*4+wn] = s0; wsum[r1*4+wn] = s1; }
        }
        __syncthreads();

        if (tid < 128) {
            float mo = mrun[tid];
            float mt2 = fmaxf(fmaxf(wmax[tid*4+0], wmax[tid*4+1]), fmaxf(wmax[tid*4+2], wmax[tid*4+3]));
            float mn = fmaxf(mo, mt2);
            mrun[tid] = mn;
            lrun[tid] = lrun[tid]*__expf(mo - mn) +
                        wsum[tid*4+0] + wsum[tid*4+1] + wsum[tid*4+2] + wsum[tid*4+3];
        }
        #pragma unroll
        for (int k2 = 0; k2 < 4; k2++) {
            int kr = k2 * 8 + q4;
            uint32_t af[4][4], bfr[2][2];
            int mr = wm0 + g;
            #pragma unroll
            for (int mt = 0; mt < 4; mt++) {
                af[mt][0] = Ps[kr*136 + mr + mt*16];
                af[mt][1] = Ps[kr*136 + mr + mt*16 + 8];
                af[mt][2] = Ps[(kr+4)*136 + mr + mt*16];
                af[mt][3] = Ps[(kr+4)*136 + mr + mt*16 + 8];
            }
            int nr = wn0 + g;
            #pragma unroll
            for (int nt = 0; nt < 2; nt++) {
                bfr[nt][0] = Vsm[kr*72 + nr + nt*8];
                bfr[nt][1] = Vsm[(kr+4)*72 + nr + nt*8];
            }
            #pragma unroll
            for (int mt = 0; mt < 4; mt++)
                #pragma unroll
                for (int nt = 0; nt < 2; nt++)
                    mma16(acc[mt][nt], af[mt], bfr[nt]);
        }
    }
    __syncthreads();

    size_t ob = (size_t)(bh * KS + ksp) * MM + m0;
    #pragma unroll
    for (int mt = 0; mt < 4; mt++) {
        #pragma unroll
        for (int nt = 0; nt < 2; nt++) {
            int r0 = wm0 + mt*16 + g;
            int c = wn0 + nt*8 + q4*2;
            *(float2*)(g_p3 + (ob + r0)*DH + c)     = make_float2(acc[mt][nt][0], acc[mt][nt][1]);
            *(float2*)(g_p3 + (ob + r0 + 8)*DH + c) = make_float2(acc[mt][nt][2], acc[mt][nt][3]);
        }
    }
    if (tid < 128) {
        g_m3[ob + tid] = mrun[tid];
        g_l3[ob + tid] = lrun[tid];
    }
}

__global__ __launch_bounds__(256) void combine3() {
    int warp = threadIdx.x >> 5, lane = threadIdx.x & 31;
    int rowg = blockIdx.x * 8 + warp;
    int bh = rowg >> 8, r = rowg & 255;
    size_t base = (size_t)(bh * KS) * MM + r;
    float mv = (lane < 16) ? g_m3[base + (size_t)lane * MM] : -1e30f;
    #pragma unroll
    for (int o = 16; o; o >>= 1) mv = fmaxf(mv, __shfl_xor_sync(~0u, mv, o));
    float M = mv;
    float lv = (lane < 16) ? g_l3[base + (size_t)lane * MM] *
                             __expf(g_m3[base + (size_t)lane * MM] - M) : 0.f;
    #pragma unroll
    for (int o = 16; o; o >>= 1) lv += __shfl_xor_sync(~0u, lv, o);
    float invL = 1.f / lv;
    float a0 = 0.f, a1 = 0.f;
    for (int kk = 0; kk < KS; kk++) {
        float w = __expf(g_m3[base + (size_t)kk * MM] - M);
        float2 p = *(const float2*)(g_p3 + (base + (size_t)kk * MM) * DH + lane * 2);
        a0 += p.x * w; a1 += p.y * w;
    }
    *(float2*)(g_out3 + ((size_t)bh * MM + r) * DH + lane * 2) =
        make_float2(a0 * invL, a1 * invL);
}

// ---------------------------------------------------------------------------
// TF32 128x128x16 device tile (persistent pinv)
// ---------------------------------------------------------------------------
__device__ __forceinline__ void tc_tile(
    const float* Ab, const float* Bb, float* C, const float* X1,
    int N, int K, int lda, int ldb, long long cbase,
    float alpha, float beta, int m0, int n0,
    uint32_t (*As)[16][136], uint32_t (*Bs)[16][136])
{
    constexpr int BK = 16;
    int tid = threadIdx.x, lane = tid & 31, warp = tid >> 5;
    int wm0 = (warp >> 2) * 64;
    int wn0 = (warp & 3) * 32;
    float4 ra[2], rb[2];
    float acc[4][4][4];
    #pragma unroll
    for (int i = 0; i < 4; i++)
        #pragma unroll
        for (int j = 0; j < 4; j++)
            #pragma unroll
            for (int r = 0; r < 4; r++) acc[i][j][r] = 0.f;

    auto LOAD = [&](int kb) {
        #pragma unroll
        for (int c = 0; c < 2; c++) {
            int id = c * 256 + tid;
            int m = id >> 2, kq = id & 3;
            ra[c] = *(const float4*)(Ab + (size_t)(m0 + m) * lda + kb * BK + kq * 4);
        }
        #pragma unroll
        for (int c = 0; c < 2; c++) {
            int id = c * 256 + tid;
            int k = id >> 5, nq = id & 31;
            rb[c] = *(const float4*)(Bb + (size_t)(kb * BK + k) * ldb + n0 + nq * 4);
        }
    };
    auto COMMIT = [&](int bf) {
        #pragma unroll
        for (int c = 0; c < 2; c++) {
            int id = c * 256 + tid;
            int m = id >> 2, kq = id & 3;
            As[bf][kq*4+0][m] = f2tf(ra[c].x); As[bf][kq*4+1][m] = f2tf(ra[c].y);
            As[bf][kq*4+2][m] = f2tf(ra[c].z); As[bf][kq*4+3][m] = f2tf(ra[c].w);
        }
        #pragma unroll
        for (int c = 0; c < 2; c++) {
            int id = c * 256 + tid;
            int k = id >> 5, nq = id & 31;
            Bs[bf][k][nq*4+0] = f2tf(rb[c].x); Bs[bf][k][nq*4+1] = f2tf(rb[c].y);
            Bs[bf][k][nq*4+2] = f2tf(rb[c].z); Bs[bf][k][nq*4+3] = f2tf(rb[c].w);
        }
    };
    auto MMA = [&](int bf) {
        #pragma unroll
        for (int ks = 0; ks < 2; ks++) {
            uint32_t af[4][4], bfr[4][2];
            int kr = ks * 8 + (lane & 3);
            int mr = wm0 + (lane >> 2);
            #pragma unroll
            for (int mt = 0; mt < 4; mt++) {
                af[mt][0] = As[bf][kr    ][mr + mt*16];
                af[mt][1] = As[bf][kr    ][mr + mt*16 + 8];
                af[mt][2] = As[bf][kr + 4][mr + mt*16];
                af[mt][3] = As[bf][kr + 4][mr + mt*16 + 8];
            }
            int nr = wn0 + (lane >> 2);
            #pragma unroll
            for (int nt = 0; nt < 4; nt++) {
                bfr[nt][0] = Bs[bf][kr    ][nr + nt*8];
                bfr[nt][1] = Bs[bf][kr + 4][nr + nt*8];
            }
            #pragma unroll
            for (int mt = 0; mt < 4; mt++)
                #pragma unroll
                for (int nt = 0; nt < 4; nt++)
                    mma8(acc[mt][nt], af[mt], bfr[nt]);
        }
    };

    int nk = K / BK;
    LOAD(0); COMMIT(0);
    __syncthreads();
    for (int kb = 1; kb < nk; kb++) {
        LOAD(kb);
        MMA((kb - 1) & 1);
        COMMIT(kb & 1);
        __syncthreads();
    }
    MMA((nk - 1) & 1);

    #pragma unroll
    for (int mt = 0; mt < 4; mt++) {
        #pragma unroll
        for (int nt = 0; nt < 4; nt++) {
            int row = m0 + wm0 + mt * 16 + (lane >> 2);
            int col = n0 + wn0 + nt * 8 + (lane & 3) * 2;
            size_t r1 = cbase + (size_t)row * N + col;
            size_t r2 = cbase + (size_t)(row + 8) * N + col;
            float2 lo = make_float2(acc[mt][nt][0], acc[mt][nt][1]);
            float2 hi = make_float2(acc[mt][nt][2], acc[mt][nt][3]);
            float2 rv1 = make_float2(0.f, 0.f), rv2 = make_float2(0.f, 0.f);
            if (beta != 0.f) {
                rv1 = *(const float2*)(X1 + r1);
                rv2 = *(const float2*)(X1 + r2);
            }
            *(float2*)(C + r1) = make_float2(alpha*lo.x + beta*rv1.x, alpha*lo.y + beta*rv1.y);
            *(float2*)(C + r2) = make_float2(alpha*hi.x + beta*rv2.x, alpha*hi.y + beta*rv2.y);
        }
    }
}

__device__ __forceinline__ void gridbar(int i) {
    __syncthreads();
    if (threadIdx.x == 0) {
        __threadfence();
        atomicAdd(&g_barc[i], 1);
        while (((volatile int*)g_barc)[i] < 128) { }
        __threadfence();
    }
    __syncthreads();
}

// 6 tf32 Newton-Schulz iterations; after 6 ping-pong swaps result is in g_z
__global__ __launch_bounds__(256) void pinv_iters() {
    __shared__ uint32_t As[2][16][136];
    __shared__ uint32_t Bs[2][16][136];
    int m0 = blockIdx.y * 128, n0 = blockIdx.x * 128;
    long long base = (long long)blockIdx.z * (MM * MM);
    float* zc = g_z;
    float* zn = g_z2;
    int bi = 0;
    #pragma unroll 1
    for (int it = 0; it < 6; it++) {
        tc_tile(g_attn2 + base, zc + base, g_xz, nullptr, MM, MM, MM, MM, base,
                1.f, 0.f, m0, n0, As, Bs);
        gridbar(bi++);
        tc_tile(g_xz + base, g_xz + base, g_t, g_xz, MM, MM, MM, MM, base,
                -1.f, 7.f, m0, n0, As, Bs);
        gridbar(bi++);
        tc_tile(g_xz + base, g_t + base, g_u, g_xz, MM, MM, MM, MM, base,
                -1.f, 15.f, m0, n0, As, Bs);
        gridbar(bi++);
        tc_tile(zc + base, g_u + base, zn, zc, MM, MM, MM, MM, base,
                -0.25f, 3.25f, m0, n0, As, Bs);
        if (it < 5) gridbar(bi++);
        float* tmp = zc; zc = zn; zn = tmp;
    }
}

// Wc = z_final(g_z) @ out3, tf32
__global__ __launch_bounds__(256) void wc_gemm() {
    __shared__ uint32_t As[2][16][136];
    __shared__ uint32_t Bs[2][16][136];
    constexpr int BK = 16;
    int tid = threadIdx.x, lane = tid & 31, warp = tid >> 5;
    int wm0 = (warp >> 2) * 64;
    int wn0 = (warp & 3) * 16;
    int m0 = blockIdx.y * 128;
    long long abase = (long long)blockIdx.z * (MM * MM);
    long long cbase = (long long)blockIdx.z * (MM * DH);
    const float* Ab = g_z + abase;
    const float* Bb = g_out3 + cbase;
    float4 ra[2];
    float4 rb;
    float acc[4][2][4];
    #pragma unroll
    for (int i = 0; i < 4; i++)
        #pragma unroll
        for (int j = 0; j < 2; j++)
            #pragma unroll
            for (int r = 0; r < 4; r++) acc[i][j][r] = 0.f;

    auto LOAD = [&](int kb) {
        #pragma unroll
        for (int c = 0; c < 2; c++) {
            int id = c * 256 + tid;
            int m = id >> 2, kq = id & 3;
            ra[c] = *(const float4*)(Ab + (size_t)(m0 + m) * MM + kb * BK + kq * 4);
        }
        {
            int k = tid >> 4, nq = tid & 15;
            rb = *(const float4*)(Bb + (size_t)(kb * BK + k) * DH + nq * 4);
        }
    };
    auto COMMIT = [&](int bf) {
        #pragma unroll
        for (int c = 0; c < 2; c++) {
            int id = c * 256 + tid;
            int m = id >> 2, kq = id & 3;
            As[bf][kq*4+0][m] = f2tf(ra[c].x); As[bf][kq*4+1][m] = f2tf(ra[c].y);
            As[bf][kq*4+2][m] = f2tf(ra[c].z); As[bf][kq*4+3][m] = f2tf(ra[c].w);
        }
        {
            int k = tid >> 4, nq = tid & 15;
            Bs[bf][k][nq*4+0] = f2tf(rb.x); Bs[bf][k][nq*4+1] = f2tf(rb.y);
            Bs[bf][k][nq*4+2] = f2tf(rb.z); Bs[bf][k][nq*4+3] = f2tf(rb.w);
        }
    };
    auto MMA = [&](int bf) {
        #pragma unroll
        for (int ks = 0; ks < 2; ks++) {
            uint32_t af[4][4], bfr[2][2];
            int kr = ks * 8 + (lane & 3);
            int mr = wm0 + (lane >> 2);
            #pragma unroll
            for (int mt = 0; mt < 4; mt++) {
                af[mt][0] = As[bf][kr    ][mr + mt*16];
                af[mt][1] = As[bf][kr    ][mr + mt*16 + 8];
                af[mt][2] = As[bf][kr + 4][mr + mt*16];
                af[mt][3] = As[bf][kr + 4][mr + mt*16 + 8];
            }
            int nr = wn0 + (lane >> 2);
            #pragma unroll
            for (int nt = 0; nt < 2; nt++) {
                bfr[nt][0] = Bs[bf][kr    ][nr + nt*8];
                bfr[nt][1] = Bs[bf][kr + 4][nr + nt*8];
            }
            #pragma unroll
            for (int mt = 0; mt < 4; mt++)
                #pragma unroll
                for (int nt = 0; nt < 2; nt++)
                    mma8(acc[mt][nt], af[mt], bfr[nt]);
        }
    };

    LOAD(0); COMMIT(0);
    __syncthreads();
    for (int kb = 1; kb < 16; kb++) {
        LOAD(kb);
        MMA((kb - 1) & 1);
        COMMIT(kb & 1);
        __syncthreads();
    }
    MMA(1);

    #pragma unroll
    for (int mt = 0; mt < 4; mt++) {
        #pragma unroll
        for (int nt = 0; nt < 2; nt++) {
            int row = m0 + wm0 + mt * 16 + (lane >> 2);
            int col = wn0 + nt * 8 + (lane & 3) * 2;
            *(float2*)(g_wc + cbase + (size_t)row * DH + col) =
                make_float2(acc[mt][nt][0], acc[mt][nt][1]);
            *(float2*)(g_wc + cbase + (size_t)(row + 8) * DH + col) =
                make_float2(acc[mt][nt][2], acc[mt][nt][3]);
        }
    }
}

// ---------------------------------------------------------------------------
// BF16 GEMM (QKV -> bf16 q/k/v, out-proj)
// ---------------------------------------------------------------------------
template<int EPI, int BM, int BN, int BK>
__global__ __launch_bounds__(256) void bf_gemm(
    const float* __restrict__ Af, const float* __restrict__ Bg,
    float* __restrict__ C, const float* __restrict__ X1, const float* __restrict__ X2,
    int N, int K, int lda, int ldb)
{
    constexpr int PA = BM + 8, PB = BN + 8;
    constexpr int MT = (BM / 2) / 16;
    constexpr int NT = (BN / 4) / 8;
    constexpr int KP = BK / 2;
    constexpr int RAF = (BM * BK) / 1024;
    constexpr int RBN = (KP * (BN / 4)) / 256;
    __shared__ uint32_t As[2][KP][PA];
    __shared__ uint32_t Bs[2][KP][PB];
    float4 raf[RAF];
    float4 rb0[RBN], rb1[RBN];

    int tid = threadIdx.x, lane = tid & 31, warp = tid >> 5;
    int wm0 = (warp >> 2) * (BM / 2);
    int wn0 = (warp & 3) * (BN / 4);
    int m0 = blockIdx.y * BM, n0 = blockIdx.x * BN;

    float acc[MT][NT][4];
    #pragma unroll
    for (int i = 0; i < MT; i++)
        #pragma unroll
        for (int j = 0; j < NT; j++)
            #pragma unroll
            for (int r = 0; r < 4; r++) acc[i][j][r] = 0.f;

    auto LOAD = [&](int kb) {
        #pragma unroll
        for (int c = 0; c < RAF; c++) {
            int id = c * 256 + tid;
            int m = id / (BK / 4), kq = id % (BK / 4);
            raf[c] = *(const float4*)(Af + (size_t)(m0 + m) * lda + kb * BK + kq * 4);
        }
        #pragma unroll
        for (int c = 0; c < RBN; c++) {
            int id = c * 256 + tid;
            int kp = id / (BN / 4), nq = id % (BN / 4);
            rb0[c] = *(const float4*)(Bg + (size_t)(kb*BK + 2*kp    ) * ldb + n0 + nq * 4);
            rb1[c] = *(const float4*)(Bg + (size_t)(kb*BK + 2*kp + 1) * ldb + n0 + nq * 4);
        }
    };
    auto COMMIT = [&](int bf) {
        #pragma unroll
        for (int c = 0; c < RAF; c++) {
            int id = c * 256 + tid;
            int m = id / (BK / 4), kq = id % (BK / 4);
            As[bf][kq*2+0][m] = f2bf2(raf[c].x, raf[c].y);
            As[bf][kq*2+1][m] = f2bf2(raf[c].z, raf[c].w);
        }
        #pragma unroll
        for (int c = 0; c < RBN; c++) {
            int id = c * 256 + tid;
            int kp = id / (BN / 4), nq = id % (BN / 4);
            Bs[bf][kp][nq*4+0] = f2bf2(rb0[c].x, rb1[c].x);
            Bs[bf][kp][nq*4+1] = f2bf2(rb0[c].y, rb1[c].y);
            Bs[bf][kp][nq*4+2] = f2bf2(rb0[c].z, rb1[c].z);
            Bs[bf][kp][nq*4+3] = f2bf2(rb0[c].w, rb1[c].w);
        }
    };
    auto MMA = [&](int bf) {
        #pragma unroll
        for (int ks = 0; ks < BK / 16; ks++) {
            uint32_t af[MT][4], bfr[NT][2];
            int kr = ks * 8 + (lane & 3);
            int mr = wm0 + (lane >> 2);
            #pragma unroll
            for (int mt = 0; mt < MT; mt++) {
                af[mt][0] = As[bf][kr    ][mr + mt*16];
                af[mt][1] = As[bf][kr    ][mr + mt*16 + 8];
                af[mt][2] = As[bf][kr + 4][mr + mt*16];
                af[mt][3] = As[bf][kr + 4][mr + mt*16 + 8];
            }
            int nr = wn0 + (lane >> 2);
            #pragma unroll
            for (int nt = 0; nt < NT; nt++) {
                bfr[nt][0] = Bs[bf][kr    ][nr + nt*8];
                bfr[nt][1] = Bs[bf][kr + 4][nr + nt*8];
            }
            #pragma unroll
            for (int mt = 0; mt < MT; mt++)
                #pragma unroll
                for (int nt = 0; nt < NT; nt++)
                    mma16(acc[mt][nt], af[mt], bfr[nt]);
        }
    };

    int nk = K / BK;
    LOAD(0); COMMIT(0);
    __syncthreads();
    for (int kb = 1; kb < nk; kb++) {
        LOAD(kb);
        MMA((kb - 1) & 1);
        COMMIT(kb & 1);
        __syncthreads();
    }
    MMA((nk - 1) & 1);

    #pragma unroll
    for (int mt = 0; mt < MT; mt++) {
        #pragma unroll
        for (int nt = 0; nt < NT; nt++) {
            int row = m0 + wm0 + mt * 16 + (lane >> 2);
            int col = n0 + wn0 + nt * 8 + (lane & 3) * 2;
            float2 lo = make_float2(acc[mt][nt][0], acc[mt][nt][1]);
            float2 hi = make_float2(acc[mt][nt][2], acc[mt][nt][3]);
            if constexpr (EPI == 0) {
                int which = col >> 9, inner = col & 511;
                int h = inner >> 6, d = inner & 63;
                __nv_bfloat16* dst = which == 0 ? g_qh : (which == 1 ? g_kh : g_vh);
                float s = (which == 0) ? 0.125f : 1.f;
                int bq = row >> 13, n = row & (NN - 1);
                *(uint32_t*)(dst + (((size_t)(bq*HH+h))*NN + n    )*DH + d) = f2bf2(lo.x*s, lo.y*s);
                *(uint32_t*)(dst + (((size_t)(bq*HH+h))*NN + n + 8)*DH + d) = f2bf2(hi.x*s, hi.y*s);
            } else if constexpr (EPI == 1) {
                float2 bv = *(const float2*)(X1 + col);
                size_t r1 = (size_t)row * DD + col, r2 = (size_t)(row + 8) * DD + col;
                float2 x1 = *(const float2*)(X2 + r1);
                float2 x2 = *(const float2*)(X2 + r2);
                *(float2*)(C + r1) = make_float2(lo.x + bv.x + x1.x, lo.y + bv.y + x1.y);
                *(float2*)(C + r2) = make_float2(hi.x + bv.x + x2.x, hi.y + bv.y + x2.y);
            }
        }
    }
}

// ---------------------------------------------------------------------------
// Fused attn1: y += softmax(q @ kl^T) @ Wc  (q now bf16)
// ---------------------------------------------------------------------------
__global__ __launch_bounds__(256) void attn1_fused() {
    extern __shared__ char smraw[];
    uint32_t* As  = (uint32_t*)smraw;       // [16][72]
    uint32_t* Bs  = As + 16*72;             // [16][264]
    uint32_t* Ps  = Bs + 16*264;            // [128][72]
    uint32_t* Wcs = Ps + 128*72;            // [128][72]
    float* rmax = (float*)(Wcs + 128*72);
    float* rsum = rmax + 320;

    int tid = threadIdx.x, lane = tid & 31, warp = tid >> 5;
    int g = lane >> 2, q4 = lane & 3;
    int bh = blockIdx.y;
    int b = bh >> 3, h = bh & 7;
    int m0 = blockIdx.x * 64;
    const __nv_bfloat16* Ab = g_qh + ((size_t)bh * NN + m0) * DH;
    const float* Bb = g_kl + (size_t)bh * MM * DH;
    const float* Wg = g_wc + (size_t)bh * MM * DH;

    #pragma unroll
    for (int c = 0; c < 8; c++) {
        int id = c * 256 + tid;
        int kp = id >> 4, n4 = id & 15;
        float4 lo = *(const float4*)(Wg + (size_t)(2*kp    ) * DH + n4 * 4);
        float4 hi = *(const float4*)(Wg + (size_t)(2*kp + 1) * DH + n4 * 4);
        Wcs[kp*72 + n4*4+0] = f2bf2(lo.x, hi.x);
        Wcs[kp*72 + n4*4+1] = f2bf2(lo.y, hi.y);
        Wcs[kp*72 + n4*4+2] = f2bf2(lo.z, hi.z);
        Wcs[kp*72 + n4*4+3] = f2bf2(lo.w, hi.w);
    }

    int wm0q = (warp >> 2) * 32;
    int wn0q = (warp & 3) * 64;
    int wnq = warp & 3;
    float acc[2][8][4];
    #pragma unroll
    for (int i = 0; i < 2; i++)
        #pragma unroll
        for (int j = 0; j < 8; j++)
            #pragma unroll
            for (int r = 0; r < 4; r++) acc[i][j][r] = 0.f;

    for (int k0 = 0; k0 < 64; k0 += 32) {
        {   // A: 64 rows x 32 bf16 = 256 uint4, 1/thread
            int m = tid >> 2, kq = tid & 3;
            uint4 v = *(const uint4*)(Ab + (size_t)m * DH + k0 + kq * 8);
            As[(kq*4+0)*72 + m] = v.x; As[(kq*4+1)*72 + m] = v.y;
            As[(kq*4+2)*72 + m] = v.z; As[(kq*4+3)*72 + m] = v.w;
        }
        #pragma unroll
        for (int c = 0; c < 8; c++) {
            int id = c * 256 + tid;
            int n = id >> 3, kq = id & 7;
            float4 v = *(const float4*)(Bb + (size_t)n * DH + k0 + kq * 4);
            Bs[(kq*2+0)*264 + n] = f2bf2(v.x, v.y);
            Bs[(kq*2+1)*264 + n] = f2bf2(v.z, v.w);
        }
        __syncthreads();
        #pragma unroll
        for (int ks = 0; ks < 2; ks++) {
            uint32_t af[2][4], bfr[8][2];
            int kr = ks * 8 + q4;
            int mr = wm0q + g;
            #pragma unroll
            for (int mt = 0; mt < 2; mt++) {
                af[mt][0] = As[kr*72 + mr + mt*16];
                af[mt][1] = As[kr*72 + mr + mt*16 + 8];
                af[mt][2] = As[(kr+4)*72 + mr + mt*16];
                af[mt][3] = As[(kr+4)*72 + mr + mt*16 + 8];
            }
            int nr = wn0q + g;
            #pragma unroll
            for (int nt = 0; nt < 8; nt++) {
                bfr[nt][0] = Bs[kr*264 + nr + nt*8];
                bfr[nt][1] = Bs[(kr+4)*264 + nr + nt*8];
            }
            #pragma unroll
            for (int mt = 0; mt < 2; mt++)
                #pragma unroll
                for (int nt = 0; nt < 8; nt++)
                    mma16(acc[mt][nt], af[mt], bfr[nt]);
        }
        __syncthreads();
    }

    #pragma unroll
    for (int mt = 0; mt < 2; mt++) {
        int r0 = wm0q + mt * 16 + g;
        float m0v = -1e30f, m1v = -1e30f;
        #pragma unroll
        for (int nt = 0; nt < 8; nt++) {
            m0v = fmaxf(m0v, fmaxf(acc[mt][nt][0], acc[mt][nt][1]));
            m1v = fmaxf(m1v, fmaxf(acc[mt][nt][2], acc[mt][nt][3]));
        }
        #pragma unroll
        for (int o = 1; o < 4; o <<= 1) {
            m0v = fmaxf(m0v, __shfl_xor_sync(~0u, m0v, o));
            m1v = fmaxf(m1v, __shfl_xor_sync(~0u, m1v, o));
        }
        if (q4 == 0) { rmax[r0*5 + wnq] = m0v; rmax[(r0+8)*5 + wnq] = m1v; }
    }
    __syncthreads();
    #pragma unroll
    for (int mt = 0; mt < 2; mt++) {
        int r0 = wm0q + mt * 16 + g;
        float M0 = fmaxf(fmaxf(rmax[r0*5+0], rmax[r0*5+1]), fmaxf(rmax[r0*5+2], rmax[r0*5+3]));
        float M1 = fmaxf(fmaxf(rmax[(r0+8)*5+0], rmax[(r0+8)*5+1]),
                         fmaxf(rmax[(r0+8)*5+2], rmax[(r0+8)*5+3]));
        float s0 = 0.f, s1 = 0.f;
        #pragma unroll
        for (int nt = 0; nt < 8; nt++) {
            acc[mt][nt][0] = __expf(acc[mt][nt][0] - M0);
            acc[mt][nt][1] = __expf(acc[mt][nt][1] - M0);
            acc[mt][nt][2] = __expf(acc[mt][nt][2] - M1);
            acc[mt][nt][3] = __expf(acc[mt][nt][3] - M1);
            s0 += acc[mt][nt][0] + acc[mt][nt][1];
            s1 += acc[mt][nt][2] + acc[mt][nt][3];
        }
        #pragma unroll
        for (int o = 1; o < 4; o <<= 1) {
            s0 += __shfl_xor_sync(~0u, s0, o);
            s1 += __shfl_xor_sync(~0u, s1, o);
        }
        if (q4 == 0) { rsum[r0*5 + wnq] = s0; rsum[(r0+8)*5 + wnq] = s1; }
    }
    __syncthreads();
    #pragma unroll
    for (int mt = 0; mt < 2; mt++) {
        int r0 = wm0q + mt * 16 + g, r1 = r0 + 8;
        float i0 = 1.f / (rsum[r0*5+0] + rsum[r0*5+1] + rsum[r0*5+2] + rsum[r0*5+3]);
        float i1 = 1.f / (rsum[r1*5+0] + rsum[r1*5+1] + rsum[r1*5+2] + rsum[r1*5+3]);
        #pragma unroll
        for (int nt = 0; nt < 8; nt++) {
            int kp = (wn0q >> 1) + nt * 4 + q4;
            Ps[kp*72 + r0] = f2bf2(acc[mt][nt][0] * i0, acc[mt][nt][1] * i0);
            Ps[kp*72 + r1] = f2bf2(acc[mt][nt][2] * i1, acc[mt][nt][3] * i1);
        }
    }
    __syncthreads();

    int wm0p = (warp >> 2) * 32;
    int wn0p = (warp & 3) * 16;
    float yacc[2][2][4];
    #pragma unroll
    for (int i = 0; i < 2; i++)
        #pragma unroll
        for (int j = 0; j < 2; j++)
            #pragma unroll
            for (int r = 0; r < 4; r++) yacc[i][j][r] = 0.f;
    #pragma unroll
    for (int kc = 0; kc < 16; kc++) {
        int kr = kc * 8 + q4;
        uint32_t af[2][4], bfr[2][2];
        int mr = wm0p + g;
        #pragma unroll
        for (int mt = 0; mt < 2; mt++) {
            af[mt][0] = Ps[kr*72 + mr + mt*16];
            af[mt][1] = Ps[kr*72 + mr + mt*16 + 8];
            af[mt][2] = Ps[(kr+4)*72 + mr + mt*16];
            af[mt][3] = Ps[(kr+4)*72 + mr + mt*16 + 8];
        }
        int nr = wn0p + g;
        #pragma unroll
        for (int nt = 0; nt < 2; nt++) {
            bfr[nt][0] = Wcs[kr*72 + nr + nt*8];
            bfr[nt][1] = Wcs[(kr+4)*72 + nr + nt*8];
        }
        #pragma unroll
        for (int mt = 0; mt < 2; mt++)
            #pragma unroll
            for (int nt = 0; nt < 2; nt++)
                mma16(yacc[mt][nt], af[mt], bfr[nt]);
    }
    #pragma unroll
    for (int mt = 0; mt < 2; mt++) {
        #pragma unroll
        for (int nt = 0; nt < 2; nt++) {
            int row = m0 + wm0p + mt * 16 + g;
            int col = wn0p + nt * 8 + q4 * 2;
            size_t r1 = ((size_t)b * NN + row    ) * DD + h * 64 + col;
            size_t r2 = ((size_t)b * NN + row + 8) * DD + h * 64 + col;
            float2 y1 = *(float2*)(g_y + r1);
            float2 y2 = *(float2*)(g_y + r2);
            *(float2*)(g_y + r1) = make_float2(y1.x + yacc[mt][nt][0], y1.y + yacc[mt][nt][1]);
            *(float2*)(g_y + r2) = make_float2(y2.x + yacc[mt][nt][2], y2.y + yacc[mt][nt][3]);
        }
    }
}

// ---------------------------------------------------------------------------
// LN / landmarks(bf16) / sim2 / softmax256 / init / colrowmax / z0 / conv(bf16)
// ---------------------------------------------------------------------------
__global__ __launch_bounds__(128) void ln_kernel(const float* __restrict__ x,
                                                 const float* __restrict__ w,
                                                 const float* __restrict__ bia) {
    int row = blockIdx.x, tid = threadIdx.x;
    const float4* xr = reinterpret_cast<const float4*>(x + (size_t)row * DD);
    float4 v = xr[tid];
    float s  = v.x + v.y + v.z + v.w;
    float sq = v.x*v.x + v.y*v.y + v.z*v.z + v.w*v.w;
    __shared__ float sm[4], sm2[4];
    #pragma unroll
    for (int o = 16; o > 0; o >>= 1) {
        s  += __shfl_down_sync(0xffffffffu, s,  o);
        sq += __shfl_down_sync(0xffffffffu, sq, o);
    }
    if ((tid & 31) == 0) { sm[tid >> 5] = s; sm2[tid >> 5] = sq; }
    __syncthreads();
    if (tid == 0) {
        float a = 0.f, b2 = 0.f;
        #pragma unroll
        for (int i = 0; i < 4; i++) { a += sm[i]; b2 += sm2[i]; }
        sm[0] = a; sm2[0] = b2;
    }
    __syncthreads();
    float mean = sm[0] * (1.f / 512.f);
    float var  = sm2[0] * (1.f / 512.f) - mean * mean;
    float rstd = rsqrtf(var + 1e-5f);
    float4 wv = reinterpret_cast<const float4*>(w)[tid];
    float4 bv = reinterpret_cast<const float4*>(bia)[tid];
    float4 o;
    o.x = (v.x - mean) * rstd * wv.x + bv.x;
    o.y = (v.y - mean) * rstd * wv.y + bv.y;
    o.z = (v.z - mean) * rstd * wv.z + bv.z;
    o.w = (v.w - mean) * rstd * wv.w + bv.w;
    reinterpret_cast<float4*>(g_xn + (size_t)row * DD)[tid] = o;
}

__global__ void landmark_kernel() {
    int m = blockIdx.x, bh = blockIdx.y;
    int d = threadIdx.x;
    size_t base = ((size_t)bh * NN + (size_t)m * 32) * DH + d;
    float sq = 0.f, sk = 0.f;
    #pragma unroll
    for (int j = 0; j < 32; j++) {
        sq += __bfloat162float(g_qh[base + (size_t)j * DH]);
        sk += __bfloat162float(g_kh[base + (size_t)j * DH]);
    }
    size_t o = ((size_t)bh * MM + m) * DH + d;
    g_ql[o] = sq * (1.f / 32.f);
    g_kl[o] = sk * (1.f / 32.f);
}

__global__ __launch_bounds__(256) void gemm_sim2() {
    __shared__ float As[32][132];
    __shared__ float Bs[32][132];
    int bh = blockIdx.z;
    int n0 = blockIdx.x * 128, m0 = blockIdx.y * 128;
    const float* Ab = g_ql + ((size_t)bh * MM + m0) * DH;
    const float* Bb = g_kl + ((size_t)bh * MM + n0) * DH;
    float* Cb = g_attn2 + (size_t)bh * MM * MM;
    int tid = threadIdx.x;
    int tx = tid & 15, ty = tid >> 4;
    float acc[8][8] = {};
    for (int kk = 0; kk < 64; kk += 32) {
        #pragma unroll
        for (int u = 0; u < 4; u++) {
            int g = u * 256 + tid;
            int m = g >> 3, k4 = g & 7;
            float4 av = *(const float4*)(Ab + (size_t)m * DH + kk + k4 * 4);
            As[k4*4+0][m] = av.x; As[k4*4+1][m] = av.y;
            As[k4*4+2][m] = av.z; As[k4*4+3][m] = av.w;
        }
        #pragma unroll
        for (int u = 0; u < 4; u++) {
            int g = u * 256 + tid;
            int m = g >> 3, k4 = g & 7;
            float4 bv = *(const float4*)(Bb + (size_t)m * DH + kk + k4 * 4);
            Bs[k4*4+0][m] = bv.x; Bs[k4*4+1][m] = bv.y;
            Bs[k4*4+2][m] = bv.z; Bs[k4*4+3][m] = bv.w;
        }
        __syncthreads();
        #pragma unroll
        for (int k = 0; k < 32; k++) {
            float a[8], b[8];
            *(float4*)&a[0] = *(const float4*)&As[k][ty*8];
            *(float4*)&a[4] = *(const float4*)&As[k][ty*8+4];
            *(float4*)&b[0] = *(const float4*)&Bs[k][tx*8];
            *(float4*)&b[4] = *(const float4*)&Bs[k][tx*8+4];
            #pragma unroll
            for (int i = 0; i < 8; i++)
                #pragma unroll
                for (int j = 0; j < 8; j++)
                    acc[i][j] += a[i] * b[j];
        }
        __syncthreads();
    }
    #pragma unroll
    for (int i = 0; i < 8; i++) {
        size_t r = (size_t)(m0 + ty * 8 + i) * MM + n0 + tx * 8;
        *(float4*)(Cb + r)     = make_float4(acc[i][0], acc[i][1], acc[i][2], acc[i][3]);
        *(float4*)(Cb + r + 4) = make_float4(acc[i][4], acc[i][5], acc[i][6], acc[i][7]);
    }
}

__global__ __launch_bounds__(256) void softmax256() {
    int row = blockIdx.x, tid = threadIdx.x;
    float* p = g_attn2 + (size_t)row * MM;
    float v = p[tid];
    __shared__ float red[8];
    float m = v;
    #pragma unroll
    for (int o = 16; o; o >>= 1) m = fmaxf(m, __shfl_xor_sync(~0u, m, o));
    if ((tid & 31) == 0) red[tid >> 5] = m;
    __syncthreads();
    if (tid < 32) {
        float t = (tid < 8) ? red[tid] : -1e30f;
        #pragma unroll
        for (int o = 4; o; o >>= 1) t = fmaxf(t, __shfl_xor_sync(~0u, t, o));
        if (tid == 0) red[0] = t;
    }
    __syncthreads();
    float mx = red[0];
    __syncthreads();
    float e = __expf(v - mx);
    float s = e;
    #pragma unroll
    for (int o = 16; o; o >>= 1) s += __shfl_xor_sync(~0u, s, o);
    if ((tid & 31) == 0) red[tid >> 5] = s;
    __syncthreads();
    if (tid < 32) {
        float t = (tid < 8) ? red[tid] : 0.f;
        #pragma unroll
        for (int o = 4; o; o >>= 1) t += __shfl_xor_sync(~0u, t, o);
        if (tid == 0) red[0] = t;
    }
    __syncthreads();
    p[tid] = e / red[0];
}

__global__ void init_kernel() {
    g_maxA = 0; g_maxB = 0;
    if (threadIdx.x < 32) g_barc[threadIdx.x] = 0;
}

__global__ __launch_bounds__(256) void colrowmax_kernel() {
    int bh = blockIdx.x, tid = threadIdx.x;
    const float* a = g_attn2 + (size_t)bh * MM * MM;
    float cs = 0.f, rs = 0.f;
    for (int m = 0; m < MM; m++) cs += fabsf(a[(size_t)m * MM + tid]);
    for (int n = 0; n < MM; n++) rs += fabsf(a[(size_t)tid * MM + n]);
    __shared__ float r1[8], r2[8];
    #pragma unroll
    for (int o = 16; o; o >>= 1) {
        cs = fmaxf(cs, __shfl_xor_sync(~0u, cs, o));
        rs = fmaxf(rs, __shfl_xor_sync(~0u, rs, o));
    }
    if ((tid & 31) == 0) { r1[tid >> 5] = cs; r2[tid >> 5] = rs; }
    __syncthreads();
    if (tid == 0) {
        float a1 = r1[0], a2 = r2[0];
        #pragma unroll
        for (int i = 1; i < 8; i++) { a1 = fmaxf(a1, r1[i]); a2 = fmaxf(a2, r2[i]); }
        atomicMax(&g_maxA, __float_as_int(a1));
        atomicMax(&g_maxB, __float_as_int(a2));
    }
}

__global__ __launch_bounds__(256) void z0_kernel() {
    int bh = blockIdx.z;
    int c0 = blockIdx.x * 32, r0 = blockIdx.y * 32;
    int tid = threadIdx.x;
    __shared__ float t[32][33];
    const float* a = g_attn2 + (size_t)bh * MM * MM;
    #pragma unroll
    for (int rr = 0; rr < 4; rr++) {
        int r = rr * 8 + (tid >> 5), c = tid & 31;
        t[r][c] = a[(size_t)(r0 + r) * MM + c0 + c];
    }
    __syncthreads();
    float s = 1.f / (__int_as_float(g_maxA) * __int_as_float(g_maxB));
    float* z = g_z + (size_t)bh * MM * MM;
    #pragma unroll
    for (int rr = 0; rr < 4; rr++) {
        int r = rr * 8 + (tid >> 5), c = tid & 31;
        z[(size_t)(c0 + r) * MM + r0 + c] = t[c][r] * s;
    }
}

__global__ __launch_bounds__(256) void conv_kernel(const float* __restrict__ res_w) {
    __shared__ float sv[160][64];
    __shared__ float sw[33];
    int bh = blockIdx.y, n0 = blockIdx.x * 128;
    int b = bh >> 3, h = bh & 7;
    int tid = threadIdx.x;
    if (tid < 33) sw[tid] = res_w[h * 33 + tid];
    const __nv_bfloat16* vb = g_vh + (size_t)bh * NN * DH;
    #pragma unroll
    for (int i = 0; i < 10; i++) {
        int idx = tid + i * 256;
        int r = idx >> 4, c4 = idx & 15;
        int tok = n0 - 16 + r;
        float4 val = make_float4(0.f, 0.f, 0.f, 0.f);
        if (tok >= 0 && tok < NN) {
            uint2 u = *(const uint2*)(vb + (size_t)tok * DH + c4 * 4);
            float2 a = __bfloat1622float2(*(const __nv_bfloat162*)&u.x);
            float2 bq = __bfloat1622float2(*(const __nv_bfloat162*)&u.y);
            val = make_float4(a.x, a.y, bq.x, bq.y);
        }
        *(float4*)&sv[r][c4 * 4] = val;
    }
    __syncthreads();
    #pragma unroll
    for (int i = 0; i < 8; i++) {
        int idx = tid + i * 256;
        int nl = idx >> 4, dg = idx & 15;
        float4 acc = make_float4(0.f, 0.f, 0.f, 0.f);
        #pragma unroll
        for (int j = 0; j < 33; j++) {
            float w = sw[j];
            float4 vv = *(const float4*)&sv[nl + j][dg * 4];
            acc.x += w * vv.x; acc.y += w * vv.y;
            acc.z += w * vv.z; acc.w += w * vv.w;
        }
        *(float4*)(g_y + ((size_t)b * NN + n0 + nl) * DD + h * 64 + dg * 4) = acc;
    }
}

// ---------------------------------------------------------------------------
// Launch
// ---------------------------------------------------------------------------
extern "C" void kernel_launch(void* const* d_in, const int* in_sizes, int n_in,
                              void* d_out, int out_size) {
    const float* x     = (const float*)d_in[0];
    const float* ln_w  = (const float*)d_in[1];
    const float* ln_b  = (const float*)d_in[2];
    const float* w_qkv = (const float*)d_in[3];
    const float* w_out = (const float*)d_in[4];
    const float* b_out = (const float*)d_in[5];
    const float* res_w = (const float*)d_in[6];
    float* out = (float*)d_out;

    float *p_xn, *p_y;
    cudaGetSymbolAddress((void**)&p_xn, g_xn);
    cudaGetSymbolAddress((void**)&p_y,  g_y);

    cudaFuncSetAttribute(flash3, cudaFuncAttributeMaxDynamicSharedMemorySize, 58368);
    cudaFuncSetAttribute(attn1_fused, cudaFuncAttributeMaxDynamicSharedMemorySize, 98304);

    ln_kernel<<<BB * NN, 128>>>(x, ln_w, ln_b);
    bf_gemm<0,128,128,32><<<dim3(12, 256, 1), 256>>>(
        p_xn, w_qkv, nullptr, nullptr, nullptr, 1536, 512, 512, 1536);
    landmark_kernel<<<dim3(MM, BH), 64>>>();

    gemm_sim2<<<dim3(2, 2, BH), 256>>>();
    flash3<<<dim3(2, KS, BH), 256, 58368>>>();
    combine3<<<1024, 256>>>();
    softmax256<<<BH * MM, 256>>>();

    init_kernel<<<1, 32>>>();
    colrowmax_kernel<<<BH, 256>>>();
    z0_kernel<<<dim3(8, 8, BH), 256>>>();

    // 6 tf32 NS iterations in one persistent kernel; z_final lands in g_z
    pinv_iters<<<dim3(2, 2, BH), 256>>>();

    // Wc = z_final(g_z) @ out3 (tf32)
    wc_gemm<<<dim3(1, 2, BH), 256>>>();

    conv_kernel<<<dim3(64, BH), 256>>>(res_w);
    attn1_fused<<<dim3(128, BH), 256, 98304>>>();

    bf_gemm<1,128,128,32><<<dim3(4, 256, 1), 256>>>(
        p_y, w_out, out, b_out, x, 512, 512, 512, 512);
}

// round 13
// speedup vs baseline: 1.5093x; 1.0236x over previous
#include <cuda_runtime.h>
#include <cuda_bf16.h>
#include <stdint.h>
#include <math.h>

#define BB 4
#define NN 8192
#define DD 512
#define HH 8
#define DH 64
#define MM 256
#define BH 32
#define KS 16

__device__ __align__(16) float g_xn  [(size_t)BB*NN*DD];
__device__ __align__(16) __nv_bfloat16 g_qh[(size_t)BH*NN*DH];
__device__ __align__(16) __nv_bfloat16 g_kh[(size_t)BH*NN*DH];
__device__ __align__(16) __nv_bfloat16 g_vh[(size_t)BH*NN*DH];
__device__ __align__(16) float g_ql  [(size_t)BH*MM*DH];
__device__ __align__(16) float g_kl  [(size_t)BH*MM*DH];
__device__ __align__(16) float g_attn2[(size_t)BH*MM*MM];
__device__ __align__(16) float g_z   [(size_t)BH*MM*MM];
__device__ __align__(16) float g_z2  [(size_t)BH*MM*MM];
__device__ __align__(16) float g_xz  [(size_t)BH*MM*MM];
__device__ __align__(16) float g_t   [(size_t)BH*MM*MM];
__device__ __align__(16) float g_u   [(size_t)BH*MM*MM];
__device__ __align__(16) float g_p3  [(size_t)BH*KS*MM*DH];
__device__ __align__(16) float g_m3  [(size_t)BH*KS*MM];
__device__ __align__(16) float g_l3  [(size_t)BH*KS*MM];
__device__ __align__(16) float g_out3[(size_t)BH*MM*DH];
__device__ __align__(16) float g_wc  [(size_t)BH*MM*DH];
__device__ __align__(16) float g_y   [(size_t)BB*NN*DD];
__device__ int g_maxA;
__device__ int g_maxB;
__device__ int g_barc[32];

__device__ __forceinline__ uint32_t f2tf(float f) {
    uint32_t u;
    asm("cvt.rna.tf32.f32 %0, %1;" : "=r"(u) : "f"(f));
    return u;
}
__device__ __forceinline__ uint32_t f2bf2(float lo, float hi) {
    uint32_t r;
    asm("cvt.rn.bf16x2.f32 %0, %1, %2;" : "=r"(r) : "f"(hi), "f"(lo));
    return r;
}
__device__ __forceinline__ void mma8(float* d, const uint32_t* a, const uint32_t* b) {
    asm volatile(
        "mma.sync.aligned.m16n8k8.row.col.f32.tf32.tf32.f32 "
        "{%0,%1,%2,%3}, {%4,%5,%6,%7}, {%8,%9}, {%0,%1,%2,%3};"
        : "+f"(d[0]), "+f"(d[1]), "+f"(d[2]), "+f"(d[3])
        : "r"(a[0]), "r"(a[1]), "r"(a[2]), "r"(a[3]), "r"(b[0]), "r"(b[1]));
}
__device__ __forceinline__ void mma16(float* d, const uint32_t* a, const uint32_t* b) {
    asm volatile(
        "mma.sync.aligned.m16n8k16.row.col.f32.bf16.bf16.f32 "
        "{%0,%1,%2,%3}, {%4,%5,%6,%7}, {%8,%9}, {%0,%1,%2,%3};"
        : "+f"(d[0]), "+f"(d[1]), "+f"(d[2]), "+f"(d[3])
        : "r"(a[0]), "r"(a[1]), "r"(a[2]), "r"(a[3]), "r"(b[0]), "r"(b[1]));
}

// ---------------------------------------------------------------------------
// Flash split-KV attn3 (unchanged from R12)
// ---------------------------------------------------------------------------
__global__ __launch_bounds__(256) void flash3() {
    extern __shared__ char smraw[];
    uint32_t* Qs = (uint32_t*)smraw;
    uint32_t* Ksm = Qs + 32*136;
    uint32_t* Vsm = Ksm + 32*72;
    uint32_t* Ps = Vsm + 32*72;
    float* wmax = (float*)(Ps + 32*136);
    float* wsum = wmax + 512;
    float* mrun = wsum + 512;
    float* lrun = mrun + 128;

    int tid = threadIdx.x, lane = tid & 31, warp = tid >> 5;
    int g = lane >> 2, q4 = lane & 3;
    int wm0 = (warp >> 2) * 64;
    int wn0 = (warp & 3) * 16;
    int wn = warp & 3;
    int m0 = blockIdx.x * 128;
    int ksp = blockIdx.y, bh = blockIdx.z;

    const float* Qg = g_ql + ((size_t)bh * MM + m0) * DH;
    #pragma unroll
    for (int c = 0; c < 8; c++) {
        int id = c * 256 + tid;
        int m = id >> 4, qq = id & 15;
        float4 v = *(const float4*)(Qg + (size_t)m * DH + qq * 4);
        Qs[(qq*2+0)*136 + m] = f2bf2(v.x, v.y);
        Qs[(qq*2+1)*136 + m] = f2bf2(v.z, v.w);
    }
    if (tid < 128) { mrun[tid] = -1e30f; lrun[tid] = 0.f; }

    float acc[4][2][4];
    #pragma unroll
    for (int a = 0; a < 4; a++)
        #pragma unroll
        for (int b = 0; b < 2; b++)
            #pragma unroll
            for (int r = 0; r < 4; r++) acc[a][b][r] = 0.f;

    const __nv_bfloat16* Kg = g_kh + ((size_t)bh * NN + ksp * 512) * DH;
    const __nv_bfloat16* Vg = g_vh + ((size_t)bh * NN + ksp * 512) * DH;

    for (int t = 0; t < 8; t++) {
        __syncthreads();
        #pragma unroll
        for (int c = 0; c < 2; c++) {
            int id = c * 256 + tid;
            int n = id >> 3, qq = id & 7;
            uint4 v = *(const uint4*)(Kg + (size_t)(t*64 + n) * DH + qq * 8);
            Ksm[(qq*4+0)*72 + n] = v.x; Ksm[(qq*4+1)*72 + n] = v.y;
            Ksm[(qq*4+2)*72 + n] = v.z; Ksm[(qq*4+3)*72 + n] = v.w;
        }
        #pragma unroll
        for (int c = 0; c < 2; c++) {
            int id = c * 256 + tid;
            int kp = id >> 4, qg = id & 15;
            uint2 a = *(const uint2*)(Vg + (size_t)(t*64 + 2*kp    ) * DH + qg * 4);
            uint2 b = *(const uint2*)(Vg + (size_t)(t*64 + 2*kp + 1) * DH + qg * 4);
            Vsm[kp*72 + qg*4+0] = __byte_perm(a.x, b.x, 0x5410);
            Vsm[kp*72 + qg*4+1] = __byte_perm(a.x, b.x, 0x7632);
            Vsm[kp*72 + qg*4+2] = __byte_perm(a.y, b.y, 0x5410);
            Vsm[kp*72 + qg*4+3] = __byte_perm(a.y, b.y, 0x7632);
        }
        __syncthreads();

        float S[4][2][4];
        #pragma unroll
        for (int a = 0; a < 4; a++)
            #pragma unroll
            for (int b = 0; b < 2; b++)
                #pragma unroll
                for (int r = 0; r < 4; r++) S[a][b][r] = 0.f;
        #pragma unroll
        for (int k2 = 0; k2 < 4; k2++) {
            int kr = k2 * 8 + q4;
            uint32_t af[4][4], bfr[2][2];
            int mr = wm0 + g;
            #pragma unroll
            for (int mt = 0; mt < 4; mt++) {
                af[mt][0] = Qs[kr*136 + mr + mt*16];
                af[mt][1] = Qs[kr*136 + mr + mt*16 + 8];
                af[mt][2] = Qs[(kr+4)*136 + mr + mt*16];
                af[mt][3] = Qs[(kr+4)*136 + mr + mt*16 + 8];
            }
            int nr = wn0 + g;
            #pragma unroll
            for (int nt = 0; nt < 2; nt++) {
                bfr[nt][0] = Ksm[kr*72 + nr + nt*8];
                bfr[nt][1] = Ksm[(kr+4)*72 + nr + nt*8];
            }
            #pragma unroll
            for (int mt = 0; mt < 4; mt++)
                #pragma unroll
                for (int nt = 0; nt < 2; nt++)
                    mma16(S[mt][nt], af[mt], bfr[nt]);
        }

        #pragma unroll
        for (int mt = 0; mt < 4; mt++) {
            float m0v = fmaxf(fmaxf(S[mt][0][0], S[mt][0][1]), fmaxf(S[mt][1][0], S[mt][1][1]));
            float m1v = fmaxf(fmaxf(S[mt][0][2], S[mt][0][3]), fmaxf(S[mt][1][2], S[mt][1][3]));
            #pragma unroll
            for (int o = 1; o < 4; o <<= 1) {
                m0v = fmaxf(m0v, __shfl_xor_sync(~0u, m0v, o));
                m1v = fmaxf(m1v, __shfl_xor_sync(~0u, m1v, o));
            }
            if (q4 == 0) {
                wmax[(wm0 + mt*16 + g)*4 + wn] = m0v;
                wmax[(wm0 + mt*16 + g + 8)*4 + wn] = m1v;
            }
        }
        __syncthreads();

        #pragma unroll
        for (int mt = 0; mt < 4; mt++) {
            int r0 = wm0 + mt*16 + g, r1 = r0 + 8;
            float mo0 = mrun[r0];
            float mt0 = fmaxf(fmaxf(wmax[r0*4+0], wmax[r0*4+1]), fmaxf(wmax[r0*4+2], wmax[r0*4+3]));
            float mn0 = fmaxf(mo0, mt0);
            float sc0 = __expf(mo0 - mn0);
            float mo1 = mrun[r1];
            float mt1 = fmaxf(fmaxf(wmax[r1*4+0], wmax[r1*4+1]), fmaxf(wmax[r1*4+2], wmax[r1*4+3]));
            float mn1 = fmaxf(mo1, mt1);
            float sc1 = __expf(mo1 - mn1);
            float s0 = 0.f, s1 = 0.f;
            #pragma unroll
            for (int nt = 0; nt < 2; nt++) {
                S[mt][nt][0] = __expf(S[mt][nt][0] - mn0);
                S[mt][nt][1] = __expf(S[mt][nt][1] - mn0);
                S[mt][nt][2] = __expf(S[mt][nt][2] - mn1);
                S[mt][nt][3] = __expf(S[mt][nt][3] - mn1);
                s0 += S[mt][nt][0] + S[mt][nt][1];
                s1 += S[mt][nt][2] + S[mt][nt][3];
                int cp = wn * 8 + nt * 4 + q4;
                Ps[cp*136 + r0] = f2bf2(S[mt][nt][0], S[mt][nt][1]);
                Ps[cp*136 + r1] = f2bf2(S[mt][nt][2], S[mt][nt][3]);
                acc[mt][nt][0] *= sc0; acc[mt][nt][1] *= sc0;
                acc[mt][nt][2] *= sc1; acc[mt][nt][3] *= sc1;
            }
            #pragma unroll
            for (int o = 1; o < 4; o <<= 1) {
                s0 += __shfl_xor_sync(~0u, s0, o);
                s1 += __shfl_xor_sync(~0u, s1, o);
            }
            if (q4 == 0) { wsum[r0*4+wn] = s0; wsum[r1*4+wn] = s1; }
        }
        __syncthreads();

        if (tid < 128) {
            float mo = mrun[tid];
            float mt2 = fmaxf(fmaxf(wmax[tid*4+0], wmax[tid*4+1]), fmaxf(wmax[tid*4+2], wmax[tid*4+3]));
            float mn = fmaxf(mo, mt2);
            mrun[tid] = mn;
            lrun[tid] = lrun[tid]*__expf(mo - mn) +
                        wsum[tid*4+0] + wsum[tid*4+1] + wsum[tid*4+2] + wsum[tid*4+3];
        }
        #pragma unroll
        for (int k2 = 0; k2 < 4; k2++) {
            int kr = k2 * 8 + q4;
            uint32_t af[4][4], bfr[2][2];
            int mr = wm0 + g;
            #pragma unroll
            for (int mt = 0; mt < 4; mt++) {
                af[mt][0] = Ps[kr*136 + mr + mt*16];
                af[mt][1] = Ps[kr*136 + mr + mt*16 + 8];
                af[mt][2] = Ps[(kr+4)*136 + mr + mt*16];
                af[mt][3] = Ps[(kr+4)*136 + mr + mt*16 + 8];
            }
            int nr = wn0 + g;
            #pragma unroll
            for (int nt = 0; nt < 2; nt++) {
                bfr[nt][0] = Vsm[kr*72 + nr + nt*8];
                bfr[nt][1] = Vsm[(kr+4)*72 + nr + nt*8];
            }
            #pragma unroll
            for (int mt = 0; mt < 4; mt++)
                #pragma unroll
                for (int nt = 0; nt < 2; nt++)
                    mma16(acc[mt][nt], af[mt], bfr[nt]);
        }
    }
    __syncthreads();

    size_t ob = (size_t)(bh * KS + ksp) * MM + m0;
    #pragma unroll
    for (int mt = 0; mt < 4; mt++) {
        #pragma unroll
        for (int nt = 0; nt < 2; nt++) {
            int r0 = wm0 + mt*16 + g;
            int c = wn0 + nt*8 + q4*2;
            *(float2*)(g_p3 + (ob + r0)*DH + c)     = make_float2(acc[mt][nt][0], acc[mt][nt][1]);
            *(float2*)(g_p3 + (ob + r0 + 8)*DH + c) = make_float2(acc[mt][nt][2], acc[mt][nt][3]);
        }
    }
    if (tid < 128) {
        g_m3[ob + tid] = mrun[tid];
        g_l3[ob + tid] = lrun[tid];
    }
}

__global__ __launch_bounds__(256) void combine3() {
    int warp = threadIdx.x >> 5, lane = threadIdx.x & 31;
    int rowg = blockIdx.x * 8 + warp;
    int bh = rowg >> 8, r = rowg & 255;
    size_t base = (size_t)(bh * KS) * MM + r;
    float mv = (lane < 16) ? g_m3[base + (size_t)lane * MM] : -1e30f;
    #pragma unroll
    for (int o = 16; o; o >>= 1) mv = fmaxf(mv, __shfl_xor_sync(~0u, mv, o));
    float M = mv;
    float lv = (lane < 16) ? g_l3[base + (size_t)lane * MM] *
                             __expf(g_m3[base + (size_t)lane * MM] - M) : 0.f;
    #pragma unroll
    for (int o = 16; o; o >>= 1) lv += __shfl_xor_sync(~0u, lv, o);
    float invL = 1.f / lv;
    float a0 = 0.f, a1 = 0.f;
    for (int kk = 0; kk < KS; kk++) {
        float w = __expf(g_m3[base + (size_t)kk * MM] - M);
        float2 p = *(const float2*)(g_p3 + (base + (size_t)kk * MM) * DH + lane * 2);
        a0 += p.x * w; a1 += p.y * w;
    }
    *(float2*)(g_out3 + ((size_t)bh * MM + r) * DH + lane * 2) =
        make_float2(a0 * invL, a1 * invL);
}

// ---------------------------------------------------------------------------
// TF32 128x128x16 device tile (persistent pinv)
// ---------------------------------------------------------------------------
__device__ __forceinline__ void tc_tile(
    const float* Ab, const float* Bb, float* C, const float* X1,
    int N, int K, int lda, int ldb, long long cbase,
    float alpha, float beta, int m0, int n0,
    uint32_t (*As)[16][136], uint32_t (*Bs)[16][136])
{
    constexpr int BK = 16;
    int tid = threadIdx.x, lane = tid & 31, warp = tid >> 5;
    int wm0 = (warp >> 2) * 64;
    int wn0 = (warp & 3) * 32;
    float4 ra[2], rb[2];
    float acc[4][4][4];
    #pragma unroll
    for (int i = 0; i < 4; i++)
        #pragma unroll
        for (int j = 0; j < 4; j++)
            #pragma unroll
            for (int r = 0; r < 4; r++) acc[i][j][r] = 0.f;

    auto LOAD = [&](int kb) {
        #pragma unroll
        for (int c = 0; c < 2; c++) {
            int id = c * 256 + tid;
            int m = id >> 2, kq = id & 3;
            ra[c] = *(const float4*)(Ab + (size_t)(m0 + m) * lda + kb * BK + kq * 4);
        }
        #pragma unroll
        for (int c = 0; c < 2; c++) {
            int id = c * 256 + tid;
            int k = id >> 5, nq = id & 31;
            rb[c] = *(const float4*)(Bb + (size_t)(kb * BK + k) * ldb + n0 + nq * 4);
        }
    };
    auto COMMIT = [&](int bf) {
        #pragma unroll
        for (int c = 0; c < 2; c++) {
            int id = c * 256 + tid;
            int m = id >> 2, kq = id & 3;
            As[bf][kq*4+0][m] = f2tf(ra[c].x); As[bf][kq*4+1][m] = f2tf(ra[c].y);
            As[bf][kq*4+2][m] = f2tf(ra[c].z); As[bf][kq*4+3][m] = f2tf(ra[c].w);
        }
        #pragma unroll
        for (int c = 0; c < 2; c++) {
            int id = c * 256 + tid;
            int k = id >> 5, nq = id & 31;
            Bs[bf][k][nq*4+0] = f2tf(rb[c].x); Bs[bf][k][nq*4+1] = f2tf(rb[c].y);
            Bs[bf][k][nq*4+2] = f2tf(rb[c].z); Bs[bf][k][nq*4+3] = f2tf(rb[c].w);
        }
    };
    auto MMA = [&](int bf) {
        #pragma unroll
        for (int ks = 0; ks < 2; ks++) {
            uint32_t af[4][4], bfr[4][2];
            int kr = ks * 8 + (lane & 3);
            int mr = wm0 + (lane >> 2);
            #pragma unroll
            for (int mt = 0; mt < 4; mt++) {
                af[mt][0] = As[bf][kr    ][mr + mt*16];
                af[mt][1] = As[bf][kr    ][mr + mt*16 + 8];
                af[mt][2] = As[bf][kr + 4][mr + mt*16];
                af[mt][3] = As[bf][kr + 4][mr + mt*16 + 8];
            }
            int nr = wn0 + (lane >> 2);
            #pragma unroll
            for (int nt = 0; nt < 4; nt++) {
                bfr[nt][0] = Bs[bf][kr    ][nr + nt*8];
                bfr[nt][1] = Bs[bf][kr + 4][nr + nt*8];
            }
            #pragma unroll
            for (int mt = 0; mt < 4; mt++)
                #pragma unroll
                for (int nt = 0; nt < 4; nt++)
                    mma8(acc[mt][nt], af[mt], bfr[nt]);
        }
    };

    int nk = K / BK;
    LOAD(0); COMMIT(0);
    __syncthreads();
    for (int kb = 1; kb < nk; kb++) {
        LOAD(kb);
        MMA((kb - 1) & 1);
        COMMIT(kb & 1);
        __syncthreads();
    }
    MMA((nk - 1) & 1);

    #pragma unroll
    for (int mt = 0; mt < 4; mt++) {
        #pragma unroll
        for (int nt = 0; nt < 4; nt++) {
            int row = m0 + wm0 + mt * 16 + (lane >> 2);
            int col = n0 + wn0 + nt * 8 + (lane & 3) * 2;
            size_t r1 = cbase + (size_t)row * N + col;
            size_t r2 = cbase + (size_t)(row + 8) * N + col;
            float2 lo = make_float2(acc[mt][nt][0], acc[mt][nt][1]);
            float2 hi = make_float2(acc[mt][nt][2], acc[mt][nt][3]);
            float2 rv1 = make_float2(0.f, 0.f), rv2 = make_float2(0.f, 0.f);
            if (beta != 0.f) {
                rv1 = *(const float2*)(X1 + r1);
                rv2 = *(const float2*)(X1 + r2);
            }
            *(float2*)(C + r1) = make_float2(alpha*lo.x + beta*rv1.x, alpha*lo.y + beta*rv1.y);
            *(float2*)(C + r2) = make_float2(alpha*hi.x + beta*rv2.x, alpha*hi.y + beta*rv2.y);
        }
    }
}

__device__ __forceinline__ void gridbar(int i) {
    __syncthreads();
    if (threadIdx.x == 0) {
        __threadfence();
        atomicAdd(&g_barc[i], 1);
        while (((volatile int*)g_barc)[i] < 128) { }
        __threadfence();
    }
    __syncthreads();
}

// 6 tf32 Newton-Schulz iterations; after 6 ping-pong swaps result is in g_z
__global__ __launch_bounds__(256) void pinv_iters() {
    __shared__ uint32_t As[2][16][136];
    __shared__ uint32_t Bs[2][16][136];
    int m0 = blockIdx.y * 128, n0 = blockIdx.x * 128;
    long long base = (long long)blockIdx.z * (MM * MM);
    float* zc = g_z;
    float* zn = g_z2;
    int bi = 0;
    #pragma unroll 1
    for (int it = 0; it < 6; it++) {
        tc_tile(g_attn2 + base, zc + base, g_xz, nullptr, MM, MM, MM, MM, base,
                1.f, 0.f, m0, n0, As, Bs);
        gridbar(bi++);
        tc_tile(g_xz + base, g_xz + base, g_t, g_xz, MM, MM, MM, MM, base,
                -1.f, 7.f, m0, n0, As, Bs);
        gridbar(bi++);
        tc_tile(g_xz + base, g_t + base, g_u, g_xz, MM, MM, MM, MM, base,
                -1.f, 15.f, m0, n0, As, Bs);
        gridbar(bi++);
        tc_tile(zc + base, g_u + base, zn, zc, MM, MM, MM, MM, base,
                -0.25f, 3.25f, m0, n0, As, Bs);
        if (it < 5) gridbar(bi++);
        float* tmp = zc; zc = zn; zn = tmp;
    }
}

// Wc = z_final(g_z) @ out3, tf32
__global__ __launch_bounds__(256) void wc_gemm() {
    __shared__ uint32_t As[2][16][136];
    __shared__ uint32_t Bs[2][16][136];
    constexpr int BK = 16;
    int tid = threadIdx.x, lane = tid & 31, warp = tid >> 5;
    int wm0 = (warp >> 2) * 64;
    int wn0 = (warp & 3) * 16;
    int m0 = blockIdx.y * 128;
    long long abase = (long long)blockIdx.z * (MM * MM);
    long long cbase = (long long)blockIdx.z * (MM * DH);
    const float* Ab = g_z + abase;
    const float* Bb = g_out3 + cbase;
    float4 ra[2];
    float4 rb;
    float acc[4][2][4];
    #pragma unroll
    for (int i = 0; i < 4; i++)
        #pragma unroll
        for (int j = 0; j < 2; j++)
            #pragma unroll
            for (int r = 0; r < 4; r++) acc[i][j][r] = 0.f;

    auto LOAD = [&](int kb) {
        #pragma unroll
        for (int c = 0; c < 2; c++) {
            int id = c * 256 + tid;
            int m = id >> 2, kq = id & 3;
            ra[c] = *(const float4*)(Ab + (size_t)(m0 + m) * MM + kb * BK + kq * 4);
        }
        {
            int k = tid >> 4, nq = tid & 15;
            rb = *(const float4*)(Bb + (size_t)(kb * BK + k) * DH + nq * 4);
        }
    };
    auto COMMIT = [&](int bf) {
        #pragma unroll
        for (int c = 0; c < 2; c++) {
            int id = c * 256 + tid;
            int m = id >> 2, kq = id & 3;
            As[bf][kq*4+0][m] = f2tf(ra[c].x); As[bf][kq*4+1][m] = f2tf(ra[c].y);
            As[bf][kq*4+2][m] = f2tf(ra[c].z); As[bf][kq*4+3][m] = f2tf(ra[c].w);
        }
        {
            int k = tid >> 4, nq = tid & 15;
            Bs[bf][k][nq*4+0] = f2tf(rb.x); Bs[bf][k][nq*4+1] = f2tf(rb.y);
            Bs[bf][k][nq*4+2] = f2tf(rb.z); Bs[bf][k][nq*4+3] = f2tf(rb.w);
        }
    };
    auto MMA = [&](int bf) {
        #pragma unroll
        for (int ks = 0; ks < 2; ks++) {
            uint32_t af[4][4], bfr[2][2];
            int kr = ks * 8 + (lane & 3);
            int mr = wm0 + (lane >> 2);
            #pragma unroll
            for (int mt = 0; mt < 4; mt++) {
                af[mt][0] = As[bf][kr    ][mr + mt*16];
                af[mt][1] = As[bf][kr    ][mr + mt*16 + 8];
                af[mt][2] = As[bf][kr + 4][mr + mt*16];
                af[mt][3] = As[bf][kr + 4][mr + mt*16 + 8];
            }
            int nr = wn0 + (lane >> 2);
            #pragma unroll
            for (int nt = 0; nt < 2; nt++) {
                bfr[nt][0] = Bs[bf][kr    ][nr + nt*8];
                bfr[nt][1] = Bs[bf][kr + 4][nr + nt*8];
            }
            #pragma unroll
            for (int mt = 0; mt < 4; mt++)
                #pragma unroll
                for (int nt = 0; nt < 2; nt++)
                    mma8(acc[mt][nt], af[mt], bfr[nt]);
        }
    };

    LOAD(0); COMMIT(0);
    __syncthreads();
    for (int kb = 1; kb < 16; kb++) {
        LOAD(kb);
        MMA((kb - 1) & 1);
        COMMIT(kb & 1);
        __syncthreads();
    }
    MMA(1);

    #pragma unroll
    for (int mt = 0; mt < 4; mt++) {
        #pragma unroll
        for (int nt = 0; nt < 2; nt++) {
            int row = m0 + wm0 + mt * 16 + (lane >> 2);
            int col = wn0 + nt * 8 + (lane & 3) * 2;
            *(float2*)(g_wc + cbase + (size_t)row * DH + col) =
                make_float2(acc[mt][nt][0], acc[mt][nt][1]);
            *(float2*)(g_wc + cbase + (size_t)(row + 8) * DH + col) =
                make_float2(acc[mt][nt][2], acc[mt][nt][3]);
        }
    }
}

// ---------------------------------------------------------------------------
// BF16 GEMM (QKV -> bf16 q/k/v, out-proj)
// ---------------------------------------------------------------------------
template<int EPI, int BM, int BN, int BK>
__global__ __launch_bounds__(256) void bf_gemm(
    const float* __restrict__ Af, const float* __restrict__ Bg,
    float* __restrict__ C, const float* __restrict__ X1, const float* __restrict__ X2,
    int N, int K, int lda, int ldb)
{
    constexpr int PA = BM + 8, PB = BN + 8;
    constexpr int MT = (BM / 2) / 16;
    constexpr int NT = (BN / 4) / 8;
    constexpr int KP = BK / 2;
    constexpr int RAF = (BM * BK) / 1024;
    constexpr int RBN = (KP * (BN / 4)) / 256;
    __shared__ uint32_t As[2][KP][PA];
    __shared__ uint32_t Bs[2][KP][PB];
    float4 raf[RAF];
    float4 rb0[RBN], rb1[RBN];

    int tid = threadIdx.x, lane = tid & 31, warp = tid >> 5;
    int wm0 = (warp >> 2) * (BM / 2);
    int wn0 = (warp & 3) * (BN / 4);
    int m0 = blockIdx.y * BM, n0 = blockIdx.x * BN;

    float acc[MT][NT][4];
    #pragma unroll
    for (int i = 0; i < MT; i++)
        #pragma unroll
        for (int j = 0; j < NT; j++)
            #pragma unroll
            for (int r = 0; r < 4; r++) acc[i][j][r] = 0.f;

    auto LOAD = [&](int kb) {
        #pragma unroll
        for (int c = 0; c < RAF; c++) {
            int id = c * 256 + tid;
            int m = id / (BK / 4), kq = id % (BK / 4);
            raf[c] = *(const float4*)(Af + (size_t)(m0 + m) * lda + kb * BK + kq * 4);
        }
        #pragma unroll
        for (int c = 0; c < RBN; c++) {
            int id = c * 256 + tid;
            int kp = id / (BN / 4), nq = id % (BN / 4);
            rb0[c] = *(const float4*)(Bg + (size_t)(kb*BK + 2*kp    ) * ldb + n0 + nq * 4);
            rb1[c] = *(const float4*)(Bg + (size_t)(kb*BK + 2*kp + 1) * ldb + n0 + nq * 4);
        }
    };
    auto COMMIT = [&](int bf) {
        #pragma unroll
        for (int c = 0; c < RAF; c++) {
            int id = c * 256 + tid;
            int m = id / (BK / 4), kq = id % (BK / 4);
            As[bf][kq*2+0][m] = f2bf2(raf[c].x, raf[c].y);
            As[bf][kq*2+1][m] = f2bf2(raf[c].z, raf[c].w);
        }
        #pragma unroll
        for (int c = 0; c < RBN; c++) {
            int id = c * 256 + tid;
            int kp = id / (BN / 4), nq = id % (BN / 4);
            Bs[bf][kp][nq*4+0] = f2bf2(rb0[c].x, rb1[c].x);
            Bs[bf][kp][nq*4+1] = f2bf2(rb0[c].y, rb1[c].y);
            Bs[bf][kp][nq*4+2] = f2bf2(rb0[c].z, rb1[c].z);
            Bs[bf][kp][nq*4+3] = f2bf2(rb0[c].w, rb1[c].w);
        }
    };
    auto MMA = [&](int bf) {
        #pragma unroll
        for (int ks = 0; ks < BK / 16; ks++) {
            uint32_t af[MT][4], bfr[NT][2];
            int kr = ks * 8 + (lane & 3);
            int mr = wm0 + (lane >> 2);
            #pragma unroll
            for (int mt = 0; mt < MT; mt++) {
                af[mt][0] = As[bf][kr    ][mr + mt*16];
                af[mt][1] = As[bf][kr    ][mr + mt*16 + 8];
                af[mt][2] = As[bf][kr + 4][mr + mt*16];
                af[mt][3] = As[bf][kr + 4][mr + mt*16 + 8];
            }
            int nr = wn0 + (lane >> 2);
            #pragma unroll
            for (int nt = 0; nt < NT; nt++) {
                bfr[nt][0] = Bs[bf][kr    ][nr + nt*8];
                bfr[nt][1] = Bs[bf][kr + 4][nr + nt*8];
            }
            #pragma unroll
            for (int mt = 0; mt < MT; mt++)
                #pragma unroll
                for (int nt = 0; nt < NT; nt++)
                    mma16(acc[mt][nt], af[mt], bfr[nt]);
        }
    };

    int nk = K / BK;
    LOAD(0); COMMIT(0);
    __syncthreads();
    for (int kb = 1; kb < nk; kb++) {
        LOAD(kb);
        MMA((kb - 1) & 1);
        COMMIT(kb & 1);
        __syncthreads();
    }
    MMA((nk - 1) & 1);

    #pragma unroll
    for (int mt = 0; mt < MT; mt++) {
        #pragma unroll
        for (int nt = 0; nt < NT; nt++) {
            int row = m0 + wm0 + mt * 16 + (lane >> 2);
            int col = n0 + wn0 + nt * 8 + (lane & 3) * 2;
            float2 lo = make_float2(acc[mt][nt][0], acc[mt][nt][1]);
            float2 hi = make_float2(acc[mt][nt][2], acc[mt][nt][3]);
            if constexpr (EPI == 0) {
                int which = col >> 9, inner = col & 511;
                int h = inner >> 6, d = inner & 63;
                __nv_bfloat16* dst = which == 0 ? g_qh : (which == 1 ? g_kh : g_vh);
                float s = (which == 0) ? 0.125f : 1.f;
                int bq = row >> 13, n = row & (NN - 1);
                *(uint32_t*)(dst + (((size_t)(bq*HH+h))*NN + n    )*DH + d) = f2bf2(lo.x*s, lo.y*s);
                *(uint32_t*)(dst + (((size_t)(bq*HH+h))*NN + n + 8)*DH + d) = f2bf2(hi.x*s, hi.y*s);
            } else if constexpr (EPI == 1) {
                float2 bv = *(const float2*)(X1 + col);
                size_t r1 = (size_t)row * DD + col, r2 = (size_t)(row + 8) * DD + col;
                float2 x1 = *(const float2*)(X2 + r1);
                float2 x2 = *(const float2*)(X2 + r2);
                *(float2*)(C + r1) = make_float2(lo.x + bv.x + x1.x, lo.y + bv.y + x1.y);
                *(float2*)(C + r2) = make_float2(hi.x + bv.x + x2.x, hi.y + bv.y + x2.y);
            }
        }
    }
}

// ---------------------------------------------------------------------------
// Fused attn1 + depthwise conv: y = conv33(v) + softmax(q @ kl^T) @ Wc
// (single write of y, no RMW; conv window staged in dead As/Bs smem)
// ---------------------------------------------------------------------------
__global__ __launch_bounds__(256) void attn1_fused(const float* __restrict__ res_w) {
    extern __shared__ char smraw[];
    uint32_t* As  = (uint32_t*)smraw;       // [16][72]   (reused as Vw after mainloop)
    uint32_t* Bs  = As + 16*72;             // [16][264]
    uint32_t* Ps  = Bs + 16*264;            // [128][72]
    uint32_t* Wcs = Ps + 128*72;            // [128][72]
    float* rmax = (float*)(Wcs + 128*72);   // [64][5]
    float* rsum = rmax + 320;               // [64][5]
    float* sw   = rsum + 320;               // [33]
    uint32_t* Vw = As;                      // [96][33] bf16x2 pairs (overlaps As+Bs)

    int tid = threadIdx.x, lane = tid & 31, warp = tid >> 5;
    int g = lane >> 2, q4 = lane & 3;
    int bh = blockIdx.y;
    int b = bh >> 3, h = bh & 7;
    int m0 = blockIdx.x * 64;
    const __nv_bfloat16* Ab = g_qh + ((size_t)bh * NN + m0) * DH;
    const float* Bb = g_kl + (size_t)bh * MM * DH;
    const float* Wg = g_wc + (size_t)bh * MM * DH;
    const __nv_bfloat16* vb = g_vh + (size_t)bh * NN * DH;

    if (tid < 33) sw[tid] = res_w[h * 33 + tid];

    #pragma unroll
    for (int c = 0; c < 8; c++) {
        int id = c * 256 + tid;
        int kp = id >> 4, n4 = id & 15;
        float4 lo = *(const float4*)(Wg + (size_t)(2*kp    ) * DH + n4 * 4);
        float4 hi = *(const float4*)(Wg + (size_t)(2*kp + 1) * DH + n4 * 4);
        Wcs[kp*72 + n4*4+0] = f2bf2(lo.x, hi.x);
        Wcs[kp*72 + n4*4+1] = f2bf2(lo.y, hi.y);
        Wcs[kp*72 + n4*4+2] = f2bf2(lo.z, hi.z);
        Wcs[kp*72 + n4*4+3] = f2bf2(lo.w, hi.w);
    }

    int wm0q = (warp >> 2) * 32;
    int wn0q = (warp & 3) * 64;
    int wnq = warp & 3;
    float acc[2][8][4];
    #pragma unroll
    for (int i = 0; i < 2; i++)
        #pragma unroll
        for (int j = 0; j < 8; j++)
            #pragma unroll
            for (int r = 0; r < 4; r++) acc[i][j][r] = 0.f;

    for (int k0 = 0; k0 < 64; k0 += 32) {
        {
            int m = tid >> 2, kq = tid & 3;
            uint4 v = *(const uint4*)(Ab + (size_t)m * DH + k0 + kq * 8);
            As[(kq*4+0)*72 + m] = v.x; As[(kq*4+1)*72 + m] = v.y;
            As[(kq*4+2)*72 + m] = v.z; As[(kq*4+3)*72 + m] = v.w;
        }
        #pragma unroll
        for (int c = 0; c < 8; c++) {
            int id = c * 256 + tid;
            int n = id >> 3, kq = id & 7;
            float4 v = *(const float4*)(Bb + (size_t)n * DH + k0 + kq * 4);
            Bs[(kq*2+0)*264 + n] = f2bf2(v.x, v.y);
            Bs[(kq*2+1)*264 + n] = f2bf2(v.z, v.w);
        }
        __syncthreads();
        #pragma unroll
        for (int ks = 0; ks < 2; ks++) {
            uint32_t af[2][4], bfr[8][2];
            int kr = ks * 8 + q4;
            int mr = wm0q + g;
            #pragma unroll
            for (int mt = 0; mt < 2; mt++) {
                af[mt][0] = As[kr*72 + mr + mt*16];
                af[mt][1] = As[kr*72 + mr + mt*16 + 8];
                af[mt][2] = As[(kr+4)*72 + mr + mt*16];
                af[mt][3] = As[(kr+4)*72 + mr + mt*16 + 8];
            }
            int nr = wn0q + g;
            #pragma unroll
            for (int nt = 0; nt < 8; nt++) {
                bfr[nt][0] = Bs[kr*264 + nr + nt*8];
                bfr[nt][1] = Bs[(kr+4)*264 + nr + nt*8];
            }
            #pragma unroll
            for (int mt = 0; mt < 2; mt++)
                #pragma unroll
                for (int nt = 0; nt < 8; nt++)
                    mma16(acc[mt][nt], af[mt], bfr[nt]);
        }
        __syncthreads();
    }

    // ---- load conv v window into dead As/Bs region: 96 rows x 32 bf16x2
    #pragma unroll
    for (int c = 0; c < 6; c++) {
        int id = c * 256 + tid;           // 1536 uint2 = 96 x 16
        int row = id >> 4, up = id & 15;
        int tok = m0 - 16 + row;
        uint2 u = make_uint2(0u, 0u);
        if (tok >= 0 && tok < NN)
            u = *(const uint2*)(vb + (size_t)tok * DH + up * 4);
        Vw[row*33 + up*2]     = u.x;
        Vw[row*33 + up*2 + 1] = u.y;
    }

    // ---- softmax over 256-wide rows
    #pragma unroll
    for (int mt = 0; mt < 2; mt++) {
        int r0 = wm0q + mt * 16 + g;
        float m0v = -1e30f, m1v = -1e30f;
        #pragma unroll
        for (int nt = 0; nt < 8; nt++) {
            m0v = fmaxf(m0v, fmaxf(acc[mt][nt][0], acc[mt][nt][1]));
            m1v = fmaxf(m1v, fmaxf(acc[mt][nt][2], acc[mt][nt][3]));
        }
        #pragma unroll
        for (int o = 1; o < 4; o <<= 1) {
            m0v = fmaxf(m0v, __shfl_xor_sync(~0u, m0v, o));
            m1v = fmaxf(m1v, __shfl_xor_sync(~0u, m1v, o));
        }
        if (q4 == 0) { rmax[r0*5 + wnq] = m0v; rmax[(r0+8)*5 + wnq] = m1v; }
    }
    __syncthreads();
    #pragma unroll
    for (int mt = 0; mt < 2; mt++) {
        int r0 = wm0q + mt * 16 + g;
        float M0 = fmaxf(fmaxf(rmax[r0*5+0], rmax[r0*5+1]), fmaxf(rmax[r0*5+2], rmax[r0*5+3]));
        float M1 = fmaxf(fmaxf(rmax[(r0+8)*5+0], rmax[(r0+8)*5+1]),
                         fmaxf(rmax[(r0+8)*5+2], rmax[(r0+8)*5+3]));
        float s0 = 0.f, s1 = 0.f;
        #pragma unroll
        for (int nt = 0; nt < 8; nt++) {
            acc[mt][nt][0] = __expf(acc[mt][nt][0] - M0);
            acc[mt][nt][1] = __expf(acc[mt][nt][1] - M0);
            acc[mt][nt][2] = __expf(acc[mt][nt][2] - M1);
            acc[mt][nt][3] = __expf(acc[mt][nt][3] - M1);
            s0 += acc[mt][nt][0] + acc[mt][nt][1];
            s1 += acc[mt][nt][2] + acc[mt][nt][3];
        }
        #pragma unroll
        for (int o = 1; o < 4; o <<= 1) {
            s0 += __shfl_xor_sync(~0u, s0, o);
            s1 += __shfl_xor_sync(~0u, s1, o);
        }
        if (q4 == 0) { rsum[r0*5 + wnq] = s0; rsum[(r0+8)*5 + wnq] = s1; }
    }
    __syncthreads();
    #pragma unroll
    for (int mt = 0; mt < 2; mt++) {
        int r0 = wm0q + mt * 16 + g, r1 = r0 + 8;
        float i0 = 1.f / (rsum[r0*5+0] + rsum[r0*5+1] + rsum[r0*5+2] + rsum[r0*5+3]);
        float i1 = 1.f / (rsum[r1*5+0] + rsum[r1*5+1] + rsum[r1*5+2] + rsum[r1*5+3]);
        #pragma unroll
        for (int nt = 0; nt < 8; nt++) {
            int kp = (wn0q >> 1) + nt * 4 + q4;
            Ps[kp*72 + r0] = f2bf2(acc[mt][nt][0] * i0, acc[mt][nt][1] * i0);
            Ps[kp*72 + r1] = f2bf2(acc[mt][nt][2] * i1, acc[mt][nt][3] * i1);
        }
    }
    __syncthreads();

    // ---- y = P @ Wc + conv
    int wm0p = (warp >> 2) * 32;
    int wn0p = (warp & 3) * 16;
    float yacc[2][2][4];
    #pragma unroll
    for (int i = 0; i < 2; i++)
        #pragma unroll
        for (int j = 0; j < 2; j++)
            #pragma unroll
            for (int r = 0; r < 4; r++) yacc[i][j][r] = 0.f;
    #pragma unroll
    for (int kc = 0; kc < 16; kc++) {
        int kr = kc * 8 + q4;
        uint32_t af[2][4], bfr[2][2];
        int mr = wm0p + g;
        #pragma unroll
        for (int mt = 0; mt < 2; mt++) {
            af[mt][0] = Ps[kr*72 + mr + mt*16];
            af[mt][1] = Ps[kr*72 + mr + mt*16 + 8];
            af[mt][2] = Ps[(kr+4)*72 + mr + mt*16];
            af[mt][3] = Ps[(kr+4)*72 + mr + mt*16 + 8];
        }
        int nr = wn0p + g;
        #pragma unroll
        for (int nt = 0; nt < 2; nt++) {
            bfr[nt][0] = Wcs[kr*72 + nr + nt*8];
            bfr[nt][1] = Wcs[(kr+4)*72 + nr + nt*8];
        }
        #pragma unroll
        for (int mt = 0; mt < 2; mt++)
            #pragma unroll
            for (int nt = 0; nt < 2; nt++)
                mma16(yacc[mt][nt], af[mt], bfr[nt]);
    }
    #pragma unroll
    for (int mt = 0; mt < 2; mt++) {
        #pragma unroll
        for (int nt = 0; nt < 2; nt++) {
            int rl = wm0p + mt * 16 + g;          // local row (0..55), +8 for hi
            int col = wn0p + nt * 8 + q4 * 2;
            int cp = col >> 1;
            float c00 = 0.f, c01 = 0.f, c10 = 0.f, c11 = 0.f;
            #pragma unroll
            for (int j = 0; j < 33; j++) {
                float w = sw[j];
                float2 f0 = __bfloat1622float2(
                    *(const __nv_bfloat162*)&Vw[(rl + j) * 33 + cp]);
                float2 f1 = __bfloat1622float2(
                    *(const __nv_bfloat162*)&Vw[(rl + 8 + j) * 33 + cp]);
                c00 += w * f0.x; c01 += w * f0.y;
                c10 += w * f1.x; c11 += w * f1.y;
            }
            int row = m0 + rl;
            size_t r1 = ((size_t)b * NN + row    ) * DD + h * 64 + col;
            size_t r2 = ((size_t)b * NN + row + 8) * DD + h * 64 + col;
            *(float2*)(g_y + r1) = make_float2(c00 + yacc[mt][nt][0], c01 + yacc[mt][nt][1]);
            *(float2*)(g_y + r2) = make_float2(c10 + yacc[mt][nt][2], c11 + yacc[mt][nt][3]);
        }
    }
}

// ---------------------------------------------------------------------------
// LN / landmarks / sim2 / softmax256 / init / colrowmax / z0
// ---------------------------------------------------------------------------
__global__ __launch_bounds__(128) void ln_kernel(const float* __restrict__ x,
                                                 const float* __restrict__ w,
                                                 const float* __restrict__ bia) {
    int row = blockIdx.x, tid = threadIdx.x;
    const float4* xr = reinterpret_cast<const float4*>(x + (size_t)row * DD);
    float4 v = xr[tid];
    float s  = v.x + v.y + v.z + v.w;
    float sq = v.x*v.x + v.y*v.y + v.z*v.z + v.w*v.w;
    __shared__ float sm[4], sm2[4];
    #pragma unroll
    for (int o = 16; o > 0; o >>= 1) {
        s  += __shfl_down_sync(0xffffffffu, s,  o);
        sq += __shfl_down_sync(0xffffffffu, sq, o);
    }
    if ((tid & 31) == 0) { sm[tid >> 5] = s; sm2[tid >> 5] = sq; }
    __syncthreads();
    if (tid == 0) {
        float a = 0.f, b2 = 0.f;
        #pragma unroll
        for (int i = 0; i < 4; i++) { a += sm[i]; b2 += sm2[i]; }
        sm[0] = a; sm2[0] = b2;
    }
    __syncthreads();
    float mean = sm[0] * (1.f / 512.f);
    float var  = sm2[0] * (1.f / 512.f) - mean * mean;
    float rstd = rsqrtf(var + 1e-5f);
    float4 wv = reinterpret_cast<const float4*>(w)[tid];
    float4 bv = reinterpret_cast<const float4*>(bia)[tid];
    float4 o;
    o.x = (v.x - mean) * rstd * wv.x + bv.x;
    o.y = (v.y - mean) * rstd * wv.y + bv.y;
    o.z = (v.z - mean) * rstd * wv.z + bv.z;
    o.w = (v.w - mean) * rstd * wv.w + bv.w;
    reinterpret_cast<float4*>(g_xn + (size_t)row * DD)[tid] = o;
}

__global__ void landmark_kernel() {
    int m = blockIdx.x, bh = blockIdx.y;
    int d = threadIdx.x;
    size_t base = ((size_t)bh * NN + (size_t)m * 32) * DH + d;
    float sq = 0.f, sk = 0.f;
    #pragma unroll
    for (int j = 0; j < 32; j++) {
        sq += __bfloat162float(g_qh[base + (size_t)j * DH]);
        sk += __bfloat162float(g_kh[base + (size_t)j * DH]);
    }
    size_t o = ((size_t)bh * MM + m) * DH + d;
    g_ql[o] = sq * (1.f / 32.f);
    g_kl[o] = sk * (1.f / 32.f);
}

__global__ __launch_bounds__(256) void gemm_sim2() {
    __shared__ float As[32][132];
    __shared__ float Bs[32][132];
    int bh = blockIdx.z;
    int n0 = blockIdx.x * 128, m0 = blockIdx.y * 128;
    const float* Ab = g_ql + ((size_t)bh * MM + m0) * DH;
    const float* Bb = g_kl + ((size_t)bh * MM + n0) * DH;
    float* Cb = g_attn2 + (size_t)bh * MM * MM;
    int tid = threadIdx.x;
    int tx = tid & 15, ty = tid >> 4;
    float acc[8][8] = {};
    for (int kk = 0; kk < 64; kk += 32) {
        #pragma unroll
        for (int u = 0; u < 4; u++) {
            int g = u * 256 + tid;
            int m = g >> 3, k4 = g & 7;
            float4 av = *(const float4*)(Ab + (size_t)m * DH + kk + k4 * 4);
            As[k4*4+0][m] = av.x; As[k4*4+1][m] = av.y;
            As[k4*4+2][m] = av.z; As[k4*4+3][m] = av.w;
        }
        #pragma unroll
        for (int u = 0; u < 4; u++) {
            int g = u * 256 + tid;
            int m = g >> 3, k4 = g & 7;
            float4 bv = *(const float4*)(Bb + (size_t)m * DH + kk + k4 * 4);
            Bs[k4*4+0][m] = bv.x; Bs[k4*4+1][m] = bv.y;
            Bs[k4*4+2][m] = bv.z; Bs[k4*4+3][m] = bv.w;
        }
        __syncthreads();
        #pragma unroll
        for (int k = 0; k < 32; k++) {
            float a[8], b[8];
            *(float4*)&a[0] = *(const float4*)&As[k][ty*8];
            *(float4*)&a[4] = *(const float4*)&As[k][ty*8+4];
            *(float4*)&b[0] = *(const float4*)&Bs[k][tx*8];
            *(float4*)&b[4] = *(const float4*)&Bs[k][tx*8+4];
            #pragma unroll
            for (int i = 0; i < 8; i++)
                #pragma unroll
                for (int j = 0; j < 8; j++)
                    acc[i][j] += a[i] * b[j];
        }
        __syncthreads();
    }
    #pragma unroll
    for (int i = 0; i < 8; i++) {
        size_t r = (size_t)(m0 + ty * 8 + i) * MM + n0 + tx * 8;
        *(float4*)(Cb + r)     = make_float4(acc[i][0], acc[i][1], acc[i][2], acc[i][3]);
        *(float4*)(Cb + r + 4) = make_float4(acc[i][4], acc[i][5], acc[i][6], acc[i][7]);
    }
}

__global__ __launch_bounds__(256) void softmax256() {
    int row = blockIdx.x, tid = threadIdx.x;
    float* p = g_attn2 + (size_t)row * MM;
    float v = p[tid];
    __shared__ float red[8];
    float m = v;
    #pragma unroll
    for (int o = 16; o; o >>= 1) m = fmaxf(m, __shfl_xor_sync(~0u, m, o));
    if ((tid & 31) == 0) red[tid >> 5] = m;
    __syncthreads();
    if (tid < 32) {
        float t = (tid < 8) ? red[tid] : -1e30f;
        #pragma unroll
        for (int o = 4; o; o >>= 1) t = fmaxf(t, __shfl_xor_sync(~0u, t, o));
        if (tid == 0) red[0] = t;
    }
    __syncthreads();
    float mx = red[0];
    __syncthreads();
    float e = __expf(v - mx);
    float s = e;
    #pragma unroll
    for (int o = 16; o; o >>= 1) s += __shfl_xor_sync(~0u, s, o);
    if ((tid & 31) == 0) red[tid >> 5] = s;
    __syncthreads();
    if (tid < 32) {
        float t = (tid < 8) ? red[tid] : 0.f;
        #pragma unroll
        for (int o = 4; o; o >>= 1) t += __shfl_xor_sync(~0u, t, o);
        if (tid == 0) red[0] = t;
    }
    __syncthreads();
    p[tid] = e / red[0];
}

__global__ void init_kernel() {
    g_maxA = 0; g_maxB = 0;
    if (threadIdx.x < 32) g_barc[threadIdx.x] = 0;
}

__global__ __launch_bounds__(256) void colrowmax_kernel() {
    int bh = blockIdx.x, tid = threadIdx.x;
    const float* a = g_attn2 + (size_t)bh * MM * MM;
    float cs = 0.f, rs = 0.f;
    for (int m = 0; m < MM; m++) cs += fabsf(a[(size_t)m * MM + tid]);
    for (int n = 0; n < MM; n++) rs += fabsf(a[(size_t)tid * MM + n]);
    __shared__ float r1[8], r2[8];
    #pragma unroll
    for (int o = 16; o; o >>= 1) {
        cs = fmaxf(cs, __shfl_xor_sync(~0u, cs, o));
        rs = fmaxf(rs, __shfl_xor_sync(~0u, rs, o));
    }
    if ((tid & 31) == 0) { r1[tid >> 5] = cs; r2[tid >> 5] = rs; }
    __syncthreads();
    if (tid == 0) {
        float a1 = r1[0], a2 = r2[0];
        #pragma unroll
        for (int i = 1; i < 8; i++) { a1 = fmaxf(a1, r1[i]); a2 = fmaxf(a2, r2[i]); }
        atomicMax(&g_maxA, __float_as_int(a1));
        atomicMax(&g_maxB, __float_as_int(a2));
    }
}

__global__ __launch_bounds__(256) void z0_kernel() {
    int bh = blockIdx.z;
    int c0 = blockIdx.x * 32, r0 = blockIdx.y * 32;
    int tid = threadIdx.x;
    __shared__ float t[32][33];
    const float* a = g_attn2 + (size_t)bh * MM * MM;
    #pragma unroll
    for (int rr = 0; rr < 4; rr++) {
        int r = rr * 8 + (tid >> 5), c = tid & 31;
        t[r][c] = a[(size_t)(r0 + r) * MM + c0 + c];
    }
    __syncthreads();
    float s = 1.f / (__int_as_float(g_maxA) * __int_as_float(g_maxB));
    float* z = g_z + (size_t)bh * MM * MM;
    #pragma unroll
    for (int rr = 0; rr < 4; rr++) {
        int r = rr * 8 + (tid >> 5), c = tid & 31;
        z[(size_t)(c0 + r) * MM + r0 + c] = t[c][r] * s;
    }
}

// ---------------------------------------------------------------------------
// Launch
// ---------------------------------------------------------------------------
extern "C" void kernel_launch(void* const* d_in, const int* in_sizes, int n_in,
                              void* d_out, int out_size) {
    const float* x     = (const float*)d_in[0];
    const float* ln_w  = (const float*)d_in[1];
    const float* ln_b  = (const float*)d_in[2];
    const float* w_qkv = (const float*)d_in[3];
    const float* w_out = (const float*)d_in[4];
    const float* b_out = (const float*)d_in[5];
    const float* res_w = (const float*)d_in[6];
    float* out = (float*)d_out;

    float *p_xn, *p_y;
    cudaGetSymbolAddress((void**)&p_xn, g_xn);
    cudaGetSymbolAddress((void**)&p_y,  g_y);

    cudaFuncSetAttribute(flash3, cudaFuncAttributeMaxDynamicSharedMemorySize, 58368);
    cudaFuncSetAttribute(attn1_fused, cudaFuncAttributeMaxDynamicSharedMemorySize, 98304);

    ln_kernel<<<BB * NN, 128>>>(x, ln_w, ln_b);
    bf_gemm<0,128,128,32><<<dim3(12, 256, 1), 256>>>(
        p_xn, w_qkv, nullptr, nullptr, nullptr, 1536, 512, 512, 1536);
    landmark_kernel<<<dim3(MM, BH), 64>>>();

    gemm_sim2<<<dim3(2, 2, BH), 256>>>();
    flash3<<<dim3(2, KS, BH), 256, 58368>>>();
    combine3<<<1024, 256>>>();
    softmax256<<<BH * MM, 256>>>();

    init_kernel<<<1, 32>>>();
    colrowmax_kernel<<<BH, 256>>>();
    z0_kernel<<<dim3(8, 8, BH), 256>>>();

    pinv_iters<<<dim3(2, 2, BH), 256>>>();
    wc_gemm<<<dim3(1, 2, BH), 256>>>();

    attn1_fused<<<dim3(128, BH), 256, 98304>>>(res_w);

    bf_gemm<1,128,128,32><<<dim3(4, 256, 1), 256>>>(
        p_y, w_out, out, b_out, x, 512, 512, 512, 512);
}

// round 14
// speedup vs baseline: 1.5713x; 1.0410x over previous
#include <cuda_runtime.h>
#include <cuda_bf16.h>
#include <stdint.h>
#include <math.h>

#define BB 4
#define NN 8192
#define DD 512
#define HH 8
#define DH 64
#define MM 256
#define BH 32
#define KS 16

__device__ __align__(16) __nv_bfloat16 g_xh[(size_t)BB*NN*DD];
__device__ __align__(16) __nv_bfloat16 g_qh[(size_t)BH*NN*DH];
__device__ __align__(16) __nv_bfloat16 g_kh[(size_t)BH*NN*DH];
__device__ __align__(16) __nv_bfloat16 g_vh[(size_t)BH*NN*DH];
__device__ __align__(16) float g_ql  [(size_t)BH*MM*DH];
__device__ __align__(16) float g_kl  [(size_t)BH*MM*DH];
__device__ __align__(16) float g_attn2[(size_t)BH*MM*MM];
__device__ __align__(16) float g_z   [(size_t)BH*MM*MM];
__device__ __align__(16) float g_z2  [(size_t)BH*MM*MM];
__device__ __align__(16) float g_xz  [(size_t)BH*MM*MM];
__device__ __align__(16) float g_t   [(size_t)BH*MM*MM];
__device__ __align__(16) float g_u   [(size_t)BH*MM*MM];
__device__ __align__(16) float g_p3  [(size_t)BH*KS*MM*DH];
__device__ __align__(16) float g_m3  [(size_t)BH*KS*MM];
__device__ __align__(16) float g_l3  [(size_t)BH*KS*MM];
__device__ __align__(16) float g_out3[(size_t)BH*MM*DH];
__device__ __align__(16) float g_wc  [(size_t)BH*MM*DH];
__device__ __align__(16) __nv_bfloat16 g_yh[(size_t)BB*NN*DD];
__device__ int g_maxA;
__device__ int g_maxB;
__device__ int g_barc[BH * 24];

__device__ __forceinline__ uint32_t f2tf(float f) {
    uint32_t u;
    asm("cvt.rna.tf32.f32 %0, %1;" : "=r"(u) : "f"(f));
    return u;
}
__device__ __forceinline__ uint32_t f2bf2(float lo, float hi) {
    uint32_t r;
    asm("cvt.rn.bf16x2.f32 %0, %1, %2;" : "=r"(r) : "f"(hi), "f"(lo));
    return r;
}
__device__ __forceinline__ void mma8(float* d, const uint32_t* a, const uint32_t* b) {
    asm volatile(
        "mma.sync.aligned.m16n8k8.row.col.f32.tf32.tf32.f32 "
        "{%0,%1,%2,%3}, {%4,%5,%6,%7}, {%8,%9}, {%0,%1,%2,%3};"
        : "+f"(d[0]), "+f"(d[1]), "+f"(d[2]), "+f"(d[3])
        : "r"(a[0]), "r"(a[1]), "r"(a[2]), "r"(a[3]), "r"(b[0]), "r"(b[1]));
}
__device__ __forceinline__ void mma16(float* d, const uint32_t* a, const uint32_t* b) {
    asm volatile(
        "mma.sync.aligned.m16n8k16.row.col.f32.bf16.bf16.f32 "
        "{%0,%1,%2,%3}, {%4,%5,%6,%7}, {%8,%9}, {%0,%1,%2,%3};"
        : "+f"(d[0]), "+f"(d[1]), "+f"(d[2]), "+f"(d[3])
        : "r"(a[0]), "r"(a[1]), "r"(a[2]), "r"(a[3]), "r"(b[0]), "r"(b[1]));
}

// ---------------------------------------------------------------------------
// Flash split-KV attn3 (unchanged)
// ---------------------------------------------------------------------------
__global__ __launch_bounds__(256) void flash3() {
    extern __shared__ char smraw[];
    uint32_t* Qs = (uint32_t*)smraw;
    uint32_t* Ksm = Qs + 32*136;
    uint32_t* Vsm = Ksm + 32*72;
    uint32_t* Ps = Vsm + 32*72;
    float* wmax = (float*)(Ps + 32*136);
    float* wsum = wmax + 512;
    float* mrun = wsum + 512;
    float* lrun = mrun + 128;

    int tid = threadIdx.x, lane = tid & 31, warp = tid >> 5;
    int g = lane >> 2, q4 = lane & 3;
    int wm0 = (warp >> 2) * 64;
    int wn0 = (warp & 3) * 16;
    int wn = warp & 3;
    int m0 = blockIdx.x * 128;
    int ksp = blockIdx.y, bh = blockIdx.z;

    const float* Qg = g_ql + ((size_t)bh * MM + m0) * DH;
    #pragma unroll
    for (int c = 0; c < 8; c++) {
        int id = c * 256 + tid;
        int m = id >> 4, qq = id & 15;
        float4 v = *(const float4*)(Qg + (size_t)m * DH + qq * 4);
        Qs[(qq*2+0)*136 + m] = f2bf2(v.x, v.y);
        Qs[(qq*2+1)*136 + m] = f2bf2(v.z, v.w);
    }
    if (tid < 128) { mrun[tid] = -1e30f; lrun[tid] = 0.f; }

    float acc[4][2][4];
    #pragma unroll
    for (int a = 0; a < 4; a++)
        #pragma unroll
        for (int b = 0; b < 2; b++)
            #pragma unroll
            for (int r = 0; r < 4; r++) acc[a][b][r] = 0.f;

    const __nv_bfloat16* Kg = g_kh + ((size_t)bh * NN + ksp * 512) * DH;
    const __nv_bfloat16* Vg = g_vh + ((size_t)bh * NN + ksp * 512) * DH;

    for (int t = 0; t < 8; t++) {
        __syncthreads();
        #pragma unroll
        for (int c = 0; c < 2; c++) {
            int id = c * 256 + tid;
            int n = id >> 3, qq = id & 7;
            uint4 v = *(const uint4*)(Kg + (size_t)(t*64 + n) * DH + qq * 8);
            Ksm[(qq*4+0)*72 + n] = v.x; Ksm[(qq*4+1)*72 + n] = v.y;
            Ksm[(qq*4+2)*72 + n] = v.z; Ksm[(qq*4+3)*72 + n] = v.w;
        }
        #pragma unroll
        for (int c = 0; c < 2; c++) {
            int id = c * 256 + tid;
            int kp = id >> 4, qg = id & 15;
            uint2 a = *(const uint2*)(Vg + (size_t)(t*64 + 2*kp    ) * DH + qg * 4);
            uint2 b = *(const uint2*)(Vg + (size_t)(t*64 + 2*kp + 1) * DH + qg * 4);
            Vsm[kp*72 + qg*4+0] = __byte_perm(a.x, b.x, 0x5410);
            Vsm[kp*72 + qg*4+1] = __byte_perm(a.x, b.x, 0x7632);
            Vsm[kp*72 + qg*4+2] = __byte_perm(a.y, b.y, 0x5410);
            Vsm[kp*72 + qg*4+3] = __byte_perm(a.y, b.y, 0x7632);
        }
        __syncthreads();

        float S[4][2][4];
        #pragma unroll
        for (int a = 0; a < 4; a++)
            #pragma unroll
            for (int b = 0; b < 2; b++)
                #pragma unroll
                for (int r = 0; r < 4; r++) S[a][b][r] = 0.f;
        #pragma unroll
        for (int k2 = 0; k2 < 4; k2++) {
            int kr = k2 * 8 + q4;
            uint32_t af[4][4], bfr[2][2];
            int mr = wm0 + g;
            #pragma unroll
            for (int mt = 0; mt < 4; mt++) {
                af[mt][0] = Qs[kr*136 + mr + mt*16];
                af[mt][1] = Qs[kr*136 + mr + mt*16 + 8];
                af[mt][2] = Qs[(kr+4)*136 + mr + mt*16];
                af[mt][3] = Qs[(kr+4)*136 + mr + mt*16 + 8];
            }
            int nr = wn0 + g;
            #pragma unroll
            for (int nt = 0; nt < 2; nt++) {
                bfr[nt][0] = Ksm[kr*72 + nr + nt*8];
                bfr[nt][1] = Ksm[(kr+4)*72 + nr + nt*8];
            }
            #pragma unroll
            for (int mt = 0; mt < 4; mt++)
                #pragma unroll
                for (int nt = 0; nt < 2; nt++)
                    mma16(S[mt][nt], af[mt], bfr[nt]);
        }

        #pragma unroll
        for (int mt = 0; mt < 4; mt++) {
            float m0v = fmaxf(fmaxf(S[mt][0][0], S[mt][0][1]), fmaxf(S[mt][1][0], S[mt][1][1]));
            float m1v = fmaxf(fmaxf(S[mt][0][2], S[mt][0][3]), fmaxf(S[mt][1][2], S[mt][1][3]));
            #pragma unroll
            for (int o = 1; o < 4; o <<= 1) {
                m0v = fmaxf(m0v, __shfl_xor_sync(~0u, m0v, o));
                m1v = fmaxf(m1v, __shfl_xor_sync(~0u, m1v, o));
            }
            if (q4 == 0) {
                wmax[(wm0 + mt*16 + g)*4 + wn] = m0v;
                wmax[(wm0 + mt*16 + g + 8)*4 + wn] = m1v;
            }
        }
        __syncthreads();

        #pragma unroll
        for (int mt = 0; mt < 4; mt++) {
            int r0 = wm0 + mt*16 + g, r1 = r0 + 8;
            float mo0 = mrun[r0];
            float mt0 = fmaxf(fmaxf(wmax[r0*4+0], wmax[r0*4+1]), fmaxf(wmax[r0*4+2], wmax[r0*4+3]));
            float mn0 = fmaxf(mo0, mt0);
            float sc0 = __expf(mo0 - mn0);
            float mo1 = mrun[r1];
            float mt1 = fmaxf(fmaxf(wmax[r1*4+0], wmax[r1*4+1]), fmaxf(wmax[r1*4+2], wmax[r1*4+3]));
            float mn1 = fmaxf(mo1, mt1);
            float sc1 = __expf(mo1 - mn1);
            float s0 = 0.f, s1 = 0.f;
            #pragma unroll
            for (int nt = 0; nt < 2; nt++) {
                S[mt][nt][0] = __expf(S[mt][nt][0] - mn0);
                S[mt][nt][1] = __expf(S[mt][nt][1] - mn0);
                S[mt][nt][2] = __expf(S[mt][nt][2] - mn1);
                S[mt][nt][3] = __expf(S[mt][nt][3] - mn1);
                s0 += S[mt][nt][0] + S[mt][nt][1];
                s1 += S[mt][nt][2] + S[mt][nt][3];
                int cp = wn * 8 + nt * 4 + q4;
                Ps[cp*136 + r0] = f2bf2(S[mt][nt][0], S[mt][nt][1]);
                Ps[cp*136 + r1] = f2bf2(S[mt][nt][2], S[mt][nt][3]);
                acc[mt][nt][0] *= sc0; acc[mt][nt][1] *= sc0;
                acc[mt][nt][2] *= sc1; acc[mt][nt][3] *= sc1;
            }
            #pragma unroll
            for (int o = 1; o < 4; o <<= 1) {
                s0 += __shfl_xor_sync(~0u, s0, o);
                s1 += __shfl_xor_sync(~0u, s1, o);
            }
            if (q4 == 0) { wsum[r0*4+wn] = s0; wsum[r1*4+wn] = s1; }
        }
        __syncthreads();

        if (tid < 128) {
            float mo = mrun[tid];
            float mt2 = fmaxf(fmaxf(wmax[tid*4+0], wmax[tid*4+1]), fmaxf(wmax[tid*4+2], wmax[tid*4+3]));
            float mn = fmaxf(mo, mt2);
            mrun[tid] = mn;
            lrun[tid] = lrun[tid]*__expf(mo - mn) +
                        wsum[tid*4+0] + wsum[tid*4+1] + wsum[tid*4+2] + wsum[tid*4+3];
        }
        #pragma unroll
        for (int k2 = 0; k2 < 4; k2++) {
            int kr = k2 * 8 + q4;
            uint32_t af[4][4], bfr[2][2];
            int mr = wm0 + g;
            #pragma unroll
            for (int mt = 0; mt < 4; mt++) {
                af[mt][0] = Ps[kr*136 + mr + mt*16];
                af[mt][1] = Ps[kr*136 + mr + mt*16 + 8];
                af[mt][2] = Ps[(kr+4)*136 + mr + mt*16];
                af[mt][3] = Ps[(kr+4)*136 + mr + mt*16 + 8];
            }
            int nr = wn0 + g;
            #pragma unroll
            for (int nt = 0; nt < 2; nt++) {
                bfr[nt][0] = Vsm[kr*72 + nr + nt*8];
                bfr[nt][1] = Vsm[(kr+4)*72 + nr + nt*8];
            }
            #pragma unroll
            for (int mt = 0; mt < 4; mt++)
                #pragma unroll
                for (int nt = 0; nt < 2; nt++)
                    mma16(acc[mt][nt], af[mt], bfr[nt]);
        }
    }
    __syncthreads();

    size_t ob = (size_t)(bh * KS + ksp) * MM + m0;
    #pragma unroll
    for (int mt = 0; mt < 4; mt++) {
        #pragma unroll
        for (int nt = 0; nt < 2; nt++) {
            int r0 = wm0 + mt*16 + g;
            int c = wn0 + nt*8 + q4*2;
            *(float2*)(g_p3 + (ob + r0)*DH + c)     = make_float2(acc[mt][nt][0], acc[mt][nt][1]);
            *(float2*)(g_p3 + (ob + r0 + 8)*DH + c) = make_float2(acc[mt][nt][2], acc[mt][nt][3]);
        }
    }
    if (tid < 128) {
        g_m3[ob + tid] = mrun[tid];
        g_l3[ob + tid] = lrun[tid];
    }
}

__global__ __launch_bounds__(256) void combine3() {
    int warp = threadIdx.x >> 5, lane = threadIdx.x & 31;
    int rowg = blockIdx.x * 8 + warp;
    int bh = rowg >> 8, r = rowg & 255;
    size_t base = (size_t)(bh * KS) * MM + r;
    float mv = (lane < 16) ? g_m3[base + (size_t)lane * MM] : -1e30f;
    #pragma unroll
    for (int o = 16; o; o >>= 1) mv = fmaxf(mv, __shfl_xor_sync(~0u, mv, o));
    float M = mv;
    float lv = (lane < 16) ? g_l3[base + (size_t)lane * MM] *
                             __expf(g_m3[base + (size_t)lane * MM] - M) : 0.f;
    #pragma unroll
    for (int o = 16; o; o >>= 1) lv += __shfl_xor_sync(~0u, lv, o);
    float invL = 1.f / lv;
    float a0 = 0.f, a1 = 0.f;
    for (int kk = 0; kk < KS; kk++) {
        float w = __expf(g_m3[base + (size_t)kk * MM] - M);
        float2 p = *(const float2*)(g_p3 + (base + (size_t)kk * MM) * DH + lane * 2);
        a0 += p.x * w; a1 += p.y * w;
    }
    *(float2*)(g_out3 + ((size_t)bh * MM + r) * DH + lane * 2) =
        make_float2(a0 * invL, a1 * invL);
}

// ---------------------------------------------------------------------------
// TF32 128x128x16 device tile (persistent pinv)
// ---------------------------------------------------------------------------
__device__ __forceinline__ void tc_tile(
    const float* Ab, const float* Bb, float* C, const float* X1,
    int N, int K, int lda, int ldb, long long cbase,
    float alpha, float beta, int m0, int n0,
    uint32_t (*As)[16][136], uint32_t (*Bs)[16][136])
{
    constexpr int BK = 16;
    int tid = threadIdx.x, lane = tid & 31, warp = tid >> 5;
    int wm0 = (warp >> 2) * 64;
    int wn0 = (warp & 3) * 32;
    float4 ra[2], rb[2];
    float acc[4][4][4];
    #pragma unroll
    for (int i = 0; i < 4; i++)
        #pragma unroll
        for (int j = 0; j < 4; j++)
            #pragma unroll
            for (int r = 0; r < 4; r++) acc[i][j][r] = 0.f;

    auto LOAD = [&](int kb) {
        #pragma unroll
        for (int c = 0; c < 2; c++) {
            int id = c * 256 + tid;
            int m = id >> 2, kq = id & 3;
            ra[c] = *(const float4*)(Ab + (size_t)(m0 + m) * lda + kb * BK + kq * 4);
        }
        #pragma unroll
        for (int c = 0; c < 2; c++) {
            int id = c * 256 + tid;
            int k = id >> 5, nq = id & 31;
            rb[c] = *(const float4*)(Bb + (size_t)(kb * BK + k) * ldb + n0 + nq * 4);
        }
    };
    auto COMMIT = [&](int bf) {
        #pragma unroll
        for (int c = 0; c < 2; c++) {
            int id = c * 256 + tid;
            int m = id >> 2, kq = id & 3;
            As[bf][kq*4+0][m] = f2tf(ra[c].x); As[bf][kq*4+1][m] = f2tf(ra[c].y);
            As[bf][kq*4+2][m] = f2tf(ra[c].z); As[bf][kq*4+3][m] = f2tf(ra[c].w);
        }
        #pragma unroll
        for (int c = 0; c < 2; c++) {
            int id = c * 256 + tid;
            int k = id >> 5, nq = id & 31;
            Bs[bf][k][nq*4+0] = f2tf(rb[c].x); Bs[bf][k][nq*4+1] = f2tf(rb[c].y);
            Bs[bf][k][nq*4+2] = f2tf(rb[c].z); Bs[bf][k][nq*4+3] = f2tf(rb[c].w);
        }
    };
    auto MMA = [&](int bf) {
        #pragma unroll
        for (int ks = 0; ks < 2; ks++) {
            uint32_t af[4][4], bfr[4][2];
            int kr = ks * 8 + (lane & 3);
            int mr = wm0 + (lane >> 2);
            #pragma unroll
            for (int mt = 0; mt < 4; mt++) {
                af[mt][0] = As[bf][kr    ][mr + mt*16];
                af[mt][1] = As[bf][kr    ][mr + mt*16 + 8];
                af[mt][2] = As[bf][kr + 4][mr + mt*16];
                af[mt][3] = As[bf][kr + 4][mr + mt*16 + 8];
            }
            int nr = wn0 + (lane >> 2);
            #pragma unroll
            for (int nt = 0; nt < 4; nt++) {
                bfr[nt][0] = Bs[bf][kr    ][nr + nt*8];
                bfr[nt][1] = Bs[bf][kr + 4][nr + nt*8];
            }
            #pragma unroll
            for (int mt = 0; mt < 4; mt++)
                #pragma unroll
                for (int nt = 0; nt < 4; nt++)
                    mma8(acc[mt][nt], af[mt], bfr[nt]);
        }
    };

    int nk = K / BK;
    LOAD(0); COMMIT(0);
    __syncthreads();
    for (int kb = 1; kb < nk; kb++) {
        LOAD(kb);
        MMA((kb - 1) & 1);
        COMMIT(kb & 1);
        __syncthreads();
    }
    MMA((nk - 1) & 1);

    #pragma unroll
    for (int mt = 0; mt < 4; mt++) {
        #pragma unroll
        for (int nt = 0; nt < 4; nt++) {
            int row = m0 + wm0 + mt * 16 + (lane >> 2);
            int col = n0 + wn0 + nt * 8 + (lane & 3) * 2;
            size_t r1 = cbase + (size_t)row * N + col;
            size_t r2 = cbase + (size_t)(row + 8) * N + col;
            float2 lo = make_float2(acc[mt][nt][0], acc[mt][nt][1]);
            float2 hi = make_float2(acc[mt][nt][2], acc[mt][nt][3]);
            float2 rv1 = make_float2(0.f, 0.f), rv2 = make_float2(0.f, 0.f);
            if (beta != 0.f) {
                rv1 = *(const float2*)(X1 + r1);
                rv2 = *(const float2*)(X1 + r2);
            }
            *(float2*)(C + r1) = make_float2(alpha*lo.x + beta*rv1.x, alpha*lo.y + beta*rv1.y);
            *(float2*)(C + r2) = make_float2(alpha*hi.x + beta*rv2.x, alpha*hi.y + beta*rv2.y);
        }
    }
}

// per-bh barrier: only the 4 blocks of this bh must arrive
__device__ __forceinline__ void gridbar(int bh, int i) {
    __syncthreads();
    if (threadIdx.x == 0) {
        int idx = bh * 24 + i;
        __threadfence();
        atomicAdd(&g_barc[idx], 1);
        while (((volatile int*)g_barc)[idx] < 4) { }
        __threadfence();
    }
    __syncthreads();
}

// 6 tf32 Newton-Schulz iterations; after 6 ping-pong swaps result is in g_z
__global__ __launch_bounds__(256) void pinv_iters() {
    __shared__ uint32_t As[2][16][136];
    __shared__ uint32_t Bs[2][16][136];
    int m0 = blockIdx.y * 128, n0 = blockIdx.x * 128;
    int bh = blockIdx.z;
    long long base = (long long)bh * (MM * MM);
    float* zc = g_z;
    float* zn = g_z2;
    int bi = 0;
    #pragma unroll 1
    for (int it = 0; it < 6; it++) {
        tc_tile(g_attn2 + base, zc + base, g_xz, nullptr, MM, MM, MM, MM, base,
                1.f, 0.f, m0, n0, As, Bs);
        gridbar(bh, bi++);
        tc_tile(g_xz + base, g_xz + base, g_t, g_xz, MM, MM, MM, MM, base,
                -1.f, 7.f, m0, n0, As, Bs);
        gridbar(bh, bi++);
        tc_tile(g_xz + base, g_t + base, g_u, g_xz, MM, MM, MM, MM, base,
                -1.f, 15.f, m0, n0, As, Bs);
        gridbar(bh, bi++);
        tc_tile(zc + base, g_u + base, zn, zc, MM, MM, MM, MM, base,
                -0.25f, 3.25f, m0, n0, As, Bs);
        if (it < 5) gridbar(bh, bi++);
        float* tmp = zc; zc = zn; zn = tmp;
    }
}

// Wc = z_final(g_z) @ out3, tf32
__global__ __launch_bounds__(256) void wc_gemm() {
    __shared__ uint32_t As[2][16][136];
    __shared__ uint32_t Bs[2][16][136];
    constexpr int BK = 16;
    int tid = threadIdx.x, lane = tid & 31, warp = tid >> 5;
    int wm0 = (warp >> 2) * 64;
    int wn0 = (warp & 3) * 16;
    int m0 = blockIdx.y * 128;
    long long abase = (long long)blockIdx.z * (MM * MM);
    long long cbase = (long long)blockIdx.z * (MM * DH);
    const float* Ab = g_z + abase;
    const float* Bb = g_out3 + cbase;
    float4 ra[2];
    float4 rb;
    float acc[4][2][4];
    #pragma unroll
    for (int i = 0; i < 4; i++)
        #pragma unroll
        for (int j = 0; j < 2; j++)
            #pragma unroll
            for (int r = 0; r < 4; r++) acc[i][j][r] = 0.f;

    auto LOAD = [&](int kb) {
        #pragma unroll
        for (int c = 0; c < 2; c++) {
            int id = c * 256 + tid;
            int m = id >> 2, kq = id & 3;
            ra[c] = *(const float4*)(Ab + (size_t)(m0 + m) * MM + kb * BK + kq * 4);
        }
        {
            int k = tid >> 4, nq = tid & 15;
            rb = *(const float4*)(Bb + (size_t)(kb * BK + k) * DH + nq * 4);
        }
    };
    auto COMMIT = [&](int bf) {
        #pragma unroll
        for (int c = 0; c < 2; c++) {
            int id = c * 256 + tid;
            int m = id >> 2, kq = id & 3;
            As[bf][kq*4+0][m] = f2tf(ra[c].x); As[bf][kq*4+1][m] = f2tf(ra[c].y);
            As[bf][kq*4+2][m] = f2tf(ra[c].z); As[bf][kq*4+3][m] = f2tf(ra[c].w);
        }
        {
            int k = tid >> 4, nq = tid & 15;
            Bs[bf][k][nq*4+0] = f2tf(rb.x); Bs[bf][k][nq*4+1] = f2tf(rb.y);
            Bs[bf][k][nq*4+2] = f2tf(rb.z); Bs[bf][k][nq*4+3] = f2tf(rb.w);
        }
    };
    auto MMA = [&](int bf) {
        #pragma unroll
        for (int ks = 0; ks < 2; ks++) {
            uint32_t af[4][4], bfr[2][2];
            int kr = ks * 8 + (lane & 3);
            int mr = wm0 + (lane >> 2);
            #pragma unroll
            for (int mt = 0; mt < 4; mt++) {
                af[mt][0] = As[bf][kr    ][mr + mt*16];
                af[mt][1] = As[bf][kr    ][mr + mt*16 + 8];
                af[mt][2] = As[bf][kr + 4][mr + mt*16];
                af[mt][3] = As[bf][kr + 4][mr + mt*16 + 8];
            }
            int nr = wn0 + (lane >> 2);
            #pragma unroll
            for (int nt = 0; nt < 2; nt++) {
                bfr[nt][0] = Bs[bf][kr    ][nr + nt*8];
                bfr[nt][1] = Bs[bf][kr + 4][nr + nt*8];
            }
            #pragma unroll
            for (int mt = 0; mt < 4; mt++)
                #pragma unroll
                for (int nt = 0; nt < 2; nt++)
                    mma8(acc[mt][nt], af[mt], bfr[nt]);
        }
    };

    LOAD(0); COMMIT(0);
    __syncthreads();
    for (int kb = 1; kb < 16; kb++) {
        LOAD(kb);
        MMA((kb - 1) & 1);
        COMMIT(kb & 1);
        __syncthreads();
    }
    MMA(1);

    #pragma unroll
    for (int mt = 0; mt < 4; mt++) {
        #pragma unroll
        for (int nt = 0; nt < 2; nt++) {
            int row = m0 + wm0 + mt * 16 + (lane >> 2);
            int col = wn0 + nt * 8 + (lane & 3) * 2;
            *(float2*)(g_wc + cbase + (size_t)row * DH + col) =
                make_float2(acc[mt][nt][0], acc[mt][nt][1]);
            *(float2*)(g_wc + cbase + (size_t)(row + 8) * DH + col) =
                make_float2(acc[mt][nt][2], acc[mt][nt][3]);
        }
    }
}

// ---------------------------------------------------------------------------
// BF16 GEMM, A operand bf16 in gmem. EPI0: QKV scatter; EPI1: out+bias+x
// ---------------------------------------------------------------------------
template<int EPI, int BM, int BN, int BK>
__global__ __launch_bounds__(256) void bf_gemm(
    const __nv_bfloat16* __restrict__ Ah, const float* __restrict__ Bg,
    float* __restrict__ C, const float* __restrict__ X1, const float* __restrict__ X2,
    int N, int K, int lda, int ldb)
{
    constexpr int PA = BM + 8, PB = BN + 8;
    constexpr int MT = (BM / 2) / 16;
    constexpr int NT = (BN / 4) / 8;
    constexpr int KP = BK / 2;
    constexpr int RAH = (BM * BK) / 2048;
    constexpr int RBN = (KP * (BN / 4)) / 256;
    __shared__ uint32_t As[2][KP][PA];
    __shared__ uint32_t Bs[2][KP][PB];
    uint4  rah[RAH];
    float4 rb0[RBN], rb1[RBN];

    int tid = threadIdx.x, lane = tid & 31, warp = tid >> 5;
    int wm0 = (warp >> 2) * (BM / 2);
    int wn0 = (warp & 3) * (BN / 4);
    int m0 = blockIdx.y * BM, n0 = blockIdx.x * BN;

    float acc[MT][NT][4];
    #pragma unroll
    for (int i = 0; i < MT; i++)
        #pragma unroll
        for (int j = 0; j < NT; j++)
            #pragma unroll
            for (int r = 0; r < 4; r++) acc[i][j][r] = 0.f;

    auto LOAD = [&](int kb) {
        #pragma unroll
        for (int c = 0; c < RAH; c++) {
            int id = c * 256 + tid;
            int m = id / (BK / 8), kq = id % (BK / 8);
            rah[c] = *(const uint4*)(Ah + (size_t)(m0 + m) * lda + kb * BK + kq * 8);
        }
        #pragma unroll
        for (int c = 0; c < RBN; c++) {
            int id = c * 256 + tid;
            int kp = id / (BN / 4), nq = id % (BN / 4);
            rb0[c] = *(const float4*)(Bg + (size_t)(kb*BK + 2*kp    ) * ldb + n0 + nq * 4);
            rb1[c] = *(const float4*)(Bg + (size_t)(kb*BK + 2*kp + 1) * ldb + n0 + nq * 4);
        }
    };
    auto COMMIT = [&](int bf) {
        #pragma unroll
        for (int c = 0; c < RAH; c++) {
            int id = c * 256 + tid;
            int m = id / (BK / 8), kq = id % (BK / 8);
            As[bf][kq*4+0][m] = rah[c].x; As[bf][kq*4+1][m] = rah[c].y;
            As[bf][kq*4+2][m] = rah[c].z; As[bf][kq*4+3][m] = rah[c].w;
        }
        #pragma unroll
        for (int c = 0; c < RBN; c++) {
            int id = c * 256 + tid;
            int kp = id / (BN / 4), nq = id % (BN / 4);
            Bs[bf][kp][nq*4+0] = f2bf2(rb0[c].x, rb1[c].x);
            Bs[bf][kp][nq*4+1] = f2bf2(rb0[c].y, rb1[c].y);
            Bs[bf][kp][nq*4+2] = f2bf2(rb0[c].z, rb1[c].z);
            Bs[bf][kp][nq*4+3] = f2bf2(rb0[c].w, rb1[c].w);
        }
    };
    auto MMA = [&](int bf) {
        #pragma unroll
        for (int ks = 0; ks < BK / 16; ks++) {
            uint32_t af[MT][4], bfr[NT][2];
            int kr = ks * 8 + (lane & 3);
            int mr = wm0 + (lane >> 2);
            #pragma unroll
            for (int mt = 0; mt < MT; mt++) {
                af[mt][0] = As[bf][kr    ][mr + mt*16];
                af[mt][1] = As[bf][kr    ][mr + mt*16 + 8];
                af[mt][2] = As[bf][kr + 4][mr + mt*16];
                af[mt][3] = As[bf][kr + 4][mr + mt*16 + 8];
            }
            int nr = wn0 + (lane >> 2);
            #pragma unroll
            for (int nt = 0; nt < NT; nt++) {
                bfr[nt][0] = Bs[bf][kr    ][nr + nt*8];
                bfr[nt][1] = Bs[bf][kr + 4][nr + nt*8];
            }
            #pragma unroll
            for (int mt = 0; mt < MT; mt++)
                #pragma unroll
                for (int nt = 0; nt < NT; nt++)
                    mma16(acc[mt][nt], af[mt], bfr[nt]);
        }
    };

    int nk = K / BK;
    LOAD(0); COMMIT(0);
    __syncthreads();
    for (int kb = 1; kb < nk; kb++) {
        LOAD(kb);
        MMA((kb - 1) & 1);
        COMMIT(kb & 1);
        __syncthreads();
    }
    MMA((nk - 1) & 1);

    #pragma unroll
    for (int mt = 0; mt < MT; mt++) {
        #pragma unroll
        for (int nt = 0; nt < NT; nt++) {
            int row = m0 + wm0 + mt * 16 + (lane >> 2);
            int col = n0 + wn0 + nt * 8 + (lane & 3) * 2;
            float2 lo = make_float2(acc[mt][nt][0], acc[mt][nt][1]);
            float2 hi = make_float2(acc[mt][nt][2], acc[mt][nt][3]);
            if constexpr (EPI == 0) {
                int which = col >> 9, inner = col & 511;
                int h = inner >> 6, d = inner & 63;
                __nv_bfloat16* dst = which == 0 ? g_qh : (which == 1 ? g_kh : g_vh);
                float s = (which == 0) ? 0.125f : 1.f;
                int bq = row >> 13, n = row & (NN - 1);
                *(uint32_t*)(dst + (((size_t)(bq*HH+h))*NN + n    )*DH + d) = f2bf2(lo.x*s, lo.y*s);
                *(uint32_t*)(dst + (((size_t)(bq*HH+h))*NN + n + 8)*DH + d) = f2bf2(hi.x*s, hi.y*s);
            } else if constexpr (EPI == 1) {
                float2 bv = *(const float2*)(X1 + col);
                size_t r1 = (size_t)row * DD + col, r2 = (size_t)(row + 8) * DD + col;
                float2 x1 = *(const float2*)(X2 + r1);
                float2 x2 = *(const float2*)(X2 + r2);
                *(float2*)(C + r1) = make_float2(lo.x + bv.x + x1.x, lo.y + bv.y + x1.y);
                *(float2*)(C + r2) = make_float2(hi.x + bv.x + x2.x, hi.y + bv.y + x2.y);
            }
        }
    }
}

// ---------------------------------------------------------------------------
// Fused attn1 + depthwise conv: y(bf16) = conv33(v) + softmax(q @ kl^T) @ Wc
// ---------------------------------------------------------------------------
__global__ __launch_bounds__(256) void attn1_fused(const float* __restrict__ res_w) {
    extern __shared__ char smraw[];
    uint32_t* As  = (uint32_t*)smraw;
    uint32_t* Bs  = As + 16*72;
    uint32_t* Ps  = Bs + 16*264;
    uint32_t* Wcs = Ps + 128*72;
    float* rmax = (float*)(Wcs + 128*72);
    float* rsum = rmax + 320;
    float* sw   = rsum + 320;
    uint32_t* Vw = As;

    int tid = threadIdx.x, lane = tid & 31, warp = tid >> 5;
    int g = lane >> 2, q4 = lane & 3;
    int bh = blockIdx.y;
    int b = bh >> 3, h = bh & 7;
    int m0 = blockIdx.x * 64;
    const __nv_bfloat16* Ab = g_qh + ((size_t)bh * NN + m0) * DH;
    const float* Bb = g_kl + (size_t)bh * MM * DH;
    const float* Wg = g_wc + (size_t)bh * MM * DH;
    const __nv_bfloat16* vb = g_vh + (size_t)bh * NN * DH;

    if (tid < 33) sw[tid] = res_w[h * 33 + tid];

    #pragma unroll
    for (int c = 0; c < 8; c++) {
        int id = c * 256 + tid;
        int kp = id >> 4, n4 = id & 15;
        float4 lo = *(const float4*)(Wg + (size_t)(2*kp    ) * DH + n4 * 4);
        float4 hi = *(const float4*)(Wg + (size_t)(2*kp + 1) * DH + n4 * 4);
        Wcs[kp*72 + n4*4+0] = f2bf2(lo.x, hi.x);
        Wcs[kp*72 + n4*4+1] = f2bf2(lo.y, hi.y);
        Wcs[kp*72 + n4*4+2] = f2bf2(lo.z, hi.z);
        Wcs[kp*72 + n4*4+3] = f2bf2(lo.w, hi.w);
    }

    int wm0q = (warp >> 2) * 32;
    int wn0q = (warp & 3) * 64;
    int wnq = warp & 3;
    float acc[2][8][4];
    #pragma unroll
    for (int i = 0; i < 2; i++)
        #pragma unroll
        for (int j = 0; j < 8; j++)
            #pragma unroll
            for (int r = 0; r < 4; r++) acc[i][j][r] = 0.f;

    for (int k0 = 0; k0 < 64; k0 += 32) {
        {
            int m = tid >> 2, kq = tid & 3;
            uint4 v = *(const uint4*)(Ab + (size_t)m * DH + k0 + kq * 8);
            As[(kq*4+0)*72 + m] = v.x; As[(kq*4+1)*72 + m] = v.y;
            As[(kq*4+2)*72 + m] = v.z; As[(kq*4+3)*72 + m] = v.w;
        }
        #pragma unroll
        for (int c = 0; c < 8; c++) {
            int id = c * 256 + tid;
            int n = id >> 3, kq = id & 7;
            float4 v = *(const float4*)(Bb + (size_t)n * DH + k0 + kq * 4);
            Bs[(kq*2+0)*264 + n] = f2bf2(v.x, v.y);
            Bs[(kq*2+1)*264 + n] = f2bf2(v.z, v.w);
        }
        __syncthreads();
        #pragma unroll
        for (int ks = 0; ks < 2; ks++) {
            uint32_t af[2][4], bfr[8][2];
            int kr = ks * 8 + q4;
            int mr = wm0q + g;
            #pragma unroll
            for (int mt = 0; mt < 2; mt++) {
                af[mt][0] = As[kr*72 + mr + mt*16];
                af[mt][1] = As[kr*72 + mr + mt*16 + 8];
                af[mt][2] = As[(kr+4)*72 + mr + mt*16];
                af[mt][3] = As[(kr+4)*72 + mr + mt*16 + 8];
            }
            int nr = wn0q + g;
            #pragma unroll
            for (int nt = 0; nt < 8; nt++) {
                bfr[nt][0] = Bs[kr*264 + nr + nt*8];
                bfr[nt][1] = Bs[(kr+4)*264 + nr + nt*8];
            }
            #pragma unroll
            for (int mt = 0; mt < 2; mt++)
                #pragma unroll
                for (int nt = 0; nt < 8; nt++)
                    mma16(acc[mt][nt], af[mt], bfr[nt]);
        }
        __syncthreads();
    }

    #pragma unroll
    for (int c = 0; c < 6; c++) {
        int id = c * 256 + tid;
        int row = id >> 4, up = id & 15;
        int tok = m0 - 16 + row;
        uint2 u = make_uint2(0u, 0u);
        if (tok >= 0 && tok < NN)
            u = *(const uint2*)(vb + (size_t)tok * DH + up * 4);
        Vw[row*33 + up*2]     = u.x;
        Vw[row*33 + up*2 + 1] = u.y;
    }

    #pragma unroll
    for (int mt = 0; mt < 2; mt++) {
        int r0 = wm0q + mt * 16 + g;
        float m0v = -1e30f, m1v = -1e30f;
        #pragma unroll
        for (int nt = 0; nt < 8; nt++) {
            m0v = fmaxf(m0v, fmaxf(acc[mt][nt][0], acc[mt][nt][1]));
            m1v = fmaxf(m1v, fmaxf(acc[mt][nt][2], acc[mt][nt][3]));
        }
        #pragma unroll
        for (int o = 1; o < 4; o <<= 1) {
            m0v = fmaxf(m0v, __shfl_xor_sync(~0u, m0v, o));
            m1v = fmaxf(m1v, __shfl_xor_sync(~0u, m1v, o));
        }
        if (q4 == 0) { rmax[r0*5 + wnq] = m0v; rmax[(r0+8)*5 + wnq] = m1v; }
    }
    __syncthreads();
    #pragma unroll
    for (int mt = 0; mt < 2; mt++) {
        int r0 = wm0q + mt * 16 + g;
        float M0 = fmaxf(fmaxf(rmax[r0*5+0], rmax[r0*5+1]), fmaxf(rmax[r0*5+2], rmax[r0*5+3]));
        float M1 = fmaxf(fmaxf(rmax[(r0+8)*5+0], rmax[(r0+8)*5+1]),
                         fmaxf(rmax[(r0+8)*5+2], rmax[(r0+8)*5+3]));
        float s0 = 0.f, s1 = 0.f;
        #pragma unroll
        for (int nt = 0; nt < 8; nt++) {
            acc[mt][nt][0] = __expf(acc[mt][nt][0] - M0);
            acc[mt][nt][1] = __expf(acc[mt][nt][1] - M0);
            acc[mt][nt][2] = __expf(acc[mt][nt][2] - M1);
            acc[mt][nt][3] = __expf(acc[mt][nt][3] - M1);
            s0 += acc[mt][nt][0] + acc[mt][nt][1];
            s1 += acc[mt][nt][2] + acc[mt][nt][3];
        }
        #pragma unroll
        for (int o = 1; o < 4; o <<= 1) {
            s0 += __shfl_xor_sync(~0u, s0, o);
            s1 += __shfl_xor_sync(~0u, s1, o);
        }
        if (q4 == 0) { rsum[r0*5 + wnq] = s0; rsum[(r0+8)*5 + wnq] = s1; }
    }
    __syncthreads();
    #pragma unroll
    for (int mt = 0; mt < 2; mt++) {
        int r0 = wm0q + mt * 16 + g, r1 = r0 + 8;
        float i0 = 1.f / (rsum[r0*5+0] + rsum[r0*5+1] + rsum[r0*5+2] + rsum[r0*5+3]);
        float i1 = 1.f / (rsum[r1*5+0] + rsum[r1*5+1] + rsum[r1*5+2] + rsum[r1*5+3]);
        #pragma unroll
        for (int nt = 0; nt < 8; nt++) {
            int kp = (wn0q >> 1) + nt * 4 + q4;
            Ps[kp*72 + r0] = f2bf2(acc[mt][nt][0] * i0, acc[mt][nt][1] * i0);
            Ps[kp*72 + r1] = f2bf2(acc[mt][nt][2] * i1, acc[mt][nt][3] * i1);
        }
    }
    __syncthreads();

    int wm0p = (warp >> 2) * 32;
    int wn0p = (warp & 3) * 16;
    float yacc[2][2][4];
    #pragma unroll
    for (int i = 0; i < 2; i++)
        #pragma unroll
        for (int j = 0; j < 2; j++)
            #pragma unroll
            for (int r = 0; r < 4; r++) yacc[i][j][r] = 0.f;
    #pragma unroll
    for (int kc = 0; kc < 16; kc++) {
        int kr = kc * 8 + q4;
        uint32_t af[2][4], bfr[2][2];
        int mr = wm0p + g;
        #pragma unroll
        for (int mt = 0; mt < 2; mt++) {
            af[mt][0] = Ps[kr*72 + mr + mt*16];
            af[mt][1] = Ps[kr*72 + mr + mt*16 + 8];
            af[mt][2] = Ps[(kr+4)*72 + mr + mt*16];
            af[mt][3] = Ps[(kr+4)*72 + mr + mt*16 + 8];
        }
        int nr = wn0p + g;
        #pragma unroll
        for (int nt = 0; nt < 2; nt++) {
            bfr[nt][0] = Wcs[kr*72 + nr + nt*8];
            bfr[nt][1] = Wcs[(kr+4)*72 + nr + nt*8];
        }
        #pragma unroll
        for (int mt = 0; mt < 2; mt++)
            #pragma unroll
            for (int nt = 0; nt < 2; nt++)
                mma16(yacc[mt][nt], af[mt], bfr[nt]);
    }
    #pragma unroll
    for (int mt = 0; mt < 2; mt++) {
        #pragma unroll
        for (int nt = 0; nt < 2; nt++) {
            int rl = wm0p + mt * 16 + g;
            int col = wn0p + nt * 8 + q4 * 2;
            int cp = col >> 1;
            float c00 = 0.f, c01 = 0.f, c10 = 0.f, c11 = 0.f;
            #pragma unroll
            for (int j = 0; j < 33; j++) {
                float w = sw[j];
                float2 f0 = __bfloat1622float2(
                    *(const __nv_bfloat162*)&Vw[(rl + j) * 33 + cp]);
                float2 f1 = __bfloat1622float2(
                    *(const __nv_bfloat162*)&Vw[(rl + 8 + j) * 33 + cp]);
                c00 += w * f0.x; c01 += w * f0.y;
                c10 += w * f1.x; c11 += w * f1.y;
            }
            int row = m0 + rl;
            size_t r1 = ((size_t)b * NN + row    ) * DD + h * 64 + col;
            size_t r2 = ((size_t)b * NN + row + 8) * DD + h * 64 + col;
            *(uint32_t*)(g_yh + r1) = f2bf2(c00 + yacc[mt][nt][0], c01 + yacc[mt][nt][1]);
            *(uint32_t*)(g_yh + r2) = f2bf2(c10 + yacc[mt][nt][2], c11 + yacc[mt][nt][3]);
        }
    }
}

// ---------------------------------------------------------------------------
// LN (bf16 out) / landmarks / sim2 / softmax256 / init / colrowmax / z0
// ---------------------------------------------------------------------------
__global__ __launch_bounds__(128) void ln_kernel(const float* __restrict__ x,
                                                 const float* __restrict__ w,
                                                 const float* __restrict__ bia) {
    int row = blockIdx.x, tid = threadIdx.x;
    const float4* xr = reinterpret_cast<const float4*>(x + (size_t)row * DD);
    float4 v = xr[tid];
    float s  = v.x + v.y + v.z + v.w;
    float sq = v.x*v.x + v.y*v.y + v.z*v.z + v.w*v.w;
    __shared__ float sm[4], sm2[4];
    #pragma unroll
    for (int o = 16; o > 0; o >>= 1) {
        s  += __shfl_down_sync(0xffffffffu, s,  o);
        sq += __shfl_down_sync(0xffffffffu, sq, o);
    }
    if ((tid & 31) == 0) { sm[tid >> 5] = s; sm2[tid >> 5] = sq; }
    __syncthreads();
    if (tid == 0) {
        float a = 0.f, b2 = 0.f;
        #pragma unroll
        for (int i = 0; i < 4; i++) { a += sm[i]; b2 += sm2[i]; }
        sm[0] = a; sm2[0] = b2;
    }
    __syncthreads();
    float mean = sm[0] * (1.f / 512.f);
    float var  = sm2[0] * (1.f / 512.f) - mean * mean;
    float rstd = rsqrtf(var + 1e-5f);
    float4 wv = reinterpret_cast<const float4*>(w)[tid];
    float4 bv = reinterpret_cast<const float4*>(bia)[tid];
    float ox = (v.x - mean) * rstd * wv.x + bv.x;
    float oy = (v.y - mean) * rstd * wv.y + bv.y;
    float oz = (v.z - mean) * rstd * wv.z + bv.z;
    float ow = (v.w - mean) * rstd * wv.w + bv.w;
    *(uint2*)(g_xh + (size_t)row * DD + tid * 4) =
        make_uint2(f2bf2(ox, oy), f2bf2(oz, ow));
}

__global__ void landmark_kernel() {
    int m = blockIdx.x, bh = blockIdx.y;
    int d = threadIdx.x;
    size_t base = ((size_t)bh * NN + (size_t)m * 32) * DH + d;
    float sq = 0.f, sk = 0.f;
    #pragma unroll
    for (int j = 0; j < 32; j++) {
        sq += __bfloat162float(g_qh[base + (size_t)j * DH]);
        sk += __bfloat162float(g_kh[base + (size_t)j * DH]);
    }
    size_t o = ((size_t)bh * MM + m) * DH + d;
    g_ql[o] = sq * (1.f / 32.f);
    g_kl[o] = sk * (1.f / 32.f);
}

__global__ __launch_bounds__(256) void gemm_sim2() {
    __shared__ float As[32][132];
    __shared__ float Bs[32][132];
    int bh = blockIdx.z;
    int n0 = blockIdx.x * 128, m0 = blockIdx.y * 128;
    const float* Ab = g_ql + ((size_t)bh * MM + m0) * DH;
    const float* Bb = g_kl + ((size_t)bh * MM + n0) * DH;
    float* Cb = g_attn2 + (size_t)bh * MM * MM;
    int tid = threadIdx.x;
    int tx = tid & 15, ty = tid >> 4;
    float acc[8][8] = {};
    for (int kk = 0; kk < 64; kk += 32) {
        #pragma unroll
        for (int u = 0; u < 4; u++) {
            int g = u * 256 + tid;
            int m = g >> 3, k4 = g & 7;
            float4 av = *(const float4*)(Ab + (size_t)m * DH + kk + k4 * 4);
            As[k4*4+0][m] = av.x; As[k4*4+1][m] = av.y;
            As[k4*4+2][m] = av.z; As[k4*4+3][m] = av.w;
        }
        #pragma unroll
        for (int u = 0; u < 4; u++) {
            int g = u * 256 + tid;
            int m = g >> 3, k4 = g & 7;
            float4 bv = *(const float4*)(Bb + (size_t)m * DH + kk + k4 * 4);
            Bs[k4*4+0][m] = bv.x; Bs[k4*4+1][m] = bv.y;
            Bs[k4*4+2][m] = bv.z; Bs[k4*4+3][m] = bv.w;
        }
        __syncthreads();
        #pragma unroll
        for (int k = 0; k < 32; k++) {
            float a[8], b[8];
            *(float4*)&a[0] = *(const float4*)&As[k][ty*8];
            *(float4*)&a[4] = *(const float4*)&As[k][ty*8+4];
            *(float4*)&b[0] = *(const float4*)&Bs[k][tx*8];
            *(float4*)&b[4] = *(const float4*)&Bs[k][tx*8+4];
            #pragma unroll
            for (int i = 0; i < 8; i++)
                #pragma unroll
                for (int j = 0; j < 8; j++)
                    acc[i][j] += a[i] * b[j];
        }
        __syncthreads();
    }
    #pragma unroll
    for (int i = 0; i < 8; i++) {
        size_t r = (size_t)(m0 + ty * 8 + i) * MM + n0 + tx * 8;
        *(float4*)(Cb + r)     = make_float4(acc[i][0], acc[i][1], acc[i][2], acc[i][3]);
        *(float4*)(Cb + r + 4) = make_float4(acc[i][4], acc[i][5], acc[i][6], acc[i][7]);
    }
}

__global__ __launch_bounds__(256) void softmax256() {
    int row = blockIdx.x, tid = threadIdx.x;
    float* p = g_attn2 + (size_t)row * MM;
    float v = p[tid];
    __shared__ float red[8];
    float m = v;
    #pragma unroll
    for (int o = 16; o; o >>= 1) m = fmaxf(m, __shfl_xor_sync(~0u, m, o));
    if ((tid & 31) == 0) red[tid >> 5] = m;
    __syncthreads();
    if (tid < 32) {
        float t = (tid < 8) ? red[tid] : -1e30f;
        #pragma unroll
        for (int o = 4; o; o >>= 1) t = fmaxf(t, __shfl_xor_sync(~0u, t, o));
        if (tid == 0) red[0] = t;
    }
    __syncthreads();
    float mx = red[0];
    __syncthreads();
    float e = __expf(v - mx);
    float s = e;
    #pragma unroll
    for (int o = 16; o; o >>= 1) s += __shfl_xor_sync(~0u, s, o);
    if ((tid & 31) == 0) red[tid >> 5] = s;
    __syncthreads();
    if (tid < 32) {
        float t = (tid < 8) ? red[tid] : 0.f;
        #pragma unroll
        for (int o = 4; o; o >>= 1) t += __shfl_xor_sync(~0u, t, o);
        if (tid == 0) red[0] = t;
    }
    __syncthreads();
    p[tid] = e / red[0];
}

__global__ void init_kernel() {
    g_maxA = 0; g_maxB = 0;
    for (int i = threadIdx.x; i < BH * 24; i += 256) g_barc[i] = 0;
}

__global__ __launch_bounds__(256) void colrowmax_kernel() {
    int bh = blockIdx.x, tid = threadIdx.x;
    const float* a = g_attn2 + (size_t)bh * MM * MM;
    float cs = 0.f, rs = 0.f;
    for (int m = 0; m < MM; m++) cs += fabsf(a[(size_t)m * MM + tid]);
    for (int n = 0; n < MM; n++) rs += fabsf(a[(size_t)tid * MM + n]);
    __shared__ float r1[8], r2[8];
    #pragma unroll
    for (int o = 16; o; o >>= 1) {
        cs = fmaxf(cs, __shfl_xor_sync(~0u, cs, o));
        rs = fmaxf(rs, __shfl_xor_sync(~0u, rs, o));
    }
    if ((tid & 31) == 0) { r1[tid >> 5] = cs; r2[tid >> 5] = rs; }
    __syncthreads();
    if (tid == 0) {
        float a1 = r1[0], a2 = r2[0];
        #pragma unroll
        for (int i = 1; i < 8; i++) { a1 = fmaxf(a1, r1[i]); a2 = fmaxf(a2, r2[i]); }
        atomicMax(&g_maxA, __float_as_int(a1));
        atomicMax(&g_maxB, __float_as_int(a2));
    }
}

__global__ __launch_bounds__(256) void z0_kernel() {
    int bh = blockIdx.z;
    int c0 = blockIdx.x * 32, r0 = blockIdx.y * 32;
    int tid = threadIdx.x;
    __shared__ float t[32][33];
    const float* a = g_attn2 + (size_t)bh * MM * MM;
    #pragma unroll
    for (int rr = 0; rr < 4; rr++) {
        int r = rr * 8 + (tid >> 5), c = tid & 31;
        t[r][c] = a[(size_t)(r0 + r) * MM + c0 + c];
    }
    __syncthreads();
    float s = 1.f / (__int_as_float(g_maxA) * __int_as_float(g_maxB));
    float* z = g_z + (size_t)bh * MM * MM;
    #pragma unroll
    for (int rr = 0; rr < 4; rr++) {
        int r = rr * 8 + (tid >> 5), c = tid & 31;
        z[(size_t)(c0 + r) * MM + r0 + c] = t[c][r] * s;
    }
}

// ---------------------------------------------------------------------------
// Launch
// ---------------------------------------------------------------------------
extern "C" void kernel_launch(void* const* d_in, const int* in_sizes, int n_in,
                              void* d_out, int out_size) {
    const float* x     = (const float*)d_in[0];
    const float* ln_w  = (const float*)d_in[1];
    const float* ln_b  = (const float*)d_in[2];
    const float* w_qkv = (const float*)d_in[3];
    const float* w_out = (const float*)d_in[4];
    const float* b_out = (const float*)d_in[5];
    const float* res_w = (const float*)d_in[6];
    float* out = (float*)d_out;

    __nv_bfloat16 *p_xh, *p_yh;
    cudaGetSymbolAddress((void**)&p_xh, g_xh);
    cudaGetSymbolAddress((void**)&p_yh, g_yh);

    cudaFuncSetAttribute(flash3, cudaFuncAttributeMaxDynamicSharedMemorySize, 58368);
    cudaFuncSetAttribute(attn1_fused, cudaFuncAttributeMaxDynamicSharedMemorySize, 98304);

    ln_kernel<<<BB * NN, 128>>>(x, ln_w, ln_b);
    bf_gemm<0,128,128,32><<<dim3(12, 256, 1), 256>>>(
        p_xh, w_qkv, nullptr, nullptr, nullptr, 1536, 512, 512, 1536);
    landmark_kernel<<<dim3(MM, BH), 64>>>();

    gemm_sim2<<<dim3(2, 2, BH), 256>>>();
    flash3<<<dim3(2, KS, BH), 256, 58368>>>();
    combine3<<<1024, 256>>>();
    softmax256<<<BH * MM, 256>>>();

    init_kernel<<<1, 256>>>();
    colrowmax_kernel<<<BH, 256>>>();
    z0_kernel<<<dim3(8, 8, BH), 256>>>();

    pinv_iters<<<dim3(2, 2, BH), 256>>>();
    wc_gemm<<<dim3(1, 2, BH), 256>>>();

    attn1_fused<<<dim3(128, BH), 256, 98304>>>(res_w);

    bf_gemm<1,128,128,32><<<dim3(4, 256, 1), 256>>>(
        p_yh, w_out, out, b_out, x, 512, 512, 512, 512);
}

// round 15
// speedup vs baseline: 1.5861x; 1.0094x over previous
#include <cuda_runtime.h>
#include <cuda_bf16.h>
#include <stdint.h>
#include <math.h>

#define BB 4
#define NN 8192
#define DD 512
#define HH 8
#define DH 64
#define MM 256
#define BH 32
#define KS 16

__device__ __align__(16) __nv_bfloat16 g_xh[(size_t)BB*NN*DD];
__device__ __align__(16) __nv_bfloat16 g_qh[(size_t)BH*NN*DH];
__device__ __align__(16) __nv_bfloat16 g_kh[(size_t)BH*NN*DH];
__device__ __align__(16) __nv_bfloat16 g_vh[(size_t)BH*NN*DH];
__device__ __align__(16) float g_ql  [(size_t)BH*MM*DH];
__device__ __align__(16) float g_kl  [(size_t)BH*MM*DH];
__device__ __align__(16) float g_attn2[(size_t)BH*MM*MM];
__device__ __align__(16) float g_z   [(size_t)BH*MM*MM];
__device__ __align__(16) float g_z2  [(size_t)BH*MM*MM];
__device__ __align__(16) float g_xz  [(size_t)BH*MM*MM];
__device__ __align__(16) float g_t   [(size_t)BH*MM*MM];
__device__ __align__(16) float g_u   [(size_t)BH*MM*MM];
__device__ __align__(16) float g_p3  [(size_t)BH*KS*MM*DH];
__device__ __align__(16) float g_m3  [(size_t)BH*KS*MM];
__device__ __align__(16) float g_l3  [(size_t)BH*KS*MM];
__device__ __align__(16) float g_out3[(size_t)BH*MM*DH];
__device__ __align__(16) float g_wc  [(size_t)BH*MM*DH];
__device__ __align__(16) __nv_bfloat16 g_yh[(size_t)BB*NN*DD];
__device__ int g_maxA;
__device__ int g_maxB;
__device__ int g_barc[BH * 24];

// side stream + fork/join events, created once at module init (pre-checkpoint)
static cudaStream_t g_s2;
static cudaEvent_t g_e1, g_e2;
static struct StreamInit {
    StreamInit() {
        cudaStreamCreateWithFlags(&g_s2, cudaStreamNonBlocking);
        cudaEventCreateWithFlags(&g_e1, cudaEventDisableTiming);
        cudaEventCreateWithFlags(&g_e2, cudaEventDisableTiming);
    }
} g_stream_init;

__device__ __forceinline__ uint32_t f2tf(float f) {
    uint32_t u;
    asm("cvt.rna.tf32.f32 %0, %1;" : "=r"(u) : "f"(f));
    return u;
}
__device__ __forceinline__ uint32_t f2bf2(float lo, float hi) {
    uint32_t r;
    asm("cvt.rn.bf16x2.f32 %0, %1, %2;" : "=r"(r) : "f"(hi), "f"(lo));
    return r;
}
__device__ __forceinline__ void mma8(float* d, const uint32_t* a, const uint32_t* b) {
    asm volatile(
        "mma.sync.aligned.m16n8k8.row.col.f32.tf32.tf32.f32 "
        "{%0,%1,%2,%3}, {%4,%5,%6,%7}, {%8,%9}, {%0,%1,%2,%3};"
        : "+f"(d[0]), "+f"(d[1]), "+f"(d[2]), "+f"(d[3])
        : "r"(a[0]), "r"(a[1]), "r"(a[2]), "r"(a[3]), "r"(b[0]), "r"(b[1]));
}
__device__ __forceinline__ void mma16(float* d, const uint32_t* a, const uint32_t* b) {
    asm volatile(
        "mma.sync.aligned.m16n8k16.row.col.f32.bf16.bf16.f32 "
        "{%0,%1,%2,%3}, {%4,%5,%6,%7}, {%8,%9}, {%0,%1,%2,%3};"
        : "+f"(d[0]), "+f"(d[1]), "+f"(d[2]), "+f"(d[3])
        : "r"(a[0]), "r"(a[1]), "r"(a[2]), "r"(a[3]), "r"(b[0]), "r"(b[1]));
}

// ---------------------------------------------------------------------------
// Flash split-KV attn3 (unchanged)
// ---------------------------------------------------------------------------
__global__ __launch_bounds__(256) void flash3() {
    extern __shared__ char smraw[];
    uint32_t* Qs = (uint32_t*)smraw;
    uint32_t* Ksm = Qs + 32*136;
    uint32_t* Vsm = Ksm + 32*72;
    uint32_t* Ps = Vsm + 32*72;
    float* wmax = (float*)(Ps + 32*136);
    float* wsum = wmax + 512;
    float* mrun = wsum + 512;
    float* lrun = mrun + 128;

    int tid = threadIdx.x, lane = tid & 31, warp = tid >> 5;
    int g = lane >> 2, q4 = lane & 3;
    int wm0 = (warp >> 2) * 64;
    int wn0 = (warp & 3) * 16;
    int wn = warp & 3;
    int m0 = blockIdx.x * 128;
    int ksp = blockIdx.y, bh = blockIdx.z;

    const float* Qg = g_ql + ((size_t)bh * MM + m0) * DH;
    #pragma unroll
    for (int c = 0; c < 8; c++) {
        int id = c * 256 + tid;
        int m = id >> 4, qq = id & 15;
        float4 v = *(const float4*)(Qg + (size_t)m * DH + qq * 4);
        Qs[(qq*2+0)*136 + m] = f2bf2(v.x, v.y);
        Qs[(qq*2+1)*136 + m] = f2bf2(v.z, v.w);
    }
    if (tid < 128) { mrun[tid] = -1e30f; lrun[tid] = 0.f; }

    float acc[4][2][4];
    #pragma unroll
    for (int a = 0; a < 4; a++)
        #pragma unroll
        for (int b = 0; b < 2; b++)
            #pragma unroll
            for (int r = 0; r < 4; r++) acc[a][b][r] = 0.f;

    const __nv_bfloat16* Kg = g_kh + ((size_t)bh * NN + ksp * 512) * DH;
    const __nv_bfloat16* Vg = g_vh + ((size_t)bh * NN + ksp * 512) * DH;

    for (int t = 0; t < 8; t++) {
        __syncthreads();
        #pragma unroll
        for (int c = 0; c < 2; c++) {
            int id = c * 256 + tid;
            int n = id >> 3, qq = id & 7;
            uint4 v = *(const uint4*)(Kg + (size_t)(t*64 + n) * DH + qq * 8);
            Ksm[(qq*4+0)*72 + n] = v.x; Ksm[(qq*4+1)*72 + n] = v.y;
            Ksm[(qq*4+2)*72 + n] = v.z; Ksm[(qq*4+3)*72 + n] = v.w;
        }
        #pragma unroll
        for (int c = 0; c < 2; c++) {
            int id = c * 256 + tid;
            int kp = id >> 4, qg = id & 15;
            uint2 a = *(const uint2*)(Vg + (size_t)(t*64 + 2*kp    ) * DH + qg * 4);
            uint2 b = *(const uint2*)(Vg + (size_t)(t*64 + 2*kp + 1) * DH + qg * 4);
            Vsm[kp*72 + qg*4+0] = __byte_perm(a.x, b.x, 0x5410);
            Vsm[kp*72 + qg*4+1] = __byte_perm(a.x, b.x, 0x7632);
            Vsm[kp*72 + qg*4+2] = __byte_perm(a.y, b.y, 0x5410);
            Vsm[kp*72 + qg*4+3] = __byte_perm(a.y, b.y, 0x7632);
        }
        __syncthreads();

        float S[4][2][4];
        #pragma unroll
        for (int a = 0; a < 4; a++)
            #pragma unroll
            for (int b = 0; b < 2; b++)
                #pragma unroll
                for (int r = 0; r < 4; r++) S[a][b][r] = 0.f;
        #pragma unroll
        for (int k2 = 0; k2 < 4; k2++) {
            int kr = k2 * 8 + q4;
            uint32_t af[4][4], bfr[2][2];
            int mr = wm0 + g;
            #pragma unroll
            for (int mt = 0; mt < 4; mt++) {
                af[mt][0] = Qs[kr*136 + mr + mt*16];
                af[mt][1] = Qs[kr*136 + mr + mt*16 + 8];
                af[mt][2] = Qs[(kr+4)*136 + mr + mt*16];
                af[mt][3] = Qs[(kr+4)*136 + mr + mt*16 + 8];
            }
            int nr = wn0 + g;
            #pragma unroll
            for (int nt = 0; nt < 2; nt++) {
                bfr[nt][0] = Ksm[kr*72 + nr + nt*8];
                bfr[nt][1] = Ksm[(kr+4)*72 + nr + nt*8];
            }
            #pragma unroll
            for (int mt = 0; mt < 4; mt++)
                #pragma unroll
                for (int nt = 0; nt < 2; nt++)
                    mma16(S[mt][nt], af[mt], bfr[nt]);
        }

        #pragma unroll
        for (int mt = 0; mt < 4; mt++) {
            float m0v = fmaxf(fmaxf(S[mt][0][0], S[mt][0][1]), fmaxf(S[mt][1][0], S[mt][1][1]));
            float m1v = fmaxf(fmaxf(S[mt][0][2], S[mt][0][3]), fmaxf(S[mt][1][2], S[mt][1][3]));
            #pragma unroll
            for (int o = 1; o < 4; o <<= 1) {
                m0v = fmaxf(m0v, __shfl_xor_sync(~0u, m0v, o));
                m1v = fmaxf(m1v, __shfl_xor_sync(~0u, m1v, o));
            }
            if (q4 == 0) {
                wmax[(wm0 + mt*16 + g)*4 + wn] = m0v;
                wmax[(wm0 + mt*16 + g + 8)*4 + wn] = m1v;
            }
        }
        __syncthreads();

        #pragma unroll
        for (int mt = 0; mt < 4; mt++) {
            int r0 = wm0 + mt*16 + g, r1 = r0 + 8;
            float mo0 = mrun[r0];
            float mt0 = fmaxf(fmaxf(wmax[r0*4+0], wmax[r0*4+1]), fmaxf(wmax[r0*4+2], wmax[r0*4+3]));
            float mn0 = fmaxf(mo0, mt0);
            float sc0 = __expf(mo0 - mn0);
            float mo1 = mrun[r1];
            float mt1 = fmaxf(fmaxf(wmax[r1*4+0], wmax[r1*4+1]), fmaxf(wmax[r1*4+2], wmax[r1*4+3]));
            float mn1 = fmaxf(mo1, mt1);
            float sc1 = __expf(mo1 - mn1);
            float s0 = 0.f, s1 = 0.f;
            #pragma unroll
            for (int nt = 0; nt < 2; nt++) {
                S[mt][nt][0] = __expf(S[mt][nt][0] - mn0);
                S[mt][nt][1] = __expf(S[mt][nt][1] - mn0);
                S[mt][nt][2] = __expf(S[mt][nt][2] - mn1);
                S[mt][nt][3] = __expf(S[mt][nt][3] - mn1);
                s0 += S[mt][nt][0] + S[mt][nt][1];
                s1 += S[mt][nt][2] + S[mt][nt][3];
                int cp = wn * 8 + nt * 4 + q4;
                Ps[cp*136 + r0] = f2bf2(S[mt][nt][0], S[mt][nt][1]);
                Ps[cp*136 + r1] = f2bf2(S[mt][nt][2], S[mt][nt][3]);
                acc[mt][nt][0] *= sc0; acc[mt][nt][1] *= sc0;
                acc[mt][nt][2] *= sc1; acc[mt][nt][3] *= sc1;
            }
            #pragma unroll
            for (int o = 1; o < 4; o <<= 1) {
                s0 += __shfl_xor_sync(~0u, s0, o);
                s1 += __shfl_xor_sync(~0u, s1, o);
            }
            if (q4 == 0) { wsum[r0*4+wn] = s0; wsum[r1*4+wn] = s1; }
        }
        __syncthreads();

        if (tid < 128) {
            float mo = mrun[tid];
            float mt2 = fmaxf(fmaxf(wmax[tid*4+0], wmax[tid*4+1]), fmaxf(wmax[tid*4+2], wmax[tid*4+3]));
            float mn = fmaxf(mo, mt2);
            mrun[tid] = mn;
            lrun[tid] = lrun[tid]*__expf(mo - mn) +
                        wsum[tid*4+0] + wsum[tid*4+1] + wsum[tid*4+2] + wsum[tid*4+3];
        }
        #pragma unroll
        for (int k2 = 0; k2 < 4; k2++) {
            int kr = k2 * 8 + q4;
            uint32_t af[4][4], bfr[2][2];
            int mr = wm0 + g;
            #pragma unroll
            for (int mt = 0; mt < 4; mt++) {
                af[mt][0] = Ps[kr*136 + mr + mt*16];
                af[mt][1] = Ps[kr*136 + mr + mt*16 + 8];
                af[mt][2] = Ps[(kr+4)*136 + mr + mt*16];
                af[mt][3] = Ps[(kr+4)*136 + mr + mt*16 + 8];
            }
            int nr = wn0 + g;
            #pragma unroll
            for (int nt = 0; nt < 2; nt++) {
                bfr[nt][0] = Vsm[kr*72 + nr + nt*8];
                bfr[nt][1] = Vsm[(kr+4)*72 + nr + nt*8];
            }
            #pragma unroll
            for (int mt = 0; mt < 4; mt++)
                #pragma unroll
                for (int nt = 0; nt < 2; nt++)
                    mma16(acc[mt][nt], af[mt], bfr[nt]);
        }
    }
    __syncthreads();

    size_t ob = (size_t)(bh * KS + ksp) * MM + m0;
    #pragma unroll
    for (int mt = 0; mt < 4; mt++) {
        #pragma unroll
        for (int nt = 0; nt < 2; nt++) {
            int r0 = wm0 + mt*16 + g;
            int c = wn0 + nt*8 + q4*2;
            *(float2*)(g_p3 + (ob + r0)*DH + c)     = make_float2(acc[mt][nt][0], acc[mt][nt][1]);
            *(float2*)(g_p3 + (ob + r0 + 8)*DH + c) = make_float2(acc[mt][nt][2], acc[mt][nt][3]);
        }
    }
    if (tid < 128) {
        g_m3[ob + tid] = mrun[tid];
        g_l3[ob + tid] = lrun[tid];
    }
}

__global__ __launch_bounds__(256) void combine3() {
    int warp = threadIdx.x >> 5, lane = threadIdx.x & 31;
    int rowg = blockIdx.x * 8 + warp;
    int bh = rowg >> 8, r = rowg & 255;
    size_t base = (size_t)(bh * KS) * MM + r;
    float mv = (lane < 16) ? g_m3[base + (size_t)lane * MM] : -1e30f;
    #pragma unroll
    for (int o = 16; o; o >>= 1) mv = fmaxf(mv, __shfl_xor_sync(~0u, mv, o));
    float M = mv;
    float lv = (lane < 16) ? g_l3[base + (size_t)lane * MM] *
                             __expf(g_m3[base + (size_t)lane * MM] - M) : 0.f;
    #pragma unroll
    for (int o = 16; o; o >>= 1) lv += __shfl_xor_sync(~0u, lv, o);
    float invL = 1.f / lv;
    float a0 = 0.f, a1 = 0.f;
    for (int kk = 0; kk < KS; kk++) {
        float w = __expf(g_m3[base + (size_t)kk * MM] - M);
        float2 p = *(const float2*)(g_p3 + (base + (size_t)kk * MM) * DH + lane * 2);
        a0 += p.x * w; a1 += p.y * w;
    }
    *(float2*)(g_out3 + ((size_t)bh * MM + r) * DH + lane * 2) =
        make_float2(a0 * invL, a1 * invL);
}

// ---------------------------------------------------------------------------
// TF32 128x128x16 device tile (persistent pinv)
// ---------------------------------------------------------------------------
__device__ __forceinline__ void tc_tile(
    const float* Ab, const float* Bb, float* C, const float* X1,
    int N, int K, int lda, int ldb, long long cbase,
    float alpha, float beta, int m0, int n0,
    uint32_t (*As)[16][136], uint32_t (*Bs)[16][136])
{
    constexpr int BK = 16;
    int tid = threadIdx.x, lane = tid & 31, warp = tid >> 5;
    int wm0 = (warp >> 2) * 64;
    int wn0 = (warp & 3) * 32;
    float4 ra[2], rb[2];
    float acc[4][4][4];
    #pragma unroll
    for (int i = 0; i < 4; i++)
        #pragma unroll
        for (int j = 0; j < 4; j++)
            #pragma unroll
            for (int r = 0; r < 4; r++) acc[i][j][r] = 0.f;

    auto LOAD = [&](int kb) {
        #pragma unroll
        for (int c = 0; c < 2; c++) {
            int id = c * 256 + tid;
            int m = id >> 2, kq = id & 3;
            ra[c] = *(const float4*)(Ab + (size_t)(m0 + m) * lda + kb * BK + kq * 4);
        }
        #pragma unroll
        for (int c = 0; c < 2; c++) {
            int id = c * 256 + tid;
            int k = id >> 5, nq = id & 31;
            rb[c] = *(const float4*)(Bb + (size_t)(kb * BK + k) * ldb + n0 + nq * 4);
        }
    };
    auto COMMIT = [&](int bf) {
        #pragma unroll
        for (int c = 0; c < 2; c++) {
            int id = c * 256 + tid;
            int m = id >> 2, kq = id & 3;
            As[bf][kq*4+0][m] = f2tf(ra[c].x); As[bf][kq*4+1][m] = f2tf(ra[c].y);
            As[bf][kq*4+2][m] = f2tf(ra[c].z); As[bf][kq*4+3][m] = f2tf(ra[c].w);
        }
        #pragma unroll
        for (int c = 0; c < 2; c++) {
            int id = c * 256 + tid;
            int k = id >> 5, nq = id & 31;
            Bs[bf][k][nq*4+0] = f2tf(rb[c].x); Bs[bf][k][nq*4+1] = f2tf(rb[c].y);
            Bs[bf][k][nq*4+2] = f2tf(rb[c].z); Bs[bf][k][nq*4+3] = f2tf(rb[c].w);
        }
    };
    auto MMA = [&](int bf) {
        #pragma unroll
        for (int ks = 0; ks < 2; ks++) {
            uint32_t af[4][4], bfr[4][2];
            int kr = ks * 8 + (lane & 3);
            int mr = wm0 + (lane >> 2);
            #pragma unroll
            for (int mt = 0; mt < 4; mt++) {
                af[mt][0] = As[bf][kr    ][mr + mt*16];
                af[mt][1] = As[bf][kr    ][mr + mt*16 + 8];
                af[mt][2] = As[bf][kr + 4][mr + mt*16];
                af[mt][3] = As[bf][kr + 4][mr + mt*16 + 8];
            }
            int nr = wn0 + (lane >> 2);
            #pragma unroll
            for (int nt = 0; nt < 4; nt++) {
                bfr[nt][0] = Bs[bf][kr    ][nr + nt*8];
                bfr[nt][1] = Bs[bf][kr + 4][nr + nt*8];
            }
            #pragma unroll
            for (int mt = 0; mt < 4; mt++)
                #pragma unroll
                for (int nt = 0; nt < 4; nt++)
                    mma8(acc[mt][nt], af[mt], bfr[nt]);
        }
    };

    int nk = K / BK;
    LOAD(0); COMMIT(0);
    __syncthreads();
    for (int kb = 1; kb < nk; kb++) {
        LOAD(kb);
        MMA((kb - 1) & 1);
        COMMIT(kb & 1);
        __syncthreads();
    }
    MMA((nk - 1) & 1);

    #pragma unroll
    for (int mt = 0; mt < 4; mt++) {
        #pragma unroll
        for (int nt = 0; nt < 4; nt++) {
            int row = m0 + wm0 + mt * 16 + (lane >> 2);
            int col = n0 + wn0 + nt * 8 + (lane & 3) * 2;
            size_t r1 = cbase + (size_t)row * N + col;
            size_t r2 = cbase + (size_t)(row + 8) * N + col;
            float2 lo = make_float2(acc[mt][nt][0], acc[mt][nt][1]);
            float2 hi = make_float2(acc[mt][nt][2], acc[mt][nt][3]);
            float2 rv1 = make_float2(0.f, 0.f), rv2 = make_float2(0.f, 0.f);
            if (beta != 0.f) {
                rv1 = *(const float2*)(X1 + r1);
                rv2 = *(const float2*)(X1 + r2);
            }
            *(float2*)(C + r1) = make_float2(alpha*lo.x + beta*rv1.x, alpha*lo.y + beta*rv1.y);
            *(float2*)(C + r2) = make_float2(alpha*hi.x + beta*rv2.x, alpha*hi.y + beta*rv2.y);
        }
    }
}

// per-bh barrier: only the 4 blocks of this bh must arrive
__device__ __forceinline__ void gridbar(int bh, int i) {
    __syncthreads();
    if (threadIdx.x == 0) {
        int idx = bh * 24 + i;
        __threadfence();
        atomicAdd(&g_barc[idx], 1);
        while (((volatile int*)g_barc)[idx] < 4) { }
        __threadfence();
    }
    __syncthreads();
}

// 6 tf32 Newton-Schulz iterations; after 6 ping-pong swaps result is in g_z
__global__ __launch_bounds__(256) void pinv_iters() {
    __shared__ uint32_t As[2][16][136];
    __shared__ uint32_t Bs[2][16][136];
    int m0 = blockIdx.y * 128, n0 = blockIdx.x * 128;
    int bh = blockIdx.z;
    long long base = (long long)bh * (MM * MM);
    float* zc = g_z;
    float* zn = g_z2;
    int bi = 0;
    #pragma unroll 1
    for (int it = 0; it < 6; it++) {
        tc_tile(g_attn2 + base, zc + base, g_xz, nullptr, MM, MM, MM, MM, base,
                1.f, 0.f, m0, n0, As, Bs);
        gridbar(bh, bi++);
        tc_tile(g_xz + base, g_xz + base, g_t, g_xz, MM, MM, MM, MM, base,
                -1.f, 7.f, m0, n0, As, Bs);
        gridbar(bh, bi++);
        tc_tile(g_xz + base, g_t + base, g_u, g_xz, MM, MM, MM, MM, base,
                -1.f, 15.f, m0, n0, As, Bs);
        gridbar(bh, bi++);
        tc_tile(zc + base, g_u + base, zn, zc, MM, MM, MM, MM, base,
                -0.25f, 3.25f, m0, n0, As, Bs);
        if (it < 5) gridbar(bh, bi++);
        float* tmp = zc; zc = zn; zn = tmp;
    }
}

// Wc = z_final(g_z) @ out3, tf32
__global__ __launch_bounds__(256) void wc_gemm() {
    __shared__ uint32_t As[2][16][136];
    __shared__ uint32_t Bs[2][16][136];
    constexpr int BK = 16;
    int tid = threadIdx.x, lane = tid & 31, warp = tid >> 5;
    int wm0 = (warp >> 2) * 64;
    int wn0 = (warp & 3) * 16;
    int m0 = blockIdx.y * 128;
    long long abase = (long long)blockIdx.z * (MM * MM);
    long long cbase = (long long)blockIdx.z * (MM * DH);
    const float* Ab = g_z + abase;
    const float* Bb = g_out3 + cbase;
    float4 ra[2];
    float4 rb;
    float acc[4][2][4];
    #pragma unroll
    for (int i = 0; i < 4; i++)
        #pragma unroll
        for (int j = 0; j < 2; j++)
            #pragma unroll
            for (int r = 0; r < 4; r++) acc[i][j][r] = 0.f;

    auto LOAD = [&](int kb) {
        #pragma unroll
        for (int c = 0; c < 2; c++) {
            int id = c * 256 + tid;
            int m = id >> 2, kq = id & 3;
            ra[c] = *(const float4*)(Ab + (size_t)(m0 + m) * MM + kb * BK + kq * 4);
        }
        {
            int k = tid >> 4, nq = tid & 15;
            rb = *(const float4*)(Bb + (size_t)(kb * BK + k) * DH + nq * 4);
        }
    };
    auto COMMIT = [&](int bf) {
        #pragma unroll
        for (int c = 0; c < 2; c++) {
            int id = c * 256 + tid;
            int m = id >> 2, kq = id & 3;
            As[bf][kq*4+0][m] = f2tf(ra[c].x); As[bf][kq*4+1][m] = f2tf(ra[c].y);
            As[bf][kq*4+2][m] = f2tf(ra[c].z); As[bf][kq*4+3][m] = f2tf(ra[c].w);
        }
        {
            int k = tid >> 4, nq = tid & 15;
            Bs[bf][k][nq*4+0] = f2tf(rb.x); Bs[bf][k][nq*4+1] = f2tf(rb.y);
            Bs[bf][k][nq*4+2] = f2tf(rb.z); Bs[bf][k][nq*4+3] = f2tf(rb.w);
        }
    };
    auto MMA = [&](int bf) {
        #pragma unroll
        for (int ks = 0; ks < 2; ks++) {
            uint32_t af[4][4], bfr[2][2];
            int kr = ks * 8 + (lane & 3);
            int mr = wm0 + (lane >> 2);
            #pragma unroll
            for (int mt = 0; mt < 4; mt++) {
                af[mt][0] = As[bf][kr    ][mr + mt*16];
                af[mt][1] = As[bf][kr    ][mr + mt*16 + 8];
                af[mt][2] = As[bf][kr + 4][mr + mt*16];
                af[mt][3] = As[bf][kr + 4][mr + mt*16 + 8];
            }
            int nr = wn0 + (lane >> 2);
            #pragma unroll
            for (int nt = 0; nt < 2; nt++) {
                bfr[nt][0] = Bs[bf][kr    ][nr + nt*8];
                bfr[nt][1] = Bs[bf][kr + 4][nr + nt*8];
            }
            #pragma unroll
            for (int mt = 0; mt < 4; mt++)
                #pragma unroll
                for (int nt = 0; nt < 2; nt++)
                    mma8(acc[mt][nt], af[mt], bfr[nt]);
        }
    };

    LOAD(0); COMMIT(0);
    __syncthreads();
    for (int kb = 1; kb < 16; kb++) {
        LOAD(kb);
        MMA((kb - 1) & 1);
        COMMIT(kb & 1);
        __syncthreads();
    }
    MMA(1);

    #pragma unroll
    for (int mt = 0; mt < 4; mt++) {
        #pragma unroll
        for (int nt = 0; nt < 2; nt++) {
            int row = m0 + wm0 + mt * 16 + (lane >> 2);
            int col = wn0 + nt * 8 + (lane & 3) * 2;
            *(float2*)(g_wc + cbase + (size_t)row * DH + col) =
                make_float2(acc[mt][nt][0], acc[mt][nt][1]);
            *(float2*)(g_wc + cbase + (size_t)(row + 8) * DH + col) =
                make_float2(acc[mt][nt][2], acc[mt][nt][3]);
        }
    }
}

// ---------------------------------------------------------------------------
// BF16 GEMM, A operand bf16 in gmem. EPI0: QKV scatter; EPI1: out+bias+x
// ---------------------------------------------------------------------------
template<int EPI, int BM, int BN, int BK>
__global__ __launch_bounds__(256) void bf_gemm(
    const __nv_bfloat16* __restrict__ Ah, const float* __restrict__ Bg,
    float* __restrict__ C, const float* __restrict__ X1, const float* __restrict__ X2,
    int N, int K, int lda, int ldb)
{
    constexpr int PA = BM + 8, PB = BN + 8;
    constexpr int MT = (BM / 2) / 16;
    constexpr int NT = (BN / 4) / 8;
    constexpr int KP = BK / 2;
    constexpr int RAH = (BM * BK) / 2048;
    constexpr int RBN = (KP * (BN / 4)) / 256;
    __shared__ uint32_t As[2][KP][PA];
    __shared__ uint32_t Bs[2][KP][PB];
    uint4  rah[RAH];
    float4 rb0[RBN], rb1[RBN];

    int tid = threadIdx.x, lane = tid & 31, warp = tid >> 5;
    int wm0 = (warp >> 2) * (BM / 2);
    int wn0 = (warp & 3) * (BN / 4);
    int m0 = blockIdx.y * BM, n0 = blockIdx.x * BN;

    float acc[MT][NT][4];
    #pragma unroll
    for (int i = 0; i < MT; i++)
        #pragma unroll
        for (int j = 0; j < NT; j++)
            #pragma unroll
            for (int r = 0; r < 4; r++) acc[i][j][r] = 0.f;

    auto LOAD = [&](int kb) {
        #pragma unroll
        for (int c = 0; c < RAH; c++) {
            int id = c * 256 + tid;
            int m = id / (BK / 8), kq = id % (BK / 8);
            rah[c] = *(const uint4*)(Ah + (size_t)(m0 + m) * lda + kb * BK + kq * 8);
        }
        #pragma unroll
        for (int c = 0; c < RBN; c++) {
            int id = c * 256 + tid;
            int kp = id / (BN / 4), nq = id % (BN / 4);
            rb0[c] = *(const float4*)(Bg + (size_t)(kb*BK + 2*kp    ) * ldb + n0 + nq * 4);
            rb1[c] = *(const float4*)(Bg + (size_t)(kb*BK + 2*kp + 1) * ldb + n0 + nq * 4);
        }
    };
    auto COMMIT = [&](int bf) {
        #pragma unroll
        for (int c = 0; c < RAH; c++) {
            int id = c * 256 + tid;
            int m = id / (BK / 8), kq = id % (BK / 8);
            As[bf][kq*4+0][m] = rah[c].x; As[bf][kq*4+1][m] = rah[c].y;
            As[bf][kq*4+2][m] = rah[c].z; As[bf][kq*4+3][m] = rah[c].w;
        }
        #pragma unroll
        for (int c = 0; c < RBN; c++) {
            int id = c * 256 + tid;
            int kp = id / (BN / 4), nq = id % (BN / 4);
            Bs[bf][kp][nq*4+0] = f2bf2(rb0[c].x, rb1[c].x);
            Bs[bf][kp][nq*4+1] = f2bf2(rb0[c].y, rb1[c].y);
            Bs[bf][kp][nq*4+2] = f2bf2(rb0[c].z, rb1[c].z);
            Bs[bf][kp][nq*4+3] = f2bf2(rb0[c].w, rb1[c].w);
        }
    };
    auto MMA = [&](int bf) {
        #pragma unroll
        for (int ks = 0; ks < BK / 16; ks++) {
            uint32_t af[MT][4], bfr[NT][2];
            int kr = ks * 8 + (lane & 3);
            int mr = wm0 + (lane >> 2);
            #pragma unroll
            for (int mt = 0; mt < MT; mt++) {
                af[mt][0] = As[bf][kr    ][mr + mt*16];
                af[mt][1] = As[bf][kr    ][mr + mt*16 + 8];
                af[mt][2] = As[bf][kr + 4][mr + mt*16];
                af[mt][3] = As[bf][kr + 4][mr + mt*16 + 8];
            }
            int nr = wn0 + (lane >> 2);
            #pragma unroll
            for (int nt = 0; nt < NT; nt++) {
                bfr[nt][0] = Bs[bf][kr    ][nr + nt*8];
                bfr[nt][1] = Bs[bf][kr + 4][nr + nt*8];
            }
            #pragma unroll
            for (int mt = 0; mt < MT; mt++)
                #pragma unroll
                for (int nt = 0; nt < NT; nt++)
                    mma16(acc[mt][nt], af[mt], bfr[nt]);
        }
    };

    int nk = K / BK;
    LOAD(0); COMMIT(0);
    __syncthreads();
    for (int kb = 1; kb < nk; kb++) {
        LOAD(kb);
        MMA((kb - 1) & 1);
        COMMIT(kb & 1);
        __syncthreads();
    }
    MMA((nk - 1) & 1);

    #pragma unroll
    for (int mt = 0; mt < MT; mt++) {
        #pragma unroll
        for (int nt = 0; nt < NT; nt++) {
            int row = m0 + wm0 + mt * 16 + (lane >> 2);
            int col = n0 + wn0 + nt * 8 + (lane & 3) * 2;
            float2 lo = make_float2(acc[mt][nt][0], acc[mt][nt][1]);
            float2 hi = make_float2(acc[mt][nt][2], acc[mt][nt][3]);
            if constexpr (EPI == 0) {
                int which = col >> 9, inner = col & 511;
                int h = inner >> 6, d = inner & 63;
                __nv_bfloat16* dst = which == 0 ? g_qh : (which == 1 ? g_kh : g_vh);
                float s = (which == 0) ? 0.125f : 1.f;
                int bq = row >> 13, n = row & (NN - 1);
                *(uint32_t*)(dst + (((size_t)(bq*HH+h))*NN + n    )*DH + d) = f2bf2(lo.x*s, lo.y*s);
                *(uint32_t*)(dst + (((size_t)(bq*HH+h))*NN + n + 8)*DH + d) = f2bf2(hi.x*s, hi.y*s);
            } else if constexpr (EPI == 1) {
                float2 bv = *(const float2*)(X1 + col);
                size_t r1 = (size_t)row * DD + col, r2 = (size_t)(row + 8) * DD + col;
                float2 x1 = *(const float2*)(X2 + r1);
                float2 x2 = *(const float2*)(X2 + r2);
                *(float2*)(C + r1) = make_float2(lo.x + bv.x + x1.x, lo.y + bv.y + x1.y);
                *(float2*)(C + r2) = make_float2(hi.x + bv.x + x2.x, hi.y + bv.y + x2.y);
            }
        }
    }
}

// ---------------------------------------------------------------------------
// Fused attn1 + depthwise conv: y(bf16) = conv33(v) + softmax(q @ kl^T) @ Wc
// ---------------------------------------------------------------------------
__global__ __launch_bounds__(256) void attn1_fused(const float* __restrict__ res_w) {
    extern __shared__ char smraw[];
    uint32_t* As  = (uint32_t*)smraw;
    uint32_t* Bs  = As + 16*72;
    uint32_t* Ps  = Bs + 16*264;
    uint32_t* Wcs = Ps + 128*72;
    float* rmax = (float*)(Wcs + 128*72);
    float* rsum = rmax + 320;
    float* sw   = rsum + 320;
    uint32_t* Vw = As;

    int tid = threadIdx.x, lane = tid & 31, warp = tid >> 5;
    int g = lane >> 2, q4 = lane & 3;
    int bh = blockIdx.y;
    int b = bh >> 3, h = bh & 7;
    int m0 = blockIdx.x * 64;
    const __nv_bfloat16* Ab = g_qh + ((size_t)bh * NN + m0) * DH;
    const float* Bb = g_kl + (size_t)bh * MM * DH;
    const float* Wg = g_wc + (size_t)bh * MM * DH;
    const __nv_bfloat16* vb = g_vh + (size_t)bh * NN * DH;

    if (tid < 33) sw[tid] = res_w[h * 33 + tid];

    #pragma unroll
    for (int c = 0; c < 8; c++) {
        int id = c * 256 + tid;
        int kp = id >> 4, n4 = id & 15;
        float4 lo = *(const float4*)(Wg + (size_t)(2*kp    ) * DH + n4 * 4);
        float4 hi = *(const float4*)(Wg + (size_t)(2*kp + 1) * DH + n4 * 4);
        Wcs[kp*72 + n4*4+0] = f2bf2(lo.x, hi.x);
        Wcs[kp*72 + n4*4+1] = f2bf2(lo.y, hi.y);
        Wcs[kp*72 + n4*4+2] = f2bf2(lo.z, hi.z);
        Wcs[kp*72 + n4*4+3] = f2bf2(lo.w, hi.w);
    }

    int wm0q = (warp >> 2) * 32;
    int wn0q = (warp & 3) * 64;
    int wnq = warp & 3;
    float acc[2][8][4];
    #pragma unroll
    for (int i = 0; i < 2; i++)
        #pragma unroll
        for (int j = 0; j < 8; j++)
            #pragma unroll
            for (int r = 0; r < 4; r++) acc[i][j][r] = 0.f;

    for (int k0 = 0; k0 < 64; k0 += 32) {
        {
            int m = tid >> 2, kq = tid & 3;
            uint4 v = *(const uint4*)(Ab + (size_t)m * DH + k0 + kq * 8);
            As[(kq*4+0)*72 + m] = v.x; As[(kq*4+1)*72 + m] = v.y;
            As[(kq*4+2)*72 + m] = v.z; As[(kq*4+3)*72 + m] = v.w;
        }
        #pragma unroll
        for (int c = 0; c < 8; c++) {
            int id = c * 256 + tid;
            int n = id >> 3, kq = id & 7;
            float4 v = *(const float4*)(Bb + (size_t)n * DH + k0 + kq * 4);
            Bs[(kq*2+0)*264 + n] = f2bf2(v.x, v.y);
            Bs[(kq*2+1)*264 + n] = f2bf2(v.z, v.w);
        }
        __syncthreads();
        #pragma unroll
        for (int ks = 0; ks < 2; ks++) {
            uint32_t af[2][4], bfr[8][2];
            int kr = ks * 8 + q4;
            int mr = wm0q + g;
            #pragma unroll
            for (int mt = 0; mt < 2; mt++) {
                af[mt][0] = As[kr*72 + mr + mt*16];
                af[mt][1] = As[kr*72 + mr + mt*16 + 8];
                af[mt][2] = As[(kr+4)*72 + mr + mt*16];
                af[mt][3] = As[(kr+4)*72 + mr + mt*16 + 8];
            }
            int nr = wn0q + g;
            #pragma unroll
            for (int nt = 0; nt < 8; nt++) {
                bfr[nt][0] = Bs[kr*264 + nr + nt*8];
                bfr[nt][1] = Bs[(kr+4)*264 + nr + nt*8];
            }
            #pragma unroll
            for (int mt = 0; mt < 2; mt++)
                #pragma unroll
                for (int nt = 0; nt < 8; nt++)
                    mma16(acc[mt][nt], af[mt], bfr[nt]);
        }
        __syncthreads();
    }

    #pragma unroll
    for (int c = 0; c < 6; c++) {
        int id = c * 256 + tid;
        int row = id >> 4, up = id & 15;
        int tok = m0 - 16 + row;
        uint2 u = make_uint2(0u, 0u);
        if (tok >= 0 && tok < NN)
            u = *(const uint2*)(vb + (size_t)tok * DH + up * 4);
        Vw[row*33 + up*2]     = u.x;
        Vw[row*33 + up*2 + 1] = u.y;
    }

    #pragma unroll
    for (int mt = 0; mt < 2; mt++) {
        int r0 = wm0q + mt * 16 + g;
        float m0v = -1e30f, m1v = -1e30f;
        #pragma unroll
        for (int nt = 0; nt < 8; nt++) {
            m0v = fmaxf(m0v, fmaxf(acc[mt][nt][0], acc[mt][nt][1]));
            m1v = fmaxf(m1v, fmaxf(acc[mt][nt][2], acc[mt][nt][3]));
        }
        #pragma unroll
        for (int o = 1; o < 4; o <<= 1) {
            m0v = fmaxf(m0v, __shfl_xor_sync(~0u, m0v, o));
            m1v = fmaxf(m1v, __shfl_xor_sync(~0u, m1v, o));
        }
        if (q4 == 0) { rmax[r0*5 + wnq] = m0v; rmax[(r0+8)*5 + wnq] = m1v; }
    }
    __syncthreads();
    #pragma unroll
    for (int mt = 0; mt < 2; mt++) {
        int r0 = wm0q + mt * 16 + g;
        float M0 = fmaxf(fmaxf(rmax[r0*5+0], rmax[r0*5+1]), fmaxf(rmax[r0*5+2], rmax[r0*5+3]));
        float M1 = fmaxf(fmaxf(rmax[(r0+8)*5+0], rmax[(r0+8)*5+1]),
                         fmaxf(rmax[(r0+8)*5+2], rmax[(r0+8)*5+3]));
        float s0 = 0.f, s1 = 0.f;
        #pragma unroll
        for (int nt = 0; nt < 8; nt++) {
            acc[mt][nt][0] = __expf(acc[mt][nt][0] - M0);
            acc[mt][nt][1] = __expf(acc[mt][nt][1] - M0);
            acc[mt][nt][2] = __expf(acc[mt][nt][2] - M1);
            acc[mt][nt][3] = __expf(acc[mt][nt][3] - M1);
            s0 += acc[mt][nt][0] + acc[mt][nt][1];
            s1 += acc[mt][nt][2] + acc[mt][nt][3];
        }
        #pragma unroll
        for (int o = 1; o < 4; o <<= 1) {
            s0 += __shfl_xor_sync(~0u, s0, o);
            s1 += __shfl_xor_sync(~0u, s1, o);
        }
        if (q4 == 0) { rsum[r0*5 + wnq] = s0; rsum[(r0+8)*5 + wnq] = s1; }
    }
    __syncthreads();
    #pragma unroll
    for (int mt = 0; mt < 2; mt++) {
        int r0 = wm0q + mt * 16 + g, r1 = r0 + 8;
        float i0 = 1.f / (rsum[r0*5+0] + rsum[r0*5+1] + rsum[r0*5+2] + rsum[r0*5+3]);
        float i1 = 1.f / (rsum[r1*5+0] + rsum[r1*5+1] + rsum[r1*5+2] + rsum[r1*5+3]);
        #pragma unroll
        for (int nt = 0; nt < 8; nt++) {
            int kp = (wn0q >> 1) + nt * 4 + q4;
            Ps[kp*72 + r0] = f2bf2(acc[mt][nt][0] * i0, acc[mt][nt][1] * i0);
            Ps[kp*72 + r1] = f2bf2(acc[mt][nt][2] * i1, acc[mt][nt][3] * i1);
        }
    }
    __syncthreads();

    int wm0p = (warp >> 2) * 32;
    int wn0p = (warp & 3) * 16;
    float yacc[2][2][4];
    #pragma unroll
    for (int i = 0; i < 2; i++)
        #pragma unroll
        for (int j = 0; j < 2; j++)
            #pragma unroll
            for (int r = 0; r < 4; r++) yacc[i][j][r] = 0.f;
    #pragma unroll
    for (int kc = 0; kc < 16; kc++) {
        int kr = kc * 8 + q4;
        uint32_t af[2][4], bfr[2][2];
        int mr = wm0p + g;
        #pragma unroll
        for (int mt = 0; mt < 2; mt++) {
            af[mt][0] = Ps[kr*72 + mr + mt*16];
            af[mt][1] = Ps[kr*72 + mr + mt*16 + 8];
            af[mt][2] = Ps[(kr+4)*72 + mr + mt*16];
            af[mt][3] = Ps[(kr+4)*72 + mr + mt*16 + 8];
        }
        int nr = wn0p + g;
        #pragma unroll
        for (int nt = 0; nt < 2; nt++) {
            bfr[nt][0] = Wcs[kr*72 + nr + nt*8];
            bfr[nt][1] = Wcs[(kr+4)*72 + nr + nt*8];
        }
        #pragma unroll
        for (int mt = 0; mt < 2; mt++)
            #pragma unroll
            for (int nt = 0; nt < 2; nt++)
                mma16(yacc[mt][nt], af[mt], bfr[nt]);
    }
    #pragma unroll
    for (int mt = 0; mt < 2; mt++) {
        #pragma unroll
        for (int nt = 0; nt < 2; nt++) {
            int rl = wm0p + mt * 16 + g;
            int col = wn0p + nt * 8 + q4 * 2;
            int cp = col >> 1;
            float c00 = 0.f, c01 = 0.f, c10 = 0.f, c11 = 0.f;
            #pragma unroll
            for (int j = 0; j < 33; j++) {
                float w = sw[j];
                float2 f0 = __bfloat1622float2(
                    *(const __nv_bfloat162*)&Vw[(rl + j) * 33 + cp]);
                float2 f1 = __bfloat1622float2(
                    *(const __nv_bfloat162*)&Vw[(rl + 8 + j) * 33 + cp]);
                c00 += w * f0.x; c01 += w * f0.y;
                c10 += w * f1.x; c11 += w * f1.y;
            }
            int row = m0 + rl;
            size_t r1 = ((size_t)b * NN + row    ) * DD + h * 64 + col;
            size_t r2 = ((size_t)b * NN + row + 8) * DD + h * 64 + col;
            *(uint32_t*)(g_yh + r1) = f2bf2(c00 + yacc[mt][nt][0], c01 + yacc[mt][nt][1]);
            *(uint32_t*)(g_yh + r2) = f2bf2(c10 + yacc[mt][nt][2], c11 + yacc[mt][nt][3]);
        }
    }
}

// ---------------------------------------------------------------------------
// LN (bf16 out) / landmarks / sim2 / softmax256 / init / colrowmax / z0
// ---------------------------------------------------------------------------
__global__ __launch_bounds__(128) void ln_kernel(const float* __restrict__ x,
                                                 const float* __restrict__ w,
                                                 const float* __restrict__ bia) {
    int row = blockIdx.x, tid = threadIdx.x;
    const float4* xr = reinterpret_cast<const float4*>(x + (size_t)row * DD);
    float4 v = xr[tid];
    float s  = v.x + v.y + v.z + v.w;
    float sq = v.x*v.x + v.y*v.y + v.z*v.z + v.w*v.w;
    __shared__ float sm[4], sm2[4];
    #pragma unroll
    for (int o = 16; o > 0; o >>= 1) {
        s  += __shfl_down_sync(0xffffffffu, s,  o);
        sq += __shfl_down_sync(0xffffffffu, sq, o);
    }
    if ((tid & 31) == 0) { sm[tid >> 5] = s; sm2[tid >> 5] = sq; }
    __syncthreads();
    if (tid == 0) {
        float a = 0.f, b2 = 0.f;
        #pragma unroll
        for (int i = 0; i < 4; i++) { a += sm[i]; b2 += sm2[i]; }
        sm[0] = a; sm2[0] = b2;
    }
    __syncthreads();
    float mean = sm[0] * (1.f / 512.f);
    float var  = sm2[0] * (1.f / 512.f) - mean * mean;
    float rstd = rsqrtf(var + 1e-5f);
    float4 wv = reinterpret_cast<const float4*>(w)[tid];
    float4 bv = reinterpret_cast<const float4*>(bia)[tid];
    float ox = (v.x - mean) * rstd * wv.x + bv.x;
    float oy = (v.y - mean) * rstd * wv.y + bv.y;
    float oz = (v.z - mean) * rstd * wv.z + bv.z;
    float ow = (v.w - mean) * rstd * wv.w + bv.w;
    *(uint2*)(g_xh + (size_t)row * DD + tid * 4) =
        make_uint2(f2bf2(ox, oy), f2bf2(oz, ow));
}

__global__ void landmark_kernel() {
    int m = blockIdx.x, bh = blockIdx.y;
    int d = threadIdx.x;
    size_t base = ((size_t)bh * NN + (size_t)m * 32) * DH + d;
    float sq = 0.f, sk = 0.f;
    #pragma unroll
    for (int j = 0; j < 32; j++) {
        sq += __bfloat162float(g_qh[base + (size_t)j * DH]);
        sk += __bfloat162float(g_kh[base + (size_t)j * DH]);
    }
    size_t o = ((size_t)bh * MM + m) * DH + d;
    g_ql[o] = sq * (1.f / 32.f);
    g_kl[o] = sk * (1.f / 32.f);
}

__global__ __launch_bounds__(256) void gemm_sim2() {
    __shared__ float As[32][132];
    __shared__ float Bs[32][132];
    int bh = blockIdx.z;
    int n0 = blockIdx.x * 128, m0 = blockIdx.y * 128;
    const float* Ab = g_ql + ((size_t)bh * MM + m0) * DH;
    const float* Bb = g_kl + ((size_t)bh * MM + n0) * DH;
    float* Cb = g_attn2 + (size_t)bh * MM * MM;
    int tid = threadIdx.x;
    int tx = tid & 15, ty = tid >> 4;
    float acc[8][8] = {};
    for (int kk = 0; kk < 64; kk += 32) {
        #pragma unroll
        for (int u = 0; u < 4; u++) {
            int g = u * 256 + tid;
            int m = g >> 3, k4 = g & 7;
            float4 av = *(const float4*)(Ab + (size_t)m * DH + kk + k4 * 4);
            As[k4*4+0][m] = av.x; As[k4*4+1][m] = av.y;
            As[k4*4+2][m] = av.z; As[k4*4+3][m] = av.w;
        }
        #pragma unroll
        for (int u = 0; u < 4; u++) {
            int g = u * 256 + tid;
            int m = g >> 3, k4 = g & 7;
            float4 bv = *(const float4*)(Bb + (size_t)m * DH + kk + k4 * 4);
            Bs[k4*4+0][m] = bv.x; Bs[k4*4+1][m] = bv.y;
            Bs[k4*4+2][m] = bv.z; Bs[k4*4+3][m] = bv.w;
        }
        __syncthreads();
        #pragma unroll
        for (int k = 0; k < 32; k++) {
            float a[8], b[8];
            *(float4*)&a[0] = *(const float4*)&As[k][ty*8];
            *(float4*)&a[4] = *(const float4*)&As[k][ty*8+4];
            *(float4*)&b[0] = *(const float4*)&Bs[k][tx*8];
            *(float4*)&b[4] = *(const float4*)&Bs[k][tx*8+4];
            #pragma unroll
            for (int i = 0; i < 8; i++)
                #pragma unroll
                for (int j = 0; j < 8; j++)
                    acc[i][j] += a[i] * b[j];
        }
        __syncthreads();
    }
    #pragma unroll
    for (int i = 0; i < 8; i++) {
        size_t r = (size_t)(m0 + ty * 8 + i) * MM + n0 + tx * 8;
        *(float4*)(Cb + r)     = make_float4(acc[i][0], acc[i][1], acc[i][2], acc[i][3]);
        *(float4*)(Cb + r + 4) = make_float4(acc[i][4], acc[i][5], acc[i][6], acc[i][7]);
    }
}

__global__ __launch_bounds__(256) void softmax256() {
    int row = blockIdx.x, tid = threadIdx.x;
    float* p = g_attn2 + (size_t)row * MM;
    float v = p[tid];
    __shared__ float red[8];
    float m = v;
    #pragma unroll
    for (int o = 16; o; o >>= 1) m = fmaxf(m, __shfl_xor_sync(~0u, m, o));
    if ((tid & 31) == 0) red[tid >> 5] = m;
    __syncthreads();
    if (tid < 32) {
        float t = (tid < 8) ? red[tid] : -1e30f;
        #pragma unroll
        for (int o = 4; o; o >>= 1) t = fmaxf(t, __shfl_xor_sync(~0u, t, o));
        if (tid == 0) red[0] = t;
    }
    __syncthreads();
    float mx = red[0];
    __syncthreads();
    float e = __expf(v - mx);
    float s = e;
    #pragma unroll
    for (int o = 16; o; o >>= 1) s += __shfl_xor_sync(~0u, s, o);
    if ((tid & 31) == 0) red[tid >> 5] = s;
    __syncthreads();
    if (tid < 32) {
        float t = (tid < 8) ? red[tid] : 0.f;
        #pragma unroll
        for (int o = 4; o; o >>= 1) t += __shfl_xor_sync(~0u, t, o);
        if (tid == 0) red[0] = t;
    }
    __syncthreads();
    p[tid] = e / red[0];
}

__global__ void init_kernel() {
    g_maxA = 0; g_maxB = 0;
    for (int i = threadIdx.x; i < BH * 24; i += 256) g_barc[i] = 0;
}

__global__ __launch_bounds__(256) void colrowmax_kernel() {
    int bh = blockIdx.x, tid = threadIdx.x;
    const float* a = g_attn2 + (size_t)bh * MM * MM;
    float cs = 0.f, rs = 0.f;
    for (int m = 0; m < MM; m++) cs += fabsf(a[(size_t)m * MM + tid]);
    for (int n = 0; n < MM; n++) rs += fabsf(a[(size_t)tid * MM + n]);
    __shared__ float r1[8], r2[8];
    #pragma unroll
    for (int o = 16; o; o >>= 1) {
        cs = fmaxf(cs, __shfl_xor_sync(~0u, cs, o));
        rs = fmaxf(rs, __shfl_xor_sync(~0u, rs, o));
    }
    if ((tid & 31) == 0) { r1[tid >> 5] = cs; r2[tid >> 5] = rs; }
    __syncthreads();
    if (tid == 0) {
        float a1 = r1[0], a2 = r2[0];
        #pragma unroll
        for (int i = 1; i < 8; i++) { a1 = fmaxf(a1, r1[i]); a2 = fmaxf(a2, r2[i]); }
        atomicMax(&g_maxA, __float_as_int(a1));
        atomicMax(&g_maxB, __float_as_int(a2));
    }
}

__global__ __launch_bounds__(256) void z0_kernel() {
    int bh = blockIdx.z;
    int c0 = blockIdx.x * 32, r0 = blockIdx.y * 32;
    int tid = threadIdx.x;
    __shared__ float t[32][33];
    const float* a = g_attn2 + (size_t)bh * MM * MM;
    #pragma unroll
    for (int rr = 0; rr < 4; rr++) {
        int r = rr * 8 + (tid >> 5), c = tid & 31;
        t[r][c] = a[(size_t)(r0 + r) * MM + c0 + c];
    }
    __syncthreads();
    float s = 1.f / (__int_as_float(g_maxA) * __int_as_float(g_maxB));
    float* z = g_z + (size_t)bh * MM * MM;
    #pragma unroll
    for (int rr = 0; rr < 4; rr++) {
        int r = rr * 8 + (tid >> 5), c = tid & 31;
        z[(size_t)(c0 + r) * MM + r0 + c] = t[c][r] * s;
    }
}

// ---------------------------------------------------------------------------
// Launch: fork attn3 chain (flash3+combine3) onto side stream, join before wc
// ---------------------------------------------------------------------------
extern "C" void kernel_launch(void* const* d_in, const int* in_sizes, int n_in,
                              void* d_out, int out_size) {
    const float* x     = (const float*)d_in[0];
    const float* ln_w  = (const float*)d_in[1];
    const float* ln_b  = (const float*)d_in[2];
    const float* w_qkv = (const float*)d_in[3];
    const float* w_out = (const float*)d_in[4];
    const float* b_out = (const float*)d_in[5];
    const float* res_w = (const float*)d_in[6];
    float* out = (float*)d_out;

    __nv_bfloat16 *p_xh, *p_yh;
    cudaGetSymbolAddress((void**)&p_xh, g_xh);
    cudaGetSymbolAddress((void**)&p_yh, g_yh);

    cudaFuncSetAttribute(flash3, cudaFuncAttributeMaxDynamicSharedMemorySize, 58368);
    cudaFuncSetAttribute(attn1_fused, cudaFuncAttributeMaxDynamicSharedMemorySize, 98304);

    ln_kernel<<<BB * NN, 128>>>(x, ln_w, ln_b);
    bf_gemm<0,128,128,32><<<dim3(12, 256, 1), 256>>>(
        p_xh, w_qkv, nullptr, nullptr, nullptr, 1536, 512, 512, 1536);
    landmark_kernel<<<dim3(MM, BH), 64>>>();

    // fork: attn3 chain on side stream (needs only ql/kh/vh)
    cudaEventRecord(g_e1, 0);
    cudaStreamWaitEvent(g_s2, g_e1, 0);
    flash3<<<dim3(2, KS, BH), 256, 58368, g_s2>>>();
    combine3<<<1024, 256, 0, g_s2>>>();
    cudaEventRecord(g_e2, g_s2);

    // main: pinv chain
    gemm_sim2<<<dim3(2, 2, BH), 256>>>();
    softmax256<<<BH * MM, 256>>>();
    init_kernel<<<1, 256>>>();
    colrowmax_kernel<<<BH, 256>>>();
    z0_kernel<<<dim3(8, 8, BH), 256>>>();
    pinv_iters<<<dim3(2, 2, BH), 256>>>();

    // join: wc needs z (main) + out3 (side)
    cudaStreamWaitEvent(0, g_e2, 0);
    wc_gemm<<<dim3(1, 2, BH), 256>>>();

    attn1_fused<<<dim3(128, BH), 256, 98304>>>(res_w);

    bf_gemm<1,128,128,32><<<dim3(4, 256, 1), 256>>>(
        p_yh, w_out, out, b_out, x, 512, 512, 512, 512);
}

// round 16
// speedup vs baseline: 1.6102x; 1.0152x over previous
#include <cuda_runtime.h>
#include <cuda_bf16.h>
#include <stdint.h>
#include <math.h>

#define BB 4
#define NN 8192
#define DD 512
#define HH 8
#define DH 64
#define MM 256
#define BH 32
#define KS 16

__device__ __align__(16) __nv_bfloat16 g_xh[(size_t)BB*NN*DD];
__device__ __align__(16) __nv_bfloat16 g_qh[(size_t)BH*NN*DH];
__device__ __align__(16) __nv_bfloat16 g_kh[(size_t)BH*NN*DH];
__device__ __align__(16) __nv_bfloat16 g_vh[(size_t)BH*NN*DH];
__device__ __align__(16) float g_ql  [(size_t)BH*MM*DH];
__device__ __align__(16) float g_kl  [(size_t)BH*MM*DH];
__device__ __align__(16) float g_attn2[(size_t)BH*MM*MM];
__device__ __align__(16) float g_z   [(size_t)BH*MM*MM];
__device__ __align__(16) float g_z2  [(size_t)BH*MM*MM];
__device__ __align__(16) float g_xz  [(size_t)BH*MM*MM];
__device__ __align__(16) float g_t   [(size_t)BH*MM*MM];
__device__ __align__(16) float g_u   [(size_t)BH*MM*MM];
__device__ __align__(16) float g_p3  [(size_t)BH*KS*MM*DH];
__device__ __align__(16) float g_m3  [(size_t)BH*KS*MM];
__device__ __align__(16) float g_l3  [(size_t)BH*KS*MM];
__device__ __align__(16) float g_out3[(size_t)BH*MM*DH];
__device__ __align__(16) float g_wc  [(size_t)BH*MM*DH];
__device__ __align__(16) __nv_bfloat16 g_yh[(size_t)BB*NN*DD];
__device__ int g_maxA;
__device__ int g_maxB;
__device__ int g_barc[BH * 24];

static cudaStream_t g_s2;
static cudaEvent_t g_e1, g_e2;
static struct StreamInit {
    StreamInit() {
        cudaStreamCreateWithFlags(&g_s2, cudaStreamNonBlocking);
        cudaEventCreateWithFlags(&g_e1, cudaEventDisableTiming);
        cudaEventCreateWithFlags(&g_e2, cudaEventDisableTiming);
    }
} g_stream_init;

__device__ __forceinline__ uint32_t f2tf(float f) {
    uint32_t u;
    asm("cvt.rna.tf32.f32 %0, %1;" : "=r"(u) : "f"(f));
    return u;
}
__device__ __forceinline__ uint32_t f2bf2(float lo, float hi) {
    uint32_t r;
    asm("cvt.rn.bf16x2.f32 %0, %1, %2;" : "=r"(r) : "f"(hi), "f"(lo));
    return r;
}
__device__ __forceinline__ void mma8(float* d, const uint32_t* a, const uint32_t* b) {
    asm volatile(
        "mma.sync.aligned.m16n8k8.row.col.f32.tf32.tf32.f32 "
        "{%0,%1,%2,%3}, {%4,%5,%6,%7}, {%8,%9}, {%0,%1,%2,%3};"
        : "+f"(d[0]), "+f"(d[1]), "+f"(d[2]), "+f"(d[3])
        : "r"(a[0]), "r"(a[1]), "r"(a[2]), "r"(a[3]), "r"(b[0]), "r"(b[1]));
}
__device__ __forceinline__ void mma16(float* d, const uint32_t* a, const uint32_t* b) {
    asm volatile(
        "mma.sync.aligned.m16n8k16.row.col.f32.bf16.bf16.f32 "
        "{%0,%1,%2,%3}, {%4,%5,%6,%7}, {%8,%9}, {%0,%1,%2,%3};"
        : "+f"(d[0]), "+f"(d[1]), "+f"(d[2]), "+f"(d[3])
        : "r"(a[0]), "r"(a[1]), "r"(a[2]), "r"(a[3]), "r"(b[0]), "r"(b[1]));
}

// ---------------------------------------------------------------------------
// Flash split-KV attn3, warp-owned-row variant:
// each warp owns 16 q-rows x full 64-key tile; softmax = quad shuffles only;
// P stays in registers (C-frag == A-frag); K/V double-buffered, 1 sync/tile
// ---------------------------------------------------------------------------
__global__ __launch_bounds__(256) void flash3() {
    extern __shared__ char smraw[];
    uint32_t* Qs  = (uint32_t*)smraw;          // [32][136] staging (dead after init)
    uint32_t* Ksm = Qs + 32*136;               // [2][32][72]
    uint32_t* Vsm = Ksm + 2*32*72;             // [2][32][72]

    int tid = threadIdx.x, lane = tid & 31, warp = tid >> 5;
    int g = lane >> 2, q4 = lane & 3;
    int wr = warp * 16;                        // warp's 16-row slice
    int m0 = blockIdx.x * 128;
    int ksp = blockIdx.y, bh = blockIdx.z;

    // ---- stage Q (f32 -> bf16x2 k-major), then hoist A-frags to registers
    const float* Qg = g_ql + ((size_t)bh * MM + m0) * DH;
    #pragma unroll
    for (int c = 0; c < 8; c++) {
        int id = c * 256 + tid;
        int m = id >> 4, qq = id & 15;
        float4 v = *(const float4*)(Qg + (size_t)m * DH + qq * 4);
        Qs[(qq*2+0)*136 + m] = f2bf2(v.x, v.y);
        Qs[(qq*2+1)*136 + m] = f2bf2(v.z, v.w);
    }
    __syncthreads();
    uint32_t afq[4][4];
    #pragma unroll
    for (int kc = 0; kc < 4; kc++) {
        afq[kc][0] = Qs[(8*kc + q4    )*136 + wr + g];
        afq[kc][1] = Qs[(8*kc + q4    )*136 + wr + g + 8];
        afq[kc][2] = Qs[(8*kc + q4 + 4)*136 + wr + g];
        afq[kc][3] = Qs[(8*kc + q4 + 4)*136 + wr + g + 8];
    }

    float mrun0 = -1e30f, mrun1 = -1e30f, lrun0 = 0.f, lrun1 = 0.f;
    float acc[8][4];
    #pragma unroll
    for (int i = 0; i < 8; i++)
        #pragma unroll
        for (int r = 0; r < 4; r++) acc[i][r] = 0.f;

    const __nv_bfloat16* Kg = g_kh + ((size_t)bh * NN + ksp * 512) * DH;
    const __nv_bfloat16* Vg = g_vh + ((size_t)bh * NN + ksp * 512) * DH;

    auto loadKV = [&](int t, int buf) {
        uint32_t* Kb = Ksm + buf * 32*72;
        uint32_t* Vb = Vsm + buf * 32*72;
        #pragma unroll
        for (int c = 0; c < 2; c++) {
            int id = c * 256 + tid;
            int n = id >> 3, qq = id & 7;
            uint4 v = *(const uint4*)(Kg + (size_t)(t*64 + n) * DH + qq * 8);
            Kb[(qq*4+0)*72 + n] = v.x; Kb[(qq*4+1)*72 + n] = v.y;
            Kb[(qq*4+2)*72 + n] = v.z; Kb[(qq*4+3)*72 + n] = v.w;
        }
        #pragma unroll
        for (int c = 0; c < 2; c++) {
            int id = c * 256 + tid;
            int kp = id >> 4, qg = id & 15;
            uint2 a = *(const uint2*)(Vg + (size_t)(t*64 + 2*kp    ) * DH + qg * 4);
            uint2 b = *(const uint2*)(Vg + (size_t)(t*64 + 2*kp + 1) * DH + qg * 4);
            Vb[kp*72 + qg*4+0] = __byte_perm(a.x, b.x, 0x5410);
            Vb[kp*72 + qg*4+1] = __byte_perm(a.x, b.x, 0x7632);
            Vb[kp*72 + qg*4+2] = __byte_perm(a.y, b.y, 0x5410);
            Vb[kp*72 + qg*4+3] = __byte_perm(a.y, b.y, 0x7632);
        }
    };

    loadKV(0, 0);
    __syncthreads();

    for (int t = 0; t < 8; t++) {
        int buf = t & 1;
        if (t < 7) loadKV(t + 1, 1 - buf);     // prefetch into other buffer
        const uint32_t* Kb = Ksm + buf * 32*72;
        const uint32_t* Vb = Vsm + buf * 32*72;

        // ---- S = Q @ K^T : 16 rows x 64 cols per warp
        float S[8][4];
        #pragma unroll
        for (int i = 0; i < 8; i++)
            #pragma unroll
            for (int r = 0; r < 4; r++) S[i][r] = 0.f;
        #pragma unroll
        for (int k2 = 0; k2 < 4; k2++) {
            #pragma unroll
            for (int nt = 0; nt < 8; nt++) {
                uint32_t bfr[2];
                bfr[0] = Kb[(8*k2 + q4    )*72 + nt*8 + g];
                bfr[1] = Kb[(8*k2 + q4 + 4)*72 + nt*8 + g];
                mma16(S[nt], afq[k2], bfr);
            }
        }

        // ---- online softmax, quad-local
        float m0v = -1e30f, m1v = -1e30f;
        #pragma unroll
        for (int nt = 0; nt < 8; nt++) {
            m0v = fmaxf(m0v, fmaxf(S[nt][0], S[nt][1]));
            m1v = fmaxf(m1v, fmaxf(S[nt][2], S[nt][3]));
        }
        #pragma unroll
        for (int o = 1; o < 4; o <<= 1) {
            m0v = fmaxf(m0v, __shfl_xor_sync(~0u, m0v, o));
            m1v = fmaxf(m1v, __shfl_xor_sync(~0u, m1v, o));
        }
        float mn0 = fmaxf(mrun0, m0v);
        float mn1 = fmaxf(mrun1, m1v);
        float sc0 = __expf(mrun0 - mn0);
        float sc1 = __expf(mrun1 - mn1);
        float s0 = 0.f, s1 = 0.f;
        #pragma unroll
        for (int nt = 0; nt < 8; nt++) {
            S[nt][0] = __expf(S[nt][0] - mn0);
            S[nt][1] = __expf(S[nt][1] - mn0);
            S[nt][2] = __expf(S[nt][2] - mn1);
            S[nt][3] = __expf(S[nt][3] - mn1);
            s0 += S[nt][0] + S[nt][1];
            s1 += S[nt][2] + S[nt][3];
        }
        #pragma unroll
        for (int o = 1; o < 4; o <<= 1) {
            s0 += __shfl_xor_sync(~0u, s0, o);
            s1 += __shfl_xor_sync(~0u, s1, o);
        }
        lrun0 = lrun0 * sc0 + s0;
        lrun1 = lrun1 * sc1 + s1;
        mrun0 = mn0;
        mrun1 = mn1;
        #pragma unroll
        for (int i = 0; i < 8; i++) {
            acc[i][0] *= sc0; acc[i][1] *= sc0;
            acc[i][2] *= sc1; acc[i][3] *= sc1;
        }

        // ---- acc += P @ V : P A-frags straight from S registers
        #pragma unroll
        for (int kc = 0; kc < 4; kc++) {
            uint32_t afp[4];
            afp[0] = f2bf2(S[2*kc  ][0], S[2*kc  ][1]);
            afp[1] = f2bf2(S[2*kc  ][2], S[2*kc  ][3]);
            afp[2] = f2bf2(S[2*kc+1][0], S[2*kc+1][1]);
            afp[3] = f2bf2(S[2*kc+1][2], S[2*kc+1][3]);
            #pragma unroll
            for (int nt = 0; nt < 8; nt++) {
                uint32_t bfr[2];
                bfr[0] = Vb[(8*kc + q4    )*72 + nt*8 + g];
                bfr[1] = Vb[(8*kc + q4 + 4)*72 + nt*8 + g];
                mma16(acc[nt], afp, bfr);
            }
        }
        __syncthreads();
    }

    // ---- epilogue: partials
    size_t ob = (size_t)(bh * KS + ksp) * MM + m0;
    int r0 = wr + g;
    #pragma unroll
    for (int nt = 0; nt < 8; nt++) {
        int c = nt * 8 + q4 * 2;
        *(float2*)(g_p3 + (ob + r0    )*DH + c) = make_float2(acc[nt][0], acc[nt][1]);
        *(float2*)(g_p3 + (ob + r0 + 8)*DH + c) = make_float2(acc[nt][2], acc[nt][3]);
    }
    if (q4 == 0) {
        g_m3[ob + r0]     = mrun0;
        g_m3[ob + r0 + 8] = mrun1;
        g_l3[ob + r0]     = lrun0;
        g_l3[ob + r0 + 8] = lrun1;
    }
}

__global__ __launch_bounds__(256) void combine3() {
    int warp = threadIdx.x >> 5, lane = threadIdx.x & 31;
    int rowg = blockIdx.x * 8 + warp;
    int bh = rowg >> 8, r = rowg & 255;
    size_t base = (size_t)(bh * KS) * MM + r;
    float mv = (lane < 16) ? g_m3[base + (size_t)lane * MM] : -1e30f;
    #pragma unroll
    for (int o = 16; o; o >>= 1) mv = fmaxf(mv, __shfl_xor_sync(~0u, mv, o));
    float M = mv;
    float lv = (lane < 16) ? g_l3[base + (size_t)lane * MM] *
                             __expf(g_m3[base + (size_t)lane * MM] - M) : 0.f;
    #pragma unroll
    for (int o = 16; o; o >>= 1) lv += __shfl_xor_sync(~0u, lv, o);
    float invL = 1.f / lv;
    float a0 = 0.f, a1 = 0.f;
    for (int kk = 0; kk < KS; kk++) {
        float w = __expf(g_m3[base + (size_t)kk * MM] - M);
        float2 p = *(const float2*)(g_p3 + (base + (size_t)kk * MM) * DH + lane * 2);
        a0 += p.x * w; a1 += p.y * w;
    }
    *(float2*)(g_out3 + ((size_t)bh * MM + r) * DH + lane * 2) =
        make_float2(a0 * invL, a1 * invL);
}

// ---------------------------------------------------------------------------
// TF32 128x128x16 device tile (persistent pinv) — unchanged
// ---------------------------------------------------------------------------
__device__ __forceinline__ void tc_tile(
    const float* Ab, const float* Bb, float* C, const float* X1,
    int N, int K, int lda, int ldb, long long cbase,
    float alpha, float beta, int m0, int n0,
    uint32_t (*As)[16][136], uint32_t (*Bs)[16][136])
{
    constexpr int BK = 16;
    int tid = threadIdx.x, lane = tid & 31, warp = tid >> 5;
    int wm0 = (warp >> 2) * 64;
    int wn0 = (warp & 3) * 32;
    float4 ra[2], rb[2];
    float acc[4][4][4];
    #pragma unroll
    for (int i = 0; i < 4; i++)
        #pragma unroll
        for (int j = 0; j < 4; j++)
            #pragma unroll
            for (int r = 0; r < 4; r++) acc[i][j][r] = 0.f;

    auto LOAD = [&](int kb) {
        #pragma unroll
        for (int c = 0; c < 2; c++) {
            int id = c * 256 + tid;
            int m = id >> 2, kq = id & 3;
            ra[c] = *(const float4*)(Ab + (size_t)(m0 + m) * lda + kb * BK + kq * 4);
        }
        #pragma unroll
        for (int c = 0; c < 2; c++) {
            int id = c * 256 + tid;
            int k = id >> 5, nq = id & 31;
            rb[c] = *(const float4*)(Bb + (size_t)(kb * BK + k) * ldb + n0 + nq * 4);
        }
    };
    auto COMMIT = [&](int bf) {
        #pragma unroll
        for (int c = 0; c < 2; c++) {
            int id = c * 256 + tid;
            int m = id >> 2, kq = id & 3;
            As[bf][kq*4+0][m] = f2tf(ra[c].x); As[bf][kq*4+1][m] = f2tf(ra[c].y);
            As[bf][kq*4+2][m] = f2tf(ra[c].z); As[bf][kq*4+3][m] = f2tf(ra[c].w);
        }
        #pragma unroll
        for (int c = 0; c < 2; c++) {
            int id = c * 256 + tid;
            int k = id >> 5, nq = id & 31;
            Bs[bf][k][nq*4+0] = f2tf(rb[c].x); Bs[bf][k][nq*4+1] = f2tf(rb[c].y);
            Bs[bf][k][nq*4+2] = f2tf(rb[c].z); Bs[bf][k][nq*4+3] = f2tf(rb[c].w);
        }
    };
    auto MMA = [&](int bf) {
        #pragma unroll
        for (int ks = 0; ks < 2; ks++) {
            uint32_t af[4][4], bfr[4][2];
            int kr = ks * 8 + (lane & 3);
            int mr = wm0 + (lane >> 2);
            #pragma unroll
            for (int mt = 0; mt < 4; mt++) {
                af[mt][0] = As[bf][kr    ][mr + mt*16];
                af[mt][1] = As[bf][kr    ][mr + mt*16 + 8];
                af[mt][2] = As[bf][kr + 4][mr + mt*16];
                af[mt][3] = As[bf][kr + 4][mr + mt*16 + 8];
            }
            int nr = wn0 + (lane >> 2);
            #pragma unroll
            for (int nt = 0; nt < 4; nt++) {
                bfr[nt][0] = Bs[bf][kr    ][nr + nt*8];
                bfr[nt][1] = Bs[bf][kr + 4][nr + nt*8];
            }
            #pragma unroll
            for (int mt = 0; mt < 4; mt++)
                #pragma unroll
                for (int nt = 0; nt < 4; nt++)
                    mma8(acc[mt][nt], af[mt], bfr[nt]);
        }
    };

    int nk = K / BK;
    LOAD(0); COMMIT(0);
    __syncthreads();
    for (int kb = 1; kb < nk; kb++) {
        LOAD(kb);
        MMA((kb - 1) & 1);
        COMMIT(kb & 1);
        __syncthreads();
    }
    MMA((nk - 1) & 1);

    #pragma unroll
    for (int mt = 0; mt < 4; mt++) {
        #pragma unroll
        for (int nt = 0; nt < 4; nt++) {
            int row = m0 + wm0 + mt * 16 + (lane >> 2);
            int col = n0 + wn0 + nt * 8 + (lane & 3) * 2;
            size_t r1 = cbase + (size_t)row * N + col;
            size_t r2 = cbase + (size_t)(row + 8) * N + col;
            float2 lo = make_float2(acc[mt][nt][0], acc[mt][nt][1]);
            float2 hi = make_float2(acc[mt][nt][2], acc[mt][nt][3]);
            float2 rv1 = make_float2(0.f, 0.f), rv2 = make_float2(0.f, 0.f);
            if (beta != 0.f) {
                rv1 = *(const float2*)(X1 + r1);
                rv2 = *(const float2*)(X1 + r2);
            }
            *(float2*)(C + r1) = make_float2(alpha*lo.x + beta*rv1.x, alpha*lo.y + beta*rv1.y);
            *(float2*)(C + r2) = make_float2(alpha*hi.x + beta*rv2.x, alpha*hi.y + beta*rv2.y);
        }
    }
}

__device__ __forceinline__ void gridbar(int bh, int i) {
    __syncthreads();
    if (threadIdx.x == 0) {
        int idx = bh * 24 + i;
        __threadfence();
        atomicAdd(&g_barc[idx], 1);
        while (((volatile int*)g_barc)[idx] < 4) { }
        __threadfence();
    }
    __syncthreads();
}

__global__ __launch_bounds__(256) void pinv_iters() {
    __shared__ uint32_t As[2][16][136];
    __shared__ uint32_t Bs[2][16][136];
    int m0 = blockIdx.y * 128, n0 = blockIdx.x * 128;
    int bh = blockIdx.z;
    long long base = (long long)bh * (MM * MM);
    float* zc = g_z;
    float* zn = g_z2;
    int bi = 0;
    #pragma unroll 1
    for (int it = 0; it < 6; it++) {
        tc_tile(g_attn2 + base, zc + base, g_xz, nullptr, MM, MM, MM, MM, base,
                1.f, 0.f, m0, n0, As, Bs);
        gridbar(bh, bi++);
        tc_tile(g_xz + base, g_xz + base, g_t, g_xz, MM, MM, MM, MM, base,
                -1.f, 7.f, m0, n0, As, Bs);
        gridbar(bh, bi++);
        tc_tile(g_xz + base, g_t + base, g_u, g_xz, MM, MM, MM, MM, base,
                -1.f, 15.f, m0, n0, As, Bs);
        gridbar(bh, bi++);
        tc_tile(zc + base, g_u + base, zn, zc, MM, MM, MM, MM, base,
                -0.25f, 3.25f, m0, n0, As, Bs);
        if (it < 5) gridbar(bh, bi++);
        float* tmp = zc; zc = zn; zn = tmp;
    }
}

// Wc = z_final(g_z) @ out3, tf32
__global__ __launch_bounds__(256) void wc_gemm() {
    __shared__ uint32_t As[2][16][136];
    __shared__ uint32_t Bs[2][16][136];
    constexpr int BK = 16;
    int tid = threadIdx.x, lane = tid & 31, warp = tid >> 5;
    int wm0 = (warp >> 2) * 64;
    int wn0 = (warp & 3) * 16;
    int m0 = blockIdx.y * 128;
    long long abase = (long long)blockIdx.z * (MM * MM);
    long long cbase = (long long)blockIdx.z * (MM * DH);
    const float* Ab = g_z + abase;
    const float* Bb = g_out3 + cbase;
    float4 ra[2];
    float4 rb;
    float acc[4][2][4];
    #pragma unroll
    for (int i = 0; i < 4; i++)
        #pragma unroll
        for (int j = 0; j < 2; j++)
            #pragma unroll
            for (int r = 0; r < 4; r++) acc[i][j][r] = 0.f;

    auto LOAD = [&](int kb) {
        #pragma unroll
        for (int c = 0; c < 2; c++) {
            int id = c * 256 + tid;
            int m = id >> 2, kq = id & 3;
            ra[c] = *(const float4*)(Ab + (size_t)(m0 + m) * MM + kb * BK + kq * 4);
        }
        {
            int k = tid >> 4, nq = tid & 15;
            rb = *(const float4*)(Bb + (size_t)(kb * BK + k) * DH + nq * 4);
        }
    };
    auto COMMIT = [&](int bf) {
        #pragma unroll
        for (int c = 0; c < 2; c++) {
            int id = c * 256 + tid;
            int m = id >> 2, kq = id & 3;
            As[bf][kq*4+0][m] = f2tf(ra[c].x); As[bf][kq*4+1][m] = f2tf(ra[c].y);
            As[bf][kq*4+2][m] = f2tf(ra[c].z); As[bf][kq*4+3][m] = f2tf(ra[c].w);
        }
        {
            int k = tid >> 4, nq = tid & 15;
            Bs[bf][k][nq*4+0] = f2tf(rb.x); Bs[bf][k][nq*4+1] = f2tf(rb.y);
            Bs[bf][k][nq*4+2] = f2tf(rb.z); Bs[bf][k][nq*4+3] = f2tf(rb.w);
        }
    };
    auto MMA = [&](int bf) {
        #pragma unroll
        for (int ks = 0; ks < 2; ks++) {
            uint32_t af[4][4], bfr[2][2];
            int kr = ks * 8 + (lane & 3);
            int mr = wm0 + (lane >> 2);
            #pragma unroll
            for (int mt = 0; mt < 4; mt++) {
                af[mt][0] = As[bf][kr    ][mr + mt*16];
                af[mt][1] = As[bf][kr    ][mr + mt*16 + 8];
                af[mt][2] = As[bf][kr + 4][mr + mt*16];
                af[mt][3] = As[bf][kr + 4][mr + mt*16 + 8];
            }
            int nr = wn0 + (lane >> 2);
            #pragma unroll
            for (int nt = 0; nt < 2; nt++) {
                bfr[nt][0] = Bs[bf][kr    ][nr + nt*8];
                bfr[nt][1] = Bs[bf][kr + 4][nr + nt*8];
            }
            #pragma unroll
            for (int mt = 0; mt < 4; mt++)
                #pragma unroll
                for (int nt = 0; nt < 2; nt++)
                    mma8(acc[mt][nt], af[mt], bfr[nt]);
        }
    };

    LOAD(0); COMMIT(0);
    __syncthreads();
    for (int kb = 1; kb < 16; kb++) {
        LOAD(kb);
        MMA((kb - 1) & 1);
        COMMIT(kb & 1);
        __syncthreads();
    }
    MMA(1);

    #pragma unroll
    for (int mt = 0; mt < 4; mt++) {
        #pragma unroll
        for (int nt = 0; nt < 2; nt++) {
            int row = m0 + wm0 + mt * 16 + (lane >> 2);
            int col = wn0 + nt * 8 + (lane & 3) * 2;
            *(float2*)(g_wc + cbase + (size_t)row * DH + col) =
                make_float2(acc[mt][nt][0], acc[mt][nt][1]);
            *(float2*)(g_wc + cbase + (size_t)(row + 8) * DH + col) =
                make_float2(acc[mt][nt][2], acc[mt][nt][3]);
        }
    }
}

// ---------------------------------------------------------------------------
// BF16 GEMM, A operand bf16 in gmem. EPI0: QKV scatter; EPI1: out+bias+x
// ---------------------------------------------------------------------------
template<int EPI, int BM, int BN, int BK>
__global__ __launch_bounds__(256) void bf_gemm(
    const __nv_bfloat16* __restrict__ Ah, const float* __restrict__ Bg,
    float* __restrict__ C, const float* __restrict__ X1, const float* __restrict__ X2,
    int N, int K, int lda, int ldb)
{
    constexpr int PA = BM + 8, PB = BN + 8;
    constexpr int MT = (BM / 2) / 16;
    constexpr int NT = (BN / 4) / 8;
    constexpr int KP = BK / 2;
    constexpr int RAH = (BM * BK) / 2048;
    constexpr int RBN = (KP * (BN / 4)) / 256;
    __shared__ uint32_t As[2][KP][PA];
    __shared__ uint32_t Bs[2][KP][PB];
    uint4  rah[RAH];
    float4 rb0[RBN], rb1[RBN];

    int tid = threadIdx.x, lane = tid & 31, warp = tid >> 5;
    int wm0 = (warp >> 2) * (BM / 2);
    int wn0 = (warp & 3) * (BN / 4);
    int m0 = blockIdx.y * BM, n0 = blockIdx.x * BN;

    float acc[MT][NT][4];
    #pragma unroll
    for (int i = 0; i < MT; i++)
        #pragma unroll
        for (int j = 0; j < NT; j++)
            #pragma unroll
            for (int r = 0; r < 4; r++) acc[i][j][r] = 0.f;

    auto LOAD = [&](int kb) {
        #pragma unroll
        for (int c = 0; c < RAH; c++) {
            int id = c * 256 + tid;
            int m = id / (BK / 8), kq = id % (BK / 8);
            rah[c] = *(const uint4*)(Ah + (size_t)(m0 + m) * lda + kb * BK + kq * 8);
        }
        #pragma unroll
        for (int c = 0; c < RBN; c++) {
            int id = c * 256 + tid;
            int kp = id / (BN / 4), nq = id % (BN / 4);
            rb0[c] = *(const float4*)(Bg + (size_t)(kb*BK + 2*kp    ) * ldb + n0 + nq * 4);
            rb1[c] = *(const float4*)(Bg + (size_t)(kb*BK + 2*kp + 1) * ldb + n0 + nq * 4);
        }
    };
    auto COMMIT = [&](int bf) {
        #pragma unroll
        for (int c = 0; c < RAH; c++) {
            int id = c * 256 + tid;
            int m = id / (BK / 8), kq = id % (BK / 8);
            As[bf][kq*4+0][m] = rah[c].x; As[bf][kq*4+1][m] = rah[c].y;
            As[bf][kq*4+2][m] = rah[c].z; As[bf][kq*4+3][m] = rah[c].w;
        }
        #pragma unroll
        for (int c = 0; c < RBN; c++) {
            int id = c * 256 + tid;
            int kp = id / (BN / 4), nq = id % (BN / 4);
            Bs[bf][kp][nq*4+0] = f2bf2(rb0[c].x, rb1[c].x);
            Bs[bf][kp][nq*4+1] = f2bf2(rb0[c].y, rb1[c].y);
            Bs[bf][kp][nq*4+2] = f2bf2(rb0[c].z, rb1[c].z);
            Bs[bf][kp][nq*4+3] = f2bf2(rb0[c].w, rb1[c].w);
        }
    };
    auto MMA = [&](int bf) {
        #pragma unroll
        for (int ks = 0; ks < BK / 16; ks++) {
            uint32_t af[MT][4], bfr[NT][2];
            int kr = ks * 8 + (lane & 3);
            int mr = wm0 + (lane >> 2);
            #pragma unroll
            for (int mt = 0; mt < MT; mt++) {
                af[mt][0] = As[bf][kr    ][mr + mt*16];
                af[mt][1] = As[bf][kr    ][mr + mt*16 + 8];
                af[mt][2] = As[bf][kr + 4][mr + mt*16];
                af[mt][3] = As[bf][kr + 4][mr + mt*16 + 8];
            }
            int nr = wn0 + (lane >> 2);
            #pragma unroll
            for (int nt = 0; nt < NT; nt++) {
                bfr[nt][0] = Bs[bf][kr    ][nr + nt*8];
                bfr[nt][1] = Bs[bf][kr + 4][nr + nt*8];
            }
            #pragma unroll
            for (int mt = 0; mt < MT; mt++)
                #pragma unroll
                for (int nt = 0; nt < NT; nt++)
                    mma16(acc[mt][nt], af[mt], bfr[nt]);
        }
    };

    int nk = K / BK;
    LOAD(0); COMMIT(0);
    __syncthreads();
    for (int kb = 1; kb < nk; kb++) {
        LOAD(kb);
        MMA((kb - 1) & 1);
        COMMIT(kb & 1);
        __syncthreads();
    }
    MMA((nk - 1) & 1);

    #pragma unroll
    for (int mt = 0; mt < MT; mt++) {
        #pragma unroll
        for (int nt = 0; nt < NT; nt++) {
            int row = m0 + wm0 + mt * 16 + (lane >> 2);
            int col = n0 + wn0 + nt * 8 + (lane & 3) * 2;
            float2 lo = make_float2(acc[mt][nt][0], acc[mt][nt][1]);
            float2 hi = make_float2(acc[mt][nt][2], acc[mt][nt][3]);
            if constexpr (EPI == 0) {
                int which = col >> 9, inner = col & 511;
                int h = inner >> 6, d = inner & 63;
                __nv_bfloat16* dst = which == 0 ? g_qh : (which == 1 ? g_kh : g_vh);
                float s = (which == 0) ? 0.125f : 1.f;
                int bq = row >> 13, n = row & (NN - 1);
                *(uint32_t*)(dst + (((size_t)(bq*HH+h))*NN + n    )*DH + d) = f2bf2(lo.x*s, lo.y*s);
                *(uint32_t*)(dst + (((size_t)(bq*HH+h))*NN + n + 8)*DH + d) = f2bf2(hi.x*s, hi.y*s);
            } else if constexpr (EPI == 1) {
                float2 bv = *(const float2*)(X1 + col);
                size_t r1 = (size_t)row * DD + col, r2 = (size_t)(row + 8) * DD + col;
                float2 x1 = *(const float2*)(X2 + r1);
                float2 x2 = *(const float2*)(X2 + r2);
                *(float2*)(C + r1) = make_float2(lo.x + bv.x + x1.x, lo.y + bv.y + x1.y);
                *(float2*)(C + r2) = make_float2(hi.x + bv.x + x2.x, hi.y + bv.y + x2.y);
            }
        }
    }
}

// ---------------------------------------------------------------------------
// Fused attn1 + depthwise conv: y(bf16) = conv33(v) + softmax(q @ kl^T) @ Wc
// ---------------------------------------------------------------------------
__global__ __launch_bounds__(256) void attn1_fused(const float* __restrict__ res_w) {
    extern __shared__ char smraw[];
    uint32_t* As  = (uint32_t*)smraw;
    uint32_t* Bs  = As + 16*72;
    uint32_t* Ps  = Bs + 16*264;
    uint32_t* Wcs = Ps + 128*72;
    float* rmax = (float*)(Wcs + 128*72);
    float* rsum = rmax + 320;
    float* sw   = rsum + 320;
    uint32_t* Vw = As;

    int tid = threadIdx.x, lane = tid & 31, warp = tid >> 5;
    int g = lane >> 2, q4 = lane & 3;
    int bh = blockIdx.y;
    int b = bh >> 3, h = bh & 7;
    int m0 = blockIdx.x * 64;
    const __nv_bfloat16* Ab = g_qh + ((size_t)bh * NN + m0) * DH;
    const float* Bb = g_kl + (size_t)bh * MM * DH;
    const float* Wg = g_wc + (size_t)bh * MM * DH;
    const __nv_bfloat16* vb = g_vh + (size_t)bh * NN * DH;

    if (tid < 33) sw[tid] = res_w[h * 33 + tid];

    #pragma unroll
    for (int c = 0; c < 8; c++) {
        int id = c * 256 + tid;
        int kp = id >> 4, n4 = id & 15;
        float4 lo = *(const float4*)(Wg + (size_t)(2*kp    ) * DH + n4 * 4);
        float4 hi = *(const float4*)(Wg + (size_t)(2*kp + 1) * DH + n4 * 4);
        Wcs[kp*72 + n4*4+0] = f2bf2(lo.x, hi.x);
        Wcs[kp*72 + n4*4+1] = f2bf2(lo.y, hi.y);
        Wcs[kp*72 + n4*4+2] = f2bf2(lo.z, hi.z);
        Wcs[kp*72 + n4*4+3] = f2bf2(lo.w, hi.w);
    }

    int wm0q = (warp >> 2) * 32;
    int wn0q = (warp & 3) * 64;
    int wnq = warp & 3;
    float acc[2][8][4];
    #pragma unroll
    for (int i = 0; i < 2; i++)
        #pragma unroll
        for (int j = 0; j < 8; j++)
            #pragma unroll
            for (int r = 0; r < 4; r++) acc[i][j][r] = 0.f;

    for (int k0 = 0; k0 < 64; k0 += 32) {
        {
            int m = tid >> 2, kq = tid & 3;
            uint4 v = *(const uint4*)(Ab + (size_t)m * DH + k0 + kq * 8);
            As[(kq*4+0)*72 + m] = v.x; As[(kq*4+1)*72 + m] = v.y;
            As[(kq*4+2)*72 + m] = v.z; As[(kq*4+3)*72 + m] = v.w;
        }
        #pragma unroll
        for (int c = 0; c < 8; c++) {
            int id = c * 256 + tid;
            int n = id >> 3, kq = id & 7;
            float4 v = *(const float4*)(Bb + (size_t)n * DH + k0 + kq * 4);
            Bs[(kq*2+0)*264 + n] = f2bf2(v.x, v.y);
            Bs[(kq*2+1)*264 + n] = f2bf2(v.z, v.w);
        }
        __syncthreads();
        #pragma unroll
        for (int ks = 0; ks < 2; ks++) {
            uint32_t af[2][4], bfr[8][2];
            int kr = ks * 8 + q4;
            int mr = wm0q + g;
            #pragma unroll
            for (int mt = 0; mt < 2; mt++) {
                af[mt][0] = As[kr*72 + mr + mt*16];
                af[mt][1] = As[kr*72 + mr + mt*16 + 8];
                af[mt][2] = As[(kr+4)*72 + mr + mt*16];
                af[mt][3] = As[(kr+4)*72 + mr + mt*16 + 8];
            }
            int nr = wn0q + g;
            #pragma unroll
            for (int nt = 0; nt < 8; nt++) {
                bfr[nt][0] = Bs[kr*264 + nr + nt*8];
                bfr[nt][1] = Bs[(kr+4)*264 + nr + nt*8];
            }
            #pragma unroll
            for (int mt = 0; mt < 2; mt++)
                #pragma unroll
                for (int nt = 0; nt < 8; nt++)
                    mma16(acc[mt][nt], af[mt], bfr[nt]);
        }
        __syncthreads();
    }

    #pragma unroll
    for (int c = 0; c < 6; c++) {
        int id = c * 256 + tid;
        int row = id >> 4, up = id & 15;
        int tok = m0 - 16 + row;
        uint2 u = make_uint2(0u, 0u);
        if (tok >= 0 && tok < NN)
            u = *(const uint2*)(vb + (size_t)tok * DH + up * 4);
        Vw[row*33 + up*2]     = u.x;
        Vw[row*33 + up*2 + 1] = u.y;
    }

    #pragma unroll
    for (int mt = 0; mt < 2; mt++) {
        int r0 = wm0q + mt * 16 + g;
        float m0v = -1e30f, m1v = -1e30f;
        #pragma unroll
        for (int nt = 0; nt < 8; nt++) {
            m0v = fmaxf(m0v, fmaxf(acc[mt][nt][0], acc[mt][nt][1]));
            m1v = fmaxf(m1v, fmaxf(acc[mt][nt][2], acc[mt][nt][3]));
        }
        #pragma unroll
        for (int o = 1; o < 4; o <<= 1) {
            m0v = fmaxf(m0v, __shfl_xor_sync(~0u, m0v, o));
            m1v = fmaxf(m1v, __shfl_xor_sync(~0u, m1v, o));
        }
        if (q4 == 0) { rmax[r0*5 + wnq] = m0v; rmax[(r0+8)*5 + wnq] = m1v; }
    }
    __syncthreads();
    #pragma unroll
    for (int mt = 0; mt < 2; mt++) {
        int r0 = wm0q + mt * 16 + g;
        float M0 = fmaxf(fmaxf(rmax[r0*5+0], rmax[r0*5+1]), fmaxf(rmax[r0*5+2], rmax[r0*5+3]));
        float M1 = fmaxf(fmaxf(rmax[(r0+8)*5+0], rmax[(r0+8)*5+1]),
                         fmaxf(rmax[(r0+8)*5+2], rmax[(r0+8)*5+3]));
        float s0 = 0.f, s1 = 0.f;
        #pragma unroll
        for (int nt = 0; nt < 8; nt++) {
            acc[mt][nt][0] = __expf(acc[mt][nt][0] - M0);
            acc[mt][nt][1] = __expf(acc[mt][nt][1] - M0);
            acc[mt][nt][2] = __expf(acc[mt][nt][2] - M1);
            acc[mt][nt][3] = __expf(acc[mt][nt][3] - M1);
            s0 += acc[mt][nt][0] + acc[mt][nt][1];
            s1 += acc[mt][nt][2] + acc[mt][nt][3];
        }
        #pragma unroll
        for (int o = 1; o < 4; o <<= 1) {
            s0 += __shfl_xor_sync(~0u, s0, o);
            s1 += __shfl_xor_sync(~0u, s1, o);
        }
        if (q4 == 0) { rsum[r0*5 + wnq] = s0; rsum[(r0+8)*5 + wnq] = s1; }
    }
    __syncthreads();
    #pragma unroll
    for (int mt = 0; mt < 2; mt++) {
        int r0 = wm0q + mt * 16 + g, r1 = r0 + 8;
        float i0 = 1.f / (rsum[r0*5+0] + rsum[r0*5+1] + rsum[r0*5+2] + rsum[r0*5+3]);
        float i1 = 1.f / (rsum[r1*5+0] + rsum[r1*5+1] + rsum[r1*5+2] + rsum[r1*5+3]);
        #pragma unroll
        for (int nt = 0; nt < 8; nt++) {
            int kp = (wn0q >> 1) + nt * 4 + q4;
            Ps[kp*72 + r0] = f2bf2(acc[mt][nt][0] * i0, acc[mt][nt][1] * i0);
            Ps[kp*72 + r1] = f2bf2(acc[mt][nt][2] * i1, acc[mt][nt][3] * i1);
        }
    }
    __syncthreads();

    int wm0p = (warp >> 2) * 32;
    int wn0p = (warp & 3) * 16;
    float yacc[2][2][4];
    #pragma unroll
    for (int i = 0; i < 2; i++)
        #pragma unroll
        for (int j = 0; j < 2; j++)
            #pragma unroll
            for (int r = 0; r < 4; r++) yacc[i][j][r] = 0.f;
    #pragma unroll
    for (int kc = 0; kc < 16; kc++) {
        int kr = kc * 8 + q4;
        uint32_t af[2][4], bfr[2][2];
        int mr = wm0p + g;
        #pragma unroll
        for (int mt = 0; mt < 2; mt++) {
            af[mt][0] = Ps[kr*72 + mr + mt*16];
            af[mt][1] = Ps[kr*72 + mr + mt*16 + 8];
            af[mt][2] = Ps[(kr+4)*72 + mr + mt*16];
            af[mt][3] = Ps[(kr+4)*72 + mr + mt*16 + 8];
        }
        int nr = wn0p + g;
        #pragma unroll
        for (int nt = 0; nt < 2; nt++) {
            bfr[nt][0] = Wcs[kr*72 + nr + nt*8];
            bfr[nt][1] = Wcs[(kr+4)*72 + nr + nt*8];
        }
        #pragma unroll
        for (int mt = 0; mt < 2; mt++)
            #pragma unroll
            for (int nt = 0; nt < 2; nt++)
                mma16(yacc[mt][nt], af[mt], bfr[nt]);
    }
    #pragma unroll
    for (int mt = 0; mt < 2; mt++) {
        #pragma unroll
        for (int nt = 0; nt < 2; nt++) {
            int rl = wm0p + mt * 16 + g;
            int col = wn0p + nt * 8 + q4 * 2;
            int cp = col >> 1;
            float c00 = 0.f, c01 = 0.f, c10 = 0.f, c11 = 0.f;
            #pragma unroll
            for (int j = 0; j < 33; j++) {
                float w = sw[j];
                float2 f0 = __bfloat1622float2(
                    *(const __nv_bfloat162*)&Vw[(rl + j) * 33 + cp]);
                float2 f1 = __bfloat1622float2(
                    *(const __nv_bfloat162*)&Vw[(rl + 8 + j) * 33 + cp]);
                c00 += w * f0.x; c01 += w * f0.y;
                c10 += w * f1.x; c11 += w * f1.y;
            }
            int row = m0 + rl;
            size_t r1 = ((size_t)b * NN + row    ) * DD + h * 64 + col;
            size_t r2 = ((size_t)b * NN + row + 8) * DD + h * 64 + col;
            *(uint32_t*)(g_yh + r1) = f2bf2(c00 + yacc[mt][nt][0], c01 + yacc[mt][nt][1]);
            *(uint32_t*)(g_yh + r2) = f2bf2(c10 + yacc[mt][nt][2], c11 + yacc[mt][nt][3]);
        }
    }
}

// ---------------------------------------------------------------------------
// LN (bf16 out) / landmarks / sim2 / softmax256 / init / colrowmax / z0
// ---------------------------------------------------------------------------
__global__ __launch_bounds__(128) void ln_kernel(const float* __restrict__ x,
                                                 const float* __restrict__ w,
                                                 const float* __restrict__ bia) {
    int row = blockIdx.x, tid = threadIdx.x;
    const float4* xr = reinterpret_cast<const float4*>(x + (size_t)row * DD);
    float4 v = xr[tid];
    float s  = v.x + v.y + v.z + v.w;
    float sq = v.x*v.x + v.y*v.y + v.z*v.z + v.w*v.w;
    __shared__ float sm[4], sm2[4];
    #pragma unroll
    for (int o = 16; o > 0; o >>= 1) {
        s  += __shfl_down_sync(0xffffffffu, s,  o);
        sq += __shfl_down_sync(0xffffffffu, sq, o);
    }
    if ((tid & 31) == 0) { sm[tid >> 5] = s; sm2[tid >> 5] = sq; }
    __syncthreads();
    if (tid == 0) {
        float a = 0.f, b2 = 0.f;
        #pragma unroll
        for (int i = 0; i < 4; i++) { a += sm[i]; b2 += sm2[i]; }
        sm[0] = a; sm2[0] = b2;
    }
    __syncthreads();
    float mean = sm[0] * (1.f / 512.f);
    float var  = sm2[0] * (1.f / 512.f) - mean * mean;
    float rstd = rsqrtf(var + 1e-5f);
    float4 wv = reinterpret_cast<const float4*>(w)[tid];
    float4 bv = reinterpret_cast<const float4*>(bia)[tid];
    float ox = (v.x - mean) * rstd * wv.x + bv.x;
    float oy = (v.y - mean) * rstd * wv.y + bv.y;
    float oz = (v.z - mean) * rstd * wv.z + bv.z;
    float ow = (v.w - mean) * rstd * wv.w + bv.w;
    *(uint2*)(g_xh + (size_t)row * DD + tid * 4) =
        make_uint2(f2bf2(ox, oy), f2bf2(oz, ow));
}

__global__ void landmark_kernel() {
    int m = blockIdx.x, bh = blockIdx.y;
    int d = threadIdx.x;
    size_t base = ((size_t)bh * NN + (size_t)m * 32) * DH + d;
    float sq = 0.f, sk = 0.f;
    #pragma unroll
    for (int j = 0; j < 32; j++) {
        sq += __bfloat162float(g_qh[base + (size_t)j * DH]);
        sk += __bfloat162float(g_kh[base + (size_t)j * DH]);
    }
    size_t o = ((size_t)bh * MM + m) * DH + d;
    g_ql[o] = sq * (1.f / 32.f);
    g_kl[o] = sk * (1.f / 32.f);
}

__global__ __launch_bounds__(256) void gemm_sim2() {
    __shared__ float As[32][132];
    __shared__ float Bs[32][132];
    int bh = blockIdx.z;
    int n0 = blockIdx.x * 128, m0 = blockIdx.y * 128;
    const float* Ab = g_ql + ((size_t)bh * MM + m0) * DH;
    const float* Bb = g_kl + ((size_t)bh * MM + n0) * DH;
    float* Cb = g_attn2 + (size_t)bh * MM * MM;
    int tid = threadIdx.x;
    int tx = tid & 15, ty = tid >> 4;
    float acc[8][8] = {};
    for (int kk = 0; kk < 64; kk += 32) {
        #pragma unroll
        for (int u = 0; u < 4; u++) {
            int g = u * 256 + tid;
            int m = g >> 3, k4 = g & 7;
            float4 av = *(const float4*)(Ab + (size_t)m * DH + kk + k4 * 4);
            As[k4*4+0][m] = av.x; As[k4*4+1][m] = av.y;
            As[k4*4+2][m] = av.z; As[k4*4+3][m] = av.w;
        }
        #pragma unroll
        for (int u = 0; u < 4; u++) {
            int g = u * 256 + tid;
            int m = g >> 3, k4 = g & 7;
            float4 bv = *(const float4*)(Bb + (size_t)m * DH + kk + k4 * 4);
            Bs[k4*4+0][m] = bv.x; Bs[k4*4+1][m] = bv.y;
            Bs[k4*4+2][m] = bv.z; Bs[k4*4+3][m] = bv.w;
        }
        __syncthreads();
        #pragma unroll
        for (int k = 0; k < 32; k++) {
            float a[8], b[8];
            *(float4*)&a[0] = *(const float4*)&As[k][ty*8];
            *(float4*)&a[4] = *(const float4*)&As[k][ty*8+4];
            *(float4*)&b[0] = *(const float4*)&Bs[k][tx*8];
            *(float4*)&b[4] = *(const float4*)&Bs[k][tx*8+4];
            #pragma unroll
            for (int i = 0; i < 8; i++)
                #pragma unroll
                for (int j = 0; j < 8; j++)
                    acc[i][j] += a[i] * b[j];
        }
        __syncthreads();
    }
    #pragma unroll
    for (int i = 0; i < 8; i++) {
        size_t r = (size_t)(m0 + ty * 8 + i) * MM + n0 + tx * 8;
        *(float4*)(Cb + r)     = make_float4(acc[i][0], acc[i][1], acc[i][2], acc[i][3]);
        *(float4*)(Cb + r + 4) = make_float4(acc[i][4], acc[i][5], acc[i][6], acc[i][7]);
    }
}

__global__ __launch_bounds__(256) void softmax256() {
    int row = blockIdx.x, tid = threadIdx.x;
    float* p = g_attn2 + (size_t)row * MM;
    float v = p[tid];
    __shared__ float red[8];
    float m = v;
    #pragma unroll
    for (int o = 16; o; o >>= 1) m = fmaxf(m, __shfl_xor_sync(~0u, m, o));
    if ((tid & 31) == 0) red[tid >> 5] = m;
    __syncthreads();
    if (tid < 32) {
        float t = (tid < 8) ? red[tid] : -1e30f;
        #pragma unroll
        for (int o = 4; o; o >>= 1) t = fmaxf(t, __shfl_xor_sync(~0u, t, o));
        if (tid == 0) red[0] = t;
    }
    __syncthreads();
    float mx = red[0];
    __syncthreads();
    float e = __expf(v - mx);
    float s = e;
    #pragma unroll
    for (int o = 16; o; o >>= 1) s += __shfl_xor_sync(~0u, s, o);
    if ((tid & 31) == 0) red[tid >> 5] = s;
    __syncthreads();
    if (tid < 32) {
        float t = (tid < 8) ? red[tid] : 0.f;
        #pragma unroll
        for (int o = 4; o; o >>= 1) t += __shfl_xor_sync(~0u, t, o);
        if (tid == 0) red[0] = t;
    }
    __syncthreads();
    p[tid] = e / red[0];
}

__global__ void init_kernel() {
    g_maxA = 0; g_maxB = 0;
    for (int i = threadIdx.x; i < BH * 24; i += 256) g_barc[i] = 0;
}

__global__ __launch_bounds__(256) void colrowmax_kernel() {
    int bh = blockIdx.x, tid = threadIdx.x;
    const float* a = g_attn2 + (size_t)bh * MM * MM;
    float cs = 0.f, rs = 0.f;
    for (int m = 0; m < MM; m++) cs += fabsf(a[(size_t)m * MM + tid]);
    for (int n = 0; n < MM; n++) rs += fabsf(a[(size_t)tid * MM + n]);
    __shared__ float r1[8], r2[8];
    #pragma unroll
    for (int o = 16; o; o >>= 1) {
        cs = fmaxf(cs, __shfl_xor_sync(~0u, cs, o));
        rs = fmaxf(rs, __shfl_xor_sync(~0u, rs, o));
    }
    if ((tid & 31) == 0) { r1[tid >> 5] = cs; r2[tid >> 5] = rs; }
    __syncthreads();
    if (tid == 0) {
        float a1 = r1[0], a2 = r2[0];
        #pragma unroll
        for (int i = 1; i < 8; i++) { a1 = fmaxf(a1, r1[i]); a2 = fmaxf(a2, r2[i]); }
        atomicMax(&g_maxA, __float_as_int(a1));
        atomicMax(&g_maxB, __float_as_int(a2));
    }
}

__global__ __launch_bounds__(256) void z0_kernel() {
    int bh = blockIdx.z;
    int c0 = blockIdx.x * 32, r0 = blockIdx.y * 32;
    int tid = threadIdx.x;
    __shared__ float t[32][33];
    const float* a = g_attn2 + (size_t)bh * MM * MM;
    #pragma unroll
    for (int rr = 0; rr < 4; rr++) {
        int r = rr * 8 + (tid >> 5), c = tid & 31;
        t[r][c] = a[(size_t)(r0 + r) * MM + c0 + c];
    }
    __syncthreads();
    float s = 1.f / (__int_as_float(g_maxA) * __int_as_float(g_maxB));
    float* z = g_z + (size_t)bh * MM * MM;
    #pragma unroll
    for (int rr = 0; rr < 4; rr++) {
        int r = rr * 8 + (tid >> 5), c = tid & 31;
        z[(size_t)(c0 + r) * MM + r0 + c] = t[c][r] * s;
    }
}

// ---------------------------------------------------------------------------
// Launch: fork attn3 chain onto side stream, join before wc
// ---------------------------------------------------------------------------
extern "C" void kernel_launch(void* const* d_in, const int* in_sizes, int n_in,
                              void* d_out, int out_size) {
    const float* x     = (const float*)d_in[0];
    const float* ln_w  = (const float*)d_in[1];
    const float* ln_b  = (const float*)d_in[2];
    const float* w_qkv = (const float*)d_in[3];
    const float* w_out = (const float*)d_in[4];
    const float* b_out = (const float*)d_in[5];
    const float* res_w = (const float*)d_in[6];
    float* out = (float*)d_out;

    __nv_bfloat16 *p_xh, *p_yh;
    cudaGetSymbolAddress((void**)&p_xh, g_xh);
    cudaGetSymbolAddress((void**)&p_yh, g_yh);

    cudaFuncSetAttribute(flash3, cudaFuncAttributeMaxDynamicSharedMemorySize, 58368);
    cudaFuncSetAttribute(attn1_fused, cudaFuncAttributeMaxDynamicSharedMemorySize, 98304);

    ln_kernel<<<BB * NN, 128>>>(x, ln_w, ln_b);
    bf_gemm<0,128,128,32><<<dim3(12, 256, 1), 256>>>(
        p_xh, w_qkv, nullptr, nullptr, nullptr, 1536, 512, 512, 1536);
    landmark_kernel<<<dim3(MM, BH), 64>>>();

    cudaEventRecord(g_e1, 0);
    cudaStreamWaitEvent(g_s2, g_e1, 0);
    flash3<<<dim3(2, KS, BH), 256, 58368, g_s2>>>();
    combine3<<<1024, 256, 0, g_s2>>>();
    cudaEventRecord(g_e2, g_s2);

    gemm_sim2<<<dim3(2, 2, BH), 256>>>();
    softmax256<<<BH * MM, 256>>>();
    init_kernel<<<1, 256>>>();
    colrowmax_kernel<<<BH, 256>>>();
    z0_kernel<<<dim3(8, 8, BH), 256>>>();
    pinv_iters<<<dim3(2, 2, BH), 256>>>();

    cudaStreamWaitEvent(0, g_e2, 0);
    wc_gemm<<<dim3(1, 2, BH), 256>>>();

    attn1_fused<<<dim3(128, BH), 256, 98304>>>(res_w);

    bf_gemm<1,128,128,32><<<dim3(4, 256, 1), 256>>>(
        p_yh, w_out, out, b_out, x, 512, 512, 512, 512);
}